// round 9
// baseline (speedup 1.0000x reference)
#include <cuda_runtime.h>
#include <cuda_bf16.h>
#include <math.h>
#include <stdint.h>

#define SEQ 2048
#define HID 1024
#define NHEAD 16
#define HD 128
#define QDIM 512
#define NEXP 32
#define IDIM 1024
#define QKV_N 768
#define SCALE 0.08838834764831845f   // 1/sqrt(128)

// ------------------------- device scratch ----------------------------------
__device__ float g_qkv[SEQ*QKV_N];
__device__ float g_qproj[SEQ*NHEAD*HD];
__device__ float g_resid2[SEQ*HID];
__device__ float g_h2[SEQ*HID];
__device__ float2 g_cs[SEQ*64];

__device__ __nv_bfloat16 g_hnh[SEQ*HID],  g_hnl[SEQ*HID];
__device__ __nv_bfloat16 g_qnh[SEQ*QDIM], g_qnl[SEQ*QDIM];
__device__ __nv_bfloat16 g_qh[SEQ*2048],  g_ql[SEQ*2048];
__device__ __nv_bfloat16 g_kth[128*SEQ],  g_ktl[128*SEQ];   // transposed [d][token]
__device__ __nv_bfloat16 g_vh[SEQ*128],   g_vl[SEQ*128];
__device__ __nv_bfloat16 g_aoh[SEQ*2048], g_aol[SEQ*2048];
__device__ __nv_bfloat16 g_h2h[SEQ*HID],  g_h2l[SEQ*HID];
__device__ __nv_bfloat16 g_aseh[SEQ*IDIM],g_asel[SEQ*IDIM];
__device__ __nv_bfloat16 g_aceh[SEQ*3*IDIM], g_acel[SEQ*3*IDIM];

// pre-split dense weights (bf16 hi/lo)
__device__ __nv_bfloat16 g_wqkvh[HID*QKV_N],   g_wqkvl[HID*QKV_N];
__device__ __nv_bfloat16 g_wqh[QDIM*2048],     g_wql[QDIM*2048];
__device__ __nv_bfloat16 g_woh[2048*HID],      g_wol[2048*HID];
__device__ __nv_bfloat16 g_wguh[HID*2*IDIM],   g_wgul[HID*2*IDIM];
__device__ __nv_bfloat16 g_wdh[IDIM*HID],      g_wdl[IDIM*HID];

__device__ int   g_topi[SEQ*3];
__device__ float g_topw[SEQ*3];
__device__ int   g_cnt[NEXP];
__device__ int   g_off[NEXP];
__device__ int   g_fill[NEXP];
__device__ int   g_ptok[SEQ*3];
__device__ float g_pw[SEQ*3];

// ------------------------- helpers -----------------------------------------
__device__ __forceinline__ uint32_t s2u(const void* p) {
    uint32_t a;
    asm("{ .reg .u64 t; cvta.to.shared.u64 t, %1; cvt.u32.u64 %0, t; }" : "=r"(a) : "l"(p));
    return a;
}
__device__ __forceinline__ void ldsm4(uint32_t* r, uint32_t addr) {
    asm volatile("ldmatrix.sync.aligned.m8n8.x4.shared.b16 {%0,%1,%2,%3}, [%4];"
        : "=r"(r[0]), "=r"(r[1]), "=r"(r[2]), "=r"(r[3]) : "r"(addr));
}
__device__ __forceinline__ void ldsm4t(uint32_t* r, uint32_t addr) {
    asm volatile("ldmatrix.sync.aligned.m8n8.x4.trans.shared.b16 {%0,%1,%2,%3}, [%4];"
        : "=r"(r[0]), "=r"(r[1]), "=r"(r[2]), "=r"(r[3]) : "r"(addr));
}
__device__ __forceinline__ void mma16816(float* c, const uint32_t* a, uint32_t b0, uint32_t b1) {
    asm volatile("mma.sync.aligned.m16n8k16.row.col.f32.bf16.bf16.f32 "
        "{%0,%1,%2,%3}, {%4,%5,%6,%7}, {%8,%9}, {%0,%1,%2,%3};"
        : "+f"(c[0]), "+f"(c[1]), "+f"(c[2]), "+f"(c[3])
        : "r"(a[0]), "r"(a[1]), "r"(a[2]), "r"(a[3]), "r"(b0), "r"(b1));
}
__device__ __forceinline__ void cpa16(uint32_t dst, const void* src) {
    asm volatile("cp.async.cg.shared.global [%0], [%1], 16;" :: "r"(dst), "l"(src));
}
#define CPA_COMMIT() asm volatile("cp.async.commit_group;" ::: "memory")
#define CPA_WAIT0()  asm volatile("cp.async.wait_group 0;" ::: "memory")
#define CPA_WAIT1()  asm volatile("cp.async.wait_group 1;" ::: "memory")

__device__ __forceinline__ uint32_t pack_hi(float f0, float f1) {
    __nv_bfloat162 h = __floats2bfloat162_rn(f0, f1);
    return *(uint32_t*)&h;
}
__device__ __forceinline__ uint32_t pack_lo(float f0, float f1, uint32_t hibits) {
    __nv_bfloat162 h = *(__nv_bfloat162*)&hibits;
    __nv_bfloat162 l = __floats2bfloat162_rn(f0 - __bfloat162float(h.x),
                                             f1 - __bfloat162float(h.y));
    return *(uint32_t*)&l;
}
__device__ __forceinline__ void split2(float a, float b, uint32_t& hi, uint32_t& lo) {
    hi = pack_hi(a, b);
    lo = pack_lo(a, b, hi);
}
// FFMA-only exp (rel err ~4e-5), avoids MUFU
__device__ __forceinline__ float fexp(float x) {
    x = fminf(fmaxf(x, -80.f), 80.f);
    float y = x * 1.4426950408889634f;
    float n = rintf(y);
    float f = y - n;
    float p = fmaf(f, 0.009618130f, 0.055504110f);
    p = fmaf(p, f, 0.240226507f);
    p = fmaf(p, f, 0.693147181f);
    p = fmaf(p, f, 1.0f);
    return p * __int_as_float(((int)n + 127) << 23);
}

// weight pre-split: fp32 -> bf16 hi/lo
__global__ void split_w_k(const float* __restrict__ W,
                          __nv_bfloat16* __restrict__ Wh, __nv_bfloat16* __restrict__ Wl,
                          int n4)
{
    int i = blockIdx.x * 256 + threadIdx.x;
    if (i < n4) {
        float4 v = ((const float4*)W)[i];
        uint32_t h0, l0, h1, l1;
        split2(v.x, v.y, h0, l0);
        split2(v.z, v.w, h1, l1);
        ((uint2*)Wh)[i] = make_uint2(h0, h1);
        ((uint2*)Wl)[i] = make_uint2(l0, l1);
    }
}

// ------------------------- GEMM: 64-row tiles, 128 thr ----------------------
#define LDA 40
#define LDB 136
#define ASZ (64*LDA*2)           // 5120 bytes per A array
#define BSZ (32*LDB*2)           // 8704 bytes per B array
#define OFF_AH(b) ((b) * (2*ASZ))
#define OFF_AL(b) ((b) * (2*ASZ) + ASZ)
#define OFF_BH(b) (6*ASZ + (b) * (2*BSZ))
#define OFF_BL(b) (6*ASZ + (b) * (2*BSZ) + BSZ)
#define OFF_TOK   (6*ASZ + 6*BSZ)
#define SMEM_TOTAL_G (OFF_TOK + 64*4)

// MODE 0: plain  C = A@B (+add) fp32       (64 rows x 128 out cols / CTA)
// MODE 1: gated  Ch/Cl = split(silu(A@Bg)*(A@Bu))  (64 rows x 64 cols, up at +upOff)
// MODE 2: moe gathered gated -> split rows off+r
// MODE 3: moe scatter: C[tok] += w * (A@B)  fp32 atomic
// BSPLIT=1: B1/B2 are pre-split bf16 hi/lo (pure cp.async, 3-stage ring)
// BSPLIT=0: B1 is fp32, inline convert (2-stage)
template<int MODE, int BSPLIT>
__global__ __launch_bounds__(128, 2) void gemm_tc(
    const __nv_bfloat16* __restrict__ Ah, const __nv_bfloat16* __restrict__ Al,
    const void* __restrict__ B1, const void* __restrict__ B2,
    float* __restrict__ C, __nv_bfloat16* __restrict__ Ch, __nv_bfloat16* __restrict__ Cl,
    const float* __restrict__ add,
    int K, int lda, int ldb, int ldc, int upOff, size_t bStride)
{
    int cnt = 0, off = 0;
    size_t bOff = 0;
    if (MODE >= 2) {
        int e = blockIdx.z;
        cnt = g_cnt[e];
        if ((int)blockIdx.y * 64 >= cnt) return;
        off = g_off[e];
        bOff = bStride * e;
    }
    const int m0 = blockIdx.y * 64;
    const int nb = blockIdx.x * ((MODE == 1 || MODE == 2) ? 64 : 128);

    extern __shared__ __align__(16) char sm[];
    int* sTok = (int*)(sm + OFF_TOK);
    const uint32_t sb = s2u(sm);

    const int tid = threadIdx.x;
    const int wid = tid >> 5, lane = tid & 31;
    const int wm = wid >> 1, wn = wid & 1;

    if (MODE == 2 && tid < 64) {
        int gr = m0 + tid;
        sTok[tid] = (gr < cnt) ? g_ptok[off + gr] : 0;
    }
    __syncthreads();

    float acc[2][8][4] = {};
    const int lrow = lane & 15, lcol8 = (lane >> 4) * 8;
    const int nkt = K >> 5;

    // per-thread A cp.async indices: 2 segments (tid, tid+128); 256 segs total
    const int am0 = tid >> 2, aseg0 = (tid & 3);
    const int am1 = (tid + 128) >> 2, aseg1 = ((tid + 128) & 3);
    size_t arow0, arow1;
    {
        if (MODE == 2) {
            arow0 = (size_t)sTok[am0] * lda;
            arow1 = (size_t)sTok[am1] * lda;
        } else if (MODE == 3) {
            int r0 = (m0 + am0 < cnt) ? m0 + am0 : 0;
            int r1 = (m0 + am1 < cnt) ? m0 + am1 : 0;
            arow0 = (size_t)(off + r0) * lda;
            arow1 = (size_t)(off + r1) * lda;
        } else {
            arow0 = (size_t)(m0 + am0) * lda;
            arow1 = (size_t)(m0 + am1) * lda;
        }
    }
    const uint32_t adst0 = sb + am0 * (LDA*2) + aseg0 * 16;
    const uint32_t adst1 = sb + am1 * (LDA*2) + aseg1 * 16;
    const int aoff0 = aseg0 * 8, aoff1 = aseg1 * 8;

    if (BSPLIT) {
        // ============= pure cp.async path (dense weights pre-split) =========
        const __nv_bfloat16* Bh = (const __nv_bfloat16*)B1;
        const __nv_bfloat16* Bl = (const __nv_bfloat16*)B2;

        // B cp.async indexing: 4 segments of 8 cols per thread (512 total)
        uint32_t bdst[4]; size_t bsrc[4];
        #pragma unroll
        for (int it = 0; it < 4; it++) {
            int seg = tid + it * 128;
            int kk = seg >> 4, cs = (seg & 15) * 8;
            int col;
            if (MODE == 1) col = (cs < 64) ? nb + cs : upOff + nb + (cs - 64);
            else           col = nb + cs;
            bsrc[it] = (size_t)kk * ldb + col;
            bdst[it] = sb + kk * (LDB*2) + cs * 2;
        }

        auto issue = [&](int bf, int k0) {
            cpa16(adst0 + OFF_AH(bf), Ah + arow0 + k0 + aoff0);
            cpa16(adst0 + OFF_AL(bf), Al + arow0 + k0 + aoff0);
            cpa16(adst1 + OFF_AH(bf), Ah + arow1 + k0 + aoff1);
            cpa16(adst1 + OFF_AL(bf), Al + arow1 + k0 + aoff1);
            #pragma unroll
            for (int it = 0; it < 4; it++) {
                size_t s = bsrc[it] + (size_t)k0 * ldb;
                cpa16(bdst[it] + OFF_BH(bf), Bh + s);
                cpa16(bdst[it] + OFF_BL(bf), Bl + s);
            }
            CPA_COMMIT();
        };

        issue(0, 0);
        if (nkt > 1) issue(1, 32);

        int bf = 0;
        for (int c = 0; c < nkt; c++) {
            if (c + 1 < nkt) { CPA_WAIT1(); } else { CPA_WAIT0(); }
            __syncthreads();
            if (c + 2 < nkt) {
                int nb3 = bf + 2; if (nb3 >= 3) nb3 -= 3;
                issue(nb3, (c + 2) << 5);
            }
            const uint32_t uAh = sb + OFF_AH(bf), uAl = sb + OFF_AL(bf);
            const uint32_t uBh = sb + OFF_BH(bf), uBl = sb + OFF_BL(bf);
            #pragma unroll
            for (int ks = 0; ks < 2; ks++) {
                uint32_t ah[2][4], al[2][4];
                #pragma unroll
                for (int mf = 0; mf < 2; mf++) {
                    uint32_t ro = (uint32_t)((wm * 32 + mf * 16 + lrow) * LDA + ks * 16 + lcol8) * 2;
                    ldsm4(ah[mf], uAh + ro);
                    ldsm4(al[mf], uAl + ro);
                }
                #pragma unroll
                for (int nh = 0; nh < 4; nh++) {
                    uint32_t bh[4], bl[4];
                    uint32_t ro = (uint32_t)((ks * 16 + lrow) * LDB + wn * 64 + nh * 16 + lcol8) * 2;
                    ldsm4t(bh, uBh + ro);
                    ldsm4t(bl, uBl + ro);
                    #pragma unroll
                    for (int mf = 0; mf < 2; mf++)
                        #pragma unroll
                        for (int sub = 0; sub < 2; sub++) {
                            int nf = nh * 2 + sub;
                            mma16816(acc[mf][nf], ah[mf], bh[sub*2], bh[sub*2+1]);
                            mma16816(acc[mf][nf], ah[mf], bl[sub*2], bl[sub*2+1]);
                            mma16816(acc[mf][nf], al[mf], bh[sub*2], bh[sub*2+1]);
                        }
                }
            }
            bf++; if (bf >= 3) bf = 0;
        }
        __syncthreads();
    } else {
        // ============= fp32-B inline convert path (MoE) ======================
        const float* B = (const float*)B1 + bOff;
        int bcol[8]; size_t brow[8];
        #pragma unroll
        for (int it = 0; it < 8; it++) {
            int i = tid + it * 128;
            int kk = i >> 5;
            int n4 = (i & 31) << 2;
            int col;
            if (MODE == 2) col = (n4 < 64) ? nb + n4 : upOff + nb + (n4 - 64);
            else           col = nb + n4;
            bcol[it] = n4;
            brow[it] = (size_t)kk * ldb + col;
        }
        float4 br[8];
        {
            cpa16(adst0 + OFF_AH(0), Ah + arow0 + aoff0);
            cpa16(adst0 + OFF_AL(0), Al + arow0 + aoff0);
            cpa16(adst1 + OFF_AH(0), Ah + arow1 + aoff1);
            cpa16(adst1 + OFF_AL(0), Al + arow1 + aoff1);
            CPA_COMMIT();
            #pragma unroll
            for (int it = 0; it < 8; it++) br[it] = *(const float4*)(B + brow[it]);
            CPA_WAIT0();
            __syncthreads();
            #pragma unroll
            for (int it = 0; it < 8; it++) {
                int i = tid + it * 128;
                int kk = i >> 5;
                uint32_t h0, l0, h1, l1;
                split2(br[it].x, br[it].y, h0, l0);
                split2(br[it].z, br[it].w, h1, l1);
                uint32_t* ph = (uint32_t*)(sm + OFF_BH(0) + kk * (LDB*2) + bcol[it] * 2);
                uint32_t* pl = (uint32_t*)(sm + OFF_BL(0) + kk * (LDB*2) + bcol[it] * 2);
                ph[0] = h0; ph[1] = h1;
                pl[0] = l0; pl[1] = l1;
            }
            __syncthreads();
        }
        int p = 0;
        for (int c = 0; c < nkt; c++) {
            const int q = p ^ 1;
            const bool more = (c + 1 < nkt);
            if (more) {
                const int k1 = (c + 1) << 5;
                cpa16(adst0 + OFF_AH(q), Ah + arow0 + k1 + aoff0);
                cpa16(adst0 + OFF_AL(q), Al + arow0 + k1 + aoff0);
                cpa16(adst1 + OFF_AH(q), Ah + arow1 + k1 + aoff1);
                cpa16(adst1 + OFF_AL(q), Al + arow1 + k1 + aoff1);
                CPA_COMMIT();
                #pragma unroll
                for (int it = 0; it < 8; it++)
                    br[it] = *(const float4*)(B + (size_t)k1 * ldb + brow[it]);
            }
            const uint32_t uAh = sb + OFF_AH(p), uAl = sb + OFF_AL(p);
            const uint32_t uBh = sb + OFF_BH(p), uBl = sb + OFF_BL(p);
            #pragma unroll
            for (int ks = 0; ks < 2; ks++) {
                uint32_t ah[2][4], al[2][4];
                #pragma unroll
                for (int mf = 0; mf < 2; mf++) {
                    uint32_t ro = (uint32_t)((wm * 32 + mf * 16 + lrow) * LDA + ks * 16 + lcol8) * 2;
                    ldsm4(ah[mf], uAh + ro);
                    ldsm4(al[mf], uAl + ro);
                }
                #pragma unroll
                for (int nh = 0; nh < 4; nh++) {
                    uint32_t bh[4], bl[4];
                    uint32_t ro = (uint32_t)((ks * 16 + lrow) * LDB + wn * 64 + nh * 16 + lcol8) * 2;
                    ldsm4t(bh, uBh + ro);
                    ldsm4t(bl, uBl + ro);
                    #pragma unroll
                    for (int mf = 0; mf < 2; mf++)
                        #pragma unroll
                        for (int sub = 0; sub < 2; sub++) {
                            int nf = nh * 2 + sub;
                            mma16816(acc[mf][nf], ah[mf], bh[sub*2], bh[sub*2+1]);
                            mma16816(acc[mf][nf], ah[mf], bl[sub*2], bl[sub*2+1]);
                            mma16816(acc[mf][nf], al[mf], bh[sub*2], bh[sub*2+1]);
                        }
                }
            }
            if (more) {
                #pragma unroll
                for (int it = 0; it < 8; it++) {
                    int i = tid + it * 128;
                    int kk = i >> 5;
                    uint32_t h0, l0, h1, l1;
                    split2(br[it].x, br[it].y, h0, l0);
                    split2(br[it].z, br[it].w, h1, l1);
                    uint32_t* ph = (uint32_t*)(sm + OFF_BH(q) + kk * (LDB*2) + bcol[it] * 2);
                    uint32_t* pl = (uint32_t*)(sm + OFF_BL(q) + kk * (LDB*2) + bcol[it] * 2);
                    ph[0] = h0; ph[1] = h1;
                    pl[0] = l0; pl[1] = l1;
                }
                CPA_WAIT0();
                __syncthreads();
            }
            p = q;
        }
        __syncthreads();
    }

    // ---- epilogue ----
    const int r4 = lane >> 2, c2 = (lane & 3) * 2;
    if (MODE == 0) {
        #pragma unroll
        for (int mf = 0; mf < 2; mf++) {
            #pragma unroll
            for (int nf = 0; nf < 8; nf++) {
                int col = nb + wn * 64 + nf * 8 + c2;
                size_t r1 = (size_t)(m0 + wm * 32 + mf * 16 + r4);
                size_t r2 = r1 + 8;
                float v0 = acc[mf][nf][0], v1 = acc[mf][nf][1];
                float v2 = acc[mf][nf][2], v3 = acc[mf][nf][3];
                if (add) {
                    v0 += add[r1 * ldc + col]; v1 += add[r1 * ldc + col + 1];
                    v2 += add[r2 * ldc + col]; v3 += add[r2 * ldc + col + 1];
                }
                *(float2*)(C + r1 * ldc + col) = make_float2(v0, v1);
                *(float2*)(C + r2 * ldc + col) = make_float2(v2, v3);
            }
        }
    } else if (MODE == 1 || MODE == 2) {
        float* sG = (float*)sm;              // [64][65]
        if (wn == 0) {                        // gate cols 0..63
            #pragma unroll
            for (int mf = 0; mf < 2; mf++)
                #pragma unroll
                for (int nf = 0; nf < 8; nf++) {
                    int col = nf * 8 + c2;
                    int rr1 = wm * 32 + mf * 16 + r4, rr2 = rr1 + 8;
                    sG[rr1 * 65 + col]     = acc[mf][nf][0];
                    sG[rr1 * 65 + col + 1] = acc[mf][nf][1];
                    sG[rr2 * 65 + col]     = acc[mf][nf][2];
                    sG[rr2 * 65 + col + 1] = acc[mf][nf][3];
                }
        }
        __syncthreads();
        if (wn == 1) {                        // up cols -> combine
            #pragma unroll
            for (int mf = 0; mf < 2; mf++)
                #pragma unroll
                for (int nf = 0; nf < 8; nf++) {
                    int col = nf * 8 + c2;
                    int rr1 = wm * 32 + mf * 16 + r4;
                    #pragma unroll
                    for (int half = 0; half < 2; half++) {
                        int rr = rr1 + half * 8;
                        bool ok = (MODE == 1) || (m0 + rr < cnt);
                        if (ok) {
                            size_t row = (MODE == 1) ? (size_t)(m0 + rr) : (size_t)(off + m0 + rr);
                            float g0 = sG[rr * 65 + col], g1 = sG[rr * 65 + col + 1];
                            float u0 = acc[mf][nf][half * 2], u1 = acc[mf][nf][half * 2 + 1];
                            float o0 = g0 / (1.f + fexp(-g0)) * u0;
                            float o1 = g1 / (1.f + fexp(-g1)) * u1;
                            uint32_t hi, lo;
                            split2(o0, o1, hi, lo);
                            *(uint32_t*)(Ch + row * ldc + nb + col) = hi;
                            *(uint32_t*)(Cl + row * ldc + nb + col) = lo;
                        }
                    }
                }
        }
    } else {  // MODE 3
        #pragma unroll
        for (int mf = 0; mf < 2; mf++) {
            int rr1 = wm * 32 + mf * 16 + r4;
            #pragma unroll
            for (int half = 0; half < 2; half++) {
                int rr = rr1 + half * 8;
                if (m0 + rr < cnt) {
                    int tok = g_ptok[off + m0 + rr];
                    float w = g_pw[off + m0 + rr];
                    float* dst = C + (size_t)tok * ldc;
                    #pragma unroll
                    for (int nf = 0; nf < 8; nf++) {
                        int col = nb + wn * 64 + nf * 8 + c2;
                        atomicAdd(dst + col,     w * acc[mf][nf][half * 2]);
                        atomicAdd(dst + col + 1, w * acc[mf][nf][half * 2 + 1]);
                    }
                }
            }
        }
    }
}

// ------------------------- small kernels ------------------------------------
__global__ void zero_counts_k() {
    if (threadIdx.x < NEXP) g_cnt[threadIdx.x] = 0;
}

__global__ void cs_prep_k(const int* __restrict__ pos) {
    int t = blockIdx.x, i = threadIdx.x;   // 64 threads
    double e = exp(-((double)(2 * i) / 128.0) * log(500000.0));
    float f = (float)pos[t] * (float)e;
    float sn, cs; sincosf(f, &sn, &cs);
    g_cs[t * 64 + i] = make_float2(cs, sn);
}

// rmsnorm: writes optional fp32 y + optional bf16 split yh/yl
__global__ void rmsnorm_k(const float* __restrict__ x, const float* __restrict__ w,
                          float* __restrict__ y,
                          __nv_bfloat16* __restrict__ yh, __nv_bfloat16* __restrict__ yl,
                          int cols, int ldx, int ldy)
{
    int row = blockIdx.x;
    const float* xr = x + (size_t)row * ldx;
    float ss = 0.f;
    for (int c = threadIdx.x; c < cols; c += 256) { float v = xr[c]; ss = fmaf(v, v, ss); }
    __shared__ float wred[8];
    #pragma unroll
    for (int d = 16; d; d >>= 1) ss += __shfl_xor_sync(0xffffffffu, ss, d);
    if ((threadIdx.x & 31) == 0) wred[threadIdx.x >> 5] = ss;
    __syncthreads();
    if (threadIdx.x < 32) {
        float v = (threadIdx.x < 8) ? wred[threadIdx.x] : 0.f;
        #pragma unroll
        for (int d = 4; d; d >>= 1) v += __shfl_xor_sync(0xffffffffu, v, d);
        if (threadIdx.x == 0) wred[0] = v;
    }
    __syncthreads();
    float r = rsqrtf(wred[0] / (float)cols + 1e-5f);
    for (int c = threadIdx.x; c < cols; c += 256) {
        float v = xr[c] * r * w[c];
        if (y) y[(size_t)row * ldy + c] = v;
        if (yh) {
            __nv_bfloat16 h = __float2bfloat16_rn(v);
            yh[(size_t)row * ldy + c] = h;
            yl[(size_t)row * ldy + c] = __float2bfloat16_rn(v - __bfloat162float(h));
        }
    }
}

// rope on q (reads qproj fp32, writes split bf16 with SCALE folded)
__global__ void rope_q_k(const float* __restrict__ qp,
                         __nv_bfloat16* __restrict__ qh, __nv_bfloat16* __restrict__ ql)
{
    int t = blockIdx.x;
    for (int idx = threadIdx.x; idx < NHEAD * 64; idx += 256) {
        int hh = idx >> 6, i = idx & 63;
        float2 cs = g_cs[t * 64 + i];
        const float* b = qp + (size_t)t * 2048 + hh * HD;
        float x1 = b[i], x2 = b[i + 64];
        float y1 = (x1 * cs.x - x2 * cs.y) * SCALE;
        float y2 = (x2 * cs.x + x1 * cs.y) * SCALE;
        size_t o1 = (size_t)t * 2048 + hh * HD + i;
        __nv_bfloat16 h1 = __float2bfloat16_rn(y1);
        qh[o1] = h1; ql[o1] = __float2bfloat16_rn(y1 - __bfloat162float(h1));
        __nv_bfloat16 h2 = __float2bfloat16_rn(y2);
        qh[o1 + 64] = h2; ql[o1 + 64] = __float2bfloat16_rn(y2 - __bfloat162float(h2));
    }
}

// K rope + transpose split; V split
__global__ void kv_prep_k(const float* __restrict__ qkv)
{
    int t = blockIdx.x;
    int tid = threadIdx.x;   // 128
    if (tid < 64) {
        int i = tid;
        float2 cs = g_cs[t * 64 + i];
        const float* kb = qkv + (size_t)t * QKV_N + QDIM;
        float x1 = kb[i], x2 = kb[i + 64];
        float y1 = x1 * cs.x - x2 * cs.y;
        float y2 = x2 * cs.x + x1 * cs.y;
        __nv_bfloat16 h1 = __float2bfloat16_rn(y1);
        g_kth[(size_t)i * SEQ + t] = h1;
        g_ktl[(size_t)i * SEQ + t] = __float2bfloat16_rn(y1 - __bfloat162float(h1));
        __nv_bfloat16 h2 = __float2bfloat16_rn(y2);
        g_kth[(size_t)(i + 64) * SEQ + t] = h2;
        g_ktl[(size_t)(i + 64) * SEQ + t] = __float2bfloat16_rn(y2 - __bfloat162float(h2));
    }
    {
        float v = qkv[(size_t)t * QKV_N + QDIM + HD + tid];
        __nv_bfloat16 h = __float2bfloat16_rn(v);
        g_vh[(size_t)t * HD + tid] = h;
        g_vl[(size_t)t * HD + tid] = __float2bfloat16_rn(v - __bfloat162float(h));
    }
}

// ------------------------- attention: bf16 HMMA flash ----------------------
#define AQ_LD 136
#define AK_LD 72
#define AV_LD 136
#define AP_LD 72
#define AOF_QH 0
#define AOF_QL 34816
#define AOF_KH 69632
#define AOF_KL 88064
#define AOF_VH 106496
#define AOF_VL 123904
#define AOF_PH 141312
#define AOF_PL 159744
#define AOF_M  178176
#define AOF_L  178688
#define AOF_RMAX 179200
#define AOF_RSUM 180224
#define ATTN_SMEM 181248

__global__ __launch_bounds__(256, 1) void attn_k(
    const __nv_bfloat16* __restrict__ Qh, const __nv_bfloat16* __restrict__ Ql,
    __nv_bfloat16* __restrict__ Oh, __nv_bfloat16* __restrict__ Ol)
{
    extern __shared__ __align__(16) char sm[];
    const int bx = blockIdx.x;
    const int qt = 15 - (bx >> 4);     // longest tiles first
    const int h = bx & 15;
    const int q0 = qt * 128;

    const int tid = threadIdx.x;
    const int wid = tid >> 5, lane = tid & 31;
    const int wm = wid >> 1, wn = wid & 1;
    const int lrow = lane & 15, lcol8 = (lane >> 4) * 8;
    const int r4 = lane >> 2, c2 = (lane & 3) * 2;

    float* sM = (float*)(sm + AOF_M);
    float* sL = (float*)(sm + AOF_L);
    float* sRmax = (float*)(sm + AOF_RMAX);   // [2][128]
    float* sRsum = (float*)(sm + AOF_RSUM);   // [2][128]
    const uint32_t uQh = s2u(sm + AOF_QH), uQl = s2u(sm + AOF_QL);
    const uint32_t uKh = s2u(sm + AOF_KH), uKl = s2u(sm + AOF_KL);
    const uint32_t uVh = s2u(sm + AOF_VH), uVl = s2u(sm + AOF_VL);
    const uint32_t uPh = s2u(sm + AOF_PH), uPl = s2u(sm + AOF_PL);

    // load Q tile (128 x 128, hi+lo)
    #pragma unroll
    for (int it = 0; it < 8; it++) {
        int i = tid + it * 256;          // 2048 uint4 per copy
        int r = i >> 4, c = (i & 15) << 3;
        size_t src = (size_t)(q0 + r) * 2048 + h * HD + c;
        *(uint4*)(sm + AOF_QH + r * (AQ_LD*2) + c * 2) = *(const uint4*)(Qh + src);
        *(uint4*)(sm + AOF_QL + r * (AQ_LD*2) + c * 2) = *(const uint4*)(Ql + src);
    }
    if (tid < 128) { sM[tid] = -3.0e30f; sL[tid] = 0.f; }

    float o[2][8][4] = {};
    const int nkt = 2 * qt + 2;

    for (int kt = 0; kt < nkt; kt++) {
        const int k0 = kt * 64;
        __syncthreads();
        // load K tile (transposed source [d][tok]): 128 x 64
        #pragma unroll
        for (int it = 0; it < 4; it++) {
            int i = tid + it * 256;      // 1024 uint4 per copy
            int d = i >> 3, tc = (i & 7) << 3;
            size_t src = (size_t)d * SEQ + k0 + tc;
            *(uint4*)(sm + AOF_KH + d * (AK_LD*2) + tc * 2) = *(const uint4*)(g_kth + src);
            *(uint4*)(sm + AOF_KL + d * (AK_LD*2) + tc * 2) = *(const uint4*)(g_ktl + src);
        }
        // load V tile: 64 x 128
        #pragma unroll
        for (int it = 0; it < 4; it++) {
            int i = tid + it * 256;
            int r = i >> 4, c = (i & 15) << 3;
            size_t src = (size_t)(k0 + r) * HD + c;
            *(uint4*)(sm + AOF_VH + r * (AV_LD*2) + c * 2) = *(const uint4*)(g_vh + src);
            *(uint4*)(sm + AOF_VL + r * (AV_LD*2) + c * 2) = *(const uint4*)(g_vl + src);
        }
        __syncthreads();

        // ---- S = Q K^T (3-pass split) ----
        float sacc[2][4][4] = {};
        #pragma unroll
        for (int ks = 0; ks < 8; ks++) {
            uint32_t ah[2][4], al[2][4], bh[2][4], bl[2][4];
            #pragma unroll
            for (int mf = 0; mf < 2; mf++) {
                uint32_t ro = (uint32_t)((wm * 32 + mf * 16 + lrow) * AQ_LD + ks * 16 + lcol8) * 2;
                ldsm4(ah[mf], uQh + ro);
                ldsm4(al[mf], uQl + ro);
            }
            #pragma unroll
            for (int nh = 0; nh < 2; nh++) {
                uint32_t ro = (uint32_t)((ks * 16 + lrow) * AK_LD + wn * 32 + nh * 16 + lcol8) * 2;
                ldsm4t(bh[nh], uKh + ro);
                ldsm4t(bl[nh], uKl + ro);
            }
            #pragma unroll
            for (int mf = 0; mf < 2; mf++)
                #pragma unroll
                for (int nf = 0; nf < 4; nf++) {
                    uint32_t b0h = bh[nf >> 1][(nf & 1) * 2], b1h = bh[nf >> 1][(nf & 1) * 2 + 1];
                    uint32_t b0l = bl[nf >> 1][(nf & 1) * 2], b1l = bl[nf >> 1][(nf & 1) * 2 + 1];
                    mma16816(sacc[mf][nf], ah[mf], b0h, b1h);
                    mma16816(sacc[mf][nf], ah[mf], b0l, b1l);
                    mma16816(sacc[mf][nf], al[mf], b0h, b1h);
                }
        }

        // causal mask on diagonal tiles
        if (kt >= nkt - 2) {
            #pragma unroll
            for (int mf = 0; mf < 2; mf++)
                #pragma unroll
                for (int nf = 0; nf < 4; nf++)
                    #pragma unroll
                    for (int v = 0; v < 4; v++) {
                        int row = q0 + wm * 32 + mf * 16 + r4 + (v >= 2 ? 8 : 0);
                        int col = k0 + wn * 32 + nf * 8 + c2 + (v & 1);
                        if (col > row) sacc[mf][nf][v] = -1.0e30f;
                    }
        }

        // ---- row max (warp-local then cross-warp) ----
        float rmax[4] = {-3.0e30f, -3.0e30f, -3.0e30f, -3.0e30f};
        #pragma unroll
        for (int mf = 0; mf < 2; mf++)
            #pragma unroll
            for (int nf = 0; nf < 4; nf++) {
                rmax[mf*2]   = fmaxf(rmax[mf*2],   fmaxf(sacc[mf][nf][0], sacc[mf][nf][1]));
                rmax[mf*2+1] = fmaxf(rmax[mf*2+1], fmaxf(sacc[mf][nf][2], sacc[mf][nf][3]));
            }
        #pragma unroll
        for (int s = 0; s < 4; s++) {
            rmax[s] = fmaxf(rmax[s], __shfl_xor_sync(0xffffffffu, rmax[s], 1));
            rmax[s] = fmaxf(rmax[s], __shfl_xor_sync(0xffffffffu, rmax[s], 2));
        }
        if ((lane & 3) == 0) {
            #pragma unroll
            for (int s = 0; s < 4; s++) {
                int lr = wm * 32 + (s >> 1) * 16 + r4 + (s & 1) * 8;
                sRmax[wn * 128 + lr] = rmax[s];
            }
        }
        __syncthreads();

        float mn[4], fct[4];
        #pragma unroll
        for (int s = 0; s < 4; s++) {
            int lr = wm * 32 + (s >> 1) * 16 + r4 + (s & 1) * 8;
            float mo = sM[lr];
            float m2 = fmaxf(sRmax[lr], sRmax[128 + lr]);
            mn[s] = fmaxf(mo, m2);
            fct[s] = fexp(mo - mn[s]);
        }

        // ---- p = exp(s-mn), store split P, partial sums, rescale o ----
        float rsum[4] = {0.f, 0.f, 0.f, 0.f};
        #pragma unroll
        for (int mf = 0; mf < 2; mf++) {
            int lr0 = wm * 32 + mf * 16 + r4;
            #pragma unroll
            for (int nf = 0; nf < 4; nf++) {
                int col = wn * 32 + nf * 8 + c2;
                float p0 = fexp(sacc[mf][nf][0] - mn[mf*2]);
                float p1 = fexp(sacc[mf][nf][1] - mn[mf*2]);
                float p2 = fexp(sacc[mf][nf][2] - mn[mf*2+1]);
                float p3 = fexp(sacc[mf][nf][3] - mn[mf*2+1]);
                rsum[mf*2]   += p0 + p1;
                rsum[mf*2+1] += p2 + p3;
                uint32_t hi, lo;
                split2(p0, p1, hi, lo);
                *(uint32_t*)(sm + AOF_PH + (lr0 * AP_LD + col) * 2) = hi;
                *(uint32_t*)(sm + AOF_PL + (lr0 * AP_LD + col) * 2) = lo;
                split2(p2, p3, hi, lo);
                *(uint32_t*)(sm + AOF_PH + ((lr0 + 8) * AP_LD + col) * 2) = hi;
                *(uint32_t*)(sm + AOF_PL + ((lr0 + 8) * AP_LD + col) * 2) = lo;
            }
        }
        #pragma unroll
        for (int mf = 0; mf < 2; mf++)
            #pragma unroll
            for (int nf8 = 0; nf8 < 8; nf8++) {
                o[mf][nf8][0] *= fct[mf*2];   o[mf][nf8][1] *= fct[mf*2];
                o[mf][nf8][2] *= fct[mf*2+1]; o[mf][nf8][3] *= fct[mf*2+1];
            }
        #pragma unroll
        for (int s = 0; s < 4; s++) {
            rsum[s] += __shfl_xor_sync(0xffffffffu, rsum[s], 1);
            rsum[s] += __shfl_xor_sync(0xffffffffu, rsum[s], 2);
        }
        if ((lane & 3) == 0) {
            #pragma unroll
            for (int s = 0; s < 4; s++) {
                int lr = wm * 32 + (s >> 1) * 16 + r4 + (s & 1) * 8;
                sRsum[wn * 128 + lr] = rsum[s];
            }
        }
        __syncthreads();
        if (wn == 0 && (lane & 3) == 0) {
            #pragma unroll
            for (int s = 0; s < 4; s++) {
                int lr = wm * 32 + (s >> 1) * 16 + r4 + (s & 1) * 8;
                sL[lr] = sL[lr] * fct[s] + sRsum[lr] + sRsum[128 + lr];
                sM[lr] = mn[s];
            }
        }

        // ---- O += P V (3-pass split) ----
        #pragma unroll
        for (int ks = 0; ks < 4; ks++) {
            uint32_t aph[2][4], apl[2][4], bvh[4][4], bvl[4][4];
            #pragma unroll
            for (int mf = 0; mf < 2; mf++) {
                uint32_t ro = (uint32_t)((wm * 32 + mf * 16 + lrow) * AP_LD + ks * 16 + lcol8) * 2;
                ldsm4(aph[mf], uPh + ro);
                ldsm4(apl[mf], uPl + ro);
            }
            #pragma unroll
            for (int nh = 0; nh < 4; nh++) {
                uint32_t ro = (uint32_t)((ks * 16 + lrow) * AV_LD + wn * 64 + nh * 16 + lcol8) * 2;
                ldsm4t(bvh[nh], uVh + ro);
                ldsm4t(bvl[nh], uVl + ro);
            }
            #pragma unroll
            for (int mf = 0; mf < 2; mf++)
                #pragma unroll
                for (int nf8 = 0; nf8 < 8; nf8++) {
                    uint32_t b0h = bvh[nf8 >> 1][(nf8 & 1) * 2], b1h = bvh[nf8 >> 1][(nf8 & 1) * 2 + 1];
                    uint32_t b0l = bvl[nf8 >> 1][(nf8 & 1) * 2], b1l = bvl[nf8 >> 1][(nf8 & 1) * 2 + 1];
                    mma16816(o[mf][nf8], aph[mf], b0h, b1h);
                    mma16816(o[mf][nf8], aph[mf], b0l, b1l);
                    mma16816(o[mf][nf8], apl[mf], b0h, b1h);
                }
        }
    }
    __syncthreads();

    // ---- write O (split bf16) ----
    float inv[4];
    #pragma unroll
    for (int s = 0; s < 4; s++) {
        int lr = wm * 32 + (s >> 1) * 16 + r4 + (s & 1) * 8;
        inv[s] = 1.f / sL[lr];
    }
    #pragma unroll
    for (int mf = 0; mf < 2; mf++) {
        int row0 = q0 + wm * 32 + mf * 16 + r4;
        #pragma unroll
        for (int nf8 = 0; nf8 < 8; nf8++) {
            int col = h * HD + wn * 64 + nf8 * 8 + c2;
            uint32_t hi, lo;
            split2(o[mf][nf8][0] * inv[mf*2], o[mf][nf8][1] * inv[mf*2], hi, lo);
            *(uint32_t*)(Oh + (size_t)row0 * 2048 + col) = hi;
            *(uint32_t*)(Ol + (size_t)row0 * 2048 + col) = lo;
            split2(o[mf][nf8][2] * inv[mf*2+1], o[mf][nf8][3] * inv[mf*2+1], hi, lo);
            *(uint32_t*)(Oh + (size_t)(row0 + 8) * 2048 + col) = hi;
            *(uint32_t*)(Ol + (size_t)(row0 + 8) * 2048 + col) = lo;
        }
    }
}

// ------------------------- router / topk / scan / fill ---------------------
__global__ __launch_bounds__(256) void router_k(const float* __restrict__ X,
                                                const float* __restrict__ Wr)
{
    __shared__ float part[8][32];
    int t = blockIdx.x;
    int e = threadIdx.x & 31, p = threadIdx.x >> 5;
    const float* xr = X + (size_t)t * HID;
    float s = 0.f;
    for (int k = p * 128; k < p * 128 + 128; k++) s = fmaf(xr[k], Wr[k * 32 + e], s);
    part[p][e] = s;
    __syncthreads();
    if (threadIdx.x < 32) {
        float logit = 0.f;
        #pragma unroll
        for (int q = 0; q < 8; q++) logit += part[q][e];
        float m = logit;
        for (int d = 16; d; d >>= 1) m = fmaxf(m, __shfl_xor_sync(0xffffffffu, m, d));
        float ex = __expf(logit - m);
        float cur = ex;
        float wsel[3]; int isel[3];
        #pragma unroll
        for (int kk = 0; kk < 3; kk++) {
            float v = cur; int idx = e;
            for (int d = 16; d; d >>= 1) {
                float v2 = __shfl_xor_sync(0xffffffffu, v, d);
                int   i2 = __shfl_xor_sync(0xffffffffu, idx, d);
                if (v2 > v || (v2 == v && i2 < idx)) { v = v2; idx = i2; }
            }
            wsel[kk] = v; isel[kk] = idx;
            if (e == idx) cur = -1.f;
        }
        float tot = wsel[0] + wsel[1] + wsel[2];
        if (e < 3) { g_topi[t * 3 + e] = isel[e]; g_topw[t * 3 + e] = wsel[e] / tot; }
        if (e == 0) {
            atomicAdd(&g_cnt[isel[0]], 1);
            atomicAdd(&g_cnt[isel[1]], 1);
            atomicAdd(&g_cnt[isel[2]], 1);
        }
    }
}

__global__ void scan_k()
{
    int e = threadIdx.x;
    int c = g_cnt[e];
    int x = c;
    for (int d = 1; d < 32; d <<= 1) {
        int y = __shfl_up_sync(0xffffffffu, x, d);
        if (e >= d) x += y;
    }
    int excl = x - c;
    g_off[e] = excl;
    g_fill[e] = excl;
}

__global__ void fill_k()
{
    int t = blockIdx.x * 256 + threadIdx.x;
    if (t < SEQ) {
        #pragma unroll
        for (int k = 0; k < 3; k++) {
            int e = g_topi[t * 3 + k];
            int slot = atomicAdd(&g_fill[e], 1);
            g_ptok[slot] = t;
            g_pw[slot] = g_topw[t * 3 + k];
        }
    }
}

// ------------------------- launch ------------------------------------------
extern "C" void kernel_launch(void* const* d_in, const int* in_sizes, int n_in,
                              void* d_out, int out_size)
{
    const float* hidden   = (const float*)d_in[0];
    const float* w_in     = (const float*)d_in[1];
    const float* w_qkv    = (const float*)d_in[2];
    const float* w_inter  = (const float*)d_in[3];
    const float* w_q      = (const float*)d_in[4];
    const float* w_o      = (const float*)d_in[5];
    const float* w_post   = (const float*)d_in[6];
    const float* w_guse   = (const float*)d_in[7];
    const float* w_dse    = (const float*)d_in[8];
    const float* w_router = (const float*)d_in[9];
    const float* w_gue    = (const float*)d_in[10];
    const float* w_de     = (const float*)d_in[11];
    const int*   pos      = (const int*)d_in[12];
    float* out = (float*)d_out;

    float *qkv, *qproj, *resid2, *h2;
    cudaGetSymbolAddress((void**)&qkv,    g_qkv);
    cudaGetSymbolAddress((void**)&qproj,  g_qproj);
    cudaGetSymbolAddress((void**)&resid2, g_resid2);
    cudaGetSymbolAddress((void**)&h2,     g_h2);
    __nv_bfloat16 *hnh,*hnl,*qnh,*qnl,*qh,*ql,*aoh,*aol,*h2h,*h2l,*aseh,*asel,*aceh,*acel;
    __nv_bfloat16 *wqkvh,*wqkvl,*wqh,*wql,*woh,*wol,*wguh,*wgul,*wdh,*wdl;
    cudaGetSymbolAddress((void**)&hnh, g_hnh);   cudaGetSymbolAddress((void**)&hnl, g_hnl);
    cudaGetSymbolAddress((void**)&qnh, g_qnh);   cudaGetSymbolAddress((void**)&qnl, g_qnl);
    cudaGetSymbolAddress((void**)&qh,  g_qh);    cudaGetSymbolAddress((void**)&ql,  g_ql);
    cudaGetSymbolAddress((void**)&aoh, g_aoh);   cudaGetSymbolAddress((void**)&aol, g_aol);
    cudaGetSymbolAddress((void**)&h2h, g_h2h);   cudaGetSymbolAddress((void**)&h2l, g_h2l);
    cudaGetSymbolAddress((void**)&aseh,g_aseh);  cudaGetSymbolAddress((void**)&asel,g_asel);
    cudaGetSymbolAddress((void**)&aceh,g_aceh);  cudaGetSymbolAddress((void**)&acel,g_acel);
    cudaGetSymbolAddress((void**)&wqkvh,g_wqkvh);cudaGetSymbolAddress((void**)&wqkvl,g_wqkvl);
    cudaGetSymbolAddress((void**)&wqh, g_wqh);   cudaGetSymbolAddress((void**)&wql, g_wql);
    cudaGetSymbolAddress((void**)&woh, g_woh);   cudaGetSymbolAddress((void**)&wol, g_wol);
    cudaGetSymbolAddress((void**)&wguh,g_wguh);  cudaGetSymbolAddress((void**)&wgul,g_wgul);
    cudaGetSymbolAddress((void**)&wdh, g_wdh);   cudaGetSymbolAddress((void**)&wdl, g_wdl);

    cudaFuncSetAttribute(attn_k, cudaFuncAttributeMaxDynamicSharedMemorySize, ATTN_SMEM);
    cudaFuncSetAttribute((gemm_tc<0,1>), cudaFuncAttributeMaxDynamicSharedMemorySize, SMEM_TOTAL_G);
    cudaFuncSetAttribute((gemm_tc<1,1>), cudaFuncAttributeMaxDynamicSharedMemorySize, SMEM_TOTAL_G);
    cudaFuncSetAttribute((gemm_tc<2,0>), cudaFuncAttributeMaxDynamicSharedMemorySize, SMEM_TOTAL_G);
    cudaFuncSetAttribute((gemm_tc<3,0>), cudaFuncAttributeMaxDynamicSharedMemorySize, SMEM_TOTAL_G);

    zero_counts_k<<<1, 32>>>();
    cs_prep_k<<<SEQ, 64>>>(pos);
    // pre-split dense weights (once per launch)
    split_w_k<<<(HID*QKV_N/4)/256, 256>>>(w_qkv, wqkvh, wqkvl, HID*QKV_N/4);
    split_w_k<<<(QDIM*2048/4)/256, 256>>>(w_q, wqh, wql, QDIM*2048/4);
    split_w_k<<<(2048*HID/4)/256, 256>>>(w_o, woh, wol, 2048*HID/4);
    split_w_k<<<(HID*2*IDIM/4)/256, 256>>>(w_guse, wguh, wgul, HID*2*IDIM/4);
    split_w_k<<<(IDIM*HID/4)/256, 256>>>(w_dse, wdh, wdl, IDIM*HID/4);

    rmsnorm_k<<<SEQ, 256>>>(hidden, w_in, nullptr, hnh, hnl, HID, HID, HID);
    gemm_tc<0,1><<<dim3(QKV_N/128, SEQ/64), 128, SMEM_TOTAL_G>>>(
        hnh, hnl, wqkvh, wqkvl, qkv, nullptr, nullptr, nullptr, HID, HID, QKV_N, QKV_N, 0, 0);
    rmsnorm_k<<<SEQ, 256>>>(qkv, w_inter, nullptr, qnh, qnl, QDIM, QKV_N, QDIM);
    gemm_tc<0,1><<<dim3(2048/128, SEQ/64), 128, SMEM_TOTAL_G>>>(
        qnh, qnl, wqh, wql, qproj, nullptr, nullptr, nullptr, QDIM, QDIM, 2048, 2048, 0, 0);
    rope_q_k<<<SEQ, 256>>>(qproj, qh, ql);
    kv_prep_k<<<SEQ, 128>>>(qkv);
    attn_k<<<256, 256, ATTN_SMEM>>>(qh, ql, aoh, aol);
    gemm_tc<0,1><<<dim3(HID/128, SEQ/64), 128, SMEM_TOTAL_G>>>(
        aoh, aol, woh, wol, resid2, nullptr, nullptr, hidden, 2048, 2048, HID, HID, 0, 0);
    rmsnorm_k<<<SEQ, 256>>>(resid2, w_post, h2, h2h, h2l, HID, HID, HID);
    gemm_tc<1,1><<<dim3(IDIM/64, SEQ/64), 128, SMEM_TOTAL_G>>>(
        h2h, h2l, wguh, wgul, nullptr, aseh, asel, nullptr, HID, HID, 2*IDIM, IDIM, IDIM, 0);
    gemm_tc<0,1><<<dim3(HID/128, SEQ/64), 128, SMEM_TOTAL_G>>>(
        aseh, asel, wdh, wdl, out, nullptr, nullptr, resid2, IDIM, IDIM, HID, HID, 0, 0);
    router_k<<<SEQ, 256>>>(h2, w_router);
    scan_k<<<1, 32>>>();
    fill_k<<<SEQ/256, 256>>>();
    gemm_tc<2,0><<<dim3(IDIM/64, 32, NEXP), 128, SMEM_TOTAL_G>>>(
        h2h, h2l, w_gue, nullptr, nullptr, aceh, acel, nullptr, HID, HID, 2*IDIM, IDIM, IDIM,
        (size_t)HID * 2 * IDIM);
    gemm_tc<3,0><<<dim3(HID/128, 32, NEXP), 128, SMEM_TOTAL_G>>>(
        aceh, acel, w_de, nullptr, out, nullptr, nullptr, nullptr, IDIM, IDIM, HID, HID, 0,
        (size_t)IDIM * HID);
}

// round 10
// speedup vs baseline: 1.1098x; 1.1098x over previous
#include <cuda_runtime.h>
#include <cuda_bf16.h>
#include <math.h>
#include <stdint.h>

#define SEQ 2048
#define HID 1024
#define NHEAD 16
#define HD 128
#define QDIM 512
#define NEXP 32
#define IDIM 1024
#define QKV_N 768
#define SCALE 0.08838834764831845f   // 1/sqrt(128)

// ------------------------- device scratch ----------------------------------
__device__ float g_qkv[SEQ*QKV_N];
__device__ float g_qproj[SEQ*NHEAD*HD];
__device__ float g_resid2[SEQ*HID];
__device__ float g_h2[SEQ*HID];
__device__ float2 g_cs[SEQ*64];

__device__ __nv_bfloat16 g_hnh[SEQ*HID],  g_hnl[SEQ*HID];
__device__ __nv_bfloat16 g_qnh[SEQ*QDIM], g_qnl[SEQ*QDIM];
__device__ __nv_bfloat16 g_qh[SEQ*2048],  g_ql[SEQ*2048];
__device__ __nv_bfloat16 g_kth[128*SEQ],  g_ktl[128*SEQ];   // transposed [d][token]
__device__ __nv_bfloat16 g_vh[SEQ*128],   g_vl[SEQ*128];
__device__ __nv_bfloat16 g_aoh[SEQ*2048], g_aol[SEQ*2048];
__device__ __nv_bfloat16 g_h2h[SEQ*HID],  g_h2l[SEQ*HID];
__device__ __nv_bfloat16 g_aseh[SEQ*IDIM],g_asel[SEQ*IDIM];
__device__ __nv_bfloat16 g_aceh[SEQ*3*IDIM], g_acel[SEQ*3*IDIM];

// pre-split dense weights (bf16 hi/lo)
__device__ __nv_bfloat16 g_wqkvh[HID*QKV_N],   g_wqkvl[HID*QKV_N];
__device__ __nv_bfloat16 g_wqh[QDIM*2048],     g_wql[QDIM*2048];
__device__ __nv_bfloat16 g_woh[2048*HID],      g_wol[2048*HID];
__device__ __nv_bfloat16 g_wguh[HID*2*IDIM],   g_wgul[HID*2*IDIM];
__device__ __nv_bfloat16 g_wdh[IDIM*HID],      g_wdl[IDIM*HID];

__device__ int   g_topi[SEQ*3];
__device__ float g_topw[SEQ*3];
__device__ int   g_cnt[NEXP];
__device__ int   g_off[NEXP];
__device__ int   g_fill[NEXP];
__device__ int   g_ptok[SEQ*3];
__device__ float g_pw[SEQ*3];

// ------------------------- helpers -----------------------------------------
__device__ __forceinline__ uint32_t s2u(const void* p) {
    uint32_t a;
    asm("{ .reg .u64 t; cvta.to.shared.u64 t, %1; cvt.u32.u64 %0, t; }" : "=r"(a) : "l"(p));
    return a;
}
__device__ __forceinline__ void ldsm4(uint32_t* r, uint32_t addr) {
    asm volatile("ldmatrix.sync.aligned.m8n8.x4.shared.b16 {%0,%1,%2,%3}, [%4];"
        : "=r"(r[0]), "=r"(r[1]), "=r"(r[2]), "=r"(r[3]) : "r"(addr));
}
__device__ __forceinline__ void ldsm4t(uint32_t* r, uint32_t addr) {
    asm volatile("ldmatrix.sync.aligned.m8n8.x4.trans.shared.b16 {%0,%1,%2,%3}, [%4];"
        : "=r"(r[0]), "=r"(r[1]), "=r"(r[2]), "=r"(r[3]) : "r"(addr));
}
__device__ __forceinline__ void mma16816(float* c, const uint32_t* a, uint32_t b0, uint32_t b1) {
    asm volatile("mma.sync.aligned.m16n8k16.row.col.f32.bf16.bf16.f32 "
        "{%0,%1,%2,%3}, {%4,%5,%6,%7}, {%8,%9}, {%0,%1,%2,%3};"
        : "+f"(c[0]), "+f"(c[1]), "+f"(c[2]), "+f"(c[3])
        : "r"(a[0]), "r"(a[1]), "r"(a[2]), "r"(a[3]), "r"(b0), "r"(b1));
}
__device__ __forceinline__ void cpa16(uint32_t dst, const void* src) {
    asm volatile("cp.async.cg.shared.global [%0], [%1], 16;" :: "r"(dst), "l"(src));
}
#define CPA_COMMIT() asm volatile("cp.async.commit_group;" ::: "memory")
#define CPA_WAIT0()  asm volatile("cp.async.wait_group 0;" ::: "memory")
#define CPA_WAIT1()  asm volatile("cp.async.wait_group 1;" ::: "memory")

__device__ __forceinline__ uint32_t pack_hi(float f0, float f1) {
    __nv_bfloat162 h = __floats2bfloat162_rn(f0, f1);
    return *(uint32_t*)&h;
}
__device__ __forceinline__ uint32_t pack_lo(float f0, float f1, uint32_t hibits) {
    __nv_bfloat162 h = *(__nv_bfloat162*)&hibits;
    __nv_bfloat162 l = __floats2bfloat162_rn(f0 - __bfloat162float(h.x),
                                             f1 - __bfloat162float(h.y));
    return *(uint32_t*)&l;
}
__device__ __forceinline__ void split2(float a, float b, uint32_t& hi, uint32_t& lo) {
    hi = pack_hi(a, b);
    lo = pack_lo(a, b, hi);
}
// FFMA-only exp (rel err ~4e-5), avoids MUFU
__device__ __forceinline__ float fexp(float x) {
    x = fminf(fmaxf(x, -80.f), 80.f);
    float y = x * 1.4426950408889634f;
    float n = rintf(y);
    float f = y - n;
    float p = fmaf(f, 0.009618130f, 0.055504110f);
    p = fmaf(p, f, 0.240226507f);
    p = fmaf(p, f, 0.693147181f);
    p = fmaf(p, f, 1.0f);
    return p * __int_as_float(((int)n + 127) << 23);
}

// fused weight pre-split: all 5 dense weights in one launch
#define SPL0 (HID*QKV_N/4)
#define SPL1 (SPL0 + QDIM*2048/4)
#define SPL2 (SPL1 + 2048*HID/4)
#define SPL3 (SPL2 + HID*2*IDIM/4)
#define SPL4 (SPL3 + IDIM*HID/4)
__global__ void split_all_k(const float* __restrict__ W0, const float* __restrict__ W1,
                            const float* __restrict__ W2, const float* __restrict__ W3,
                            const float* __restrict__ W4)
{
    int i = blockIdx.x * 256 + threadIdx.x;
    if (i >= SPL4) return;
    const float* W; __nv_bfloat16 *Wh, *Wl; int j;
    if (i < SPL0)      { W = W0; Wh = g_wqkvh; Wl = g_wqkvl; j = i; }
    else if (i < SPL1) { W = W1; Wh = g_wqh;   Wl = g_wql;   j = i - SPL0; }
    else if (i < SPL2) { W = W2; Wh = g_woh;   Wl = g_wol;   j = i - SPL1; }
    else if (i < SPL3) { W = W3; Wh = g_wguh;  Wl = g_wgul;  j = i - SPL2; }
    else               { W = W4; Wh = g_wdh;   Wl = g_wdl;   j = i - SPL3; }
    float4 v = ((const float4*)W)[j];
    uint32_t h0, l0, h1, l1;
    split2(v.x, v.y, h0, l0);
    split2(v.z, v.w, h1, l1);
    ((uint2*)Wh)[j] = make_uint2(h0, h1);
    ((uint2*)Wl)[j] = make_uint2(l0, l1);
}

// ------------------------- GEMM: 64-row tiles, 128 thr ----------------------
#define LDA 40
#define LDB 136
#define ASZ (64*LDA*2)           // 5120 bytes per A array
#define BSZ (32*LDB*2)           // 8704 bytes per B array
#define OFF_AH(b) ((b) * (2*ASZ))
#define OFF_AL(b) ((b) * (2*ASZ) + ASZ)
#define OFF_BH(b) (6*ASZ + (b) * (2*BSZ))
#define OFF_BL(b) (6*ASZ + (b) * (2*BSZ) + BSZ)
#define OFF_TOK   (6*ASZ + 6*BSZ)
#define SMEM_TOTAL_G (OFF_TOK + 64*4)

// MODE 0: plain  C = A@B (+add) fp32       (64 rows x 128 out cols / CTA)
// MODE 1: gated  Ch/Cl = split(silu(A@Bg)*(A@Bu))  (64 rows x 64 cols, up at +upOff)
// MODE 2: moe gathered gated -> split rows off+r   (2-pass: B single bf16)
// MODE 3: moe scatter: C[tok] += w * (A@B)  fp32 atomic (2-pass)
// BSPLIT=1: B1/B2 pre-split bf16 hi/lo (pure cp.async, 3-stage ring, 3-pass)
// BSPLIT=0: B1 fp32, inline convert to SINGLE bf16 (2-stage, 2-pass)
template<int MODE, int BSPLIT>
__global__ __launch_bounds__(128, 2) void gemm_tc(
    const __nv_bfloat16* __restrict__ Ah, const __nv_bfloat16* __restrict__ Al,
    const void* __restrict__ B1, const void* __restrict__ B2,
    float* __restrict__ C, __nv_bfloat16* __restrict__ Ch, __nv_bfloat16* __restrict__ Cl,
    const float* __restrict__ add,
    int K, int lda, int ldb, int ldc, int upOff, size_t bStride)
{
    int cnt = 0, off = 0;
    size_t bOff = 0;
    if (MODE >= 2) {
        int e = blockIdx.z;
        cnt = g_cnt[e];
        if ((int)blockIdx.y * 64 >= cnt) return;
        off = g_off[e];
        bOff = bStride * e;
    }
    const int m0 = blockIdx.y * 64;
    const int nb = blockIdx.x * ((MODE == 1 || MODE == 2) ? 64 : 128);

    extern __shared__ __align__(16) char sm[];
    int* sTok = (int*)(sm + OFF_TOK);
    const uint32_t sb = s2u(sm);

    const int tid = threadIdx.x;
    const int wid = tid >> 5, lane = tid & 31;
    const int wm = wid >> 1, wn = wid & 1;

    if (MODE == 2 && tid < 64) {
        int gr = m0 + tid;
        sTok[tid] = (gr < cnt) ? g_ptok[off + gr] : 0;
    }
    __syncthreads();

    float acc[2][8][4] = {};
    const int lrow = lane & 15, lcol8 = (lane >> 4) * 8;
    const int nkt = K >> 5;

    // per-thread A cp.async indices: 2 segments (tid, tid+128); 256 segs total
    const int am0 = tid >> 2, aseg0 = (tid & 3);
    const int am1 = (tid + 128) >> 2, aseg1 = ((tid + 128) & 3);
    size_t arow0, arow1;
    {
        if (MODE == 2) {
            arow0 = (size_t)sTok[am0] * lda;
            arow1 = (size_t)sTok[am1] * lda;
        } else if (MODE == 3) {
            int r0 = (m0 + am0 < cnt) ? m0 + am0 : 0;
            int r1 = (m0 + am1 < cnt) ? m0 + am1 : 0;
            arow0 = (size_t)(off + r0) * lda;
            arow1 = (size_t)(off + r1) * lda;
        } else {
            arow0 = (size_t)(m0 + am0) * lda;
            arow1 = (size_t)(m0 + am1) * lda;
        }
    }
    const uint32_t adst0 = sb + am0 * (LDA*2) + aseg0 * 16;
    const uint32_t adst1 = sb + am1 * (LDA*2) + aseg1 * 16;
    const int aoff0 = aseg0 * 8, aoff1 = aseg1 * 8;

    if (BSPLIT) {
        // ============= pure cp.async path (dense weights pre-split, 3-pass) ==
        const __nv_bfloat16* Bh = (const __nv_bfloat16*)B1;
        const __nv_bfloat16* Bl = (const __nv_bfloat16*)B2;

        uint32_t bdst[4]; size_t bsrc[4];
        #pragma unroll
        for (int it = 0; it < 4; it++) {
            int seg = tid + it * 128;
            int kk = seg >> 4, cs = (seg & 15) * 8;
            int col;
            if (MODE == 1) col = (cs < 64) ? nb + cs : upOff + nb + (cs - 64);
            else           col = nb + cs;
            bsrc[it] = (size_t)kk * ldb + col;
            bdst[it] = sb + kk * (LDB*2) + cs * 2;
        }

        auto issue = [&](int bf, int k0) {
            cpa16(adst0 + OFF_AH(bf), Ah + arow0 + k0 + aoff0);
            cpa16(adst0 + OFF_AL(bf), Al + arow0 + k0 + aoff0);
            cpa16(adst1 + OFF_AH(bf), Ah + arow1 + k0 + aoff1);
            cpa16(adst1 + OFF_AL(bf), Al + arow1 + k0 + aoff1);
            #pragma unroll
            for (int it = 0; it < 4; it++) {
                size_t s = bsrc[it] + (size_t)k0 * ldb;
                cpa16(bdst[it] + OFF_BH(bf), Bh + s);
                cpa16(bdst[it] + OFF_BL(bf), Bl + s);
            }
            CPA_COMMIT();
        };

        issue(0, 0);
        if (nkt > 1) issue(1, 32);

        int bf = 0;
        for (int c = 0; c < nkt; c++) {
            if (c + 1 < nkt) { CPA_WAIT1(); } else { CPA_WAIT0(); }
            __syncthreads();
            if (c + 2 < nkt) {
                int nb3 = bf + 2; if (nb3 >= 3) nb3 -= 3;
                issue(nb3, (c + 2) << 5);
            }
            const uint32_t uAh = sb + OFF_AH(bf), uAl = sb + OFF_AL(bf);
            const uint32_t uBh = sb + OFF_BH(bf), uBl = sb + OFF_BL(bf);
            #pragma unroll
            for (int ks = 0; ks < 2; ks++) {
                uint32_t ah[2][4], al[2][4];
                #pragma unroll
                for (int mf = 0; mf < 2; mf++) {
                    uint32_t ro = (uint32_t)((wm * 32 + mf * 16 + lrow) * LDA + ks * 16 + lcol8) * 2;
                    ldsm4(ah[mf], uAh + ro);
                    ldsm4(al[mf], uAl + ro);
                }
                #pragma unroll
                for (int nh = 0; nh < 4; nh++) {
                    uint32_t bh[4], bl[4];
                    uint32_t ro = (uint32_t)((ks * 16 + lrow) * LDB + wn * 64 + nh * 16 + lcol8) * 2;
                    ldsm4t(bh, uBh + ro);
                    ldsm4t(bl, uBl + ro);
                    #pragma unroll
                    for (int mf = 0; mf < 2; mf++)
                        #pragma unroll
                        for (int sub = 0; sub < 2; sub++) {
                            int nf = nh * 2 + sub;
                            mma16816(acc[mf][nf], ah[mf], bh[sub*2], bh[sub*2+1]);
                            mma16816(acc[mf][nf], ah[mf], bl[sub*2], bl[sub*2+1]);
                            mma16816(acc[mf][nf], al[mf], bh[sub*2], bh[sub*2+1]);
                        }
                }
            }
            bf++; if (bf >= 3) bf = 0;
        }
        __syncthreads();
    } else {
        // ============= MoE path: fp32 B -> single bf16, 2-pass ===============
        const float* B = (const float*)B1 + bOff;
        int bcol[8]; size_t brow[8];
        #pragma unroll
        for (int it = 0; it < 8; it++) {
            int i = tid + it * 128;
            int kk = i >> 5;
            int n4 = (i & 31) << 2;
            int col;
            if (MODE == 2) col = (n4 < 64) ? nb + n4 : upOff + nb + (n4 - 64);
            else           col = nb + n4;
            bcol[it] = n4;
            brow[it] = (size_t)kk * ldb + col;
        }
        float4 br[8];
        {
            cpa16(adst0 + OFF_AH(0), Ah + arow0 + aoff0);
            cpa16(adst0 + OFF_AL(0), Al + arow0 + aoff0);
            cpa16(adst1 + OFF_AH(0), Ah + arow1 + aoff1);
            cpa16(adst1 + OFF_AL(0), Al + arow1 + aoff1);
            CPA_COMMIT();
            #pragma unroll
            for (int it = 0; it < 8; it++) br[it] = *(const float4*)(B + brow[it]);
            CPA_WAIT0();
            __syncthreads();
            #pragma unroll
            for (int it = 0; it < 8; it++) {
                int i = tid + it * 128;
                int kk = i >> 5;
                uint32_t h0 = pack_hi(br[it].x, br[it].y), h1 = pack_hi(br[it].z, br[it].w);
                uint32_t* ph = (uint32_t*)(sm + OFF_BH(0) + kk * (LDB*2) + bcol[it] * 2);
                ph[0] = h0; ph[1] = h1;
            }
            __syncthreads();
        }
        int p = 0;
        for (int c = 0; c < nkt; c++) {
            const int q = p ^ 1;
            const bool more = (c + 1 < nkt);
            if (more) {
                const int k1 = (c + 1) << 5;
                cpa16(adst0 + OFF_AH(q), Ah + arow0 + k1 + aoff0);
                cpa16(adst0 + OFF_AL(q), Al + arow0 + k1 + aoff0);
                cpa16(adst1 + OFF_AH(q), Ah + arow1 + k1 + aoff1);
                cpa16(adst1 + OFF_AL(q), Al + arow1 + k1 + aoff1);
                CPA_COMMIT();
                #pragma unroll
                for (int it = 0; it < 8; it++)
                    br[it] = *(const float4*)(B + (size_t)k1 * ldb + brow[it]);
            }
            const uint32_t uAh = sb + OFF_AH(p), uAl = sb + OFF_AL(p);
            const uint32_t uBh = sb + OFF_BH(p);
            #pragma unroll
            for (int ks = 0; ks < 2; ks++) {
                uint32_t ah[2][4], al[2][4];
                #pragma unroll
                for (int mf = 0; mf < 2; mf++) {
                    uint32_t ro = (uint32_t)((wm * 32 + mf * 16 + lrow) * LDA + ks * 16 + lcol8) * 2;
                    ldsm4(ah[mf], uAh + ro);
                    ldsm4(al[mf], uAl + ro);
                }
                #pragma unroll
                for (int nh = 0; nh < 4; nh++) {
                    uint32_t bh[4];
                    uint32_t ro = (uint32_t)((ks * 16 + lrow) * LDB + wn * 64 + nh * 16 + lcol8) * 2;
                    ldsm4t(bh, uBh + ro);
                    #pragma unroll
                    for (int mf = 0; mf < 2; mf++)
                        #pragma unroll
                        for (int sub = 0; sub < 2; sub++) {
                            int nf = nh * 2 + sub;
                            mma16816(acc[mf][nf], ah[mf], bh[sub*2], bh[sub*2+1]);
                            mma16816(acc[mf][nf], al[mf], bh[sub*2], bh[sub*2+1]);
                        }
                }
            }
            if (more) {
                #pragma unroll
                for (int it = 0; it < 8; it++) {
                    int i = tid + it * 128;
                    int kk = i >> 5;
                    uint32_t h0 = pack_hi(br[it].x, br[it].y), h1 = pack_hi(br[it].z, br[it].w);
                    uint32_t* ph = (uint32_t*)(sm + OFF_BH(q) + kk * (LDB*2) + bcol[it] * 2);
                    ph[0] = h0; ph[1] = h1;
                }
                CPA_WAIT0();
                __syncthreads();
            }
            p = q;
        }
        __syncthreads();
    }

    // ---- epilogue ----
    const int r4 = lane >> 2, c2 = (lane & 3) * 2;
    if (MODE == 0) {
        #pragma unroll
        for (int mf = 0; mf < 2; mf++) {
            #pragma unroll
            for (int nf = 0; nf < 8; nf++) {
                int col = nb + wn * 64 + nf * 8 + c2;
                size_t r1 = (size_t)(m0 + wm * 32 + mf * 16 + r4);
                size_t r2 = r1 + 8;
                float v0 = acc[mf][nf][0], v1 = acc[mf][nf][1];
                float v2 = acc[mf][nf][2], v3 = acc[mf][nf][3];
                if (add) {
                    v0 += add[r1 * ldc + col]; v1 += add[r1 * ldc + col + 1];
                    v2 += add[r2 * ldc + col]; v3 += add[r2 * ldc + col + 1];
                }
                *(float2*)(C + r1 * ldc + col) = make_float2(v0, v1);
                *(float2*)(C + r2 * ldc + col) = make_float2(v2, v3);
            }
        }
    } else if (MODE == 1 || MODE == 2) {
        float* sG = (float*)sm;              // [64][65]
        if (wn == 0) {                        // gate cols 0..63
            #pragma unroll
            for (int mf = 0; mf < 2; mf++)
                #pragma unroll
                for (int nf = 0; nf < 8; nf++) {
                    int col = nf * 8 + c2;
                    int rr1 = wm * 32 + mf * 16 + r4, rr2 = rr1 + 8;
                    sG[rr1 * 65 + col]     = acc[mf][nf][0];
                    sG[rr1 * 65 + col + 1] = acc[mf][nf][1];
                    sG[rr2 * 65 + col]     = acc[mf][nf][2];
                    sG[rr2 * 65 + col + 1] = acc[mf][nf][3];
                }
        }
        __syncthreads();
        if (wn == 1) {                        // up cols -> combine
            #pragma unroll
            for (int mf = 0; mf < 2; mf++)
                #pragma unroll
                for (int nf = 0; nf < 8; nf++) {
                    int col = nf * 8 + c2;
                    int rr1 = wm * 32 + mf * 16 + r4;
                    #pragma unroll
                    for (int half = 0; half < 2; half++) {
                        int rr = rr1 + half * 8;
                        bool ok = (MODE == 1) || (m0 + rr < cnt);
                        if (ok) {
                            size_t row = (MODE == 1) ? (size_t)(m0 + rr) : (size_t)(off + m0 + rr);
                            float g0 = sG[rr * 65 + col], g1 = sG[rr * 65 + col + 1];
                            float u0 = acc[mf][nf][half * 2], u1 = acc[mf][nf][half * 2 + 1];
                            float o0 = g0 / (1.f + fexp(-g0)) * u0;
                            float o1 = g1 / (1.f + fexp(-g1)) * u1;
                            uint32_t hi, lo;
                            split2(o0, o1, hi, lo);
                            *(uint32_t*)(Ch + row * ldc + nb + col) = hi;
                            *(uint32_t*)(Cl + row * ldc + nb + col) = lo;
                        }
                    }
                }
        }
    } else {  // MODE 3
        #pragma unroll
        for (int mf = 0; mf < 2; mf++) {
            int rr1 = wm * 32 + mf * 16 + r4;
            #pragma unroll
            for (int half = 0; half < 2; half++) {
                int rr = rr1 + half * 8;
                if (m0 + rr < cnt) {
                    int tok = g_ptok[off + m0 + rr];
                    float w = g_pw[off + m0 + rr];
                    float* dst = C + (size_t)tok * ldc;
                    #pragma unroll
                    for (int nf = 0; nf < 8; nf++) {
                        int col = nb + wn * 64 + nf * 8 + c2;
                        atomicAdd(dst + col,     w * acc[mf][nf][half * 2]);
                        atomicAdd(dst + col + 1, w * acc[mf][nf][half * 2 + 1]);
                    }
                }
            }
        }
    }
}

// ------------------------- small kernels ------------------------------------
__global__ void cs_prep_k(const int* __restrict__ pos) {
    int t = blockIdx.x, i = threadIdx.x;   // 64 threads
    if (t == 0 && i < NEXP) g_cnt[i] = 0;
    double e = exp(-((double)(2 * i) / 128.0) * log(500000.0));
    float f = (float)pos[t] * (float)e;
    float sn, cs; sincosf(f, &sn, &cs);
    g_cs[t * 64 + i] = make_float2(cs, sn);
}

// rmsnorm: writes optional fp32 y + optional bf16 split yh/yl
__global__ void rmsnorm_k(const float* __restrict__ x, const float* __restrict__ w,
                          float* __restrict__ y,
                          __nv_bfloat16* __restrict__ yh, __nv_bfloat16* __restrict__ yl,
                          int cols, int ldx, int ldy)
{
    int row = blockIdx.x;
    const float* xr = x + (size_t)row * ldx;
    float ss = 0.f;
    for (int c = threadIdx.x; c < cols; c += 256) { float v = xr[c]; ss = fmaf(v, v, ss); }
    __shared__ float wred[8];
    #pragma unroll
    for (int d = 16; d; d >>= 1) ss += __shfl_xor_sync(0xffffffffu, ss, d);
    if ((threadIdx.x & 31) == 0) wred[threadIdx.x >> 5] = ss;
    __syncthreads();
    if (threadIdx.x < 32) {
        float v = (threadIdx.x < 8) ? wred[threadIdx.x] : 0.f;
        #pragma unroll
        for (int d = 4; d; d >>= 1) v += __shfl_xor_sync(0xffffffffu, v, d);
        if (threadIdx.x == 0) wred[0] = v;
    }
    __syncthreads();
    float r = rsqrtf(wred[0] / (float)cols + 1e-5f);
    for (int c = threadIdx.x; c < cols; c += 256) {
        float v = xr[c] * r * w[c];
        if (y) y[(size_t)row * ldy + c] = v;
        if (yh) {
            __nv_bfloat16 h = __float2bfloat16_rn(v);
            yh[(size_t)row * ldy + c] = h;
            yl[(size_t)row * ldy + c] = __float2bfloat16_rn(v - __bfloat162float(h));
        }
    }
}

// rope on q (reads qproj fp32, writes split bf16 with SCALE folded)
__global__ void rope_q_k(const float* __restrict__ qp,
                         __nv_bfloat16* __restrict__ qh, __nv_bfloat16* __restrict__ ql)
{
    int t = blockIdx.x;
    for (int idx = threadIdx.x; idx < NHEAD * 64; idx += 256) {
        int hh = idx >> 6, i = idx & 63;
        float2 cs = g_cs[t * 64 + i];
        const float* b = qp + (size_t)t * 2048 + hh * HD;
        float x1 = b[i], x2 = b[i + 64];
        float y1 = (x1 * cs.x - x2 * cs.y) * SCALE;
        float y2 = (x2 * cs.x + x1 * cs.y) * SCALE;
        size_t o1 = (size_t)t * 2048 + hh * HD + i;
        __nv_bfloat16 h1 = __float2bfloat16_rn(y1);
        qh[o1] = h1; ql[o1] = __float2bfloat16_rn(y1 - __bfloat162float(h1));
        __nv_bfloat16 h2 = __float2bfloat16_rn(y2);
        qh[o1 + 64] = h2; ql[o1 + 64] = __float2bfloat16_rn(y2 - __bfloat162float(h2));
    }
}

// K rope + transpose split; V split
__global__ void kv_prep_k(const float* __restrict__ qkv)
{
    int t = blockIdx.x;
    int tid = threadIdx.x;   // 128
    if (tid < 64) {
        int i = tid;
        float2 cs = g_cs[t * 64 + i];
        const float* kb = qkv + (size_t)t * QKV_N + QDIM;
        float x1 = kb[i], x2 = kb[i + 64];
        float y1 = x1 * cs.x - x2 * cs.y;
        float y2 = x2 * cs.x + x1 * cs.y;
        __nv_bfloat16 h1 = __float2bfloat16_rn(y1);
        g_kth[(size_t)i * SEQ + t] = h1;
        g_ktl[(size_t)i * SEQ + t] = __float2bfloat16_rn(y1 - __bfloat162float(h1));
        __nv_bfloat16 h2 = __float2bfloat16_rn(y2);
        g_kth[(size_t)(i + 64) * SEQ + t] = h2;
        g_ktl[(size_t)(i + 64) * SEQ + t] = __float2bfloat16_rn(y2 - __bfloat162float(h2));
    }
    {
        float v = qkv[(size_t)t * QKV_N + QDIM + HD + tid];
        __nv_bfloat16 h = __float2bfloat16_rn(v);
        g_vh[(size_t)t * HD + tid] = h;
        g_vl[(size_t)t * HD + tid] = __float2bfloat16_rn(v - __bfloat162float(h));
    }
}

// ------------------------- attention: bf16 HMMA flash ----------------------
#define AQ_LD 136
#define AK_LD 72
#define AV_LD 136
#define AP_LD 72
#define AOF_QH 0
#define AOF_QL 34816
#define AOF_KH 69632
#define AOF_KL 88064
#define AOF_VH 106496
#define AOF_VL 123904
#define AOF_PH 141312
#define AOF_PL 159744
#define AOF_M  178176
#define AOF_L  178688
#define AOF_RMAX 179200
#define AOF_RSUM 180224
#define ATTN_SMEM 181248

__global__ __launch_bounds__(256, 1) void attn_k(
    const __nv_bfloat16* __restrict__ Qh, const __nv_bfloat16* __restrict__ Ql,
    __nv_bfloat16* __restrict__ Oh, __nv_bfloat16* __restrict__ Ol)
{
    extern __shared__ __align__(16) char sm[];
    const int bx = blockIdx.x;
    const int qt = 15 - (bx >> 4);     // longest tiles first
    const int h = bx & 15;
    const int q0 = qt * 128;

    const int tid = threadIdx.x;
    const int wid = tid >> 5, lane = tid & 31;
    const int wm = wid >> 1, wn = wid & 1;
    const int lrow = lane & 15, lcol8 = (lane >> 4) * 8;
    const int r4 = lane >> 2, c2 = (lane & 3) * 2;

    float* sM = (float*)(sm + AOF_M);
    float* sL = (float*)(sm + AOF_L);
    float* sRmax = (float*)(sm + AOF_RMAX);   // [2][128]
    float* sRsum = (float*)(sm + AOF_RSUM);   // [2][128]
    const uint32_t uQh = s2u(sm + AOF_QH), uQl = s2u(sm + AOF_QL);
    const uint32_t uKh = s2u(sm + AOF_KH), uKl = s2u(sm + AOF_KL);
    const uint32_t uVh = s2u(sm + AOF_VH), uVl = s2u(sm + AOF_VL);
    const uint32_t uPh = s2u(sm + AOF_PH), uPl = s2u(sm + AOF_PL);

    // load Q tile (128 x 128, hi+lo)
    #pragma unroll
    for (int it = 0; it < 8; it++) {
        int i = tid + it * 256;          // 2048 uint4 per copy
        int r = i >> 4, c = (i & 15) << 3;
        size_t src = (size_t)(q0 + r) * 2048 + h * HD + c;
        *(uint4*)(sm + AOF_QH + r * (AQ_LD*2) + c * 2) = *(const uint4*)(Qh + src);
        *(uint4*)(sm + AOF_QL + r * (AQ_LD*2) + c * 2) = *(const uint4*)(Ql + src);
    }
    if (tid < 128) { sM[tid] = -3.0e30f; sL[tid] = 0.f; }

    float o[2][8][4] = {};
    const int nkt = 2 * qt + 2;

    for (int kt = 0; kt < nkt; kt++) {
        const int k0 = kt * 64;
        __syncthreads();
        // load K tile (transposed source [d][tok]): 128 x 64
        #pragma unroll
        for (int it = 0; it < 4; it++) {
            int i = tid + it * 256;      // 1024 uint4 per copy
            int d = i >> 3, tc = (i & 7) << 3;
            size_t src = (size_t)d * SEQ + k0 + tc;
            *(uint4*)(sm + AOF_KH + d * (AK_LD*2) + tc * 2) = *(const uint4*)(g_kth + src);
            *(uint4*)(sm + AOF_KL + d * (AK_LD*2) + tc * 2) = *(const uint4*)(g_ktl + src);
        }
        // load V tile: 64 x 128
        #pragma unroll
        for (int it = 0; it < 4; it++) {
            int i = tid + it * 256;
            int r = i >> 4, c = (i & 15) << 3;
            size_t src = (size_t)(k0 + r) * HD + c;
            *(uint4*)(sm + AOF_VH + r * (AV_LD*2) + c * 2) = *(const uint4*)(g_vh + src);
            *(uint4*)(sm + AOF_VL + r * (AV_LD*2) + c * 2) = *(const uint4*)(g_vl + src);
        }
        __syncthreads();

        // ---- S = Q K^T (3-pass split) ----
        float sacc[2][4][4] = {};
        #pragma unroll
        for (int ks = 0; ks < 8; ks++) {
            uint32_t ah[2][4], al[2][4], bh[2][4], bl[2][4];
            #pragma unroll
            for (int mf = 0; mf < 2; mf++) {
                uint32_t ro = (uint32_t)((wm * 32 + mf * 16 + lrow) * AQ_LD + ks * 16 + lcol8) * 2;
                ldsm4(ah[mf], uQh + ro);
                ldsm4(al[mf], uQl + ro);
            }
            #pragma unroll
            for (int nh = 0; nh < 2; nh++) {
                uint32_t ro = (uint32_t)((ks * 16 + lrow) * AK_LD + wn * 32 + nh * 16 + lcol8) * 2;
                ldsm4t(bh[nh], uKh + ro);
                ldsm4t(bl[nh], uKl + ro);
            }
            #pragma unroll
            for (int mf = 0; mf < 2; mf++)
                #pragma unroll
                for (int nf = 0; nf < 4; nf++) {
                    uint32_t b0h = bh[nf >> 1][(nf & 1) * 2], b1h = bh[nf >> 1][(nf & 1) * 2 + 1];
                    uint32_t b0l = bl[nf >> 1][(nf & 1) * 2], b1l = bl[nf >> 1][(nf & 1) * 2 + 1];
                    mma16816(sacc[mf][nf], ah[mf], b0h, b1h);
                    mma16816(sacc[mf][nf], ah[mf], b0l, b1l);
                    mma16816(sacc[mf][nf], al[mf], b0h, b1h);
                }
        }

        // causal mask on diagonal tiles
        if (kt >= nkt - 2) {
            #pragma unroll
            for (int mf = 0; mf < 2; mf++)
                #pragma unroll
                for (int nf = 0; nf < 4; nf++)
                    #pragma unroll
                    for (int v = 0; v < 4; v++) {
                        int row = q0 + wm * 32 + mf * 16 + r4 + (v >= 2 ? 8 : 0);
                        int col = k0 + wn * 32 + nf * 8 + c2 + (v & 1);
                        if (col > row) sacc[mf][nf][v] = -1.0e30f;
                    }
        }

        // ---- row max (warp-local then cross-warp) ----
        float rmax[4] = {-3.0e30f, -3.0e30f, -3.0e30f, -3.0e30f};
        #pragma unroll
        for (int mf = 0; mf < 2; mf++)
            #pragma unroll
            for (int nf = 0; nf < 4; nf++) {
                rmax[mf*2]   = fmaxf(rmax[mf*2],   fmaxf(sacc[mf][nf][0], sacc[mf][nf][1]));
                rmax[mf*2+1] = fmaxf(rmax[mf*2+1], fmaxf(sacc[mf][nf][2], sacc[mf][nf][3]));
            }
        #pragma unroll
        for (int s = 0; s < 4; s++) {
            rmax[s] = fmaxf(rmax[s], __shfl_xor_sync(0xffffffffu, rmax[s], 1));
            rmax[s] = fmaxf(rmax[s], __shfl_xor_sync(0xffffffffu, rmax[s], 2));
        }
        if ((lane & 3) == 0) {
            #pragma unroll
            for (int s = 0; s < 4; s++) {
                int lr = wm * 32 + (s >> 1) * 16 + r4 + (s & 1) * 8;
                sRmax[wn * 128 + lr] = rmax[s];
            }
        }
        __syncthreads();

        float mn[4], fct[4];
        #pragma unroll
        for (int s = 0; s < 4; s++) {
            int lr = wm * 32 + (s >> 1) * 16 + r4 + (s & 1) * 8;
            float mo = sM[lr];
            float m2 = fmaxf(sRmax[lr], sRmax[128 + lr]);
            mn[s] = fmaxf(mo, m2);
            fct[s] = fexp(mo - mn[s]);
        }

        // ---- p = exp(s-mn), store split P, partial sums, rescale o ----
        float rsum[4] = {0.f, 0.f, 0.f, 0.f};
        #pragma unroll
        for (int mf = 0; mf < 2; mf++) {
            int lr0 = wm * 32 + mf * 16 + r4;
            #pragma unroll
            for (int nf = 0; nf < 4; nf++) {
                int col = wn * 32 + nf * 8 + c2;
                float p0 = fexp(sacc[mf][nf][0] - mn[mf*2]);
                float p1 = fexp(sacc[mf][nf][1] - mn[mf*2]);
                float p2 = fexp(sacc[mf][nf][2] - mn[mf*2+1]);
                float p3 = fexp(sacc[mf][nf][3] - mn[mf*2+1]);
                rsum[mf*2]   += p0 + p1;
                rsum[mf*2+1] += p2 + p3;
                uint32_t hi, lo;
                split2(p0, p1, hi, lo);
                *(uint32_t*)(sm + AOF_PH + (lr0 * AP_LD + col) * 2) = hi;
                *(uint32_t*)(sm + AOF_PL + (lr0 * AP_LD + col) * 2) = lo;
                split2(p2, p3, hi, lo);
                *(uint32_t*)(sm + AOF_PH + ((lr0 + 8) * AP_LD + col) * 2) = hi;
                *(uint32_t*)(sm + AOF_PL + ((lr0 + 8) * AP_LD + col) * 2) = lo;
            }
        }
        #pragma unroll
        for (int mf = 0; mf < 2; mf++)
            #pragma unroll
            for (int nf8 = 0; nf8 < 8; nf8++) {
                o[mf][nf8][0] *= fct[mf*2];   o[mf][nf8][1] *= fct[mf*2];
                o[mf][nf8][2] *= fct[mf*2+1]; o[mf][nf8][3] *= fct[mf*2+1];
            }
        #pragma unroll
        for (int s = 0; s < 4; s++) {
            rsum[s] += __shfl_xor_sync(0xffffffffu, rsum[s], 1);
            rsum[s] += __shfl_xor_sync(0xffffffffu, rsum[s], 2);
        }
        if ((lane & 3) == 0) {
            #pragma unroll
            for (int s = 0; s < 4; s++) {
                int lr = wm * 32 + (s >> 1) * 16 + r4 + (s & 1) * 8;
                sRsum[wn * 128 + lr] = rsum[s];
            }
        }
        __syncthreads();
        if (wn == 0 && (lane & 3) == 0) {
            #pragma unroll
            for (int s = 0; s < 4; s++) {
                int lr = wm * 32 + (s >> 1) * 16 + r4 + (s & 1) * 8;
                sL[lr] = sL[lr] * fct[s] + sRsum[lr] + sRsum[128 + lr];
                sM[lr] = mn[s];
            }
        }

        // ---- O += P V (3-pass split) ----
        #pragma unroll
        for (int ks = 0; ks < 4; ks++) {
            uint32_t aph[2][4], apl[2][4], bvh[4][4], bvl[4][4];
            #pragma unroll
            for (int mf = 0; mf < 2; mf++) {
                uint32_t ro = (uint32_t)((wm * 32 + mf * 16 + lrow) * AP_LD + ks * 16 + lcol8) * 2;
                ldsm4(aph[mf], uPh + ro);
                ldsm4(apl[mf], uPl + ro);
            }
            #pragma unroll
            for (int nh = 0; nh < 4; nh++) {
                uint32_t ro = (uint32_t)((ks * 16 + lrow) * AV_LD + wn * 64 + nh * 16 + lcol8) * 2;
                ldsm4t(bvh[nh], uVh + ro);
                ldsm4t(bvl[nh], uVl + ro);
            }
            #pragma unroll
            for (int mf = 0; mf < 2; mf++)
                #pragma unroll
                for (int nf8 = 0; nf8 < 8; nf8++) {
                    uint32_t b0h = bvh[nf8 >> 1][(nf8 & 1) * 2], b1h = bvh[nf8 >> 1][(nf8 & 1) * 2 + 1];
                    uint32_t b0l = bvl[nf8 >> 1][(nf8 & 1) * 2], b1l = bvl[nf8 >> 1][(nf8 & 1) * 2 + 1];
                    mma16816(o[mf][nf8], aph[mf], b0h, b1h);
                    mma16816(o[mf][nf8], aph[mf], b0l, b1l);
                    mma16816(o[mf][nf8], apl[mf], b0h, b1h);
                }
        }
    }
    __syncthreads();

    // ---- write O (split bf16) ----
    float inv[4];
    #pragma unroll
    for (int s = 0; s < 4; s++) {
        int lr = wm * 32 + (s >> 1) * 16 + r4 + (s & 1) * 8;
        inv[s] = 1.f / sL[lr];
    }
    #pragma unroll
    for (int mf = 0; mf < 2; mf++) {
        int row0 = q0 + wm * 32 + mf * 16 + r4;
        #pragma unroll
        for (int nf8 = 0; nf8 < 8; nf8++) {
            int col = h * HD + wn * 64 + nf8 * 8 + c2;
            uint32_t hi, lo;
            split2(o[mf][nf8][0] * inv[mf*2], o[mf][nf8][1] * inv[mf*2], hi, lo);
            *(uint32_t*)(Oh + (size_t)row0 * 2048 + col) = hi;
            *(uint32_t*)(Ol + (size_t)row0 * 2048 + col) = lo;
            split2(o[mf][nf8][2] * inv[mf*2+1], o[mf][nf8][3] * inv[mf*2+1], hi, lo);
            *(uint32_t*)(Oh + (size_t)(row0 + 8) * 2048 + col) = hi;
            *(uint32_t*)(Ol + (size_t)(row0 + 8) * 2048 + col) = lo;
        }
    }
}

// ------------------------- router / topk / scan / fill ---------------------
__global__ __launch_bounds__(256) void router_k(const float* __restrict__ X,
                                                const float* __restrict__ Wr)
{
    __shared__ float part[8][32];
    int t = blockIdx.x;
    int e = threadIdx.x & 31, p = threadIdx.x >> 5;
    const float* xr = X + (size_t)t * HID;
    float s = 0.f;
    for (int k = p * 128; k < p * 128 + 128; k++) s = fmaf(xr[k], Wr[k * 32 + e], s);
    part[p][e] = s;
    __syncthreads();
    if (threadIdx.x < 32) {
        float logit = 0.f;
        #pragma unroll
        for (int q = 0; q < 8; q++) logit += part[q][e];
        float m = logit;
        for (int d = 16; d; d >>= 1) m = fmaxf(m, __shfl_xor_sync(0xffffffffu, m, d));
        float ex = __expf(logit - m);
        float cur = ex;
        float wsel[3]; int isel[3];
        #pragma unroll
        for (int kk = 0; kk < 3; kk++) {
            float v = cur; int idx = e;
            for (int d = 16; d; d >>= 1) {
                float v2 = __shfl_xor_sync(0xffffffffu, v, d);
                int   i2 = __shfl_xor_sync(0xffffffffu, idx, d);
                if (v2 > v || (v2 == v && i2 < idx)) { v = v2; idx = i2; }
            }
            wsel[kk] = v; isel[kk] = idx;
            if (e == idx) cur = -1.f;
        }
        float tot = wsel[0] + wsel[1] + wsel[2];
        if (e < 3) { g_topi[t * 3 + e] = isel[e]; g_topw[t * 3 + e] = wsel[e] / tot; }
        if (e == 0) {
            atomicAdd(&g_cnt[isel[0]], 1);
            atomicAdd(&g_cnt[isel[1]], 1);
            atomicAdd(&g_cnt[isel[2]], 1);
        }
    }
}

__global__ void scan_k()
{
    int e = threadIdx.x;
    int c = g_cnt[e];
    int x = c;
    for (int d = 1; d < 32; d <<= 1) {
        int y = __shfl_up_sync(0xffffffffu, x, d);
        if (e >= d) x += y;
    }
    int excl = x - c;
    g_off[e] = excl;
    g_fill[e] = excl;
}

__global__ void fill_k()
{
    int t = blockIdx.x * 256 + threadIdx.x;
    if (t < SEQ) {
        #pragma unroll
        for (int k = 0; k < 3; k++) {
            int e = g_topi[t * 3 + k];
            int slot = atomicAdd(&g_fill[e], 1);
            g_ptok[slot] = t;
            g_pw[slot] = g_topw[t * 3 + k];
        }
    }
}

// ------------------------- launch ------------------------------------------
extern "C" void kernel_launch(void* const* d_in, const int* in_sizes, int n_in,
                              void* d_out, int out_size)
{
    const float* hidden   = (const float*)d_in[0];
    const float* w_in     = (const float*)d_in[1];
    const float* w_qkv    = (const float*)d_in[2];
    const float* w_inter  = (const float*)d_in[3];
    const float* w_q      = (const float*)d_in[4];
    const float* w_o      = (const float*)d_in[5];
    const float* w_post   = (const float*)d_in[6];
    const float* w_guse   = (const float*)d_in[7];
    const float* w_dse    = (const float*)d_in[8];
    const float* w_router = (const float*)d_in[9];
    const float* w_gue    = (const float*)d_in[10];
    const float* w_de     = (const float*)d_in[11];
    const int*   pos      = (const int*)d_in[12];
    float* out = (float*)d_out;

    float *qkv, *qproj, *resid2, *h2;
    cudaGetSymbolAddress((void**)&qkv,    g_qkv);
    cudaGetSymbolAddress((void**)&qproj,  g_qproj);
    cudaGetSymbolAddress((void**)&resid2, g_resid2);
    cudaGetSymbolAddress((void**)&h2,     g_h2);
    __nv_bfloat16 *hnh,*hnl,*qnh,*qnl,*qh,*ql,*aoh,*aol,*h2h,*h2l,*aseh,*asel,*aceh,*acel;
    __nv_bfloat16 *wqkvh,*wqkvl,*wqh,*wql,*woh,*wol,*wguh,*wgul,*wdh,*wdl;
    cudaGetSymbolAddress((void**)&hnh, g_hnh);   cudaGetSymbolAddress((void**)&hnl, g_hnl);
    cudaGetSymbolAddress((void**)&qnh, g_qnh);   cudaGetSymbolAddress((void**)&qnl, g_qnl);
    cudaGetSymbolAddress((void**)&qh,  g_qh);    cudaGetSymbolAddress((void**)&ql,  g_ql);
    cudaGetSymbolAddress((void**)&aoh, g_aoh);   cudaGetSymbolAddress((void**)&aol, g_aol);
    cudaGetSymbolAddress((void**)&h2h, g_h2h);   cudaGetSymbolAddress((void**)&h2l, g_h2l);
    cudaGetSymbolAddress((void**)&aseh,g_aseh);  cudaGetSymbolAddress((void**)&asel,g_asel);
    cudaGetSymbolAddress((void**)&aceh,g_aceh);  cudaGetSymbolAddress((void**)&acel,g_acel);
    cudaGetSymbolAddress((void**)&wqkvh,g_wqkvh);cudaGetSymbolAddress((void**)&wqkvl,g_wqkvl);
    cudaGetSymbolAddress((void**)&wqh, g_wqh);   cudaGetSymbolAddress((void**)&wql, g_wql);
    cudaGetSymbolAddress((void**)&woh, g_woh);   cudaGetSymbolAddress((void**)&wol, g_wol);
    cudaGetSymbolAddress((void**)&wguh,g_wguh);  cudaGetSymbolAddress((void**)&wgul,g_wgul);
    cudaGetSymbolAddress((void**)&wdh, g_wdh);   cudaGetSymbolAddress((void**)&wdl, g_wdl);

    cudaFuncSetAttribute(attn_k, cudaFuncAttributeMaxDynamicSharedMemorySize, ATTN_SMEM);
    cudaFuncSetAttribute((gemm_tc<0,1>), cudaFuncAttributeMaxDynamicSharedMemorySize, SMEM_TOTAL_G);
    cudaFuncSetAttribute((gemm_tc<1,1>), cudaFuncAttributeMaxDynamicSharedMemorySize, SMEM_TOTAL_G);
    cudaFuncSetAttribute((gemm_tc<2,0>), cudaFuncAttributeMaxDynamicSharedMemorySize, SMEM_TOTAL_G);
    cudaFuncSetAttribute((gemm_tc<3,0>), cudaFuncAttributeMaxDynamicSharedMemorySize, SMEM_TOTAL_G);

    cs_prep_k<<<SEQ, 64>>>(pos);
    split_all_k<<<(SPL4 + 255)/256, 256>>>(w_qkv, w_q, w_o, w_guse, w_dse);

    rmsnorm_k<<<SEQ, 256>>>(hidden, w_in, nullptr, hnh, hnl, HID, HID, HID);
    gemm_tc<0,1><<<dim3(QKV_N/128, SEQ/64), 128, SMEM_TOTAL_G>>>(
        hnh, hnl, wqkvh, wqkvl, qkv, nullptr, nullptr, nullptr, HID, HID, QKV_N, QKV_N, 0, 0);
    rmsnorm_k<<<SEQ, 256>>>(qkv, w_inter, nullptr, qnh, qnl, QDIM, QKV_N, QDIM);
    gemm_tc<0,1><<<dim3(2048/128, SEQ/64), 128, SMEM_TOTAL_G>>>(
        qnh, qnl, wqh, wql, qproj, nullptr, nullptr, nullptr, QDIM, QDIM, 2048, 2048, 0, 0);
    rope_q_k<<<SEQ, 256>>>(qproj, qh, ql);
    kv_prep_k<<<SEQ, 128>>>(qkv);
    attn_k<<<256, 256, ATTN_SMEM>>>(qh, ql, aoh, aol);
    gemm_tc<0,1><<<dim3(HID/128, SEQ/64), 128, SMEM_TOTAL_G>>>(
        aoh, aol, woh, wol, resid2, nullptr, nullptr, hidden, 2048, 2048, HID, HID, 0, 0);
    rmsnorm_k<<<SEQ, 256>>>(resid2, w_post, h2, h2h, h2l, HID, HID, HID);
    gemm_tc<1,1><<<dim3(IDIM/64, SEQ/64), 128, SMEM_TOTAL_G>>>(
        h2h, h2l, wguh, wgul, nullptr, aseh, asel, nullptr, HID, HID, 2*IDIM, IDIM, IDIM, 0);
    gemm_tc<0,1><<<dim3(HID/128, SEQ/64), 128, SMEM_TOTAL_G>>>(
        aseh, asel, wdh, wdl, out, nullptr, nullptr, resid2, IDIM, IDIM, HID, HID, 0, 0);
    router_k<<<SEQ, 256>>>(h2, w_router);
    scan_k<<<1, 32>>>();
    fill_k<<<SEQ/256, 256>>>();
    gemm_tc<2,0><<<dim3(IDIM/64, 32, NEXP), 128, SMEM_TOTAL_G>>>(
        h2h, h2l, w_gue, nullptr, nullptr, aceh, acel, nullptr, HID, HID, 2*IDIM, IDIM, IDIM,
        (size_t)HID * 2 * IDIM);
    gemm_tc<3,0><<<dim3(HID/128, 32, NEXP), 128, SMEM_TOTAL_G>>>(
        aceh, acel, w_de, nullptr, out, nullptr, nullptr, nullptr, IDIM, IDIM, HID, HID, 0,
        (size_t)IDIM * HID);
}

// round 11
// speedup vs baseline: 1.2457x; 1.1225x over previous
#include <cuda_runtime.h>
#include <cuda_bf16.h>
#include <math.h>
#include <stdint.h>

#define SEQ 2048
#define HID 1024
#define NHEAD 16
#define HD 128
#define QDIM 512
#define NEXP 32
#define IDIM 1024
#define QKV_N 768
#define SCALE 0.08838834764831845f   // 1/sqrt(128)

// ------------------------- device scratch ----------------------------------
__device__ float g_qkv[SEQ*QKV_N];
__device__ float g_qproj[SEQ*NHEAD*HD];
__device__ float g_resid2[SEQ*HID];
__device__ float g_h2[SEQ*HID];
__device__ float2 g_cs[SEQ*64];

__device__ __nv_bfloat16 g_hnh[SEQ*HID],  g_hnl[SEQ*HID];
__device__ __nv_bfloat16 g_qnh[SEQ*QDIM], g_qnl[SEQ*QDIM];
__device__ __nv_bfloat16 g_qh[SEQ*2048],  g_ql[SEQ*2048];
__device__ __nv_bfloat16 g_kth[128*SEQ],  g_ktl[128*SEQ];   // transposed [d][token]
__device__ __nv_bfloat16 g_vh[SEQ*128],   g_vl[SEQ*128];
__device__ __nv_bfloat16 g_aoh[SEQ*2048], g_aol[SEQ*2048];
__device__ __nv_bfloat16 g_h2h[SEQ*HID],  g_h2l[SEQ*HID];
__device__ __nv_bfloat16 g_aseh[SEQ*IDIM],g_asel[SEQ*IDIM];
__device__ __nv_bfloat16 g_aceh[SEQ*3*IDIM], g_acel[SEQ*3*IDIM];

// pre-rounded dense weights (single bf16)
__device__ __nv_bfloat16 g_wqkvh[HID*QKV_N];
__device__ __nv_bfloat16 g_wqh[QDIM*2048];
__device__ __nv_bfloat16 g_woh[2048*HID];
__device__ __nv_bfloat16 g_wguh[HID*2*IDIM];
__device__ __nv_bfloat16 g_wdh[IDIM*HID];

__device__ int   g_topi[SEQ*3];
__device__ float g_topw[SEQ*3];
__device__ int   g_cnt[NEXP];
__device__ int   g_off[NEXP];
__device__ int   g_fill[NEXP];
__device__ int   g_ptok[SEQ*3];
__device__ float g_pw[SEQ*3];

// ------------------------- helpers -----------------------------------------
__device__ __forceinline__ uint32_t s2u(const void* p) {
    uint32_t a;
    asm("{ .reg .u64 t; cvta.to.shared.u64 t, %1; cvt.u32.u64 %0, t; }" : "=r"(a) : "l"(p));
    return a;
}
__device__ __forceinline__ void ldsm4(uint32_t* r, uint32_t addr) {
    asm volatile("ldmatrix.sync.aligned.m8n8.x4.shared.b16 {%0,%1,%2,%3}, [%4];"
        : "=r"(r[0]), "=r"(r[1]), "=r"(r[2]), "=r"(r[3]) : "r"(addr));
}
__device__ __forceinline__ void ldsm4t(uint32_t* r, uint32_t addr) {
    asm volatile("ldmatrix.sync.aligned.m8n8.x4.trans.shared.b16 {%0,%1,%2,%3}, [%4];"
        : "=r"(r[0]), "=r"(r[1]), "=r"(r[2]), "=r"(r[3]) : "r"(addr));
}
__device__ __forceinline__ void mma16816(float* c, const uint32_t* a, uint32_t b0, uint32_t b1) {
    asm volatile("mma.sync.aligned.m16n8k16.row.col.f32.bf16.bf16.f32 "
        "{%0,%1,%2,%3}, {%4,%5,%6,%7}, {%8,%9}, {%0,%1,%2,%3};"
        : "+f"(c[0]), "+f"(c[1]), "+f"(c[2]), "+f"(c[3])
        : "r"(a[0]), "r"(a[1]), "r"(a[2]), "r"(a[3]), "r"(b0), "r"(b1));
}
__device__ __forceinline__ void cpa16(uint32_t dst, const void* src) {
    asm volatile("cp.async.cg.shared.global [%0], [%1], 16;" :: "r"(dst), "l"(src));
}
#define CPA_COMMIT() asm volatile("cp.async.commit_group;" ::: "memory")
#define CPA_WAIT0()  asm volatile("cp.async.wait_group 0;" ::: "memory")
#define CPA_WAIT1()  asm volatile("cp.async.wait_group 1;" ::: "memory")

__device__ __forceinline__ uint32_t pack_hi(float f0, float f1) {
    __nv_bfloat162 h = __floats2bfloat162_rn(f0, f1);
    return *(uint32_t*)&h;
}
__device__ __forceinline__ uint32_t pack_lo(float f0, float f1, uint32_t hibits) {
    __nv_bfloat162 h = *(__nv_bfloat162*)&hibits;
    __nv_bfloat162 l = __floats2bfloat162_rn(f0 - __bfloat162float(h.x),
                                             f1 - __bfloat162float(h.y));
    return *(uint32_t*)&l;
}
__device__ __forceinline__ void split2(float a, float b, uint32_t& hi, uint32_t& lo) {
    hi = pack_hi(a, b);
    lo = pack_lo(a, b, hi);
}
// FFMA-only exp (rel err ~4e-5), avoids MUFU
__device__ __forceinline__ float fexp(float x) {
    x = fminf(fmaxf(x, -80.f), 80.f);
    float y = x * 1.4426950408889634f;
    float n = rintf(y);
    float f = y - n;
    float p = fmaf(f, 0.009618130f, 0.055504110f);
    p = fmaf(p, f, 0.240226507f);
    p = fmaf(p, f, 0.693147181f);
    p = fmaf(p, f, 1.0f);
    return p * __int_as_float(((int)n + 127) << 23);
}

// fused weight pre-round: all 5 dense weights -> single bf16, one launch
#define SPL0 (HID*QKV_N/4)
#define SPL1 (SPL0 + QDIM*2048/4)
#define SPL2 (SPL1 + 2048*HID/4)
#define SPL3 (SPL2 + HID*2*IDIM/4)
#define SPL4 (SPL3 + IDIM*HID/4)
__global__ void split_all_k(const float* __restrict__ W0, const float* __restrict__ W1,
                            const float* __restrict__ W2, const float* __restrict__ W3,
                            const float* __restrict__ W4)
{
    int i = blockIdx.x * 256 + threadIdx.x;
    if (i >= SPL4) return;
    const float* W; __nv_bfloat16 *Wh; int j;
    if (i < SPL0)      { W = W0; Wh = g_wqkvh; j = i; }
    else if (i < SPL1) { W = W1; Wh = g_wqh;   j = i - SPL0; }
    else if (i < SPL2) { W = W2; Wh = g_woh;   j = i - SPL1; }
    else if (i < SPL3) { W = W3; Wh = g_wguh;  j = i - SPL2; }
    else               { W = W4; Wh = g_wdh;   j = i - SPL3; }
    float4 v = ((const float4*)W)[j];
    uint32_t h0 = pack_hi(v.x, v.y), h1 = pack_hi(v.z, v.w);
    ((uint2*)Wh)[j] = make_uint2(h0, h1);
}

// ------------------------- GEMM: 64-row tiles, 128 thr, 2-pass --------------
#define LDA 40
#define LDB 136
#define ASZ (64*LDA*2)           // 5120 bytes per A array
#define BSZ (32*LDB*2)           // 8704 bytes per B array
#define OFF_AH(b) ((b) * (2*ASZ))
#define OFF_AL(b) ((b) * (2*ASZ) + ASZ)
#define OFF_BH(b) (6*ASZ + (b) * BSZ)
#define OFF_TOK   (6*ASZ + 3*BSZ)
#define SMEM_TOTAL_G (OFF_TOK + 64*4)

// MODE 0: plain  C = A@B (+add) fp32       (64 rows x 128 out cols / CTA)
// MODE 1: gated  Ch/Cl = split(silu(A@Bg)*(A@Bu))  (64 rows x 64 cols, up at +upOff)
// MODE 2: moe gathered gated -> split rows off+r
// MODE 3: moe scatter: C[tok] += w * (A@B)  fp32 atomic
// BSPLIT=1: B1 pre-rounded bf16 (pure cp.async, 3-stage ring)
// BSPLIT=0: B1 fp32, inline convert to bf16 (2-stage)
// All paths 2-pass: D = Ah*B + Al*B  (B single bf16)
template<int MODE, int BSPLIT>
__global__ __launch_bounds__(128, 2) void gemm_tc(
    const __nv_bfloat16* __restrict__ Ah, const __nv_bfloat16* __restrict__ Al,
    const void* __restrict__ B1,
    float* __restrict__ C, __nv_bfloat16* __restrict__ Ch, __nv_bfloat16* __restrict__ Cl,
    const float* __restrict__ add,
    int K, int lda, int ldb, int ldc, int upOff, size_t bStride)
{
    int cnt = 0, off = 0;
    size_t bOff = 0;
    if (MODE >= 2) {
        int e = blockIdx.z;
        cnt = g_cnt[e];
        if ((int)blockIdx.y * 64 >= cnt) return;
        off = g_off[e];
        bOff = bStride * e;
    }
    const int m0 = blockIdx.y * 64;
    const int nb = blockIdx.x * ((MODE == 1 || MODE == 2) ? 64 : 128);

    extern __shared__ __align__(16) char sm[];
    int* sTok = (int*)(sm + OFF_TOK);
    const uint32_t sb = s2u(sm);

    const int tid = threadIdx.x;
    const int wid = tid >> 5, lane = tid & 31;
    const int wm = wid >> 1, wn = wid & 1;

    if (MODE == 2 && tid < 64) {
        int gr = m0 + tid;
        sTok[tid] = (gr < cnt) ? g_ptok[off + gr] : 0;
    }
    __syncthreads();

    float acc[2][8][4] = {};
    const int lrow = lane & 15, lcol8 = (lane >> 4) * 8;
    const int nkt = K >> 5;

    // per-thread A cp.async indices: 2 segments (tid, tid+128); 256 segs total
    const int am0 = tid >> 2, aseg0 = (tid & 3);
    const int am1 = (tid + 128) >> 2, aseg1 = ((tid + 128) & 3);
    size_t arow0, arow1;
    {
        if (MODE == 2) {
            arow0 = (size_t)sTok[am0] * lda;
            arow1 = (size_t)sTok[am1] * lda;
        } else if (MODE == 3) {
            int r0 = (m0 + am0 < cnt) ? m0 + am0 : 0;
            int r1 = (m0 + am1 < cnt) ? m0 + am1 : 0;
            arow0 = (size_t)(off + r0) * lda;
            arow1 = (size_t)(off + r1) * lda;
        } else {
            arow0 = (size_t)(m0 + am0) * lda;
            arow1 = (size_t)(m0 + am1) * lda;
        }
    }
    const uint32_t adst0 = sb + am0 * (LDA*2) + aseg0 * 16;
    const uint32_t adst1 = sb + am1 * (LDA*2) + aseg1 * 16;
    const int aoff0 = aseg0 * 8, aoff1 = aseg1 * 8;

    if (BSPLIT) {
        // ============= pure cp.async path (dense, B pre-rounded bf16) ========
        const __nv_bfloat16* Bh = (const __nv_bfloat16*)B1;

        uint32_t bdst[4]; size_t bsrc[4];
        #pragma unroll
        for (int it = 0; it < 4; it++) {
            int seg = tid + it * 128;
            int kk = seg >> 4, cs = (seg & 15) * 8;
            int col;
            if (MODE == 1) col = (cs < 64) ? nb + cs : upOff + nb + (cs - 64);
            else           col = nb + cs;
            bsrc[it] = (size_t)kk * ldb + col;
            bdst[it] = sb + kk * (LDB*2) + cs * 2;
        }

        auto issue = [&](int bf, int k0) {
            cpa16(adst0 + OFF_AH(bf), Ah + arow0 + k0 + aoff0);
            cpa16(adst0 + OFF_AL(bf), Al + arow0 + k0 + aoff0);
            cpa16(adst1 + OFF_AH(bf), Ah + arow1 + k0 + aoff1);
            cpa16(adst1 + OFF_AL(bf), Al + arow1 + k0 + aoff1);
            #pragma unroll
            for (int it = 0; it < 4; it++) {
                size_t s = bsrc[it] + (size_t)k0 * ldb;
                cpa16(bdst[it] + OFF_BH(bf), Bh + s);
            }
            CPA_COMMIT();
        };

        issue(0, 0);
        if (nkt > 1) issue(1, 32);

        int bf = 0;
        for (int c = 0; c < nkt; c++) {
            if (c + 1 < nkt) { CPA_WAIT1(); } else { CPA_WAIT0(); }
            __syncthreads();
            if (c + 2 < nkt) {
                int nb3 = bf + 2; if (nb3 >= 3) nb3 -= 3;
                issue(nb3, (c + 2) << 5);
            }
            const uint32_t uAh = sb + OFF_AH(bf), uAl = sb + OFF_AL(bf);
            const uint32_t uBh = sb + OFF_BH(bf);
            #pragma unroll
            for (int ks = 0; ks < 2; ks++) {
                uint32_t ah[2][4], al[2][4];
                #pragma unroll
                for (int mf = 0; mf < 2; mf++) {
                    uint32_t ro = (uint32_t)((wm * 32 + mf * 16 + lrow) * LDA + ks * 16 + lcol8) * 2;
                    ldsm4(ah[mf], uAh + ro);
                    ldsm4(al[mf], uAl + ro);
                }
                #pragma unroll
                for (int nh = 0; nh < 4; nh++) {
                    uint32_t bh[4];
                    uint32_t ro = (uint32_t)((ks * 16 + lrow) * LDB + wn * 64 + nh * 16 + lcol8) * 2;
                    ldsm4t(bh, uBh + ro);
                    #pragma unroll
                    for (int mf = 0; mf < 2; mf++)
                        #pragma unroll
                        for (int sub = 0; sub < 2; sub++) {
                            int nf = nh * 2 + sub;
                            mma16816(acc[mf][nf], ah[mf], bh[sub*2], bh[sub*2+1]);
                            mma16816(acc[mf][nf], al[mf], bh[sub*2], bh[sub*2+1]);
                        }
                }
            }
            bf++; if (bf >= 3) bf = 0;
        }
        __syncthreads();
    } else {
        // ============= MoE path: fp32 B -> single bf16, 2-pass ===============
        const float* B = (const float*)B1 + bOff;
        int bcol[8]; size_t brow[8];
        #pragma unroll
        for (int it = 0; it < 8; it++) {
            int i = tid + it * 128;
            int kk = i >> 5;
            int n4 = (i & 31) << 2;
            int col;
            if (MODE == 2) col = (n4 < 64) ? nb + n4 : upOff + nb + (n4 - 64);
            else           col = nb + n4;
            bcol[it] = n4;
            brow[it] = (size_t)kk * ldb + col;
        }
        float4 br[8];
        {
            cpa16(adst0 + OFF_AH(0), Ah + arow0 + aoff0);
            cpa16(adst0 + OFF_AL(0), Al + arow0 + aoff0);
            cpa16(adst1 + OFF_AH(0), Ah + arow1 + aoff1);
            cpa16(adst1 + OFF_AL(0), Al + arow1 + aoff1);
            CPA_COMMIT();
            #pragma unroll
            for (int it = 0; it < 8; it++) br[it] = *(const float4*)(B + brow[it]);
            CPA_WAIT0();
            __syncthreads();
            #pragma unroll
            for (int it = 0; it < 8; it++) {
                int i = tid + it * 128;
                int kk = i >> 5;
                uint32_t h0 = pack_hi(br[it].x, br[it].y), h1 = pack_hi(br[it].z, br[it].w);
                uint32_t* ph = (uint32_t*)(sm + OFF_BH(0) + kk * (LDB*2) + bcol[it] * 2);
                ph[0] = h0; ph[1] = h1;
            }
            __syncthreads();
        }
        int p = 0;
        for (int c = 0; c < nkt; c++) {
            const int q = p ^ 1;
            const bool more = (c + 1 < nkt);
            if (more) {
                const int k1 = (c + 1) << 5;
                cpa16(adst0 + OFF_AH(q), Ah + arow0 + k1 + aoff0);
                cpa16(adst0 + OFF_AL(q), Al + arow0 + k1 + aoff0);
                cpa16(adst1 + OFF_AH(q), Ah + arow1 + k1 + aoff1);
                cpa16(adst1 + OFF_AL(q), Al + arow1 + k1 + aoff1);
                CPA_COMMIT();
                #pragma unroll
                for (int it = 0; it < 8; it++)
                    br[it] = *(const float4*)(B + (size_t)k1 * ldb + brow[it]);
            }
            const uint32_t uAh = sb + OFF_AH(p), uAl = sb + OFF_AL(p);
            const uint32_t uBh = sb + OFF_BH(p);
            #pragma unroll
            for (int ks = 0; ks < 2; ks++) {
                uint32_t ah[2][4], al[2][4];
                #pragma unroll
                for (int mf = 0; mf < 2; mf++) {
                    uint32_t ro = (uint32_t)((wm * 32 + mf * 16 + lrow) * LDA + ks * 16 + lcol8) * 2;
                    ldsm4(ah[mf], uAh + ro);
                    ldsm4(al[mf], uAl + ro);
                }
                #pragma unroll
                for (int nh = 0; nh < 4; nh++) {
                    uint32_t bh[4];
                    uint32_t ro = (uint32_t)((ks * 16 + lrow) * LDB + wn * 64 + nh * 16 + lcol8) * 2;
                    ldsm4t(bh, uBh + ro);
                    #pragma unroll
                    for (int mf = 0; mf < 2; mf++)
                        #pragma unroll
                        for (int sub = 0; sub < 2; sub++) {
                            int nf = nh * 2 + sub;
                            mma16816(acc[mf][nf], ah[mf], bh[sub*2], bh[sub*2+1]);
                            mma16816(acc[mf][nf], al[mf], bh[sub*2], bh[sub*2+1]);
                        }
                }
            }
            if (more) {
                #pragma unroll
                for (int it = 0; it < 8; it++) {
                    int i = tid + it * 128;
                    int kk = i >> 5;
                    uint32_t h0 = pack_hi(br[it].x, br[it].y), h1 = pack_hi(br[it].z, br[it].w);
                    uint32_t* ph = (uint32_t*)(sm + OFF_BH(q) + kk * (LDB*2) + bcol[it] * 2);
                    ph[0] = h0; ph[1] = h1;
                }
                CPA_WAIT0();
                __syncthreads();
            }
            p = q;
        }
        __syncthreads();
    }

    // ---- epilogue ----
    const int r4 = lane >> 2, c2 = (lane & 3) * 2;
    if (MODE == 0) {
        #pragma unroll
        for (int mf = 0; mf < 2; mf++) {
            #pragma unroll
            for (int nf = 0; nf < 8; nf++) {
                int col = nb + wn * 64 + nf * 8 + c2;
                size_t r1 = (size_t)(m0 + wm * 32 + mf * 16 + r4);
                size_t r2 = r1 + 8;
                float v0 = acc[mf][nf][0], v1 = acc[mf][nf][1];
                float v2 = acc[mf][nf][2], v3 = acc[mf][nf][3];
                if (add) {
                    v0 += add[r1 * ldc + col]; v1 += add[r1 * ldc + col + 1];
                    v2 += add[r2 * ldc + col]; v3 += add[r2 * ldc + col + 1];
                }
                *(float2*)(C + r1 * ldc + col) = make_float2(v0, v1);
                *(float2*)(C + r2 * ldc + col) = make_float2(v2, v3);
            }
        }
    } else if (MODE == 1 || MODE == 2) {
        float* sG = (float*)sm;              // [64][65]
        if (wn == 0) {                        // gate cols 0..63
            #pragma unroll
            for (int mf = 0; mf < 2; mf++)
                #pragma unroll
                for (int nf = 0; nf < 8; nf++) {
                    int col = nf * 8 + c2;
                    int rr1 = wm * 32 + mf * 16 + r4, rr2 = rr1 + 8;
                    sG[rr1 * 65 + col]     = acc[mf][nf][0];
                    sG[rr1 * 65 + col + 1] = acc[mf][nf][1];
                    sG[rr2 * 65 + col]     = acc[mf][nf][2];
                    sG[rr2 * 65 + col + 1] = acc[mf][nf][3];
                }
        }
        __syncthreads();
        if (wn == 1) {                        // up cols -> combine
            #pragma unroll
            for (int mf = 0; mf < 2; mf++)
                #pragma unroll
                for (int nf = 0; nf < 8; nf++) {
                    int col = nf * 8 + c2;
                    int rr1 = wm * 32 + mf * 16 + r4;
                    #pragma unroll
                    for (int half = 0; half < 2; half++) {
                        int rr = rr1 + half * 8;
                        bool ok = (MODE == 1) || (m0 + rr < cnt);
                        if (ok) {
                            size_t row = (MODE == 1) ? (size_t)(m0 + rr) : (size_t)(off + m0 + rr);
                            float g0 = sG[rr * 65 + col], g1 = sG[rr * 65 + col + 1];
                            float u0 = acc[mf][nf][half * 2], u1 = acc[mf][nf][half * 2 + 1];
                            float o0 = g0 / (1.f + fexp(-g0)) * u0;
                            float o1 = g1 / (1.f + fexp(-g1)) * u1;
                            uint32_t hi, lo;
                            split2(o0, o1, hi, lo);
                            *(uint32_t*)(Ch + row * ldc + nb + col) = hi;
                            *(uint32_t*)(Cl + row * ldc + nb + col) = lo;
                        }
                    }
                }
        }
    } else {  // MODE 3
        #pragma unroll
        for (int mf = 0; mf < 2; mf++) {
            int rr1 = wm * 32 + mf * 16 + r4;
            #pragma unroll
            for (int half = 0; half < 2; half++) {
                int rr = rr1 + half * 8;
                if (m0 + rr < cnt) {
                    int tok = g_ptok[off + m0 + rr];
                    float w = g_pw[off + m0 + rr];
                    float* dst = C + (size_t)tok * ldc;
                    #pragma unroll
                    for (int nf = 0; nf < 8; nf++) {
                        int col = nb + wn * 64 + nf * 8 + c2;
                        atomicAdd(dst + col,     w * acc[mf][nf][half * 2]);
                        atomicAdd(dst + col + 1, w * acc[mf][nf][half * 2 + 1]);
                    }
                }
            }
        }
    }
}

// ------------------------- small kernels ------------------------------------
__global__ void cs_prep_k(const int* __restrict__ pos) {
    int t = blockIdx.x, i = threadIdx.x;   // 64 threads
    if (t == 0 && i < NEXP) g_cnt[i] = 0;
    double e = exp(-((double)(2 * i) / 128.0) * log(500000.0));
    float f = (float)pos[t] * (float)e;
    float sn, cs; sincosf(f, &sn, &cs);
    g_cs[t * 64 + i] = make_float2(cs, sn);
}

// rmsnorm: writes optional fp32 y + optional bf16 split yh/yl
__global__ void rmsnorm_k(const float* __restrict__ x, const float* __restrict__ w,
                          float* __restrict__ y,
                          __nv_bfloat16* __restrict__ yh, __nv_bfloat16* __restrict__ yl,
                          int cols, int ldx, int ldy)
{
    int row = blockIdx.x;
    const float* xr = x + (size_t)row * ldx;
    float ss = 0.f;
    for (int c = threadIdx.x; c < cols; c += 256) { float v = xr[c]; ss = fmaf(v, v, ss); }
    __shared__ float wred[8];
    #pragma unroll
    for (int d = 16; d; d >>= 1) ss += __shfl_xor_sync(0xffffffffu, ss, d);
    if ((threadIdx.x & 31) == 0) wred[threadIdx.x >> 5] = ss;
    __syncthreads();
    if (threadIdx.x < 32) {
        float v = (threadIdx.x < 8) ? wred[threadIdx.x] : 0.f;
        #pragma unroll
        for (int d = 4; d; d >>= 1) v += __shfl_xor_sync(0xffffffffu, v, d);
        if (threadIdx.x == 0) wred[0] = v;
    }
    __syncthreads();
    float r = rsqrtf(wred[0] / (float)cols + 1e-5f);
    for (int c = threadIdx.x; c < cols; c += 256) {
        float v = xr[c] * r * w[c];
        if (y) y[(size_t)row * ldy + c] = v;
        if (yh) {
            __nv_bfloat16 h = __float2bfloat16_rn(v);
            yh[(size_t)row * ldy + c] = h;
            yl[(size_t)row * ldy + c] = __float2bfloat16_rn(v - __bfloat162float(h));
        }
    }
}

// rope on q (reads qproj fp32, writes split bf16 with SCALE folded)
__global__ void rope_q_k(const float* __restrict__ qp,
                         __nv_bfloat16* __restrict__ qh, __nv_bfloat16* __restrict__ ql)
{
    int t = blockIdx.x;
    for (int idx = threadIdx.x; idx < NHEAD * 64; idx += 256) {
        int hh = idx >> 6, i = idx & 63;
        float2 cs = g_cs[t * 64 + i];
        const float* b = qp + (size_t)t * 2048 + hh * HD;
        float x1 = b[i], x2 = b[i + 64];
        float y1 = (x1 * cs.x - x2 * cs.y) * SCALE;
        float y2 = (x2 * cs.x + x1 * cs.y) * SCALE;
        size_t o1 = (size_t)t * 2048 + hh * HD + i;
        __nv_bfloat16 h1 = __float2bfloat16_rn(y1);
        qh[o1] = h1; ql[o1] = __float2bfloat16_rn(y1 - __bfloat162float(h1));
        __nv_bfloat16 h2 = __float2bfloat16_rn(y2);
        qh[o1 + 64] = h2; ql[o1 + 64] = __float2bfloat16_rn(y2 - __bfloat162float(h2));
    }
}

// K rope + transpose split; V split
__global__ void kv_prep_k(const float* __restrict__ qkv)
{
    int t = blockIdx.x;
    int tid = threadIdx.x;   // 128
    if (tid < 64) {
        int i = tid;
        float2 cs = g_cs[t * 64 + i];
        const float* kb = qkv + (size_t)t * QKV_N + QDIM;
        float x1 = kb[i], x2 = kb[i + 64];
        float y1 = x1 * cs.x - x2 * cs.y;
        float y2 = x2 * cs.x + x1 * cs.y;
        __nv_bfloat16 h1 = __float2bfloat16_rn(y1);
        g_kth[(size_t)i * SEQ + t] = h1;
        g_ktl[(size_t)i * SEQ + t] = __float2bfloat16_rn(y1 - __bfloat162float(h1));
        __nv_bfloat16 h2 = __float2bfloat16_rn(y2);
        g_kth[(size_t)(i + 64) * SEQ + t] = h2;
        g_ktl[(size_t)(i + 64) * SEQ + t] = __float2bfloat16_rn(y2 - __bfloat162float(h2));
    }
    {
        float v = qkv[(size_t)t * QKV_N + QDIM + HD + tid];
        __nv_bfloat16 h = __float2bfloat16_rn(v);
        g_vh[(size_t)t * HD + tid] = h;
        g_vl[(size_t)t * HD + tid] = __float2bfloat16_rn(v - __bfloat162float(h));
    }
}

// ------------------------- attention: bf16 HMMA flash ----------------------
#define AQ_LD 136
#define AK_LD 72
#define AV_LD 136
#define AP_LD 72
#define AOF_QH 0
#define AOF_QL 34816
#define AOF_KH 69632
#define AOF_KL 88064
#define AOF_VH 106496
#define AOF_VL 123904
#define AOF_PH 141312
#define AOF_PL 159744
#define AOF_M  178176
#define AOF_L  178688
#define AOF_RMAX 179200
#define AOF_RSUM 180224
#define ATTN_SMEM 181248

__global__ __launch_bounds__(256, 1) void attn_k(
    const __nv_bfloat16* __restrict__ Qh, const __nv_bfloat16* __restrict__ Ql,
    __nv_bfloat16* __restrict__ Oh, __nv_bfloat16* __restrict__ Ol)
{
    extern __shared__ __align__(16) char sm[];
    const int bx = blockIdx.x;
    const int qt = 15 - (bx >> 4);     // longest tiles first
    const int h = bx & 15;
    const int q0 = qt * 128;

    const int tid = threadIdx.x;
    const int wid = tid >> 5, lane = tid & 31;
    const int wm = wid >> 1, wn = wid & 1;
    const int lrow = lane & 15, lcol8 = (lane >> 4) * 8;
    const int r4 = lane >> 2, c2 = (lane & 3) * 2;

    float* sM = (float*)(sm + AOF_M);
    float* sL = (float*)(sm + AOF_L);
    float* sRmax = (float*)(sm + AOF_RMAX);   // [2][128]
    float* sRsum = (float*)(sm + AOF_RSUM);   // [2][128]
    const uint32_t uQh = s2u(sm + AOF_QH), uQl = s2u(sm + AOF_QL);
    const uint32_t uKh = s2u(sm + AOF_KH), uKl = s2u(sm + AOF_KL);
    const uint32_t uVh = s2u(sm + AOF_VH), uVl = s2u(sm + AOF_VL);
    const uint32_t uPh = s2u(sm + AOF_PH), uPl = s2u(sm + AOF_PL);

    // load Q tile (128 x 128, hi+lo)
    #pragma unroll
    for (int it = 0; it < 8; it++) {
        int i = tid + it * 256;          // 2048 uint4 per copy
        int r = i >> 4, c = (i & 15) << 3;
        size_t src = (size_t)(q0 + r) * 2048 + h * HD + c;
        *(uint4*)(sm + AOF_QH + r * (AQ_LD*2) + c * 2) = *(const uint4*)(Qh + src);
        *(uint4*)(sm + AOF_QL + r * (AQ_LD*2) + c * 2) = *(const uint4*)(Ql + src);
    }
    if (tid < 128) { sM[tid] = -3.0e30f; sL[tid] = 0.f; }

    float o[2][8][4] = {};
    const int nkt = 2 * qt + 2;

    for (int kt = 0; kt < nkt; kt++) {
        const int k0 = kt * 64;
        __syncthreads();
        // load K tile (transposed source [d][tok]): 128 x 64
        #pragma unroll
        for (int it = 0; it < 4; it++) {
            int i = tid + it * 256;      // 1024 uint4 per copy
            int d = i >> 3, tc = (i & 7) << 3;
            size_t src = (size_t)d * SEQ + k0 + tc;
            *(uint4*)(sm + AOF_KH + d * (AK_LD*2) + tc * 2) = *(const uint4*)(g_kth + src);
            *(uint4*)(sm + AOF_KL + d * (AK_LD*2) + tc * 2) = *(const uint4*)(g_ktl + src);
        }
        // load V tile: 64 x 128
        #pragma unroll
        for (int it = 0; it < 4; it++) {
            int i = tid + it * 256;
            int r = i >> 4, c = (i & 15) << 3;
            size_t src = (size_t)(k0 + r) * HD + c;
            *(uint4*)(sm + AOF_VH + r * (AV_LD*2) + c * 2) = *(const uint4*)(g_vh + src);
            *(uint4*)(sm + AOF_VL + r * (AV_LD*2) + c * 2) = *(const uint4*)(g_vl + src);
        }
        __syncthreads();

        // ---- S = Q K^T (3-pass split) ----
        float sacc[2][4][4] = {};
        #pragma unroll
        for (int ks = 0; ks < 8; ks++) {
            uint32_t ah[2][4], al[2][4], bh[2][4], bl[2][4];
            #pragma unroll
            for (int mf = 0; mf < 2; mf++) {
                uint32_t ro = (uint32_t)((wm * 32 + mf * 16 + lrow) * AQ_LD + ks * 16 + lcol8) * 2;
                ldsm4(ah[mf], uQh + ro);
                ldsm4(al[mf], uQl + ro);
            }
            #pragma unroll
            for (int nh = 0; nh < 2; nh++) {
                uint32_t ro = (uint32_t)((ks * 16 + lrow) * AK_LD + wn * 32 + nh * 16 + lcol8) * 2;
                ldsm4t(bh[nh], uKh + ro);
                ldsm4t(bl[nh], uKl + ro);
            }
            #pragma unroll
            for (int mf = 0; mf < 2; mf++)
                #pragma unroll
                for (int nf = 0; nf < 4; nf++) {
                    uint32_t b0h = bh[nf >> 1][(nf & 1) * 2], b1h = bh[nf >> 1][(nf & 1) * 2 + 1];
                    uint32_t b0l = bl[nf >> 1][(nf & 1) * 2], b1l = bl[nf >> 1][(nf & 1) * 2 + 1];
                    mma16816(sacc[mf][nf], ah[mf], b0h, b1h);
                    mma16816(sacc[mf][nf], ah[mf], b0l, b1l);
                    mma16816(sacc[mf][nf], al[mf], b0h, b1h);
                }
        }

        // causal mask on diagonal tiles
        if (kt >= nkt - 2) {
            #pragma unroll
            for (int mf = 0; mf < 2; mf++)
                #pragma unroll
                for (int nf = 0; nf < 4; nf++)
                    #pragma unroll
                    for (int v = 0; v < 4; v++) {
                        int row = q0 + wm * 32 + mf * 16 + r4 + (v >= 2 ? 8 : 0);
                        int col = k0 + wn * 32 + nf * 8 + c2 + (v & 1);
                        if (col > row) sacc[mf][nf][v] = -1.0e30f;
                    }
        }

        // ---- row max (warp-local then cross-warp) ----
        float rmax[4] = {-3.0e30f, -3.0e30f, -3.0e30f, -3.0e30f};
        #pragma unroll
        for (int mf = 0; mf < 2; mf++)
            #pragma unroll
            for (int nf = 0; nf < 4; nf++) {
                rmax[mf*2]   = fmaxf(rmax[mf*2],   fmaxf(sacc[mf][nf][0], sacc[mf][nf][1]));
                rmax[mf*2+1] = fmaxf(rmax[mf*2+1], fmaxf(sacc[mf][nf][2], sacc[mf][nf][3]));
            }
        #pragma unroll
        for (int s = 0; s < 4; s++) {
            rmax[s] = fmaxf(rmax[s], __shfl_xor_sync(0xffffffffu, rmax[s], 1));
            rmax[s] = fmaxf(rmax[s], __shfl_xor_sync(0xffffffffu, rmax[s], 2));
        }
        if ((lane & 3) == 0) {
            #pragma unroll
            for (int s = 0; s < 4; s++) {
                int lr = wm * 32 + (s >> 1) * 16 + r4 + (s & 1) * 8;
                sRmax[wn * 128 + lr] = rmax[s];
            }
        }
        __syncthreads();

        float mn[4], fct[4];
        #pragma unroll
        for (int s = 0; s < 4; s++) {
            int lr = wm * 32 + (s >> 1) * 16 + r4 + (s & 1) * 8;
            float mo = sM[lr];
            float m2 = fmaxf(sRmax[lr], sRmax[128 + lr]);
            mn[s] = fmaxf(mo, m2);
            fct[s] = fexp(mo - mn[s]);
        }

        // ---- p = exp(s-mn), store split P, partial sums, rescale o ----
        float rsum[4] = {0.f, 0.f, 0.f, 0.f};
        #pragma unroll
        for (int mf = 0; mf < 2; mf++) {
            int lr0 = wm * 32 + mf * 16 + r4;
            #pragma unroll
            for (int nf = 0; nf < 4; nf++) {
                int col = wn * 32 + nf * 8 + c2;
                float p0 = fexp(sacc[mf][nf][0] - mn[mf*2]);
                float p1 = fexp(sacc[mf][nf][1] - mn[mf*2]);
                float p2 = fexp(sacc[mf][nf][2] - mn[mf*2+1]);
                float p3 = fexp(sacc[mf][nf][3] - mn[mf*2+1]);
                rsum[mf*2]   += p0 + p1;
                rsum[mf*2+1] += p2 + p3;
                uint32_t hi, lo;
                split2(p0, p1, hi, lo);
                *(uint32_t*)(sm + AOF_PH + (lr0 * AP_LD + col) * 2) = hi;
                *(uint32_t*)(sm + AOF_PL + (lr0 * AP_LD + col) * 2) = lo;
                split2(p2, p3, hi, lo);
                *(uint32_t*)(sm + AOF_PH + ((lr0 + 8) * AP_LD + col) * 2) = hi;
                *(uint32_t*)(sm + AOF_PL + ((lr0 + 8) * AP_LD + col) * 2) = lo;
            }
        }
        #pragma unroll
        for (int mf = 0; mf < 2; mf++)
            #pragma unroll
            for (int nf8 = 0; nf8 < 8; nf8++) {
                o[mf][nf8][0] *= fct[mf*2];   o[mf][nf8][1] *= fct[mf*2];
                o[mf][nf8][2] *= fct[mf*2+1]; o[mf][nf8][3] *= fct[mf*2+1];
            }
        #pragma unroll
        for (int s = 0; s < 4; s++) {
            rsum[s] += __shfl_xor_sync(0xffffffffu, rsum[s], 1);
            rsum[s] += __shfl_xor_sync(0xffffffffu, rsum[s], 2);
        }
        if ((lane & 3) == 0) {
            #pragma unroll
            for (int s = 0; s < 4; s++) {
                int lr = wm * 32 + (s >> 1) * 16 + r4 + (s & 1) * 8;
                sRsum[wn * 128 + lr] = rsum[s];
            }
        }
        __syncthreads();
        if (wn == 0 && (lane & 3) == 0) {
            #pragma unroll
            for (int s = 0; s < 4; s++) {
                int lr = wm * 32 + (s >> 1) * 16 + r4 + (s & 1) * 8;
                sL[lr] = sL[lr] * fct[s] + sRsum[lr] + sRsum[128 + lr];
                sM[lr] = mn[s];
            }
        }

        // ---- O += P V (3-pass split) ----
        #pragma unroll
        for (int ks = 0; ks < 4; ks++) {
            uint32_t aph[2][4], apl[2][4], bvh[4][4], bvl[4][4];
            #pragma unroll
            for (int mf = 0; mf < 2; mf++) {
                uint32_t ro = (uint32_t)((wm * 32 + mf * 16 + lrow) * AP_LD + ks * 16 + lcol8) * 2;
                ldsm4(aph[mf], uPh + ro);
                ldsm4(apl[mf], uPl + ro);
            }
            #pragma unroll
            for (int nh = 0; nh < 4; nh++) {
                uint32_t ro = (uint32_t)((ks * 16 + lrow) * AV_LD + wn * 64 + nh * 16 + lcol8) * 2;
                ldsm4t(bvh[nh], uVh + ro);
                ldsm4t(bvl[nh], uVl + ro);
            }
            #pragma unroll
            for (int mf = 0; mf < 2; mf++)
                #pragma unroll
                for (int nf8 = 0; nf8 < 8; nf8++) {
                    uint32_t b0h = bvh[nf8 >> 1][(nf8 & 1) * 2], b1h = bvh[nf8 >> 1][(nf8 & 1) * 2 + 1];
                    uint32_t b0l = bvl[nf8 >> 1][(nf8 & 1) * 2], b1l = bvl[nf8 >> 1][(nf8 & 1) * 2 + 1];
                    mma16816(o[mf][nf8], aph[mf], b0h, b1h);
                    mma16816(o[mf][nf8], aph[mf], b0l, b1l);
                    mma16816(o[mf][nf8], apl[mf], b0h, b1h);
                }
        }
    }
    __syncthreads();

    // ---- write O (split bf16) ----
    float inv[4];
    #pragma unroll
    for (int s = 0; s < 4; s++) {
        int lr = wm * 32 + (s >> 1) * 16 + r4 + (s & 1) * 8;
        inv[s] = 1.f / sL[lr];
    }
    #pragma unroll
    for (int mf = 0; mf < 2; mf++) {
        int row0 = q0 + wm * 32 + mf * 16 + r4;
        #pragma unroll
        for (int nf8 = 0; nf8 < 8; nf8++) {
            int col = h * HD + wn * 64 + nf8 * 8 + c2;
            uint32_t hi, lo;
            split2(o[mf][nf8][0] * inv[mf*2], o[mf][nf8][1] * inv[mf*2], hi, lo);
            *(uint32_t*)(Oh + (size_t)row0 * 2048 + col) = hi;
            *(uint32_t*)(Ol + (size_t)row0 * 2048 + col) = lo;
            split2(o[mf][nf8][2] * inv[mf*2+1], o[mf][nf8][3] * inv[mf*2+1], hi, lo);
            *(uint32_t*)(Oh + (size_t)(row0 + 8) * 2048 + col) = hi;
            *(uint32_t*)(Ol + (size_t)(row0 + 8) * 2048 + col) = lo;
        }
    }
}

// ------------------------- router / topk / scan / fill ---------------------
__global__ __launch_bounds__(256) void router_k(const float* __restrict__ X,
                                                const float* __restrict__ Wr)
{
    __shared__ float part[8][32];
    int t = blockIdx.x;
    int e = threadIdx.x & 31, p = threadIdx.x >> 5;
    const float* xr = X + (size_t)t * HID;
    float s = 0.f;
    for (int k = p * 128; k < p * 128 + 128; k++) s = fmaf(xr[k], Wr[k * 32 + e], s);
    part[p][e] = s;
    __syncthreads();
    if (threadIdx.x < 32) {
        float logit = 0.f;
        #pragma unroll
        for (int q = 0; q < 8; q++) logit += part[q][e];
        float m = logit;
        for (int d = 16; d; d >>= 1) m = fmaxf(m, __shfl_xor_sync(0xffffffffu, m, d));
        float ex = __expf(logit - m);
        float cur = ex;
        float wsel[3]; int isel[3];
        #pragma unroll
        for (int kk = 0; kk < 3; kk++) {
            float v = cur; int idx = e;
            for (int d = 16; d; d >>= 1) {
                float v2 = __shfl_xor_sync(0xffffffffu, v, d);
                int   i2 = __shfl_xor_sync(0xffffffffu, idx, d);
                if (v2 > v || (v2 == v && i2 < idx)) { v = v2; idx = i2; }
            }
            wsel[kk] = v; isel[kk] = idx;
            if (e == idx) cur = -1.f;
        }
        float tot = wsel[0] + wsel[1] + wsel[2];
        if (e < 3) { g_topi[t * 3 + e] = isel[e]; g_topw[t * 3 + e] = wsel[e] / tot; }
        if (e == 0) {
            atomicAdd(&g_cnt[isel[0]], 1);
            atomicAdd(&g_cnt[isel[1]], 1);
            atomicAdd(&g_cnt[isel[2]], 1);
        }
    }
}

__global__ void scan_k()
{
    int e = threadIdx.x;
    int c = g_cnt[e];
    int x = c;
    for (int d = 1; d < 32; d <<= 1) {
        int y = __shfl_up_sync(0xffffffffu, x, d);
        if (e >= d) x += y;
    }
    int excl = x - c;
    g_off[e] = excl;
    g_fill[e] = excl;
}

__global__ void fill_k()
{
    int t = blockIdx.x * 256 + threadIdx.x;
    if (t < SEQ) {
        #pragma unroll
        for (int k = 0; k < 3; k++) {
            int e = g_topi[t * 3 + k];
            int slot = atomicAdd(&g_fill[e], 1);
            g_ptok[slot] = t;
            g_pw[slot] = g_topw[t * 3 + k];
        }
    }
}

// ------------------------- launch ------------------------------------------
extern "C" void kernel_launch(void* const* d_in, const int* in_sizes, int n_in,
                              void* d_out, int out_size)
{
    const float* hidden   = (const float*)d_in[0];
    const float* w_in     = (const float*)d_in[1];
    const float* w_qkv    = (const float*)d_in[2];
    const float* w_inter  = (const float*)d_in[3];
    const float* w_q      = (const float*)d_in[4];
    const float* w_o      = (const float*)d_in[5];
    const float* w_post   = (const float*)d_in[6];
    const float* w_guse   = (const float*)d_in[7];
    const float* w_dse    = (const float*)d_in[8];
    const float* w_router = (const float*)d_in[9];
    const float* w_gue    = (const float*)d_in[10];
    const float* w_de     = (const float*)d_in[11];
    const int*   pos      = (const int*)d_in[12];
    float* out = (float*)d_out;

    float *qkv, *qproj, *resid2, *h2;
    cudaGetSymbolAddress((void**)&qkv,    g_qkv);
    cudaGetSymbolAddress((void**)&qproj,  g_qproj);
    cudaGetSymbolAddress((void**)&resid2, g_resid2);
    cudaGetSymbolAddress((void**)&h2,     g_h2);
    __nv_bfloat16 *hnh,*hnl,*qnh,*qnl,*qh,*ql,*aoh,*aol,*h2h,*h2l,*aseh,*asel,*aceh,*acel;
    __nv_bfloat16 *wqkvh,*wqh,*woh,*wguh,*wdh;
    cudaGetSymbolAddress((void**)&hnh, g_hnh);   cudaGetSymbolAddress((void**)&hnl, g_hnl);
    cudaGetSymbolAddress((void**)&qnh, g_qnh);   cudaGetSymbolAddress((void**)&qnl, g_qnl);
    cudaGetSymbolAddress((void**)&qh,  g_qh);    cudaGetSymbolAddress((void**)&ql,  g_ql);
    cudaGetSymbolAddress((void**)&aoh, g_aoh);   cudaGetSymbolAddress((void**)&aol, g_aol);
    cudaGetSymbolAddress((void**)&h2h, g_h2h);   cudaGetSymbolAddress((void**)&h2l, g_h2l);
    cudaGetSymbolAddress((void**)&aseh,g_aseh);  cudaGetSymbolAddress((void**)&asel,g_asel);
    cudaGetSymbolAddress((void**)&aceh,g_aceh);  cudaGetSymbolAddress((void**)&acel,g_acel);
    cudaGetSymbolAddress((void**)&wqkvh,g_wqkvh);
    cudaGetSymbolAddress((void**)&wqh, g_wqh);
    cudaGetSymbolAddress((void**)&woh, g_woh);
    cudaGetSymbolAddress((void**)&wguh,g_wguh);
    cudaGetSymbolAddress((void**)&wdh, g_wdh);

    cudaFuncSetAttribute(attn_k, cudaFuncAttributeMaxDynamicSharedMemorySize, ATTN_SMEM);
    cudaFuncSetAttribute((gemm_tc<0,1>), cudaFuncAttributeMaxDynamicSharedMemorySize, SMEM_TOTAL_G);
    cudaFuncSetAttribute((gemm_tc<1,1>), cudaFuncAttributeMaxDynamicSharedMemorySize, SMEM_TOTAL_G);
    cudaFuncSetAttribute((gemm_tc<2,0>), cudaFuncAttributeMaxDynamicSharedMemorySize, SMEM_TOTAL_G);
    cudaFuncSetAttribute((gemm_tc<3,0>), cudaFuncAttributeMaxDynamicSharedMemorySize, SMEM_TOTAL_G);

    cs_prep_k<<<SEQ, 64>>>(pos);
    split_all_k<<<(SPL4 + 255)/256, 256>>>(w_qkv, w_q, w_o, w_guse, w_dse);

    rmsnorm_k<<<SEQ, 256>>>(hidden, w_in, nullptr, hnh, hnl, HID, HID, HID);
    gemm_tc<0,1><<<dim3(QKV_N/128, SEQ/64), 128, SMEM_TOTAL_G>>>(
        hnh, hnl, wqkvh, qkv, nullptr, nullptr, nullptr, HID, HID, QKV_N, QKV_N, 0, 0);
    rmsnorm_k<<<SEQ, 256>>>(qkv, w_inter, nullptr, qnh, qnl, QDIM, QKV_N, QDIM);
    gemm_tc<0,1><<<dim3(2048/128, SEQ/64), 128, SMEM_TOTAL_G>>>(
        qnh, qnl, wqh, qproj, nullptr, nullptr, nullptr, QDIM, QDIM, 2048, 2048, 0, 0);
    rope_q_k<<<SEQ, 256>>>(qproj, qh, ql);
    kv_prep_k<<<SEQ, 128>>>(qkv);
    attn_k<<<256, 256, ATTN_SMEM>>>(qh, ql, aoh, aol);
    gemm_tc<0,1><<<dim3(HID/128, SEQ/64), 128, SMEM_TOTAL_G>>>(
        aoh, aol, woh, resid2, nullptr, nullptr, hidden, 2048, 2048, HID, HID, 0, 0);
    rmsnorm_k<<<SEQ, 256>>>(resid2, w_post, h2, h2h, h2l, HID, HID, HID);
    gemm_tc<1,1><<<dim3(IDIM/64, SEQ/64), 128, SMEM_TOTAL_G>>>(
        h2h, h2l, wguh, nullptr, aseh, asel, nullptr, HID, HID, 2*IDIM, IDIM, IDIM, 0);
    gemm_tc<0,1><<<dim3(HID/128, SEQ/64), 128, SMEM_TOTAL_G>>>(
        aseh, asel, wdh, out, nullptr, nullptr, resid2, IDIM, IDIM, HID, HID, 0, 0);
    router_k<<<SEQ, 256>>>(h2, w_router);
    scan_k<<<1, 32>>>();
    fill_k<<<SEQ/256, 256>>>();
    gemm_tc<2,0><<<dim3(IDIM/64, 32, NEXP), 128, SMEM_TOTAL_G>>>(
        h2h, h2l, w_gue, nullptr, aceh, acel, nullptr, HID, HID, 2*IDIM, IDIM, IDIM,
        (size_t)HID * 2 * IDIM);
    gemm_tc<3,0><<<dim3(HID/128, 32, NEXP), 128, SMEM_TOTAL_G>>>(
        aceh, acel, w_de, out, nullptr, nullptr, nullptr, IDIM, IDIM, HID, HID, 0,
        (size_t)IDIM * HID);
}

// round 12
// speedup vs baseline: 1.3623x; 1.0937x over previous
#include <cuda_runtime.h>
#include <cuda_bf16.h>
#include <math.h>
#include <stdint.h>

#define SEQ 2048
#define HID 1024
#define NHEAD 16
#define HD 128
#define QDIM 512
#define NEXP 32
#define IDIM 1024
#define QKV_N 768
#define SCALE 0.08838834764831845f   // 1/sqrt(128)

// ------------------------- device scratch ----------------------------------
__device__ float g_qkv[SEQ*QKV_N];
__device__ float g_qproj[SEQ*NHEAD*HD];
__device__ float g_resid2[SEQ*HID];
__device__ float g_h2[SEQ*HID];
__device__ float2 g_cs[SEQ*64];

__device__ __nv_bfloat16 g_hnh[SEQ*HID],  g_hnl[SEQ*HID];
__device__ __nv_bfloat16 g_qnh[SEQ*QDIM], g_qnl[SEQ*QDIM];
__device__ __nv_bfloat16 g_qh[SEQ*2048],  g_ql[SEQ*2048];
__device__ __nv_bfloat16 g_kth[128*SEQ],  g_ktl[128*SEQ];   // transposed [d][token]
__device__ __nv_bfloat16 g_vh[SEQ*128];
__device__ __nv_bfloat16 g_aoh[SEQ*2048], g_aol[SEQ*2048];
__device__ __nv_bfloat16 g_h2h[SEQ*HID],  g_h2l[SEQ*HID];
__device__ __nv_bfloat16 g_aseh[SEQ*IDIM],g_asel[SEQ*IDIM];
__device__ __nv_bfloat16 g_aceh[SEQ*3*IDIM], g_acel[SEQ*3*IDIM];

// pre-rounded dense weights (single bf16)
__device__ __nv_bfloat16 g_wqkvh[HID*QKV_N];
__device__ __nv_bfloat16 g_wqh[QDIM*2048];
__device__ __nv_bfloat16 g_woh[2048*HID];
__device__ __nv_bfloat16 g_wguh[HID*2*IDIM];
__device__ __nv_bfloat16 g_wdh[IDIM*HID];

__device__ int   g_topi[SEQ*3];
__device__ float g_topw[SEQ*3];
__device__ int   g_cnt[NEXP];
__device__ int   g_off[NEXP];
__device__ int   g_fill[NEXP];
__device__ int   g_ptok[SEQ*3];
__device__ float g_pw[SEQ*3];

// ------------------------- helpers -----------------------------------------
__device__ __forceinline__ uint32_t s2u(const void* p) {
    uint32_t a;
    asm("{ .reg .u64 t; cvta.to.shared.u64 t, %1; cvt.u32.u64 %0, t; }" : "=r"(a) : "l"(p));
    return a;
}
__device__ __forceinline__ void ldsm4(uint32_t* r, uint32_t addr) {
    asm volatile("ldmatrix.sync.aligned.m8n8.x4.shared.b16 {%0,%1,%2,%3}, [%4];"
        : "=r"(r[0]), "=r"(r[1]), "=r"(r[2]), "=r"(r[3]) : "r"(addr));
}
__device__ __forceinline__ void ldsm4t(uint32_t* r, uint32_t addr) {
    asm volatile("ldmatrix.sync.aligned.m8n8.x4.trans.shared.b16 {%0,%1,%2,%3}, [%4];"
        : "=r"(r[0]), "=r"(r[1]), "=r"(r[2]), "=r"(r[3]) : "r"(addr));
}
__device__ __forceinline__ void mma16816(float* c, const uint32_t* a, uint32_t b0, uint32_t b1) {
    asm volatile("mma.sync.aligned.m16n8k16.row.col.f32.bf16.bf16.f32 "
        "{%0,%1,%2,%3}, {%4,%5,%6,%7}, {%8,%9}, {%0,%1,%2,%3};"
        : "+f"(c[0]), "+f"(c[1]), "+f"(c[2]), "+f"(c[3])
        : "r"(a[0]), "r"(a[1]), "r"(a[2]), "r"(a[3]), "r"(b0), "r"(b1));
}
__device__ __forceinline__ void cpa16(uint32_t dst, const void* src) {
    asm volatile("cp.async.cg.shared.global [%0], [%1], 16;" :: "r"(dst), "l"(src));
}
#define CPA_COMMIT() asm volatile("cp.async.commit_group;" ::: "memory")
#define CPA_WAIT0()  asm volatile("cp.async.wait_group 0;" ::: "memory")
#define CPA_WAIT1()  asm volatile("cp.async.wait_group 1;" ::: "memory")

__device__ __forceinline__ uint32_t pack_hi(float f0, float f1) {
    __nv_bfloat162 h = __floats2bfloat162_rn(f0, f1);
    return *(uint32_t*)&h;
}
__device__ __forceinline__ uint32_t pack_lo(float f0, float f1, uint32_t hibits) {
    __nv_bfloat162 h = *(__nv_bfloat162*)&hibits;
    __nv_bfloat162 l = __floats2bfloat162_rn(f0 - __bfloat162float(h.x),
                                             f1 - __bfloat162float(h.y));
    return *(uint32_t*)&l;
}
__device__ __forceinline__ void split2(float a, float b, uint32_t& hi, uint32_t& lo) {
    hi = pack_hi(a, b);
    lo = pack_lo(a, b, hi);
}
// FFMA-only exp (rel err ~4e-5), avoids MUFU
__device__ __forceinline__ float fexp(float x) {
    x = fminf(fmaxf(x, -80.f), 80.f);
    float y = x * 1.4426950408889634f;
    float n = rintf(y);
    float f = y - n;
    float p = fmaf(f, 0.009618130f, 0.055504110f);
    p = fmaf(p, f, 0.240226507f);
    p = fmaf(p, f, 0.693147181f);
    p = fmaf(p, f, 1.0f);
    return p * __int_as_float(((int)n + 127) << 23);
}

// fused weight pre-round: all 5 dense weights -> single bf16, one launch
#define SPL0 (HID*QKV_N/4)
#define SPL1 (SPL0 + QDIM*2048/4)
#define SPL2 (SPL1 + 2048*HID/4)
#define SPL3 (SPL2 + HID*2*IDIM/4)
#define SPL4 (SPL3 + IDIM*HID/4)
__global__ void split_all_k(const float* __restrict__ W0, const float* __restrict__ W1,
                            const float* __restrict__ W2, const float* __restrict__ W3,
                            const float* __restrict__ W4)
{
    int i = blockIdx.x * 256 + threadIdx.x;
    if (i >= SPL4) return;
    const float* W; __nv_bfloat16 *Wh; int j;
    if (i < SPL0)      { W = W0; Wh = g_wqkvh; j = i; }
    else if (i < SPL1) { W = W1; Wh = g_wqh;   j = i - SPL0; }
    else if (i < SPL2) { W = W2; Wh = g_woh;   j = i - SPL1; }
    else if (i < SPL3) { W = W3; Wh = g_wguh;  j = i - SPL2; }
    else               { W = W4; Wh = g_wdh;   j = i - SPL3; }
    float4 v = ((const float4*)W)[j];
    uint32_t h0 = pack_hi(v.x, v.y), h1 = pack_hi(v.z, v.w);
    ((uint2*)Wh)[j] = make_uint2(h0, h1);
}

// ------------------------- GEMM: 64-row tiles, 128 thr, 2-pass --------------
#define LDA 40
#define LDB 136
#define ASZ (64*LDA*2)           // 5120 bytes per A array
#define BSZ (32*LDB*2)           // 8704 bytes per B array
#define OFF_AH(b) ((b) * (2*ASZ))
#define OFF_AL(b) ((b) * (2*ASZ) + ASZ)
#define OFF_BH(b) (6*ASZ + (b) * BSZ)
#define OFF_TOK   (6*ASZ + 3*BSZ)
#define SMEM_TOTAL_G (OFF_TOK + 64*4)

// MODE 0: plain  C = A@B (+add) fp32       (64 rows x 128 out cols / CTA)
// MODE 1: gated  Ch/Cl = split(silu(A@Bg)*(A@Bu))  (64 rows x 64 cols, up at +upOff)
// MODE 2: moe gathered gated -> split rows off+r
// MODE 3: moe scatter: C[tok] += w * (A@B)  fp32 atomic
// BSPLIT=1: B1 pre-rounded bf16 (pure cp.async, 3-stage ring)
// BSPLIT=0: B1 fp32, inline convert to bf16 (2-stage)
// All paths 2-pass: D = Ah*B + Al*B  (B single bf16)
template<int MODE, int BSPLIT>
__global__ __launch_bounds__(128, 3) void gemm_tc(
    const __nv_bfloat16* __restrict__ Ah, const __nv_bfloat16* __restrict__ Al,
    const void* __restrict__ B1,
    float* __restrict__ C, __nv_bfloat16* __restrict__ Ch, __nv_bfloat16* __restrict__ Cl,
    const float* __restrict__ add,
    int K, int lda, int ldb, int ldc, int upOff, size_t bStride)
{
    int cnt = 0, off = 0;
    size_t bOff = 0;
    if (MODE >= 2) {
        int e = blockIdx.z;
        cnt = g_cnt[e];
        if ((int)blockIdx.y * 64 >= cnt) return;
        off = g_off[e];
        bOff = bStride * e;
    }
    const int m0 = blockIdx.y * 64;
    const int nb = blockIdx.x * ((MODE == 1 || MODE == 2) ? 64 : 128);

    extern __shared__ __align__(16) char sm[];
    int* sTok = (int*)(sm + OFF_TOK);
    const uint32_t sb = s2u(sm);

    const int tid = threadIdx.x;
    const int wid = tid >> 5, lane = tid & 31;
    const int wm = wid >> 1, wn = wid & 1;

    if (MODE == 2 && tid < 64) {
        int gr = m0 + tid;
        sTok[tid] = (gr < cnt) ? g_ptok[off + gr] : 0;
    }
    __syncthreads();

    float acc[2][8][4] = {};
    const int lrow = lane & 15, lcol8 = (lane >> 4) * 8;
    const int nkt = K >> 5;

    // per-thread A cp.async indices: 2 segments (tid, tid+128); 256 segs total
    const int am0 = tid >> 2, aseg0 = (tid & 3);
    const int am1 = (tid + 128) >> 2, aseg1 = ((tid + 128) & 3);
    size_t arow0, arow1;
    {
        if (MODE == 2) {
            arow0 = (size_t)sTok[am0] * lda;
            arow1 = (size_t)sTok[am1] * lda;
        } else if (MODE == 3) {
            int r0 = (m0 + am0 < cnt) ? m0 + am0 : 0;
            int r1 = (m0 + am1 < cnt) ? m0 + am1 : 0;
            arow0 = (size_t)(off + r0) * lda;
            arow1 = (size_t)(off + r1) * lda;
        } else {
            arow0 = (size_t)(m0 + am0) * lda;
            arow1 = (size_t)(m0 + am1) * lda;
        }
    }
    const uint32_t adst0 = sb + am0 * (LDA*2) + aseg0 * 16;
    const uint32_t adst1 = sb + am1 * (LDA*2) + aseg1 * 16;
    const int aoff0 = aseg0 * 8, aoff1 = aseg1 * 8;

    if (BSPLIT) {
        // ============= pure cp.async path (dense, B pre-rounded bf16) ========
        const __nv_bfloat16* Bh = (const __nv_bfloat16*)B1;

        uint32_t bdst[4]; size_t bsrc[4];
        #pragma unroll
        for (int it = 0; it < 4; it++) {
            int seg = tid + it * 128;
            int kk = seg >> 4, cs = (seg & 15) * 8;
            int col;
            if (MODE == 1) col = (cs < 64) ? nb + cs : upOff + nb + (cs - 64);
            else           col = nb + cs;
            bsrc[it] = (size_t)kk * ldb + col;
            bdst[it] = sb + kk * (LDB*2) + cs * 2;
        }

        auto issue = [&](int bf, int k0) {
            cpa16(adst0 + OFF_AH(bf), Ah + arow0 + k0 + aoff0);
            cpa16(adst0 + OFF_AL(bf), Al + arow0 + k0 + aoff0);
            cpa16(adst1 + OFF_AH(bf), Ah + arow1 + k0 + aoff1);
            cpa16(adst1 + OFF_AL(bf), Al + arow1 + k0 + aoff1);
            #pragma unroll
            for (int it = 0; it < 4; it++) {
                size_t s = bsrc[it] + (size_t)k0 * ldb;
                cpa16(bdst[it] + OFF_BH(bf), Bh + s);
            }
            CPA_COMMIT();
        };

        issue(0, 0);
        if (nkt > 1) issue(1, 32);

        int bf = 0;
        for (int c = 0; c < nkt; c++) {
            if (c + 1 < nkt) { CPA_WAIT1(); } else { CPA_WAIT0(); }
            __syncthreads();
            if (c + 2 < nkt) {
                int nb3 = bf + 2; if (nb3 >= 3) nb3 -= 3;
                issue(nb3, (c + 2) << 5);
            }
            const uint32_t uAh = sb + OFF_AH(bf), uAl = sb + OFF_AL(bf);
            const uint32_t uBh = sb + OFF_BH(bf);
            #pragma unroll
            for (int ks = 0; ks < 2; ks++) {
                uint32_t ah[2][4], al[2][4];
                #pragma unroll
                for (int mf = 0; mf < 2; mf++) {
                    uint32_t ro = (uint32_t)((wm * 32 + mf * 16 + lrow) * LDA + ks * 16 + lcol8) * 2;
                    ldsm4(ah[mf], uAh + ro);
                    ldsm4(al[mf], uAl + ro);
                }
                #pragma unroll
                for (int nh = 0; nh < 4; nh++) {
                    uint32_t bh[4];
                    uint32_t ro = (uint32_t)((ks * 16 + lrow) * LDB + wn * 64 + nh * 16 + lcol8) * 2;
                    ldsm4t(bh, uBh + ro);
                    #pragma unroll
                    for (int mf = 0; mf < 2; mf++)
                        #pragma unroll
                        for (int sub = 0; sub < 2; sub++) {
                            int nf = nh * 2 + sub;
                            mma16816(acc[mf][nf], ah[mf], bh[sub*2], bh[sub*2+1]);
                            mma16816(acc[mf][nf], al[mf], bh[sub*2], bh[sub*2+1]);
                        }
                }
            }
            bf++; if (bf >= 3) bf = 0;
        }
        __syncthreads();
    } else {
        // ============= MoE path: fp32 B -> single bf16, 2-pass ===============
        const float* B = (const float*)B1 + bOff;
        int bcol[8]; size_t brow[8];
        #pragma unroll
        for (int it = 0; it < 8; it++) {
            int i = tid + it * 128;
            int kk = i >> 5;
            int n4 = (i & 31) << 2;
            int col;
            if (MODE == 2) col = (n4 < 64) ? nb + n4 : upOff + nb + (n4 - 64);
            else           col = nb + n4;
            bcol[it] = n4;
            brow[it] = (size_t)kk * ldb + col;
        }
        float4 br[8];
        {
            cpa16(adst0 + OFF_AH(0), Ah + arow0 + aoff0);
            cpa16(adst0 + OFF_AL(0), Al + arow0 + aoff0);
            cpa16(adst1 + OFF_AH(0), Ah + arow1 + aoff1);
            cpa16(adst1 + OFF_AL(0), Al + arow1 + aoff1);
            CPA_COMMIT();
            #pragma unroll
            for (int it = 0; it < 8; it++) br[it] = *(const float4*)(B + brow[it]);
            CPA_WAIT0();
            __syncthreads();
            #pragma unroll
            for (int it = 0; it < 8; it++) {
                int i = tid + it * 128;
                int kk = i >> 5;
                uint32_t h0 = pack_hi(br[it].x, br[it].y), h1 = pack_hi(br[it].z, br[it].w);
                uint32_t* ph = (uint32_t*)(sm + OFF_BH(0) + kk * (LDB*2) + bcol[it] * 2);
                ph[0] = h0; ph[1] = h1;
            }
            __syncthreads();
        }
        int p = 0;
        for (int c = 0; c < nkt; c++) {
            const int q = p ^ 1;
            const bool more = (c + 1 < nkt);
            if (more) {
                const int k1 = (c + 1) << 5;
                cpa16(adst0 + OFF_AH(q), Ah + arow0 + k1 + aoff0);
                cpa16(adst0 + OFF_AL(q), Al + arow0 + k1 + aoff0);
                cpa16(adst1 + OFF_AH(q), Ah + arow1 + k1 + aoff1);
                cpa16(adst1 + OFF_AL(q), Al + arow1 + k1 + aoff1);
                CPA_COMMIT();
                #pragma unroll
                for (int it = 0; it < 8; it++)
                    br[it] = *(const float4*)(B + (size_t)k1 * ldb + brow[it]);
            }
            const uint32_t uAh = sb + OFF_AH(p), uAl = sb + OFF_AL(p);
            const uint32_t uBh = sb + OFF_BH(p);
            #pragma unroll
            for (int ks = 0; ks < 2; ks++) {
                uint32_t ah[2][4], al[2][4];
                #pragma unroll
                for (int mf = 0; mf < 2; mf++) {
                    uint32_t ro = (uint32_t)((wm * 32 + mf * 16 + lrow) * LDA + ks * 16 + lcol8) * 2;
                    ldsm4(ah[mf], uAh + ro);
                    ldsm4(al[mf], uAl + ro);
                }
                #pragma unroll
                for (int nh = 0; nh < 4; nh++) {
                    uint32_t bh[4];
                    uint32_t ro = (uint32_t)((ks * 16 + lrow) * LDB + wn * 64 + nh * 16 + lcol8) * 2;
                    ldsm4t(bh, uBh + ro);
                    #pragma unroll
                    for (int mf = 0; mf < 2; mf++)
                        #pragma unroll
                        for (int sub = 0; sub < 2; sub++) {
                            int nf = nh * 2 + sub;
                            mma16816(acc[mf][nf], ah[mf], bh[sub*2], bh[sub*2+1]);
                            mma16816(acc[mf][nf], al[mf], bh[sub*2], bh[sub*2+1]);
                        }
                }
            }
            if (more) {
                #pragma unroll
                for (int it = 0; it < 8; it++) {
                    int i = tid + it * 128;
                    int kk = i >> 5;
                    uint32_t h0 = pack_hi(br[it].x, br[it].y), h1 = pack_hi(br[it].z, br[it].w);
                    uint32_t* ph = (uint32_t*)(sm + OFF_BH(q) + kk * (LDB*2) + bcol[it] * 2);
                    ph[0] = h0; ph[1] = h1;
                }
                CPA_WAIT0();
                __syncthreads();
            }
            p = q;
        }
        __syncthreads();
    }

    // ---- epilogue ----
    const int r4 = lane >> 2, c2 = (lane & 3) * 2;
    if (MODE == 0) {
        #pragma unroll
        for (int mf = 0; mf < 2; mf++) {
            #pragma unroll
            for (int nf = 0; nf < 8; nf++) {
                int col = nb + wn * 64 + nf * 8 + c2;
                size_t r1 = (size_t)(m0 + wm * 32 + mf * 16 + r4);
                size_t r2 = r1 + 8;
                float v0 = acc[mf][nf][0], v1 = acc[mf][nf][1];
                float v2 = acc[mf][nf][2], v3 = acc[mf][nf][3];
                if (add) {
                    v0 += add[r1 * ldc + col]; v1 += add[r1 * ldc + col + 1];
                    v2 += add[r2 * ldc + col]; v3 += add[r2 * ldc + col + 1];
                }
                *(float2*)(C + r1 * ldc + col) = make_float2(v0, v1);
                *(float2*)(C + r2 * ldc + col) = make_float2(v2, v3);
            }
        }
    } else if (MODE == 1 || MODE == 2) {
        float* sG = (float*)sm;              // [64][65]
        if (wn == 0) {                        // gate cols 0..63
            #pragma unroll
            for (int mf = 0; mf < 2; mf++)
                #pragma unroll
                for (int nf = 0; nf < 8; nf++) {
                    int col = nf * 8 + c2;
                    int rr1 = wm * 32 + mf * 16 + r4, rr2 = rr1 + 8;
                    sG[rr1 * 65 + col]     = acc[mf][nf][0];
                    sG[rr1 * 65 + col + 1] = acc[mf][nf][1];
                    sG[rr2 * 65 + col]     = acc[mf][nf][2];
                    sG[rr2 * 65 + col + 1] = acc[mf][nf][3];
                }
        }
        __syncthreads();
        if (wn == 1) {                        // up cols -> combine
            #pragma unroll
            for (int mf = 0; mf < 2; mf++)
                #pragma unroll
                for (int nf = 0; nf < 8; nf++) {
                    int col = nf * 8 + c2;
                    int rr1 = wm * 32 + mf * 16 + r4;
                    #pragma unroll
                    for (int half = 0; half < 2; half++) {
                        int rr = rr1 + half * 8;
                        bool ok = (MODE == 1) || (m0 + rr < cnt);
                        if (ok) {
                            size_t row = (MODE == 1) ? (size_t)(m0 + rr) : (size_t)(off + m0 + rr);
                            float g0 = sG[rr * 65 + col], g1 = sG[rr * 65 + col + 1];
                            float u0 = acc[mf][nf][half * 2], u1 = acc[mf][nf][half * 2 + 1];
                            float o0 = g0 / (1.f + fexp(-g0)) * u0;
                            float o1 = g1 / (1.f + fexp(-g1)) * u1;
                            uint32_t hi, lo;
                            split2(o0, o1, hi, lo);
                            *(uint32_t*)(Ch + row * ldc + nb + col) = hi;
                            *(uint32_t*)(Cl + row * ldc + nb + col) = lo;
                        }
                    }
                }
        }
    } else {  // MODE 3
        #pragma unroll
        for (int mf = 0; mf < 2; mf++) {
            int rr1 = wm * 32 + mf * 16 + r4;
            #pragma unroll
            for (int half = 0; half < 2; half++) {
                int rr = rr1 + half * 8;
                if (m0 + rr < cnt) {
                    int tok = g_ptok[off + m0 + rr];
                    float w = g_pw[off + m0 + rr];
                    float* dst = C + (size_t)tok * ldc;
                    #pragma unroll
                    for (int nf = 0; nf < 8; nf++) {
                        int col = nb + wn * 64 + nf * 8 + c2;
                        atomicAdd(dst + col,     w * acc[mf][nf][half * 2]);
                        atomicAdd(dst + col + 1, w * acc[mf][nf][half * 2 + 1]);
                    }
                }
            }
        }
    }
}

// ------------------------- small kernels ------------------------------------
__global__ void cs_prep_k(const int* __restrict__ pos) {
    int t = blockIdx.x, i = threadIdx.x;   // 64 threads
    if (t == 0 && i < NEXP) g_cnt[i] = 0;
    double e = exp(-((double)(2 * i) / 128.0) * log(500000.0));
    float f = (float)pos[t] * (float)e;
    float sn, cs; sincosf(f, &sn, &cs);
    g_cs[t * 64 + i] = make_float2(cs, sn);
}

// rmsnorm: writes optional fp32 y + optional bf16 split yh/yl
__global__ void rmsnorm_k(const float* __restrict__ x, const float* __restrict__ w,
                          float* __restrict__ y,
                          __nv_bfloat16* __restrict__ yh, __nv_bfloat16* __restrict__ yl,
                          int cols, int ldx, int ldy)
{
    int row = blockIdx.x;
    const float* xr = x + (size_t)row * ldx;
    float ss = 0.f;
    for (int c = threadIdx.x; c < cols; c += 256) { float v = xr[c]; ss = fmaf(v, v, ss); }
    __shared__ float wred[8];
    #pragma unroll
    for (int d = 16; d; d >>= 1) ss += __shfl_xor_sync(0xffffffffu, ss, d);
    if ((threadIdx.x & 31) == 0) wred[threadIdx.x >> 5] = ss;
    __syncthreads();
    if (threadIdx.x < 32) {
        float v = (threadIdx.x < 8) ? wred[threadIdx.x] : 0.f;
        #pragma unroll
        for (int d = 4; d; d >>= 1) v += __shfl_xor_sync(0xffffffffu, v, d);
        if (threadIdx.x == 0) wred[0] = v;
    }
    __syncthreads();
    float r = rsqrtf(wred[0] / (float)cols + 1e-5f);
    for (int c = threadIdx.x; c < cols; c += 256) {
        float v = xr[c] * r * w[c];
        if (y) y[(size_t)row * ldy + c] = v;
        if (yh) {
            __nv_bfloat16 h = __float2bfloat16_rn(v);
            yh[(size_t)row * ldy + c] = h;
            yl[(size_t)row * ldy + c] = __float2bfloat16_rn(v - __bfloat162float(h));
        }
    }
}

// rope on q (reads qproj fp32, writes split bf16 with SCALE folded)
__global__ void rope_q_k(const float* __restrict__ qp,
                         __nv_bfloat16* __restrict__ qh, __nv_bfloat16* __restrict__ ql)
{
    int t = blockIdx.x;
    for (int idx = threadIdx.x; idx < NHEAD * 64; idx += 256) {
        int hh = idx >> 6, i = idx & 63;
        float2 cs = g_cs[t * 64 + i];
        const float* b = qp + (size_t)t * 2048 + hh * HD;
        float x1 = b[i], x2 = b[i + 64];
        float y1 = (x1 * cs.x - x2 * cs.y) * SCALE;
        float y2 = (x2 * cs.x + x1 * cs.y) * SCALE;
        size_t o1 = (size_t)t * 2048 + hh * HD + i;
        __nv_bfloat16 h1 = __float2bfloat16_rn(y1);
        qh[o1] = h1; ql[o1] = __float2bfloat16_rn(y1 - __bfloat162float(h1));
        __nv_bfloat16 h2 = __float2bfloat16_rn(y2);
        qh[o1 + 64] = h2; ql[o1 + 64] = __float2bfloat16_rn(y2 - __bfloat162float(h2));
    }
}

// K rope + transpose split; V single bf16
__global__ void kv_prep_k(const float* __restrict__ qkv)
{
    int t = blockIdx.x;
    int tid = threadIdx.x;   // 128
    if (tid < 64) {
        int i = tid;
        float2 cs = g_cs[t * 64 + i];
        const float* kb = qkv + (size_t)t * QKV_N + QDIM;
        float x1 = kb[i], x2 = kb[i + 64];
        float y1 = x1 * cs.x - x2 * cs.y;
        float y2 = x2 * cs.x + x1 * cs.y;
        __nv_bfloat16 h1 = __float2bfloat16_rn(y1);
        g_kth[(size_t)i * SEQ + t] = h1;
        g_ktl[(size_t)i * SEQ + t] = __float2bfloat16_rn(y1 - __bfloat162float(h1));
        __nv_bfloat16 h2 = __float2bfloat16_rn(y2);
        g_kth[(size_t)(i + 64) * SEQ + t] = h2;
        g_ktl[(size_t)(i + 64) * SEQ + t] = __float2bfloat16_rn(y2 - __bfloat162float(h2));
    }
    {
        float v = qkv[(size_t)t * QKV_N + QDIM + HD + tid];
        g_vh[(size_t)t * HD + tid] = __float2bfloat16_rn(v);
    }
}

// ------------------------- attention: bf16 HMMA flash ----------------------
// QK 3-pass; PV 2-pass (V single bf16)
#define AQ_LD 136
#define AK_LD 72
#define AV_LD 136
#define AP_LD 72
#define AOF_QH 0
#define AOF_QL 34816
#define AOF_KH 69632
#define AOF_KL 88064
#define AOF_VH 106496
#define AOF_PH 123904
#define AOF_PL 142336
#define AOF_M  160768
#define AOF_L  161280
#define AOF_RMAX 161792
#define AOF_RSUM 162816
#define ATTN_SMEM 163840

__global__ __launch_bounds__(256, 1) void attn_k(
    const __nv_bfloat16* __restrict__ Qh, const __nv_bfloat16* __restrict__ Ql,
    __nv_bfloat16* __restrict__ Oh, __nv_bfloat16* __restrict__ Ol)
{
    extern __shared__ __align__(16) char sm[];
    const int bx = blockIdx.x;
    const int qt = 15 - (bx >> 4);     // longest tiles first
    const int h = bx & 15;
    const int q0 = qt * 128;

    const int tid = threadIdx.x;
    const int wid = tid >> 5, lane = tid & 31;
    const int wm = wid >> 1, wn = wid & 1;
    const int lrow = lane & 15, lcol8 = (lane >> 4) * 8;
    const int r4 = lane >> 2, c2 = (lane & 3) * 2;

    float* sM = (float*)(sm + AOF_M);
    float* sL = (float*)(sm + AOF_L);
    float* sRmax = (float*)(sm + AOF_RMAX);   // [2][128]
    float* sRsum = (float*)(sm + AOF_RSUM);   // [2][128]
    const uint32_t uQh = s2u(sm + AOF_QH), uQl = s2u(sm + AOF_QL);
    const uint32_t uKh = s2u(sm + AOF_KH), uKl = s2u(sm + AOF_KL);
    const uint32_t uVh = s2u(sm + AOF_VH);
    const uint32_t uPh = s2u(sm + AOF_PH), uPl = s2u(sm + AOF_PL);

    // load Q tile (128 x 128, hi+lo)
    #pragma unroll
    for (int it = 0; it < 8; it++) {
        int i = tid + it * 256;          // 2048 uint4 per copy
        int r = i >> 4, c = (i & 15) << 3;
        size_t src = (size_t)(q0 + r) * 2048 + h * HD + c;
        *(uint4*)(sm + AOF_QH + r * (AQ_LD*2) + c * 2) = *(const uint4*)(Qh + src);
        *(uint4*)(sm + AOF_QL + r * (AQ_LD*2) + c * 2) = *(const uint4*)(Ql + src);
    }
    if (tid < 128) { sM[tid] = -3.0e30f; sL[tid] = 0.f; }

    float o[2][8][4] = {};
    const int nkt = 2 * qt + 2;

    for (int kt = 0; kt < nkt; kt++) {
        const int k0 = kt * 64;
        __syncthreads();
        // load K tile (transposed source [d][tok]): 128 x 64
        #pragma unroll
        for (int it = 0; it < 4; it++) {
            int i = tid + it * 256;      // 1024 uint4 per copy
            int d = i >> 3, tc = (i & 7) << 3;
            size_t src = (size_t)d * SEQ + k0 + tc;
            *(uint4*)(sm + AOF_KH + d * (AK_LD*2) + tc * 2) = *(const uint4*)(g_kth + src);
            *(uint4*)(sm + AOF_KL + d * (AK_LD*2) + tc * 2) = *(const uint4*)(g_ktl + src);
        }
        // load V tile: 64 x 128 (single bf16)
        #pragma unroll
        for (int it = 0; it < 2; it++) {
            int i = tid + it * 256;
            int r = i >> 4, c = (i & 15) << 3;
            size_t src = (size_t)(k0 + r * 2) * HD + c;
            *(uint4*)(sm + AOF_VH + (r * 2) * (AV_LD*2) + c * 2) = *(const uint4*)(g_vh + src);
            *(uint4*)(sm + AOF_VH + (r * 2 + 1) * (AV_LD*2) + c * 2) =
                *(const uint4*)(g_vh + src + HD);
        }
        __syncthreads();

        // ---- S = Q K^T (3-pass split) ----
        float sacc[2][4][4] = {};
        #pragma unroll
        for (int ks = 0; ks < 8; ks++) {
            uint32_t ah[2][4], al[2][4], bh[2][4], bl[2][4];
            #pragma unroll
            for (int mf = 0; mf < 2; mf++) {
                uint32_t ro = (uint32_t)((wm * 32 + mf * 16 + lrow) * AQ_LD + ks * 16 + lcol8) * 2;
                ldsm4(ah[mf], uQh + ro);
                ldsm4(al[mf], uQl + ro);
            }
            #pragma unroll
            for (int nh = 0; nh < 2; nh++) {
                uint32_t ro = (uint32_t)((ks * 16 + lrow) * AK_LD + wn * 32 + nh * 16 + lcol8) * 2;
                ldsm4t(bh[nh], uKh + ro);
                ldsm4t(bl[nh], uKl + ro);
            }
            #pragma unroll
            for (int mf = 0; mf < 2; mf++)
                #pragma unroll
                for (int nf = 0; nf < 4; nf++) {
                    uint32_t b0h = bh[nf >> 1][(nf & 1) * 2], b1h = bh[nf >> 1][(nf & 1) * 2 + 1];
                    uint32_t b0l = bl[nf >> 1][(nf & 1) * 2], b1l = bl[nf >> 1][(nf & 1) * 2 + 1];
                    mma16816(sacc[mf][nf], ah[mf], b0h, b1h);
                    mma16816(sacc[mf][nf], ah[mf], b0l, b1l);
                    mma16816(sacc[mf][nf], al[mf], b0h, b1h);
                }
        }

        // causal mask on diagonal tiles
        if (kt >= nkt - 2) {
            #pragma unroll
            for (int mf = 0; mf < 2; mf++)
                #pragma unroll
                for (int nf = 0; nf < 4; nf++)
                    #pragma unroll
                    for (int v = 0; v < 4; v++) {
                        int row = q0 + wm * 32 + mf * 16 + r4 + (v >= 2 ? 8 : 0);
                        int col = k0 + wn * 32 + nf * 8 + c2 + (v & 1);
                        if (col > row) sacc[mf][nf][v] = -1.0e30f;
                    }
        }

        // ---- row max (warp-local then cross-warp) ----
        float rmax[4] = {-3.0e30f, -3.0e30f, -3.0e30f, -3.0e30f};
        #pragma unroll
        for (int mf = 0; mf < 2; mf++)
            #pragma unroll
            for (int nf = 0; nf < 4; nf++) {
                rmax[mf*2]   = fmaxf(rmax[mf*2],   fmaxf(sacc[mf][nf][0], sacc[mf][nf][1]));
                rmax[mf*2+1] = fmaxf(rmax[mf*2+1], fmaxf(sacc[mf][nf][2], sacc[mf][nf][3]));
            }
        #pragma unroll
        for (int s = 0; s < 4; s++) {
            rmax[s] = fmaxf(rmax[s], __shfl_xor_sync(0xffffffffu, rmax[s], 1));
            rmax[s] = fmaxf(rmax[s], __shfl_xor_sync(0xffffffffu, rmax[s], 2));
        }
        if ((lane & 3) == 0) {
            #pragma unroll
            for (int s = 0; s < 4; s++) {
                int lr = wm * 32 + (s >> 1) * 16 + r4 + (s & 1) * 8;
                sRmax[wn * 128 + lr] = rmax[s];
            }
        }
        __syncthreads();

        float mn[4], fct[4];
        #pragma unroll
        for (int s = 0; s < 4; s++) {
            int lr = wm * 32 + (s >> 1) * 16 + r4 + (s & 1) * 8;
            float mo = sM[lr];
            float m2 = fmaxf(sRmax[lr], sRmax[128 + lr]);
            mn[s] = fmaxf(mo, m2);
            fct[s] = fexp(mo - mn[s]);
        }

        // ---- p = exp(s-mn), store split P, partial sums, rescale o ----
        float rsum[4] = {0.f, 0.f, 0.f, 0.f};
        #pragma unroll
        for (int mf = 0; mf < 2; mf++) {
            int lr0 = wm * 32 + mf * 16 + r4;
            #pragma unroll
            for (int nf = 0; nf < 4; nf++) {
                int col = wn * 32 + nf * 8 + c2;
                float p0 = fexp(sacc[mf][nf][0] - mn[mf*2]);
                float p1 = fexp(sacc[mf][nf][1] - mn[mf*2]);
                float p2 = fexp(sacc[mf][nf][2] - mn[mf*2+1]);
                float p3 = fexp(sacc[mf][nf][3] - mn[mf*2+1]);
                rsum[mf*2]   += p0 + p1;
                rsum[mf*2+1] += p2 + p3;
                uint32_t hi, lo;
                split2(p0, p1, hi, lo);
                *(uint32_t*)(sm + AOF_PH + (lr0 * AP_LD + col) * 2) = hi;
                *(uint32_t*)(sm + AOF_PL + (lr0 * AP_LD + col) * 2) = lo;
                split2(p2, p3, hi, lo);
                *(uint32_t*)(sm + AOF_PH + ((lr0 + 8) * AP_LD + col) * 2) = hi;
                *(uint32_t*)(sm + AOF_PL + ((lr0 + 8) * AP_LD + col) * 2) = lo;
            }
        }
        #pragma unroll
        for (int mf = 0; mf < 2; mf++)
            #pragma unroll
            for (int nf8 = 0; nf8 < 8; nf8++) {
                o[mf][nf8][0] *= fct[mf*2];   o[mf][nf8][1] *= fct[mf*2];
                o[mf][nf8][2] *= fct[mf*2+1]; o[mf][nf8][3] *= fct[mf*2+1];
            }
        #pragma unroll
        for (int s = 0; s < 4; s++) {
            rsum[s] += __shfl_xor_sync(0xffffffffu, rsum[s], 1);
            rsum[s] += __shfl_xor_sync(0xffffffffu, rsum[s], 2);
        }
        if ((lane & 3) == 0) {
            #pragma unroll
            for (int s = 0; s < 4; s++) {
                int lr = wm * 32 + (s >> 1) * 16 + r4 + (s & 1) * 8;
                sRsum[wn * 128 + lr] = rsum[s];
            }
        }
        __syncthreads();
        if (wn == 0 && (lane & 3) == 0) {
            #pragma unroll
            for (int s = 0; s < 4; s++) {
                int lr = wm * 32 + (s >> 1) * 16 + r4 + (s & 1) * 8;
                sL[lr] = sL[lr] * fct[s] + sRsum[lr] + sRsum[128 + lr];
                sM[lr] = mn[s];
            }
        }

        // ---- O += P V (2-pass: P split, V single) ----
        #pragma unroll
        for (int ks = 0; ks < 4; ks++) {
            uint32_t aph[2][4], apl[2][4];
            #pragma unroll
            for (int mf = 0; mf < 2; mf++) {
                uint32_t ro = (uint32_t)((wm * 32 + mf * 16 + lrow) * AP_LD + ks * 16 + lcol8) * 2;
                ldsm4(aph[mf], uPh + ro);
                ldsm4(apl[mf], uPl + ro);
            }
            #pragma unroll
            for (int nh = 0; nh < 4; nh++) {
                uint32_t bvh[4];
                uint32_t ro = (uint32_t)((ks * 16 + lrow) * AV_LD + wn * 64 + nh * 16 + lcol8) * 2;
                ldsm4t(bvh, uVh + ro);
                #pragma unroll
                for (int mf = 0; mf < 2; mf++)
                    #pragma unroll
                    for (int sub = 0; sub < 2; sub++) {
                        int nf8 = nh * 2 + sub;
                        mma16816(o[mf][nf8], aph[mf], bvh[sub*2], bvh[sub*2+1]);
                        mma16816(o[mf][nf8], apl[mf], bvh[sub*2], bvh[sub*2+1]);
                    }
            }
        }
    }
    __syncthreads();

    // ---- write O (split bf16) ----
    float inv[4];
    #pragma unroll
    for (int s = 0; s < 4; s++) {
        int lr = wm * 32 + (s >> 1) * 16 + r4 + (s & 1) * 8;
        inv[s] = 1.f / sL[lr];
    }
    #pragma unroll
    for (int mf = 0; mf < 2; mf++) {
        int row0 = q0 + wm * 32 + mf * 16 + r4;
        #pragma unroll
        for (int nf8 = 0; nf8 < 8; nf8++) {
            int col = h * HD + wn * 64 + nf8 * 8 + c2;
            uint32_t hi, lo;
            split2(o[mf][nf8][0] * inv[mf*2], o[mf][nf8][1] * inv[mf*2], hi, lo);
            *(uint32_t*)(Oh + (size_t)row0 * 2048 + col) = hi;
            *(uint32_t*)(Ol + (size_t)row0 * 2048 + col) = lo;
            split2(o[mf][nf8][2] * inv[mf*2+1], o[mf][nf8][3] * inv[mf*2+1], hi, lo);
            *(uint32_t*)(Oh + (size_t)(row0 + 8) * 2048 + col) = hi;
            *(uint32_t*)(Ol + (size_t)(row0 + 8) * 2048 + col) = lo;
        }
    }
}

// ------------------------- router / topk / scan / fill ---------------------
__global__ __launch_bounds__(256) void router_k(const float* __restrict__ X,
                                                const float* __restrict__ Wr)
{
    __shared__ float part[8][32];
    int t = blockIdx.x;
    int e = threadIdx.x & 31, p = threadIdx.x >> 5;
    const float* xr = X + (size_t)t * HID;
    float s = 0.f;
    for (int k = p * 128; k < p * 128 + 128; k++) s = fmaf(xr[k], Wr[k * 32 + e], s);
    part[p][e] = s;
    __syncthreads();
    if (threadIdx.x < 32) {
        float logit = 0.f;
        #pragma unroll
        for (int q = 0; q < 8; q++) logit += part[q][e];
        float m = logit;
        for (int d = 16; d; d >>= 1) m = fmaxf(m, __shfl_xor_sync(0xffffffffu, m, d));
        float ex = __expf(logit - m);
        float cur = ex;
        float wsel[3]; int isel[3];
        #pragma unroll
        for (int kk = 0; kk < 3; kk++) {
            float v = cur; int idx = e;
            for (int d = 16; d; d >>= 1) {
                float v2 = __shfl_xor_sync(0xffffffffu, v, d);
                int   i2 = __shfl_xor_sync(0xffffffffu, idx, d);
                if (v2 > v || (v2 == v && i2 < idx)) { v = v2; idx = i2; }
            }
            wsel[kk] = v; isel[kk] = idx;
            if (e == idx) cur = -1.f;
        }
        float tot = wsel[0] + wsel[1] + wsel[2];
        if (e < 3) { g_topi[t * 3 + e] = isel[e]; g_topw[t * 3 + e] = wsel[e] / tot; }
        if (e == 0) {
            atomicAdd(&g_cnt[isel[0]], 1);
            atomicAdd(&g_cnt[isel[1]], 1);
            atomicAdd(&g_cnt[isel[2]], 1);
        }
    }
}

__global__ void scan_k()
{
    int e = threadIdx.x;
    int c = g_cnt[e];
    int x = c;
    for (int d = 1; d < 32; d <<= 1) {
        int y = __shfl_up_sync(0xffffffffu, x, d);
        if (e >= d) x += y;
    }
    int excl = x - c;
    g_off[e] = excl;
    g_fill[e] = excl;
}

__global__ void fill_k()
{
    int t = blockIdx.x * 256 + threadIdx.x;
    if (t < SEQ) {
        #pragma unroll
        for (int k = 0; k < 3; k++) {
            int e = g_topi[t * 3 + k];
            int slot = atomicAdd(&g_fill[e], 1);
            g_ptok[slot] = t;
            g_pw[slot] = g_topw[t * 3 + k];
        }
    }
}

// ------------------------- launch ------------------------------------------
extern "C" void kernel_launch(void* const* d_in, const int* in_sizes, int n_in,
                              void* d_out, int out_size)
{
    const float* hidden   = (const float*)d_in[0];
    const float* w_in     = (const float*)d_in[1];
    const float* w_qkv    = (const float*)d_in[2];
    const float* w_inter  = (const float*)d_in[3];
    const float* w_q      = (const float*)d_in[4];
    const float* w_o      = (const float*)d_in[5];
    const float* w_post   = (const float*)d_in[6];
    const float* w_guse   = (const float*)d_in[7];
    const float* w_dse    = (const float*)d_in[8];
    const float* w_router = (const float*)d_in[9];
    const float* w_gue    = (const float*)d_in[10];
    const float* w_de     = (const float*)d_in[11];
    const int*   pos      = (const int*)d_in[12];
    float* out = (float*)d_out;

    float *qkv, *qproj, *resid2, *h2;
    cudaGetSymbolAddress((void**)&qkv,    g_qkv);
    cudaGetSymbolAddress((void**)&qproj,  g_qproj);
    cudaGetSymbolAddress((void**)&resid2, g_resid2);
    cudaGetSymbolAddress((void**)&h2,     g_h2);
    __nv_bfloat16 *hnh,*hnl,*qnh,*qnl,*qh,*ql,*aoh,*aol,*h2h,*h2l,*aseh,*asel,*aceh,*acel;
    __nv_bfloat16 *wqkvh,*wqh,*woh,*wguh,*wdh;
    cudaGetSymbolAddress((void**)&hnh, g_hnh);   cudaGetSymbolAddress((void**)&hnl, g_hnl);
    cudaGetSymbolAddress((void**)&qnh, g_qnh);   cudaGetSymbolAddress((void**)&qnl, g_qnl);
    cudaGetSymbolAddress((void**)&qh,  g_qh);    cudaGetSymbolAddress((void**)&ql,  g_ql);
    cudaGetSymbolAddress((void**)&aoh, g_aoh);   cudaGetSymbolAddress((void**)&aol, g_aol);
    cudaGetSymbolAddress((void**)&h2h, g_h2h);   cudaGetSymbolAddress((void**)&h2l, g_h2l);
    cudaGetSymbolAddress((void**)&aseh,g_aseh);  cudaGetSymbolAddress((void**)&asel,g_asel);
    cudaGetSymbolAddress((void**)&aceh,g_aceh);  cudaGetSymbolAddress((void**)&acel,g_acel);
    cudaGetSymbolAddress((void**)&wqkvh,g_wqkvh);
    cudaGetSymbolAddress((void**)&wqh, g_wqh);
    cudaGetSymbolAddress((void**)&woh, g_woh);
    cudaGetSymbolAddress((void**)&wguh,g_wguh);
    cudaGetSymbolAddress((void**)&wdh, g_wdh);

    cudaFuncSetAttribute(attn_k, cudaFuncAttributeMaxDynamicSharedMemorySize, ATTN_SMEM);
    cudaFuncSetAttribute((gemm_tc<0,1>), cudaFuncAttributeMaxDynamicSharedMemorySize, SMEM_TOTAL_G);
    cudaFuncSetAttribute((gemm_tc<1,1>), cudaFuncAttributeMaxDynamicSharedMemorySize, SMEM_TOTAL_G);
    cudaFuncSetAttribute((gemm_tc<2,0>), cudaFuncAttributeMaxDynamicSharedMemorySize, SMEM_TOTAL_G);
    cudaFuncSetAttribute((gemm_tc<3,0>), cudaFuncAttributeMaxDynamicSharedMemorySize, SMEM_TOTAL_G);

    cs_prep_k<<<SEQ, 64>>>(pos);
    split_all_k<<<(SPL4 + 255)/256, 256>>>(w_qkv, w_q, w_o, w_guse, w_dse);

    rmsnorm_k<<<SEQ, 256>>>(hidden, w_in, nullptr, hnh, hnl, HID, HID, HID);
    gemm_tc<0,1><<<dim3(QKV_N/128, SEQ/64), 128, SMEM_TOTAL_G>>>(
        hnh, hnl, wqkvh, qkv, nullptr, nullptr, nullptr, HID, HID, QKV_N, QKV_N, 0, 0);
    rmsnorm_k<<<SEQ, 256>>>(qkv, w_inter, nullptr, qnh, qnl, QDIM, QKV_N, QDIM);
    gemm_tc<0,1><<<dim3(2048/128, SEQ/64), 128, SMEM_TOTAL_G>>>(
        qnh, qnl, wqh, qproj, nullptr, nullptr, nullptr, QDIM, QDIM, 2048, 2048, 0, 0);
    rope_q_k<<<SEQ, 256>>>(qproj, qh, ql);
    kv_prep_k<<<SEQ, 128>>>(qkv);
    attn_k<<<256, 256, ATTN_SMEM>>>(qh, ql, aoh, aol);
    gemm_tc<0,1><<<dim3(HID/128, SEQ/64), 128, SMEM_TOTAL_G>>>(
        aoh, aol, woh, resid2, nullptr, nullptr, hidden, 2048, 2048, HID, HID, 0, 0);
    rmsnorm_k<<<SEQ, 256>>>(resid2, w_post, h2, h2h, h2l, HID, HID, HID);
    gemm_tc<1,1><<<dim3(IDIM/64, SEQ/64), 128, SMEM_TOTAL_G>>>(
        h2h, h2l, wguh, nullptr, aseh, asel, nullptr, HID, HID, 2*IDIM, IDIM, IDIM, 0);
    gemm_tc<0,1><<<dim3(HID/128, SEQ/64), 128, SMEM_TOTAL_G>>>(
        aseh, asel, wdh, out, nullptr, nullptr, resid2, IDIM, IDIM, HID, HID, 0, 0);
    router_k<<<SEQ, 256>>>(h2, w_router);
    scan_k<<<1, 32>>>();
    fill_k<<<SEQ/256, 256>>>();
    gemm_tc<2,0><<<dim3(IDIM/64, 32, NEXP), 128, SMEM_TOTAL_G>>>(
        h2h, h2l, w_gue, nullptr, aceh, acel, nullptr, HID, HID, 2*IDIM, IDIM, IDIM,
        (size_t)HID * 2 * IDIM);
    gemm_tc<3,0><<<dim3(HID/128, 32, NEXP), 128, SMEM_TOTAL_G>>>(
        aceh, acel, w_de, out, nullptr, nullptr, nullptr, IDIM, IDIM, HID, HID, 0,
        (size_t)IDIM * HID);
}

// round 13
// speedup vs baseline: 1.4562x; 1.0689x over previous
#include <cuda_runtime.h>
#include <cuda_bf16.h>
#include <math.h>
#include <stdint.h>

#define SEQ 2048
#define HID 1024
#define NHEAD 16
#define HD 128
#define QDIM 512
#define NEXP 32
#define IDIM 1024
#define QKV_N 768
#define SCALE 0.08838834764831845f   // 1/sqrt(128)

// ------------------------- device scratch ----------------------------------
__device__ float g_qkv[SEQ*QKV_N];
__device__ float g_qproj[SEQ*NHEAD*HD];
__device__ float g_resid2[SEQ*HID];
__device__ float g_h2[SEQ*HID];
__device__ float2 g_cs[SEQ*64];

__device__ __nv_bfloat16 g_hnh[SEQ*HID],  g_hnl[SEQ*HID];
__device__ __nv_bfloat16 g_qnh[SEQ*QDIM], g_qnl[SEQ*QDIM];
__device__ __nv_bfloat16 g_qh[SEQ*2048],  g_ql[SEQ*2048];
__device__ __nv_bfloat16 g_kth[128*SEQ],  g_ktl[128*SEQ];   // transposed [d][token]
__device__ __nv_bfloat16 g_vh[SEQ*128];
__device__ __nv_bfloat16 g_aoh[SEQ*2048], g_aol[SEQ*2048];
__device__ __nv_bfloat16 g_h2h[SEQ*HID],  g_h2l[SEQ*HID];
__device__ __nv_bfloat16 g_aseh[SEQ*IDIM],g_asel[SEQ*IDIM];
__device__ __nv_bfloat16 g_aceh[SEQ*3*IDIM];

// pre-rounded dense weights (single bf16)
__device__ __nv_bfloat16 g_wqkvh[HID*QKV_N];
__device__ __nv_bfloat16 g_wqh[QDIM*2048];
__device__ __nv_bfloat16 g_woh[2048*HID];
__device__ __nv_bfloat16 g_wguh[HID*2*IDIM];
__device__ __nv_bfloat16 g_wdh[IDIM*HID];

__device__ int   g_topi[SEQ*3];
__device__ float g_topw[SEQ*3];
__device__ int   g_cnt[NEXP];
__device__ int   g_off[NEXP];
__device__ int   g_fill[NEXP];
__device__ int   g_ptok[SEQ*3];
__device__ float g_pw[SEQ*3];

// ------------------------- helpers -----------------------------------------
__device__ __forceinline__ uint32_t s2u(const void* p) {
    uint32_t a;
    asm("{ .reg .u64 t; cvta.to.shared.u64 t, %1; cvt.u32.u64 %0, t; }" : "=r"(a) : "l"(p));
    return a;
}
__device__ __forceinline__ void ldsm4(uint32_t* r, uint32_t addr) {
    asm volatile("ldmatrix.sync.aligned.m8n8.x4.shared.b16 {%0,%1,%2,%3}, [%4];"
        : "=r"(r[0]), "=r"(r[1]), "=r"(r[2]), "=r"(r[3]) : "r"(addr));
}
__device__ __forceinline__ void ldsm4t(uint32_t* r, uint32_t addr) {
    asm volatile("ldmatrix.sync.aligned.m8n8.x4.trans.shared.b16 {%0,%1,%2,%3}, [%4];"
        : "=r"(r[0]), "=r"(r[1]), "=r"(r[2]), "=r"(r[3]) : "r"(addr));
}
__device__ __forceinline__ void mma16816(float* c, const uint32_t* a, uint32_t b0, uint32_t b1) {
    asm volatile("mma.sync.aligned.m16n8k16.row.col.f32.bf16.bf16.f32 "
        "{%0,%1,%2,%3}, {%4,%5,%6,%7}, {%8,%9}, {%0,%1,%2,%3};"
        : "+f"(c[0]), "+f"(c[1]), "+f"(c[2]), "+f"(c[3])
        : "r"(a[0]), "r"(a[1]), "r"(a[2]), "r"(a[3]), "r"(b0), "r"(b1));
}
__device__ __forceinline__ void cpa16(uint32_t dst, const void* src) {
    asm volatile("cp.async.cg.shared.global [%0], [%1], 16;" :: "r"(dst), "l"(src));
}
#define CPA_COMMIT() asm volatile("cp.async.commit_group;" ::: "memory")
#define CPA_WAIT0()  asm volatile("cp.async.wait_group 0;" ::: "memory")
#define CPA_WAIT1()  asm volatile("cp.async.wait_group 1;" ::: "memory")

__device__ __forceinline__ uint32_t pack_hi(float f0, float f1) {
    __nv_bfloat162 h = __floats2bfloat162_rn(f0, f1);
    return *(uint32_t*)&h;
}
__device__ __forceinline__ uint32_t pack_lo(float f0, float f1, uint32_t hibits) {
    __nv_bfloat162 h = *(__nv_bfloat162*)&hibits;
    __nv_bfloat162 l = __floats2bfloat162_rn(f0 - __bfloat162float(h.x),
                                             f1 - __bfloat162float(h.y));
    return *(uint32_t*)&l;
}
__device__ __forceinline__ void split2(float a, float b, uint32_t& hi, uint32_t& lo) {
    hi = pack_hi(a, b);
    lo = pack_lo(a, b, hi);
}
// FFMA-only exp (rel err ~4e-5), avoids MUFU
__device__ __forceinline__ float fexp(float x) {
    x = fminf(fmaxf(x, -80.f), 80.f);
    float y = x * 1.4426950408889634f;
    float n = rintf(y);
    float f = y - n;
    float p = fmaf(f, 0.009618130f, 0.055504110f);
    p = fmaf(p, f, 0.240226507f);
    p = fmaf(p, f, 0.693147181f);
    p = fmaf(p, f, 1.0f);
    return p * __int_as_float(((int)n + 127) << 23);
}

// fused weight pre-round: all 5 dense weights -> single bf16, one launch
#define SPL0 (HID*QKV_N/4)
#define SPL1 (SPL0 + QDIM*2048/4)
#define SPL2 (SPL1 + 2048*HID/4)
#define SPL3 (SPL2 + HID*2*IDIM/4)
#define SPL4 (SPL3 + IDIM*HID/4)
__global__ void split_all_k(const float* __restrict__ W0, const float* __restrict__ W1,
                            const float* __restrict__ W2, const float* __restrict__ W3,
                            const float* __restrict__ W4)
{
    int i = blockIdx.x * 256 + threadIdx.x;
    if (i >= SPL4) return;
    const float* W; __nv_bfloat16 *Wh; int j;
    if (i < SPL0)      { W = W0; Wh = g_wqkvh; j = i; }
    else if (i < SPL1) { W = W1; Wh = g_wqh;   j = i - SPL0; }
    else if (i < SPL2) { W = W2; Wh = g_woh;   j = i - SPL1; }
    else if (i < SPL3) { W = W3; Wh = g_wguh;  j = i - SPL2; }
    else               { W = W4; Wh = g_wdh;   j = i - SPL3; }
    float4 v = ((const float4*)W)[j];
    uint32_t h0 = pack_hi(v.x, v.y), h1 = pack_hi(v.z, v.w);
    ((uint2*)Wh)[j] = make_uint2(h0, h1);
}

// ------------------------- GEMM: 64-row tiles, 128 thr ----------------------
#define LDA 40
#define LDB 136
#define ASZ (64*LDA*2)           // 5120 bytes per A array
#define BSZ (32*LDB*2)           // 8704 bytes per B array
#define OFF_AH(b) ((b) * (2*ASZ))
#define OFF_AL(b) ((b) * (2*ASZ) + ASZ)
#define OFF_BH(b) (6*ASZ + (b) * BSZ)
#define OFF_TOK   (6*ASZ + 3*BSZ)
#define SMEM_TOTAL_G (OFF_TOK + 64*4)

// MODE 0: plain  C = A@B (+add) fp32, dense, A split 2-pass
// MODE 1: gated  Ch/Cl = split(silu(A@Bg)*(A@Bu)), dense, A split 2-pass
// MODE 2: moe gathered gated -> Ch (hi only), FULL 1-pass bf16
// MODE 3: moe scatter: C[tok] += w * (A@B), FULL 1-pass bf16
// BSPLIT=1: B1 pre-rounded bf16 (pure cp.async, 3-stage ring)
// BSPLIT=0: B1 fp32, inline convert to bf16 (2-stage)
template<int MODE, int BSPLIT>
__global__ __launch_bounds__(128, 3) void gemm_tc(
    const __nv_bfloat16* __restrict__ Ah, const __nv_bfloat16* __restrict__ Al,
    const void* __restrict__ B1,
    float* __restrict__ C, __nv_bfloat16* __restrict__ Ch, __nv_bfloat16* __restrict__ Cl,
    const float* __restrict__ add,
    int K, int lda, int ldb, int ldc, int upOff, size_t bStride)
{
    constexpr bool APASS2 = (MODE < 2);
    int cnt = 0, off = 0;
    size_t bOff = 0;
    if (MODE >= 2) {
        int e = blockIdx.z;
        cnt = g_cnt[e];
        if ((int)blockIdx.y * 64 >= cnt) return;
        off = g_off[e];
        bOff = bStride * e;
    }
    const int m0 = blockIdx.y * 64;
    const int nb = blockIdx.x * ((MODE == 1 || MODE == 2) ? 64 : 128);

    extern __shared__ __align__(16) char sm[];
    int* sTok = (int*)(sm + OFF_TOK);
    const uint32_t sb = s2u(sm);

    const int tid = threadIdx.x;
    const int wid = tid >> 5, lane = tid & 31;
    const int wm = wid >> 1, wn = wid & 1;

    if (MODE == 2 && tid < 64) {
        int gr = m0 + tid;
        sTok[tid] = (gr < cnt) ? g_ptok[off + gr] : 0;
    }
    __syncthreads();

    float acc[2][8][4] = {};
    const int lrow = lane & 15, lcol8 = (lane >> 4) * 8;
    const int nkt = K >> 5;

    // per-thread A cp.async indices: 2 segments (tid, tid+128); 256 segs total
    const int am0 = tid >> 2, aseg0 = (tid & 3);
    const int am1 = (tid + 128) >> 2, aseg1 = ((tid + 128) & 3);
    size_t arow0, arow1;
    {
        if (MODE == 2) {
            arow0 = (size_t)sTok[am0] * lda;
            arow1 = (size_t)sTok[am1] * lda;
        } else if (MODE == 3) {
            int r0 = (m0 + am0 < cnt) ? m0 + am0 : 0;
            int r1 = (m0 + am1 < cnt) ? m0 + am1 : 0;
            arow0 = (size_t)(off + r0) * lda;
            arow1 = (size_t)(off + r1) * lda;
        } else {
            arow0 = (size_t)(m0 + am0) * lda;
            arow1 = (size_t)(m0 + am1) * lda;
        }
    }
    const uint32_t adst0 = sb + am0 * (LDA*2) + aseg0 * 16;
    const uint32_t adst1 = sb + am1 * (LDA*2) + aseg1 * 16;
    const int aoff0 = aseg0 * 8, aoff1 = aseg1 * 8;

    if (BSPLIT) {
        // ============= pure cp.async path (dense, B pre-rounded bf16) ========
        const __nv_bfloat16* Bh = (const __nv_bfloat16*)B1;

        uint32_t bdst[4]; size_t bsrc[4];
        #pragma unroll
        for (int it = 0; it < 4; it++) {
            int seg = tid + it * 128;
            int kk = seg >> 4, cs = (seg & 15) * 8;
            int col;
            if (MODE == 1) col = (cs < 64) ? nb + cs : upOff + nb + (cs - 64);
            else           col = nb + cs;
            bsrc[it] = (size_t)kk * ldb + col;
            bdst[it] = sb + kk * (LDB*2) + cs * 2;
        }

        auto issue = [&](int bf, int k0) {
            cpa16(adst0 + OFF_AH(bf), Ah + arow0 + k0 + aoff0);
            cpa16(adst0 + OFF_AL(bf), Al + arow0 + k0 + aoff0);
            cpa16(adst1 + OFF_AH(bf), Ah + arow1 + k0 + aoff1);
            cpa16(adst1 + OFF_AL(bf), Al + arow1 + k0 + aoff1);
            #pragma unroll
            for (int it = 0; it < 4; it++) {
                size_t s = bsrc[it] + (size_t)k0 * ldb;
                cpa16(bdst[it] + OFF_BH(bf), Bh + s);
            }
            CPA_COMMIT();
        };

        issue(0, 0);
        if (nkt > 1) issue(1, 32);

        int bf = 0;
        for (int c = 0; c < nkt; c++) {
            if (c + 1 < nkt) { CPA_WAIT1(); } else { CPA_WAIT0(); }
            __syncthreads();
            if (c + 2 < nkt) {
                int nb3 = bf + 2; if (nb3 >= 3) nb3 -= 3;
                issue(nb3, (c + 2) << 5);
            }
            const uint32_t uAh = sb + OFF_AH(bf), uAl = sb + OFF_AL(bf);
            const uint32_t uBh = sb + OFF_BH(bf);
            #pragma unroll
            for (int ks = 0; ks < 2; ks++) {
                uint32_t ah[2][4], al[2][4];
                #pragma unroll
                for (int mf = 0; mf < 2; mf++) {
                    uint32_t ro = (uint32_t)((wm * 32 + mf * 16 + lrow) * LDA + ks * 16 + lcol8) * 2;
                    ldsm4(ah[mf], uAh + ro);
                    ldsm4(al[mf], uAl + ro);
                }
                #pragma unroll
                for (int nh = 0; nh < 4; nh++) {
                    uint32_t bh[4];
                    uint32_t ro = (uint32_t)((ks * 16 + lrow) * LDB + wn * 64 + nh * 16 + lcol8) * 2;
                    ldsm4t(bh, uBh + ro);
                    #pragma unroll
                    for (int mf = 0; mf < 2; mf++)
                        #pragma unroll
                        for (int sub = 0; sub < 2; sub++) {
                            int nf = nh * 2 + sub;
                            mma16816(acc[mf][nf], ah[mf], bh[sub*2], bh[sub*2+1]);
                            mma16816(acc[mf][nf], al[mf], bh[sub*2], bh[sub*2+1]);
                        }
                }
            }
            bf++; if (bf >= 3) bf = 0;
        }
        __syncthreads();
    } else {
        // ============= MoE path: 1-pass bf16 (A hi only, B rounded) ==========
        const float* B = (const float*)B1 + bOff;
        int bcol[8]; size_t brow[8];
        #pragma unroll
        for (int it = 0; it < 8; it++) {
            int i = tid + it * 128;
            int kk = i >> 5;
            int n4 = (i & 31) << 2;
            int col;
            if (MODE == 2) col = (n4 < 64) ? nb + n4 : upOff + nb + (n4 - 64);
            else           col = nb + n4;
            bcol[it] = n4;
            brow[it] = (size_t)kk * ldb + col;
        }
        float4 br[8];
        {
            cpa16(adst0 + OFF_AH(0), Ah + arow0 + aoff0);
            cpa16(adst1 + OFF_AH(0), Ah + arow1 + aoff1);
            CPA_COMMIT();
            #pragma unroll
            for (int it = 0; it < 8; it++) br[it] = *(const float4*)(B + brow[it]);
            CPA_WAIT0();
            __syncthreads();
            #pragma unroll
            for (int it = 0; it < 8; it++) {
                int i = tid + it * 128;
                int kk = i >> 5;
                uint32_t h0 = pack_hi(br[it].x, br[it].y), h1 = pack_hi(br[it].z, br[it].w);
                uint32_t* ph = (uint32_t*)(sm + OFF_BH(0) + kk * (LDB*2) + bcol[it] * 2);
                ph[0] = h0; ph[1] = h1;
            }
            __syncthreads();
        }
        int p = 0;
        for (int c = 0; c < nkt; c++) {
            const int q = p ^ 1;
            const bool more = (c + 1 < nkt);
            if (more) {
                const int k1 = (c + 1) << 5;
                cpa16(adst0 + OFF_AH(q), Ah + arow0 + k1 + aoff0);
                cpa16(adst1 + OFF_AH(q), Ah + arow1 + k1 + aoff1);
                CPA_COMMIT();
                #pragma unroll
                for (int it = 0; it < 8; it++)
                    br[it] = *(const float4*)(B + (size_t)k1 * ldb + brow[it]);
            }
            const uint32_t uAh = sb + OFF_AH(p);
            const uint32_t uBh = sb + OFF_BH(p);
            #pragma unroll
            for (int ks = 0; ks < 2; ks++) {
                uint32_t ah[2][4];
                #pragma unroll
                for (int mf = 0; mf < 2; mf++) {
                    uint32_t ro = (uint32_t)((wm * 32 + mf * 16 + lrow) * LDA + ks * 16 + lcol8) * 2;
                    ldsm4(ah[mf], uAh + ro);
                }
                #pragma unroll
                for (int nh = 0; nh < 4; nh++) {
                    uint32_t bh[4];
                    uint32_t ro = (uint32_t)((ks * 16 + lrow) * LDB + wn * 64 + nh * 16 + lcol8) * 2;
                    ldsm4t(bh, uBh + ro);
                    #pragma unroll
                    for (int mf = 0; mf < 2; mf++)
                        #pragma unroll
                        for (int sub = 0; sub < 2; sub++) {
                            int nf = nh * 2 + sub;
                            mma16816(acc[mf][nf], ah[mf], bh[sub*2], bh[sub*2+1]);
                        }
                }
            }
            if (more) {
                #pragma unroll
                for (int it = 0; it < 8; it++) {
                    int i = tid + it * 128;
                    int kk = i >> 5;
                    uint32_t h0 = pack_hi(br[it].x, br[it].y), h1 = pack_hi(br[it].z, br[it].w);
                    uint32_t* ph = (uint32_t*)(sm + OFF_BH(q) + kk * (LDB*2) + bcol[it] * 2);
                    ph[0] = h0; ph[1] = h1;
                }
                CPA_WAIT0();
                __syncthreads();
            }
            p = q;
        }
        __syncthreads();
    }

    // ---- epilogue ----
    const int r4 = lane >> 2, c2 = (lane & 3) * 2;
    if (MODE == 0) {
        #pragma unroll
        for (int mf = 0; mf < 2; mf++) {
            #pragma unroll
            for (int nf = 0; nf < 8; nf++) {
                int col = nb + wn * 64 + nf * 8 + c2;
                size_t r1 = (size_t)(m0 + wm * 32 + mf * 16 + r4);
                size_t r2 = r1 + 8;
                float v0 = acc[mf][nf][0], v1 = acc[mf][nf][1];
                float v2 = acc[mf][nf][2], v3 = acc[mf][nf][3];
                if (add) {
                    v0 += add[r1 * ldc + col]; v1 += add[r1 * ldc + col + 1];
                    v2 += add[r2 * ldc + col]; v3 += add[r2 * ldc + col + 1];
                }
                *(float2*)(C + r1 * ldc + col) = make_float2(v0, v1);
                *(float2*)(C + r2 * ldc + col) = make_float2(v2, v3);
            }
        }
    } else if (MODE == 1 || MODE == 2) {
        float* sG = (float*)sm;              // [64][65]
        if (wn == 0) {                        // gate cols 0..63
            #pragma unroll
            for (int mf = 0; mf < 2; mf++)
                #pragma unroll
                for (int nf = 0; nf < 8; nf++) {
                    int col = nf * 8 + c2;
                    int rr1 = wm * 32 + mf * 16 + r4, rr2 = rr1 + 8;
                    sG[rr1 * 65 + col]     = acc[mf][nf][0];
                    sG[rr1 * 65 + col + 1] = acc[mf][nf][1];
                    sG[rr2 * 65 + col]     = acc[mf][nf][2];
                    sG[rr2 * 65 + col + 1] = acc[mf][nf][3];
                }
        }
        __syncthreads();
        if (wn == 1) {                        // up cols -> combine
            #pragma unroll
            for (int mf = 0; mf < 2; mf++)
                #pragma unroll
                for (int nf = 0; nf < 8; nf++) {
                    int col = nf * 8 + c2;
                    int rr1 = wm * 32 + mf * 16 + r4;
                    #pragma unroll
                    for (int half = 0; half < 2; half++) {
                        int rr = rr1 + half * 8;
                        bool ok = (MODE == 1) || (m0 + rr < cnt);
                        if (ok) {
                            size_t row = (MODE == 1) ? (size_t)(m0 + rr) : (size_t)(off + m0 + rr);
                            float g0 = sG[rr * 65 + col], g1 = sG[rr * 65 + col + 1];
                            float u0 = acc[mf][nf][half * 2], u1 = acc[mf][nf][half * 2 + 1];
                            float o0 = g0 / (1.f + fexp(-g0)) * u0;
                            float o1 = g1 / (1.f + fexp(-g1)) * u1;
                            uint32_t hi, lo;
                            split2(o0, o1, hi, lo);
                            *(uint32_t*)(Ch + row * ldc + nb + col) = hi;
                            if (APASS2) *(uint32_t*)(Cl + row * ldc + nb + col) = lo;
                        }
                    }
                }
        }
    } else {  // MODE 3
        #pragma unroll
        for (int mf = 0; mf < 2; mf++) {
            int rr1 = wm * 32 + mf * 16 + r4;
            #pragma unroll
            for (int half = 0; half < 2; half++) {
                int rr = rr1 + half * 8;
                if (m0 + rr < cnt) {
                    int tok = g_ptok[off + m0 + rr];
                    float w = g_pw[off + m0 + rr];
                    float* dst = C + (size_t)tok * ldc;
                    #pragma unroll
                    for (int nf = 0; nf < 8; nf++) {
                        int col = nb + wn * 64 + nf * 8 + c2;
                        atomicAdd(dst + col,     w * acc[mf][nf][half * 2]);
                        atomicAdd(dst + col + 1, w * acc[mf][nf][half * 2 + 1]);
                    }
                }
            }
        }
    }
}

// ------------------------- small kernels ------------------------------------
__global__ void cs_prep_k(const int* __restrict__ pos) {
    int t = blockIdx.x, i = threadIdx.x;   // 64 threads
    if (t == 0 && i < NEXP) g_cnt[i] = 0;
    double e = exp(-((double)(2 * i) / 128.0) * log(500000.0));
    float f = (float)pos[t] * (float)e;
    float sn, cs; sincosf(f, &sn, &cs);
    g_cs[t * 64 + i] = make_float2(cs, sn);
}

// rmsnorm: writes optional fp32 y + optional bf16 split yh/yl
__global__ void rmsnorm_k(const float* __restrict__ x, const float* __restrict__ w,
                          float* __restrict__ y,
                          __nv_bfloat16* __restrict__ yh, __nv_bfloat16* __restrict__ yl,
                          int cols, int ldx, int ldy)
{
    int row = blockIdx.x;
    const float* xr = x + (size_t)row * ldx;
    float ss = 0.f;
    for (int c = threadIdx.x; c < cols; c += 256) { float v = xr[c]; ss = fmaf(v, v, ss); }
    __shared__ float wred[8];
    #pragma unroll
    for (int d = 16; d; d >>= 1) ss += __shfl_xor_sync(0xffffffffu, ss, d);
    if ((threadIdx.x & 31) == 0) wred[threadIdx.x >> 5] = ss;
    __syncthreads();
    if (threadIdx.x < 32) {
        float v = (threadIdx.x < 8) ? wred[threadIdx.x] : 0.f;
        #pragma unroll
        for (int d = 4; d; d >>= 1) v += __shfl_xor_sync(0xffffffffu, v, d);
        if (threadIdx.x == 0) wred[0] = v;
    }
    __syncthreads();
    float r = rsqrtf(wred[0] / (float)cols + 1e-5f);
    for (int c = threadIdx.x; c < cols; c += 256) {
        float v = xr[c] * r * w[c];
        if (y) y[(size_t)row * ldy + c] = v;
        if (yh) {
            __nv_bfloat16 h = __float2bfloat16_rn(v);
            yh[(size_t)row * ldy + c] = h;
            yl[(size_t)row * ldy + c] = __float2bfloat16_rn(v - __bfloat162float(h));
        }
    }
}

// rope on q (reads qproj fp32, writes split bf16 with SCALE folded)
__global__ void rope_q_k(const float* __restrict__ qp,
                         __nv_bfloat16* __restrict__ qh, __nv_bfloat16* __restrict__ ql)
{
    int t = blockIdx.x;
    for (int idx = threadIdx.x; idx < NHEAD * 64; idx += 256) {
        int hh = idx >> 6, i = idx & 63;
        float2 cs = g_cs[t * 64 + i];
        const float* b = qp + (size_t)t * 2048 + hh * HD;
        float x1 = b[i], x2 = b[i + 64];
        float y1 = (x1 * cs.x - x2 * cs.y) * SCALE;
        float y2 = (x2 * cs.x + x1 * cs.y) * SCALE;
        size_t o1 = (size_t)t * 2048 + hh * HD + i;
        __nv_bfloat16 h1 = __float2bfloat16_rn(y1);
        qh[o1] = h1; ql[o1] = __float2bfloat16_rn(y1 - __bfloat162float(h1));
        __nv_bfloat16 h2 = __float2bfloat16_rn(y2);
        qh[o1 + 64] = h2; ql[o1 + 64] = __float2bfloat16_rn(y2 - __bfloat162float(h2));
    }
}

// K rope + transpose split; V single bf16
__global__ void kv_prep_k(const float* __restrict__ qkv)
{
    int t = blockIdx.x;
    int tid = threadIdx.x;   // 128
    if (tid < 64) {
        int i = tid;
        float2 cs = g_cs[t * 64 + i];
        const float* kb = qkv + (size_t)t * QKV_N + QDIM;
        float x1 = kb[i], x2 = kb[i + 64];
        float y1 = x1 * cs.x - x2 * cs.y;
        float y2 = x2 * cs.x + x1 * cs.y;
        __nv_bfloat16 h1 = __float2bfloat16_rn(y1);
        g_kth[(size_t)i * SEQ + t] = h1;
        g_ktl[(size_t)i * SEQ + t] = __float2bfloat16_rn(y1 - __bfloat162float(h1));
        __nv_bfloat16 h2 = __float2bfloat16_rn(y2);
        g_kth[(size_t)(i + 64) * SEQ + t] = h2;
        g_ktl[(size_t)(i + 64) * SEQ + t] = __float2bfloat16_rn(y2 - __bfloat162float(h2));
    }
    {
        float v = qkv[(size_t)t * QKV_N + QDIM + HD + tid];
        g_vh[(size_t)t * HD + tid] = __float2bfloat16_rn(v);
    }
}

// ------------------------- attention: bf16 HMMA flash ----------------------
// QK 3-pass; PV 2-pass (V single bf16)
#define AQ_LD 136
#define AK_LD 72
#define AV_LD 136
#define AP_LD 72
#define AOF_QH 0
#define AOF_QL 34816
#define AOF_KH 69632
#define AOF_KL 88064
#define AOF_VH 106496
#define AOF_PH 123904
#define AOF_PL 142336
#define AOF_M  160768
#define AOF_L  161280
#define AOF_RMAX 161792
#define AOF_RSUM 162816
#define ATTN_SMEM 163840

__global__ __launch_bounds__(256, 1) void attn_k(
    const __nv_bfloat16* __restrict__ Qh, const __nv_bfloat16* __restrict__ Ql,
    __nv_bfloat16* __restrict__ Oh, __nv_bfloat16* __restrict__ Ol)
{
    extern __shared__ __align__(16) char sm[];
    const int bx = blockIdx.x;
    const int qt = 15 - (bx >> 4);     // longest tiles first
    const int h = bx & 15;
    const int q0 = qt * 128;

    const int tid = threadIdx.x;
    const int wid = tid >> 5, lane = tid & 31;
    const int wm = wid >> 1, wn = wid & 1;
    const int lrow = lane & 15, lcol8 = (lane >> 4) * 8;
    const int r4 = lane >> 2, c2 = (lane & 3) * 2;

    float* sM = (float*)(sm + AOF_M);
    float* sL = (float*)(sm + AOF_L);
    float* sRmax = (float*)(sm + AOF_RMAX);   // [2][128]
    float* sRsum = (float*)(sm + AOF_RSUM);   // [2][128]
    const uint32_t uQh = s2u(sm + AOF_QH), uQl = s2u(sm + AOF_QL);
    const uint32_t uKh = s2u(sm + AOF_KH), uKl = s2u(sm + AOF_KL);
    const uint32_t uVh = s2u(sm + AOF_VH);
    const uint32_t uPh = s2u(sm + AOF_PH), uPl = s2u(sm + AOF_PL);

    // load Q tile (128 x 128, hi+lo)
    #pragma unroll
    for (int it = 0; it < 8; it++) {
        int i = tid + it * 256;          // 2048 uint4 per copy
        int r = i >> 4, c = (i & 15) << 3;
        size_t src = (size_t)(q0 + r) * 2048 + h * HD + c;
        *(uint4*)(sm + AOF_QH + r * (AQ_LD*2) + c * 2) = *(const uint4*)(Qh + src);
        *(uint4*)(sm + AOF_QL + r * (AQ_LD*2) + c * 2) = *(const uint4*)(Ql + src);
    }
    if (tid < 128) { sM[tid] = -3.0e30f; sL[tid] = 0.f; }

    float o[2][8][4] = {};
    const int nkt = 2 * qt + 2;

    for (int kt = 0; kt < nkt; kt++) {
        const int k0 = kt * 64;
        __syncthreads();
        // load K tile (transposed source [d][tok]): 128 x 64
        #pragma unroll
        for (int it = 0; it < 4; it++) {
            int i = tid + it * 256;      // 1024 uint4 per copy
            int d = i >> 3, tc = (i & 7) << 3;
            size_t src = (size_t)d * SEQ + k0 + tc;
            *(uint4*)(sm + AOF_KH + d * (AK_LD*2) + tc * 2) = *(const uint4*)(g_kth + src);
            *(uint4*)(sm + AOF_KL + d * (AK_LD*2) + tc * 2) = *(const uint4*)(g_ktl + src);
        }
        // load V tile: 64 x 128 (single bf16)
        #pragma unroll
        for (int it = 0; it < 2; it++) {
            int i = tid + it * 256;
            int r = i >> 4, c = (i & 15) << 3;
            size_t src = (size_t)(k0 + r * 2) * HD + c;
            *(uint4*)(sm + AOF_VH + (r * 2) * (AV_LD*2) + c * 2) = *(const uint4*)(g_vh + src);
            *(uint4*)(sm + AOF_VH + (r * 2 + 1) * (AV_LD*2) + c * 2) =
                *(const uint4*)(g_vh + src + HD);
        }
        __syncthreads();

        // ---- S = Q K^T (3-pass split) ----
        float sacc[2][4][4] = {};
        #pragma unroll
        for (int ks = 0; ks < 8; ks++) {
            uint32_t ah[2][4], al[2][4], bh[2][4], bl[2][4];
            #pragma unroll
            for (int mf = 0; mf < 2; mf++) {
                uint32_t ro = (uint32_t)((wm * 32 + mf * 16 + lrow) * AQ_LD + ks * 16 + lcol8) * 2;
                ldsm4(ah[mf], uQh + ro);
                ldsm4(al[mf], uQl + ro);
            }
            #pragma unroll
            for (int nh = 0; nh < 2; nh++) {
                uint32_t ro = (uint32_t)((ks * 16 + lrow) * AK_LD + wn * 32 + nh * 16 + lcol8) * 2;
                ldsm4t(bh[nh], uKh + ro);
                ldsm4t(bl[nh], uKl + ro);
            }
            #pragma unroll
            for (int mf = 0; mf < 2; mf++)
                #pragma unroll
                for (int nf = 0; nf < 4; nf++) {
                    uint32_t b0h = bh[nf >> 1][(nf & 1) * 2], b1h = bh[nf >> 1][(nf & 1) * 2 + 1];
                    uint32_t b0l = bl[nf >> 1][(nf & 1) * 2], b1l = bl[nf >> 1][(nf & 1) * 2 + 1];
                    mma16816(sacc[mf][nf], ah[mf], b0h, b1h);
                    mma16816(sacc[mf][nf], ah[mf], b0l, b1l);
                    mma16816(sacc[mf][nf], al[mf], b0h, b1h);
                }
        }

        // causal mask on diagonal tiles
        if (kt >= nkt - 2) {
            #pragma unroll
            for (int mf = 0; mf < 2; mf++)
                #pragma unroll
                for (int nf = 0; nf < 4; nf++)
                    #pragma unroll
                    for (int v = 0; v < 4; v++) {
                        int row = q0 + wm * 32 + mf * 16 + r4 + (v >= 2 ? 8 : 0);
                        int col = k0 + wn * 32 + nf * 8 + c2 + (v & 1);
                        if (col > row) sacc[mf][nf][v] = -1.0e30f;
                    }
        }

        // ---- row max (warp-local then cross-warp) ----
        float rmax[4] = {-3.0e30f, -3.0e30f, -3.0e30f, -3.0e30f};
        #pragma unroll
        for (int mf = 0; mf < 2; mf++)
            #pragma unroll
            for (int nf = 0; nf < 4; nf++) {
                rmax[mf*2]   = fmaxf(rmax[mf*2],   fmaxf(sacc[mf][nf][0], sacc[mf][nf][1]));
                rmax[mf*2+1] = fmaxf(rmax[mf*2+1], fmaxf(sacc[mf][nf][2], sacc[mf][nf][3]));
            }
        #pragma unroll
        for (int s = 0; s < 4; s++) {
            rmax[s] = fmaxf(rmax[s], __shfl_xor_sync(0xffffffffu, rmax[s], 1));
            rmax[s] = fmaxf(rmax[s], __shfl_xor_sync(0xffffffffu, rmax[s], 2));
        }
        if ((lane & 3) == 0) {
            #pragma unroll
            for (int s = 0; s < 4; s++) {
                int lr = wm * 32 + (s >> 1) * 16 + r4 + (s & 1) * 8;
                sRmax[wn * 128 + lr] = rmax[s];
            }
        }
        __syncthreads();

        float mn[4], fct[4];
        #pragma unroll
        for (int s = 0; s < 4; s++) {
            int lr = wm * 32 + (s >> 1) * 16 + r4 + (s & 1) * 8;
            float mo = sM[lr];
            float m2 = fmaxf(sRmax[lr], sRmax[128 + lr]);
            mn[s] = fmaxf(mo, m2);
            fct[s] = fexp(mo - mn[s]);
        }

        // ---- p = exp(s-mn), store split P, partial sums, rescale o ----
        float rsum[4] = {0.f, 0.f, 0.f, 0.f};
        #pragma unroll
        for (int mf = 0; mf < 2; mf++) {
            int lr0 = wm * 32 + mf * 16 + r4;
            #pragma unroll
            for (int nf = 0; nf < 4; nf++) {
                int col = wn * 32 + nf * 8 + c2;
                float p0 = fexp(sacc[mf][nf][0] - mn[mf*2]);
                float p1 = fexp(sacc[mf][nf][1] - mn[mf*2]);
                float p2 = fexp(sacc[mf][nf][2] - mn[mf*2+1]);
                float p3 = fexp(sacc[mf][nf][3] - mn[mf*2+1]);
                rsum[mf*2]   += p0 + p1;
                rsum[mf*2+1] += p2 + p3;
                uint32_t hi, lo;
                split2(p0, p1, hi, lo);
                *(uint32_t*)(sm + AOF_PH + (lr0 * AP_LD + col) * 2) = hi;
                *(uint32_t*)(sm + AOF_PL + (lr0 * AP_LD + col) * 2) = lo;
                split2(p2, p3, hi, lo);
                *(uint32_t*)(sm + AOF_PH + ((lr0 + 8) * AP_LD + col) * 2) = hi;
                *(uint32_t*)(sm + AOF_PL + ((lr0 + 8) * AP_LD + col) * 2) = lo;
            }
        }
        #pragma unroll
        for (int mf = 0; mf < 2; mf++)
            #pragma unroll
            for (int nf8 = 0; nf8 < 8; nf8++) {
                o[mf][nf8][0] *= fct[mf*2];   o[mf][nf8][1] *= fct[mf*2];
                o[mf][nf8][2] *= fct[mf*2+1]; o[mf][nf8][3] *= fct[mf*2+1];
            }
        #pragma unroll
        for (int s = 0; s < 4; s++) {
            rsum[s] += __shfl_xor_sync(0xffffffffu, rsum[s], 1);
            rsum[s] += __shfl_xor_sync(0xffffffffu, rsum[s], 2);
        }
        if ((lane & 3) == 0) {
            #pragma unroll
            for (int s = 0; s < 4; s++) {
                int lr = wm * 32 + (s >> 1) * 16 + r4 + (s & 1) * 8;
                sRsum[wn * 128 + lr] = rsum[s];
            }
        }
        __syncthreads();
        if (wn == 0 && (lane & 3) == 0) {
            #pragma unroll
            for (int s = 0; s < 4; s++) {
                int lr = wm * 32 + (s >> 1) * 16 + r4 + (s & 1) * 8;
                sL[lr] = sL[lr] * fct[s] + sRsum[lr] + sRsum[128 + lr];
                sM[lr] = mn[s];
            }
        }

        // ---- O += P V (2-pass: P split, V single) ----
        #pragma unroll
        for (int ks = 0; ks < 4; ks++) {
            uint32_t aph[2][4], apl[2][4];
            #pragma unroll
            for (int mf = 0; mf < 2; mf++) {
                uint32_t ro = (uint32_t)((wm * 32 + mf * 16 + lrow) * AP_LD + ks * 16 + lcol8) * 2;
                ldsm4(aph[mf], uPh + ro);
                ldsm4(apl[mf], uPl + ro);
            }
            #pragma unroll
            for (int nh = 0; nh < 4; nh++) {
                uint32_t bvh[4];
                uint32_t ro = (uint32_t)((ks * 16 + lrow) * AV_LD + wn * 64 + nh * 16 + lcol8) * 2;
                ldsm4t(bvh, uVh + ro);
                #pragma unroll
                for (int mf = 0; mf < 2; mf++)
                    #pragma unroll
                    for (int sub = 0; sub < 2; sub++) {
                        int nf8 = nh * 2 + sub;
                        mma16816(o[mf][nf8], aph[mf], bvh[sub*2], bvh[sub*2+1]);
                        mma16816(o[mf][nf8], apl[mf], bvh[sub*2], bvh[sub*2+1]);
                    }
            }
        }
    }
    __syncthreads();

    // ---- write O (split bf16) ----
    float inv[4];
    #pragma unroll
    for (int s = 0; s < 4; s++) {
        int lr = wm * 32 + (s >> 1) * 16 + r4 + (s & 1) * 8;
        inv[s] = 1.f / sL[lr];
    }
    #pragma unroll
    for (int mf = 0; mf < 2; mf++) {
        int row0 = q0 + wm * 32 + mf * 16 + r4;
        #pragma unroll
        for (int nf8 = 0; nf8 < 8; nf8++) {
            int col = h * HD + wn * 64 + nf8 * 8 + c2;
            uint32_t hi, lo;
            split2(o[mf][nf8][0] * inv[mf*2], o[mf][nf8][1] * inv[mf*2], hi, lo);
            *(uint32_t*)(Oh + (size_t)row0 * 2048 + col) = hi;
            *(uint32_t*)(Ol + (size_t)row0 * 2048 + col) = lo;
            split2(o[mf][nf8][2] * inv[mf*2+1], o[mf][nf8][3] * inv[mf*2+1], hi, lo);
            *(uint32_t*)(Oh + (size_t)(row0 + 8) * 2048 + col) = hi;
            *(uint32_t*)(Ol + (size_t)(row0 + 8) * 2048 + col) = lo;
        }
    }
}

// ------------------------- router / topk / scan / fill ---------------------
__global__ __launch_bounds__(256) void router_k(const float* __restrict__ X,
                                                const float* __restrict__ Wr)
{
    __shared__ float part[8][32];
    int t = blockIdx.x;
    int e = threadIdx.x & 31, p = threadIdx.x >> 5;
    const float* xr = X + (size_t)t * HID;
    float s = 0.f;
    for (int k = p * 128; k < p * 128 + 128; k++) s = fmaf(xr[k], Wr[k * 32 + e], s);
    part[p][e] = s;
    __syncthreads();
    if (threadIdx.x < 32) {
        float logit = 0.f;
        #pragma unroll
        for (int q = 0; q < 8; q++) logit += part[q][e];
        float m = logit;
        for (int d = 16; d; d >>= 1) m = fmaxf(m, __shfl_xor_sync(0xffffffffu, m, d));
        float ex = __expf(logit - m);
        float cur = ex;
        float wsel[3]; int isel[3];
        #pragma unroll
        for (int kk = 0; kk < 3; kk++) {
            float v = cur; int idx = e;
            for (int d = 16; d; d >>= 1) {
                float v2 = __shfl_xor_sync(0xffffffffu, v, d);
                int   i2 = __shfl_xor_sync(0xffffffffu, idx, d);
                if (v2 > v || (v2 == v && i2 < idx)) { v = v2; idx = i2; }
            }
            wsel[kk] = v; isel[kk] = idx;
            if (e == idx) cur = -1.f;
        }
        float tot = wsel[0] + wsel[1] + wsel[2];
        if (e < 3) { g_topi[t * 3 + e] = isel[e]; g_topw[t * 3 + e] = wsel[e] / tot; }
        if (e == 0) {
            atomicAdd(&g_cnt[isel[0]], 1);
            atomicAdd(&g_cnt[isel[1]], 1);
            atomicAdd(&g_cnt[isel[2]], 1);
        }
    }
}

__global__ void scan_k()
{
    int e = threadIdx.x;
    int c = g_cnt[e];
    int x = c;
    for (int d = 1; d < 32; d <<= 1) {
        int y = __shfl_up_sync(0xffffffffu, x, d);
        if (e >= d) x += y;
    }
    int excl = x - c;
    g_off[e] = excl;
    g_fill[e] = excl;
}

__global__ void fill_k()
{
    int t = blockIdx.x * 256 + threadIdx.x;
    if (t < SEQ) {
        #pragma unroll
        for (int k = 0; k < 3; k++) {
            int e = g_topi[t * 3 + k];
            int slot = atomicAdd(&g_fill[e], 1);
            g_ptok[slot] = t;
            g_pw[slot] = g_topw[t * 3 + k];
        }
    }
}

// ------------------------- launch ------------------------------------------
extern "C" void kernel_launch(void* const* d_in, const int* in_sizes, int n_in,
                              void* d_out, int out_size)
{
    const float* hidden   = (const float*)d_in[0];
    const float* w_in     = (const float*)d_in[1];
    const float* w_qkv    = (const float*)d_in[2];
    const float* w_inter  = (const float*)d_in[3];
    const float* w_q      = (const float*)d_in[4];
    const float* w_o      = (const float*)d_in[5];
    const float* w_post   = (const float*)d_in[6];
    const float* w_guse   = (const float*)d_in[7];
    const float* w_dse    = (const float*)d_in[8];
    const float* w_router = (const float*)d_in[9];
    const float* w_gue    = (const float*)d_in[10];
    const float* w_de     = (const float*)d_in[11];
    const int*   pos      = (const int*)d_in[12];
    float* out = (float*)d_out;

    float *qkv, *qproj, *resid2, *h2;
    cudaGetSymbolAddress((void**)&qkv,    g_qkv);
    cudaGetSymbolAddress((void**)&qproj,  g_qproj);
    cudaGetSymbolAddress((void**)&resid2, g_resid2);
    cudaGetSymbolAddress((void**)&h2,     g_h2);
    __nv_bfloat16 *hnh,*hnl,*qnh,*qnl,*qh,*ql,*aoh,*aol,*h2h,*h2l,*aseh,*asel,*aceh;
    __nv_bfloat16 *wqkvh,*wqh,*woh,*wguh,*wdh;
    cudaGetSymbolAddress((void**)&hnh, g_hnh);   cudaGetSymbolAddress((void**)&hnl, g_hnl);
    cudaGetSymbolAddress((void**)&qnh, g_qnh);   cudaGetSymbolAddress((void**)&qnl, g_qnl);
    cudaGetSymbolAddress((void**)&qh,  g_qh);    cudaGetSymbolAddress((void**)&ql,  g_ql);
    cudaGetSymbolAddress((void**)&aoh, g_aoh);   cudaGetSymbolAddress((void**)&aol, g_aol);
    cudaGetSymbolAddress((void**)&h2h, g_h2h);   cudaGetSymbolAddress((void**)&h2l, g_h2l);
    cudaGetSymbolAddress((void**)&aseh,g_aseh);  cudaGetSymbolAddress((void**)&asel,g_asel);
    cudaGetSymbolAddress((void**)&aceh,g_aceh);
    cudaGetSymbolAddress((void**)&wqkvh,g_wqkvh);
    cudaGetSymbolAddress((void**)&wqh, g_wqh);
    cudaGetSymbolAddress((void**)&woh, g_woh);
    cudaGetSymbolAddress((void**)&wguh,g_wguh);
    cudaGetSymbolAddress((void**)&wdh, g_wdh);

    cudaFuncSetAttribute(attn_k, cudaFuncAttributeMaxDynamicSharedMemorySize, ATTN_SMEM);
    cudaFuncSetAttribute((gemm_tc<0,1>), cudaFuncAttributeMaxDynamicSharedMemorySize, SMEM_TOTAL_G);
    cudaFuncSetAttribute((gemm_tc<1,1>), cudaFuncAttributeMaxDynamicSharedMemorySize, SMEM_TOTAL_G);
    cudaFuncSetAttribute((gemm_tc<2,0>), cudaFuncAttributeMaxDynamicSharedMemorySize, SMEM_TOTAL_G);
    cudaFuncSetAttribute((gemm_tc<3,0>), cudaFuncAttributeMaxDynamicSharedMemorySize, SMEM_TOTAL_G);

    cs_prep_k<<<SEQ, 64>>>(pos);
    split_all_k<<<(SPL4 + 255)/256, 256>>>(w_qkv, w_q, w_o, w_guse, w_dse);

    rmsnorm_k<<<SEQ, 256>>>(hidden, w_in, nullptr, hnh, hnl, HID, HID, HID);
    gemm_tc<0,1><<<dim3(QKV_N/128, SEQ/64), 128, SMEM_TOTAL_G>>>(
        hnh, hnl, wqkvh, qkv, nullptr, nullptr, nullptr, HID, HID, QKV_N, QKV_N, 0, 0);
    rmsnorm_k<<<SEQ, 256>>>(qkv, w_inter, nullptr, qnh, qnl, QDIM, QKV_N, QDIM);
    gemm_tc<0,1><<<dim3(2048/128, SEQ/64), 128, SMEM_TOTAL_G>>>(
        qnh, qnl, wqh, qproj, nullptr, nullptr, nullptr, QDIM, QDIM, 2048, 2048, 0, 0);
    rope_q_k<<<SEQ, 256>>>(qproj, qh, ql);
    kv_prep_k<<<SEQ, 128>>>(qkv);
    attn_k<<<256, 256, ATTN_SMEM>>>(qh, ql, aoh, aol);
    gemm_tc<0,1><<<dim3(HID/128, SEQ/64), 128, SMEM_TOTAL_G>>>(
        aoh, aol, woh, resid2, nullptr, nullptr, hidden, 2048, 2048, HID, HID, 0, 0);
    rmsnorm_k<<<SEQ, 256>>>(resid2, w_post, h2, h2h, h2l, HID, HID, HID);
    gemm_tc<1,1><<<dim3(IDIM/64, SEQ/64), 128, SMEM_TOTAL_G>>>(
        h2h, h2l, wguh, nullptr, aseh, asel, nullptr, HID, HID, 2*IDIM, IDIM, IDIM, 0);
    gemm_tc<0,1><<<dim3(HID/128, SEQ/64), 128, SMEM_TOTAL_G>>>(
        aseh, asel, wdh, out, nullptr, nullptr, resid2, IDIM, IDIM, HID, HID, 0, 0);
    router_k<<<SEQ, 256>>>(h2, w_router);
    scan_k<<<1, 32>>>();
    fill_k<<<SEQ/256, 256>>>();
    gemm_tc<2,0><<<dim3(IDIM/64, 32, NEXP), 128, SMEM_TOTAL_G>>>(
        h2h, nullptr, w_gue, nullptr, aceh, nullptr, nullptr, HID, HID, 2*IDIM, IDIM, IDIM,
        (size_t)HID * 2 * IDIM);
    gemm_tc<3,0><<<dim3(HID/128, 32, NEXP), 128, SMEM_TOTAL_G>>>(
        aceh, nullptr, w_de, out, nullptr, nullptr, nullptr, IDIM, IDIM, HID, HID, 0,
        (size_t)IDIM * HID);
}

// round 14
// speedup vs baseline: 1.6598x; 1.1398x over previous
#include <cuda_runtime.h>
#include <cuda_bf16.h>
#include <math.h>
#include <stdint.h>

#define SEQ 2048
#define HID 1024
#define NHEAD 16
#define HD 128
#define QDIM 512
#define NEXP 32
#define IDIM 1024
#define QKV_N 768
#define SCALE 0.08838834764831845f   // 1/sqrt(128)

// ------------------------- device scratch ----------------------------------
__device__ float g_qkv[SEQ*QKV_N];
__device__ float g_qproj[SEQ*NHEAD*HD];
__device__ float g_resid2[SEQ*HID];
__device__ float g_h2[SEQ*HID];
__device__ float2 g_cs[SEQ*64];

__device__ __nv_bfloat16 g_hnh[SEQ*HID];
__device__ __nv_bfloat16 g_qnh[SEQ*QDIM];
__device__ __nv_bfloat16 g_qh[SEQ*2048],  g_ql[SEQ*2048];
__device__ __nv_bfloat16 g_kth[128*SEQ],  g_ktl[128*SEQ];   // transposed [d][token]
__device__ __nv_bfloat16 g_vh[SEQ*128];
__device__ __nv_bfloat16 g_aoh[SEQ*2048];
__device__ __nv_bfloat16 g_h2h[SEQ*HID];
__device__ __nv_bfloat16 g_aseh[SEQ*IDIM];
__device__ __nv_bfloat16 g_aceh[SEQ*3*IDIM];

// pre-rounded dense weights (single bf16)
__device__ __nv_bfloat16 g_wqkvh[HID*QKV_N];
__device__ __nv_bfloat16 g_wqh[QDIM*2048];
__device__ __nv_bfloat16 g_woh[2048*HID];
__device__ __nv_bfloat16 g_wguh[HID*2*IDIM];
__device__ __nv_bfloat16 g_wdh[IDIM*HID];

__device__ int   g_topi[SEQ*3];
__device__ float g_topw[SEQ*3];
__device__ int   g_cnt[NEXP];
__device__ int   g_off[NEXP];
__device__ int   g_fill[NEXP];
__device__ int   g_ptok[SEQ*3];
__device__ float g_pw[SEQ*3];

// ------------------------- helpers -----------------------------------------
__device__ __forceinline__ uint32_t s2u(const void* p) {
    uint32_t a;
    asm("{ .reg .u64 t; cvta.to.shared.u64 t, %1; cvt.u32.u64 %0, t; }" : "=r"(a) : "l"(p));
    return a;
}
__device__ __forceinline__ void ldsm4(uint32_t* r, uint32_t addr) {
    asm volatile("ldmatrix.sync.aligned.m8n8.x4.shared.b16 {%0,%1,%2,%3}, [%4];"
        : "=r"(r[0]), "=r"(r[1]), "=r"(r[2]), "=r"(r[3]) : "r"(addr));
}
__device__ __forceinline__ void ldsm4t(uint32_t* r, uint32_t addr) {
    asm volatile("ldmatrix.sync.aligned.m8n8.x4.trans.shared.b16 {%0,%1,%2,%3}, [%4];"
        : "=r"(r[0]), "=r"(r[1]), "=r"(r[2]), "=r"(r[3]) : "r"(addr));
}
__device__ __forceinline__ void mma16816(float* c, const uint32_t* a, uint32_t b0, uint32_t b1) {
    asm volatile("mma.sync.aligned.m16n8k16.row.col.f32.bf16.bf16.f32 "
        "{%0,%1,%2,%3}, {%4,%5,%6,%7}, {%8,%9}, {%0,%1,%2,%3};"
        : "+f"(c[0]), "+f"(c[1]), "+f"(c[2]), "+f"(c[3])
        : "r"(a[0]), "r"(a[1]), "r"(a[2]), "r"(a[3]), "r"(b0), "r"(b1));
}
__device__ __forceinline__ void cpa16(uint32_t dst, const void* src) {
    asm volatile("cp.async.cg.shared.global [%0], [%1], 16;" :: "r"(dst), "l"(src));
}
#define CPA_COMMIT() asm volatile("cp.async.commit_group;" ::: "memory")
#define CPA_WAIT0()  asm volatile("cp.async.wait_group 0;" ::: "memory")
#define CPA_WAIT1()  asm volatile("cp.async.wait_group 1;" ::: "memory")

__device__ __forceinline__ uint32_t pack_hi(float f0, float f1) {
    __nv_bfloat162 h = __floats2bfloat162_rn(f0, f1);
    return *(uint32_t*)&h;
}
__device__ __forceinline__ uint32_t pack_lo(float f0, float f1, uint32_t hibits) {
    __nv_bfloat162 h = *(__nv_bfloat162*)&hibits;
    __nv_bfloat162 l = __floats2bfloat162_rn(f0 - __bfloat162float(h.x),
                                             f1 - __bfloat162float(h.y));
    return *(uint32_t*)&l;
}
__device__ __forceinline__ void split2(float a, float b, uint32_t& hi, uint32_t& lo) {
    hi = pack_hi(a, b);
    lo = pack_lo(a, b, hi);
}
// FFMA-only exp (rel err ~4e-5), avoids MUFU
__device__ __forceinline__ float fexp(float x) {
    x = fminf(fmaxf(x, -80.f), 80.f);
    float y = x * 1.4426950408889634f;
    float n = rintf(y);
    float f = y - n;
    float p = fmaf(f, 0.009618130f, 0.055504110f);
    p = fmaf(p, f, 0.240226507f);
    p = fmaf(p, f, 0.693147181f);
    p = fmaf(p, f, 1.0f);
    return p * __int_as_float(((int)n + 127) << 23);
}

// fused weight pre-round: all 5 dense weights -> single bf16, one launch
#define SPL0 (HID*QKV_N/4)
#define SPL1 (SPL0 + QDIM*2048/4)
#define SPL2 (SPL1 + 2048*HID/4)
#define SPL3 (SPL2 + HID*2*IDIM/4)
#define SPL4 (SPL3 + IDIM*HID/4)
__global__ void split_all_k(const float* __restrict__ W0, const float* __restrict__ W1,
                            const float* __restrict__ W2, const float* __restrict__ W3,
                            const float* __restrict__ W4)
{
    int i = blockIdx.x * 256 + threadIdx.x;
    if (i >= SPL4) return;
    const float* W; __nv_bfloat16 *Wh; int j;
    if (i < SPL0)      { W = W0; Wh = g_wqkvh; j = i; }
    else if (i < SPL1) { W = W1; Wh = g_wqh;   j = i - SPL0; }
    else if (i < SPL2) { W = W2; Wh = g_woh;   j = i - SPL1; }
    else if (i < SPL3) { W = W3; Wh = g_wguh;  j = i - SPL2; }
    else               { W = W4; Wh = g_wdh;   j = i - SPL3; }
    float4 v = ((const float4*)W)[j];
    uint32_t h0 = pack_hi(v.x, v.y), h1 = pack_hi(v.z, v.w);
    ((uint2*)Wh)[j] = make_uint2(h0, h1);
}

// ------------------------- GEMM: 64-row tiles, 128 thr, 1-pass bf16 ---------
#define LDA 40
#define LDB 136
#define ASZ (64*LDA*2)           // 5120 bytes per A buffer
#define BSZ (32*LDB*2)           // 8704 bytes per B buffer
#define OFF_AH(b) ((b) * ASZ)
#define OFF_BH(b) (3*ASZ + (b) * BSZ)
#define OFF_TOK   (3*ASZ + 3*BSZ)
#define SMEM_TOTAL_G (OFF_TOK + 64*4)

// MODE 0: plain  C = A@B (+add) fp32       (64 rows x 128 out cols / CTA)
// MODE 1: gated  Ch = bf16(silu(A@Bg)*(A@Bu))  (64 rows x 64 cols, up at +upOff)
// MODE 2: moe gathered gated -> Ch rows off+r
// MODE 3: moe scatter: C[tok] += w * (A@B)  fp32 atomic
// BSPLIT=1: B1 pre-rounded bf16 (pure cp.async, 3-stage ring)
// BSPLIT=0: B1 fp32, inline convert to bf16 (2-stage)
template<int MODE, int BSPLIT>
__global__ __launch_bounds__(128, 4) void gemm_tc(
    const __nv_bfloat16* __restrict__ Ah,
    const void* __restrict__ B1,
    float* __restrict__ C, __nv_bfloat16* __restrict__ Ch,
    const float* __restrict__ add,
    int K, int lda, int ldb, int ldc, int upOff, size_t bStride)
{
    int cnt = 0, off = 0;
    size_t bOff = 0;
    if (MODE >= 2) {
        int e = blockIdx.z;
        cnt = g_cnt[e];
        if ((int)blockIdx.y * 64 >= cnt) return;
        off = g_off[e];
        bOff = bStride * e;
    }
    const int m0 = blockIdx.y * 64;
    const int nb = blockIdx.x * ((MODE == 1 || MODE == 2) ? 64 : 128);

    extern __shared__ __align__(16) char sm[];
    int* sTok = (int*)(sm + OFF_TOK);
    const uint32_t sb = s2u(sm);

    const int tid = threadIdx.x;
    const int wid = tid >> 5, lane = tid & 31;
    const int wm = wid >> 1, wn = wid & 1;

    if (MODE == 2 && tid < 64) {
        int gr = m0 + tid;
        sTok[tid] = (gr < cnt) ? g_ptok[off + gr] : 0;
    }
    __syncthreads();

    float acc[2][8][4] = {};
    const int lrow = lane & 15, lcol8 = (lane >> 4) * 8;
    const int nkt = K >> 5;

    // per-thread A cp.async indices: 2 segments (tid, tid+128); 256 segs total
    const int am0 = tid >> 2, aseg0 = (tid & 3);
    const int am1 = (tid + 128) >> 2, aseg1 = ((tid + 128) & 3);
    size_t arow0, arow1;
    {
        if (MODE == 2) {
            arow0 = (size_t)sTok[am0] * lda;
            arow1 = (size_t)sTok[am1] * lda;
        } else if (MODE == 3) {
            int r0 = (m0 + am0 < cnt) ? m0 + am0 : 0;
            int r1 = (m0 + am1 < cnt) ? m0 + am1 : 0;
            arow0 = (size_t)(off + r0) * lda;
            arow1 = (size_t)(off + r1) * lda;
        } else {
            arow0 = (size_t)(m0 + am0) * lda;
            arow1 = (size_t)(m0 + am1) * lda;
        }
    }
    const uint32_t adst0 = sb + am0 * (LDA*2) + aseg0 * 16;
    const uint32_t adst1 = sb + am1 * (LDA*2) + aseg1 * 16;
    const int aoff0 = aseg0 * 8, aoff1 = aseg1 * 8;

    if (BSPLIT) {
        // ============= pure cp.async path (dense, B pre-rounded bf16) ========
        const __nv_bfloat16* Bh = (const __nv_bfloat16*)B1;

        uint32_t bdst[4]; size_t bsrc[4];
        #pragma unroll
        for (int it = 0; it < 4; it++) {
            int seg = tid + it * 128;
            int kk = seg >> 4, cs = (seg & 15) * 8;
            int col;
            if (MODE == 1) col = (cs < 64) ? nb + cs : upOff + nb + (cs - 64);
            else           col = nb + cs;
            bsrc[it] = (size_t)kk * ldb + col;
            bdst[it] = sb + kk * (LDB*2) + cs * 2;
        }

        auto issue = [&](int bf, int k0) {
            cpa16(adst0 + OFF_AH(bf), Ah + arow0 + k0 + aoff0);
            cpa16(adst1 + OFF_AH(bf), Ah + arow1 + k0 + aoff1);
            #pragma unroll
            for (int it = 0; it < 4; it++) {
                size_t s = bsrc[it] + (size_t)k0 * ldb;
                cpa16(bdst[it] + OFF_BH(bf), Bh + s);
            }
            CPA_COMMIT();
        };

        issue(0, 0);
        if (nkt > 1) issue(1, 32);

        int bf = 0;
        for (int c = 0; c < nkt; c++) {
            if (c + 1 < nkt) { CPA_WAIT1(); } else { CPA_WAIT0(); }
            __syncthreads();
            if (c + 2 < nkt) {
                int nb3 = bf + 2; if (nb3 >= 3) nb3 -= 3;
                issue(nb3, (c + 2) << 5);
            }
            const uint32_t uAh = sb + OFF_AH(bf);
            const uint32_t uBh = sb + OFF_BH(bf);
            #pragma unroll
            for (int ks = 0; ks < 2; ks++) {
                uint32_t ah[2][4];
                #pragma unroll
                for (int mf = 0; mf < 2; mf++) {
                    uint32_t ro = (uint32_t)((wm * 32 + mf * 16 + lrow) * LDA + ks * 16 + lcol8) * 2;
                    ldsm4(ah[mf], uAh + ro);
                }
                #pragma unroll
                for (int nh = 0; nh < 4; nh++) {
                    uint32_t bh[4];
                    uint32_t ro = (uint32_t)((ks * 16 + lrow) * LDB + wn * 64 + nh * 16 + lcol8) * 2;
                    ldsm4t(bh, uBh + ro);
                    #pragma unroll
                    for (int mf = 0; mf < 2; mf++)
                        #pragma unroll
                        for (int sub = 0; sub < 2; sub++) {
                            int nf = nh * 2 + sub;
                            mma16816(acc[mf][nf], ah[mf], bh[sub*2], bh[sub*2+1]);
                        }
                }
            }
            bf++; if (bf >= 3) bf = 0;
        }
        __syncthreads();
    } else {
        // ============= MoE path: fp32 B -> single bf16 =======================
        const float* B = (const float*)B1 + bOff;
        int bcol[8]; size_t brow[8];
        #pragma unroll
        for (int it = 0; it < 8; it++) {
            int i = tid + it * 128;
            int kk = i >> 5;
            int n4 = (i & 31) << 2;
            int col;
            if (MODE == 2) col = (n4 < 64) ? nb + n4 : upOff + nb + (n4 - 64);
            else           col = nb + n4;
            bcol[it] = n4;
            brow[it] = (size_t)kk * ldb + col;
        }
        float4 br[8];
        {
            cpa16(adst0 + OFF_AH(0), Ah + arow0 + aoff0);
            cpa16(adst1 + OFF_AH(0), Ah + arow1 + aoff1);
            CPA_COMMIT();
            #pragma unroll
            for (int it = 0; it < 8; it++) br[it] = *(const float4*)(B + brow[it]);
            CPA_WAIT0();
            __syncthreads();
            #pragma unroll
            for (int it = 0; it < 8; it++) {
                int i = tid + it * 128;
                int kk = i >> 5;
                uint32_t h0 = pack_hi(br[it].x, br[it].y), h1 = pack_hi(br[it].z, br[it].w);
                uint32_t* ph = (uint32_t*)(sm + OFF_BH(0) + kk * (LDB*2) + bcol[it] * 2);
                ph[0] = h0; ph[1] = h1;
            }
            __syncthreads();
        }
        int p = 0;
        for (int c = 0; c < nkt; c++) {
            const int q = p ^ 1;
            const bool more = (c + 1 < nkt);
            if (more) {
                const int k1 = (c + 1) << 5;
                cpa16(adst0 + OFF_AH(q), Ah + arow0 + k1 + aoff0);
                cpa16(adst1 + OFF_AH(q), Ah + arow1 + k1 + aoff1);
                CPA_COMMIT();
                #pragma unroll
                for (int it = 0; it < 8; it++)
                    br[it] = *(const float4*)(B + (size_t)k1 * ldb + brow[it]);
            }
            const uint32_t uAh = sb + OFF_AH(p);
            const uint32_t uBh = sb + OFF_BH(p);
            #pragma unroll
            for (int ks = 0; ks < 2; ks++) {
                uint32_t ah[2][4];
                #pragma unroll
                for (int mf = 0; mf < 2; mf++) {
                    uint32_t ro = (uint32_t)((wm * 32 + mf * 16 + lrow) * LDA + ks * 16 + lcol8) * 2;
                    ldsm4(ah[mf], uAh + ro);
                }
                #pragma unroll
                for (int nh = 0; nh < 4; nh++) {
                    uint32_t bh[4];
                    uint32_t ro = (uint32_t)((ks * 16 + lrow) * LDB + wn * 64 + nh * 16 + lcol8) * 2;
                    ldsm4t(bh, uBh + ro);
                    #pragma unroll
                    for (int mf = 0; mf < 2; mf++)
                        #pragma unroll
                        for (int sub = 0; sub < 2; sub++) {
                            int nf = nh * 2 + sub;
                            mma16816(acc[mf][nf], ah[mf], bh[sub*2], bh[sub*2+1]);
                        }
                }
            }
            if (more) {
                #pragma unroll
                for (int it = 0; it < 8; it++) {
                    int i = tid + it * 128;
                    int kk = i >> 5;
                    uint32_t h0 = pack_hi(br[it].x, br[it].y), h1 = pack_hi(br[it].z, br[it].w);
                    uint32_t* ph = (uint32_t*)(sm + OFF_BH(q) + kk * (LDB*2) + bcol[it] * 2);
                    ph[0] = h0; ph[1] = h1;
                }
                CPA_WAIT0();
                __syncthreads();
            }
            p = q;
        }
        __syncthreads();
    }

    // ---- epilogue ----
    const int r4 = lane >> 2, c2 = (lane & 3) * 2;
    if (MODE == 0) {
        #pragma unroll
        for (int mf = 0; mf < 2; mf++) {
            #pragma unroll
            for (int nf = 0; nf < 8; nf++) {
                int col = nb + wn * 64 + nf * 8 + c2;
                size_t r1 = (size_t)(m0 + wm * 32 + mf * 16 + r4);
                size_t r2 = r1 + 8;
                float v0 = acc[mf][nf][0], v1 = acc[mf][nf][1];
                float v2 = acc[mf][nf][2], v3 = acc[mf][nf][3];
                if (add) {
                    v0 += add[r1 * ldc + col]; v1 += add[r1 * ldc + col + 1];
                    v2 += add[r2 * ldc + col]; v3 += add[r2 * ldc + col + 1];
                }
                *(float2*)(C + r1 * ldc + col) = make_float2(v0, v1);
                *(float2*)(C + r2 * ldc + col) = make_float2(v2, v3);
            }
        }
    } else if (MODE == 1 || MODE == 2) {
        float* sG = (float*)sm;              // [64][65]
        if (wn == 0) {                        // gate cols 0..63
            #pragma unroll
            for (int mf = 0; mf < 2; mf++)
                #pragma unroll
                for (int nf = 0; nf < 8; nf++) {
                    int col = nf * 8 + c2;
                    int rr1 = wm * 32 + mf * 16 + r4, rr2 = rr1 + 8;
                    sG[rr1 * 65 + col]     = acc[mf][nf][0];
                    sG[rr1 * 65 + col + 1] = acc[mf][nf][1];
                    sG[rr2 * 65 + col]     = acc[mf][nf][2];
                    sG[rr2 * 65 + col + 1] = acc[mf][nf][3];
                }
        }
        __syncthreads();
        if (wn == 1) {                        // up cols -> combine
            #pragma unroll
            for (int mf = 0; mf < 2; mf++)
                #pragma unroll
                for (int nf = 0; nf < 8; nf++) {
                    int col = nf * 8 + c2;
                    int rr1 = wm * 32 + mf * 16 + r4;
                    #pragma unroll
                    for (int half = 0; half < 2; half++) {
                        int rr = rr1 + half * 8;
                        bool ok = (MODE == 1) || (m0 + rr < cnt);
                        if (ok) {
                            size_t row = (MODE == 1) ? (size_t)(m0 + rr) : (size_t)(off + m0 + rr);
                            float g0 = sG[rr * 65 + col], g1 = sG[rr * 65 + col + 1];
                            float u0 = acc[mf][nf][half * 2], u1 = acc[mf][nf][half * 2 + 1];
                            float o0 = g0 / (1.f + fexp(-g0)) * u0;
                            float o1 = g1 / (1.f + fexp(-g1)) * u1;
                            *(uint32_t*)(Ch + row * ldc + nb + col) = pack_hi(o0, o1);
                        }
                    }
                }
        }
    } else {  // MODE 3
        #pragma unroll
        for (int mf = 0; mf < 2; mf++) {
            int rr1 = wm * 32 + mf * 16 + r4;
            #pragma unroll
            for (int half = 0; half < 2; half++) {
                int rr = rr1 + half * 8;
                if (m0 + rr < cnt) {
                    int tok = g_ptok[off + m0 + rr];
                    float w = g_pw[off + m0 + rr];
                    float* dst = C + (size_t)tok * ldc;
                    #pragma unroll
                    for (int nf = 0; nf < 8; nf++) {
                        int col = nb + wn * 64 + nf * 8 + c2;
                        atomicAdd(dst + col,     w * acc[mf][nf][half * 2]);
                        atomicAdd(dst + col + 1, w * acc[mf][nf][half * 2 + 1]);
                    }
                }
            }
        }
    }
}

// ------------------------- small kernels ------------------------------------
__global__ void cs_prep_k(const int* __restrict__ pos) {
    int t = blockIdx.x, i = threadIdx.x;   // 64 threads
    if (t == 0 && i < NEXP) g_cnt[i] = 0;
    double e = exp(-((double)(2 * i) / 128.0) * log(500000.0));
    float f = (float)pos[t] * (float)e;
    float sn, cs; sincosf(f, &sn, &cs);
    g_cs[t * 64 + i] = make_float2(cs, sn);
}

// rmsnorm: writes optional fp32 y + bf16 yh (hi only)
__global__ void rmsnorm_k(const float* __restrict__ x, const float* __restrict__ w,
                          float* __restrict__ y, __nv_bfloat16* __restrict__ yh,
                          int cols, int ldx, int ldy)
{
    int row = blockIdx.x;
    const float* xr = x + (size_t)row * ldx;
    float ss = 0.f;
    for (int c = threadIdx.x; c < cols; c += 256) { float v = xr[c]; ss = fmaf(v, v, ss); }
    __shared__ float wred[8];
    #pragma unroll
    for (int d = 16; d; d >>= 1) ss += __shfl_xor_sync(0xffffffffu, ss, d);
    if ((threadIdx.x & 31) == 0) wred[threadIdx.x >> 5] = ss;
    __syncthreads();
    if (threadIdx.x < 32) {
        float v = (threadIdx.x < 8) ? wred[threadIdx.x] : 0.f;
        #pragma unroll
        for (int d = 4; d; d >>= 1) v += __shfl_xor_sync(0xffffffffu, v, d);
        if (threadIdx.x == 0) wred[0] = v;
    }
    __syncthreads();
    float r = rsqrtf(wred[0] / (float)cols + 1e-5f);
    for (int c = threadIdx.x; c < cols; c += 256) {
        float v = xr[c] * r * w[c];
        if (y) y[(size_t)row * ldy + c] = v;
        yh[(size_t)row * ldy + c] = __float2bfloat16_rn(v);
    }
}

// rope on q (reads qproj fp32, writes split bf16 with SCALE folded) — attention needs split Q
__global__ void rope_q_k(const float* __restrict__ qp,
                         __nv_bfloat16* __restrict__ qh, __nv_bfloat16* __restrict__ ql)
{
    int t = blockIdx.x;
    for (int idx = threadIdx.x; idx < NHEAD * 64; idx += 256) {
        int hh = idx >> 6, i = idx & 63;
        float2 cs = g_cs[t * 64 + i];
        const float* b = qp + (size_t)t * 2048 + hh * HD;
        float x1 = b[i], x2 = b[i + 64];
        float y1 = (x1 * cs.x - x2 * cs.y) * SCALE;
        float y2 = (x2 * cs.x + x1 * cs.y) * SCALE;
        size_t o1 = (size_t)t * 2048 + hh * HD + i;
        __nv_bfloat16 h1 = __float2bfloat16_rn(y1);
        qh[o1] = h1; ql[o1] = __float2bfloat16_rn(y1 - __bfloat162float(h1));
        __nv_bfloat16 h2 = __float2bfloat16_rn(y2);
        qh[o1 + 64] = h2; ql[o1 + 64] = __float2bfloat16_rn(y2 - __bfloat162float(h2));
    }
}

// K rope + transpose split; V single bf16
__global__ void kv_prep_k(const float* __restrict__ qkv)
{
    int t = blockIdx.x;
    int tid = threadIdx.x;   // 128
    if (tid < 64) {
        int i = tid;
        float2 cs = g_cs[t * 64 + i];
        const float* kb = qkv + (size_t)t * QKV_N + QDIM;
        float x1 = kb[i], x2 = kb[i + 64];
        float y1 = x1 * cs.x - x2 * cs.y;
        float y2 = x2 * cs.x + x1 * cs.y;
        __nv_bfloat16 h1 = __float2bfloat16_rn(y1);
        g_kth[(size_t)i * SEQ + t] = h1;
        g_ktl[(size_t)i * SEQ + t] = __float2bfloat16_rn(y1 - __bfloat162float(h1));
        __nv_bfloat16 h2 = __float2bfloat16_rn(y2);
        g_kth[(size_t)(i + 64) * SEQ + t] = h2;
        g_ktl[(size_t)(i + 64) * SEQ + t] = __float2bfloat16_rn(y2 - __bfloat162float(h2));
    }
    {
        float v = qkv[(size_t)t * QKV_N + QDIM + HD + tid];
        g_vh[(size_t)t * HD + tid] = __float2bfloat16_rn(v);
    }
}

// ------------------------- attention: bf16 HMMA flash ----------------------
// QK 3-pass; PV 2-pass (V single bf16); O output hi-only bf16
#define AQ_LD 136
#define AK_LD 72
#define AV_LD 136
#define AP_LD 72
#define AOF_QH 0
#define AOF_QL 34816
#define AOF_KH 69632
#define AOF_KL 88064
#define AOF_VH 106496
#define AOF_PH 123904
#define AOF_PL 142336
#define AOF_M  160768
#define AOF_L  161280
#define AOF_RMAX 161792
#define AOF_RSUM 162816
#define ATTN_SMEM 163840

__global__ __launch_bounds__(256, 1) void attn_k(
    const __nv_bfloat16* __restrict__ Qh, const __nv_bfloat16* __restrict__ Ql,
    __nv_bfloat16* __restrict__ Oh)
{
    extern __shared__ __align__(16) char sm[];
    const int bx = blockIdx.x;
    const int qt = 15 - (bx >> 4);     // longest tiles first
    const int h = bx & 15;
    const int q0 = qt * 128;

    const int tid = threadIdx.x;
    const int wid = tid >> 5, lane = tid & 31;
    const int wm = wid >> 1, wn = wid & 1;
    const int lrow = lane & 15, lcol8 = (lane >> 4) * 8;
    const int r4 = lane >> 2, c2 = (lane & 3) * 2;

    float* sM = (float*)(sm + AOF_M);
    float* sL = (float*)(sm + AOF_L);
    float* sRmax = (float*)(sm + AOF_RMAX);   // [2][128]
    float* sRsum = (float*)(sm + AOF_RSUM);   // [2][128]
    const uint32_t uQh = s2u(sm + AOF_QH), uQl = s2u(sm + AOF_QL);
    const uint32_t uKh = s2u(sm + AOF_KH), uKl = s2u(sm + AOF_KL);
    const uint32_t uVh = s2u(sm + AOF_VH);
    const uint32_t uPh = s2u(sm + AOF_PH), uPl = s2u(sm + AOF_PL);

    // load Q tile (128 x 128, hi+lo)
    #pragma unroll
    for (int it = 0; it < 8; it++) {
        int i = tid + it * 256;          // 2048 uint4 per copy
        int r = i >> 4, c = (i & 15) << 3;
        size_t src = (size_t)(q0 + r) * 2048 + h * HD + c;
        *(uint4*)(sm + AOF_QH + r * (AQ_LD*2) + c * 2) = *(const uint4*)(Qh + src);
        *(uint4*)(sm + AOF_QL + r * (AQ_LD*2) + c * 2) = *(const uint4*)(Ql + src);
    }
    if (tid < 128) { sM[tid] = -3.0e30f; sL[tid] = 0.f; }

    float o[2][8][4] = {};
    const int nkt = 2 * qt + 2;

    for (int kt = 0; kt < nkt; kt++) {
        const int k0 = kt * 64;
        __syncthreads();
        // load K tile (transposed source [d][tok]): 128 x 64
        #pragma unroll
        for (int it = 0; it < 4; it++) {
            int i = tid + it * 256;      // 1024 uint4 per copy
            int d = i >> 3, tc = (i & 7) << 3;
            size_t src = (size_t)d * SEQ + k0 + tc;
            *(uint4*)(sm + AOF_KH + d * (AK_LD*2) + tc * 2) = *(const uint4*)(g_kth + src);
            *(uint4*)(sm + AOF_KL + d * (AK_LD*2) + tc * 2) = *(const uint4*)(g_ktl + src);
        }
        // load V tile: 64 x 128 (single bf16)
        #pragma unroll
        for (int it = 0; it < 2; it++) {
            int i = tid + it * 256;
            int r = i >> 4, c = (i & 15) << 3;
            size_t src = (size_t)(k0 + r * 2) * HD + c;
            *(uint4*)(sm + AOF_VH + (r * 2) * (AV_LD*2) + c * 2) = *(const uint4*)(g_vh + src);
            *(uint4*)(sm + AOF_VH + (r * 2 + 1) * (AV_LD*2) + c * 2) =
                *(const uint4*)(g_vh + src + HD);
        }
        __syncthreads();

        // ---- S = Q K^T (3-pass split) ----
        float sacc[2][4][4] = {};
        #pragma unroll
        for (int ks = 0; ks < 8; ks++) {
            uint32_t ah[2][4], al[2][4], bh[2][4], bl[2][4];
            #pragma unroll
            for (int mf = 0; mf < 2; mf++) {
                uint32_t ro = (uint32_t)((wm * 32 + mf * 16 + lrow) * AQ_LD + ks * 16 + lcol8) * 2;
                ldsm4(ah[mf], uQh + ro);
                ldsm4(al[mf], uQl + ro);
            }
            #pragma unroll
            for (int nh = 0; nh < 2; nh++) {
                uint32_t ro = (uint32_t)((ks * 16 + lrow) * AK_LD + wn * 32 + nh * 16 + lcol8) * 2;
                ldsm4t(bh[nh], uKh + ro);
                ldsm4t(bl[nh], uKl + ro);
            }
            #pragma unroll
            for (int mf = 0; mf < 2; mf++)
                #pragma unroll
                for (int nf = 0; nf < 4; nf++) {
                    uint32_t b0h = bh[nf >> 1][(nf & 1) * 2], b1h = bh[nf >> 1][(nf & 1) * 2 + 1];
                    uint32_t b0l = bl[nf >> 1][(nf & 1) * 2], b1l = bl[nf >> 1][(nf & 1) * 2 + 1];
                    mma16816(sacc[mf][nf], ah[mf], b0h, b1h);
                    mma16816(sacc[mf][nf], ah[mf], b0l, b1l);
                    mma16816(sacc[mf][nf], al[mf], b0h, b1h);
                }
        }

        // causal mask on diagonal tiles
        if (kt >= nkt - 2) {
            #pragma unroll
            for (int mf = 0; mf < 2; mf++)
                #pragma unroll
                for (int nf = 0; nf < 4; nf++)
                    #pragma unroll
                    for (int v = 0; v < 4; v++) {
                        int row = q0 + wm * 32 + mf * 16 + r4 + (v >= 2 ? 8 : 0);
                        int col = k0 + wn * 32 + nf * 8 + c2 + (v & 1);
                        if (col > row) sacc[mf][nf][v] = -1.0e30f;
                    }
        }

        // ---- row max (warp-local then cross-warp) ----
        float rmax[4] = {-3.0e30f, -3.0e30f, -3.0e30f, -3.0e30f};
        #pragma unroll
        for (int mf = 0; mf < 2; mf++)
            #pragma unroll
            for (int nf = 0; nf < 4; nf++) {
                rmax[mf*2]   = fmaxf(rmax[mf*2],   fmaxf(sacc[mf][nf][0], sacc[mf][nf][1]));
                rmax[mf*2+1] = fmaxf(rmax[mf*2+1], fmaxf(sacc[mf][nf][2], sacc[mf][nf][3]));
            }
        #pragma unroll
        for (int s = 0; s < 4; s++) {
            rmax[s] = fmaxf(rmax[s], __shfl_xor_sync(0xffffffffu, rmax[s], 1));
            rmax[s] = fmaxf(rmax[s], __shfl_xor_sync(0xffffffffu, rmax[s], 2));
        }
        if ((lane & 3) == 0) {
            #pragma unroll
            for (int s = 0; s < 4; s++) {
                int lr = wm * 32 + (s >> 1) * 16 + r4 + (s & 1) * 8;
                sRmax[wn * 128 + lr] = rmax[s];
            }
        }
        __syncthreads();

        float mn[4], fct[4];
        #pragma unroll
        for (int s = 0; s < 4; s++) {
            int lr = wm * 32 + (s >> 1) * 16 + r4 + (s & 1) * 8;
            float mo = sM[lr];
            float m2 = fmaxf(sRmax[lr], sRmax[128 + lr]);
            mn[s] = fmaxf(mo, m2);
            fct[s] = fexp(mo - mn[s]);
        }

        // ---- p = exp(s-mn), store split P, partial sums, rescale o ----
        float rsum[4] = {0.f, 0.f, 0.f, 0.f};
        #pragma unroll
        for (int mf = 0; mf < 2; mf++) {
            int lr0 = wm * 32 + mf * 16 + r4;
            #pragma unroll
            for (int nf = 0; nf < 4; nf++) {
                int col = wn * 32 + nf * 8 + c2;
                float p0 = fexp(sacc[mf][nf][0] - mn[mf*2]);
                float p1 = fexp(sacc[mf][nf][1] - mn[mf*2]);
                float p2 = fexp(sacc[mf][nf][2] - mn[mf*2+1]);
                float p3 = fexp(sacc[mf][nf][3] - mn[mf*2+1]);
                rsum[mf*2]   += p0 + p1;
                rsum[mf*2+1] += p2 + p3;
                uint32_t hi, lo;
                split2(p0, p1, hi, lo);
                *(uint32_t*)(sm + AOF_PH + (lr0 * AP_LD + col) * 2) = hi;
                *(uint32_t*)(sm + AOF_PL + (lr0 * AP_LD + col) * 2) = lo;
                split2(p2, p3, hi, lo);
                *(uint32_t*)(sm + AOF_PH + ((lr0 + 8) * AP_LD + col) * 2) = hi;
                *(uint32_t*)(sm + AOF_PL + ((lr0 + 8) * AP_LD + col) * 2) = lo;
            }
        }
        #pragma unroll
        for (int mf = 0; mf < 2; mf++)
            #pragma unroll
            for (int nf8 = 0; nf8 < 8; nf8++) {
                o[mf][nf8][0] *= fct[mf*2];   o[mf][nf8][1] *= fct[mf*2];
                o[mf][nf8][2] *= fct[mf*2+1]; o[mf][nf8][3] *= fct[mf*2+1];
            }
        #pragma unroll
        for (int s = 0; s < 4; s++) {
            rsum[s] += __shfl_xor_sync(0xffffffffu, rsum[s], 1);
            rsum[s] += __shfl_xor_sync(0xffffffffu, rsum[s], 2);
        }
        if ((lane & 3) == 0) {
            #pragma unroll
            for (int s = 0; s < 4; s++) {
                int lr = wm * 32 + (s >> 1) * 16 + r4 + (s & 1) * 8;
                sRsum[wn * 128 + lr] = rsum[s];
            }
        }
        __syncthreads();
        if (wn == 0 && (lane & 3) == 0) {
            #pragma unroll
            for (int s = 0; s < 4; s++) {
                int lr = wm * 32 + (s >> 1) * 16 + r4 + (s & 1) * 8;
                sL[lr] = sL[lr] * fct[s] + sRsum[lr] + sRsum[128 + lr];
                sM[lr] = mn[s];
            }
        }

        // ---- O += P V (2-pass: P split, V single) ----
        #pragma unroll
        for (int ks = 0; ks < 4; ks++) {
            uint32_t aph[2][4], apl[2][4];
            #pragma unroll
            for (int mf = 0; mf < 2; mf++) {
                uint32_t ro = (uint32_t)((wm * 32 + mf * 16 + lrow) * AP_LD + ks * 16 + lcol8) * 2;
                ldsm4(aph[mf], uPh + ro);
                ldsm4(apl[mf], uPl + ro);
            }
            #pragma unroll
            for (int nh = 0; nh < 4; nh++) {
                uint32_t bvh[4];
                uint32_t ro = (uint32_t)((ks * 16 + lrow) * AV_LD + wn * 64 + nh * 16 + lcol8) * 2;
                ldsm4t(bvh, uVh + ro);
                #pragma unroll
                for (int mf = 0; mf < 2; mf++)
                    #pragma unroll
                    for (int sub = 0; sub < 2; sub++) {
                        int nf8 = nh * 2 + sub;
                        mma16816(o[mf][nf8], aph[mf], bvh[sub*2], bvh[sub*2+1]);
                        mma16816(o[mf][nf8], apl[mf], bvh[sub*2], bvh[sub*2+1]);
                    }
            }
        }
    }
    __syncthreads();

    // ---- write O (hi bf16 only) ----
    float inv[4];
    #pragma unroll
    for (int s = 0; s < 4; s++) {
        int lr = wm * 32 + (s >> 1) * 16 + r4 + (s & 1) * 8;
        inv[s] = 1.f / sL[lr];
    }
    #pragma unroll
    for (int mf = 0; mf < 2; mf++) {
        int row0 = q0 + wm * 32 + mf * 16 + r4;
        #pragma unroll
        for (int nf8 = 0; nf8 < 8; nf8++) {
            int col = h * HD + wn * 64 + nf8 * 8 + c2;
            *(uint32_t*)(Oh + (size_t)row0 * 2048 + col) =
                pack_hi(o[mf][nf8][0] * inv[mf*2], o[mf][nf8][1] * inv[mf*2]);
            *(uint32_t*)(Oh + (size_t)(row0 + 8) * 2048 + col) =
                pack_hi(o[mf][nf8][2] * inv[mf*2+1], o[mf][nf8][3] * inv[mf*2+1]);
        }
    }
}

// ------------------------- router / topk / scan / fill ---------------------
__global__ __launch_bounds__(256) void router_k(const float* __restrict__ X,
                                                const float* __restrict__ Wr)
{
    __shared__ float part[8][32];
    int t = blockIdx.x;
    int e = threadIdx.x & 31, p = threadIdx.x >> 5;
    const float* xr = X + (size_t)t * HID;
    float s = 0.f;
    for (int k = p * 128; k < p * 128 + 128; k++) s = fmaf(xr[k], Wr[k * 32 + e], s);
    part[p][e] = s;
    __syncthreads();
    if (threadIdx.x < 32) {
        float logit = 0.f;
        #pragma unroll
        for (int q = 0; q < 8; q++) logit += part[q][e];
        float m = logit;
        for (int d = 16; d; d >>= 1) m = fmaxf(m, __shfl_xor_sync(0xffffffffu, m, d));
        float ex = __expf(logit - m);
        float cur = ex;
        float wsel[3]; int isel[3];
        #pragma unroll
        for (int kk = 0; kk < 3; kk++) {
            float v = cur; int idx = e;
            for (int d = 16; d; d >>= 1) {
                float v2 = __shfl_xor_sync(0xffffffffu, v, d);
                int   i2 = __shfl_xor_sync(0xffffffffu, idx, d);
                if (v2 > v || (v2 == v && i2 < idx)) { v = v2; idx = i2; }
            }
            wsel[kk] = v; isel[kk] = idx;
            if (e == idx) cur = -1.f;
        }
        float tot = wsel[0] + wsel[1] + wsel[2];
        if (e < 3) { g_topi[t * 3 + e] = isel[e]; g_topw[t * 3 + e] = wsel[e] / tot; }
        if (e == 0) {
            atomicAdd(&g_cnt[isel[0]], 1);
            atomicAdd(&g_cnt[isel[1]], 1);
            atomicAdd(&g_cnt[isel[2]], 1);
        }
    }
}

__global__ void scan_k()
{
    int e = threadIdx.x;
    int c = g_cnt[e];
    int x = c;
    for (int d = 1; d < 32; d <<= 1) {
        int y = __shfl_up_sync(0xffffffffu, x, d);
        if (e >= d) x += y;
    }
    int excl = x - c;
    g_off[e] = excl;
    g_fill[e] = excl;
}

__global__ void fill_k()
{
    int t = blockIdx.x * 256 + threadIdx.x;
    if (t < SEQ) {
        #pragma unroll
        for (int k = 0; k < 3; k++) {
            int e = g_topi[t * 3 + k];
            int slot = atomicAdd(&g_fill[e], 1);
            g_ptok[slot] = t;
            g_pw[slot] = g_topw[t * 3 + k];
        }
    }
}

// ------------------------- launch ------------------------------------------
extern "C" void kernel_launch(void* const* d_in, const int* in_sizes, int n_in,
                              void* d_out, int out_size)
{
    const float* hidden   = (const float*)d_in[0];
    const float* w_in     = (const float*)d_in[1];
    const float* w_qkv    = (const float*)d_in[2];
    const float* w_inter  = (const float*)d_in[3];
    const float* w_q      = (const float*)d_in[4];
    const float* w_o      = (const float*)d_in[5];
    const float* w_post   = (const float*)d_in[6];
    const float* w_guse   = (const float*)d_in[7];
    const float* w_dse    = (const float*)d_in[8];
    const float* w_router = (const float*)d_in[9];
    const float* w_gue    = (const float*)d_in[10];
    const float* w_de     = (const float*)d_in[11];
    const int*   pos      = (const int*)d_in[12];
    float* out = (float*)d_out;

    float *qkv, *qproj, *resid2, *h2;
    cudaGetSymbolAddress((void**)&qkv,    g_qkv);
    cudaGetSymbolAddress((void**)&qproj,  g_qproj);
    cudaGetSymbolAddress((void**)&resid2, g_resid2);
    cudaGetSymbolAddress((void**)&h2,     g_h2);
    __nv_bfloat16 *hnh,*qnh,*qh,*ql,*aoh,*h2h,*aseh,*aceh;
    __nv_bfloat16 *wqkvh,*wqh,*woh,*wguh,*wdh;
    cudaGetSymbolAddress((void**)&hnh, g_hnh);
    cudaGetSymbolAddress((void**)&qnh, g_qnh);
    cudaGetSymbolAddress((void**)&qh,  g_qh);    cudaGetSymbolAddress((void**)&ql,  g_ql);
    cudaGetSymbolAddress((void**)&aoh, g_aoh);
    cudaGetSymbolAddress((void**)&h2h, g_h2h);
    cudaGetSymbolAddress((void**)&aseh,g_aseh);
    cudaGetSymbolAddress((void**)&aceh,g_aceh);
    cudaGetSymbolAddress((void**)&wqkvh,g_wqkvh);
    cudaGetSymbolAddress((void**)&wqh, g_wqh);
    cudaGetSymbolAddress((void**)&woh, g_woh);
    cudaGetSymbolAddress((void**)&wguh,g_wguh);
    cudaGetSymbolAddress((void**)&wdh, g_wdh);

    cudaFuncSetAttribute(attn_k, cudaFuncAttributeMaxDynamicSharedMemorySize, ATTN_SMEM);
    cudaFuncSetAttribute((gemm_tc<0,1>), cudaFuncAttributeMaxDynamicSharedMemorySize, SMEM_TOTAL_G);
    cudaFuncSetAttribute((gemm_tc<1,1>), cudaFuncAttributeMaxDynamicSharedMemorySize, SMEM_TOTAL_G);
    cudaFuncSetAttribute((gemm_tc<2,0>), cudaFuncAttributeMaxDynamicSharedMemorySize, SMEM_TOTAL_G);
    cudaFuncSetAttribute((gemm_tc<3,0>), cudaFuncAttributeMaxDynamicSharedMemorySize, SMEM_TOTAL_G);

    cs_prep_k<<<SEQ, 64>>>(pos);
    split_all_k<<<(SPL4 + 255)/256, 256>>>(w_qkv, w_q, w_o, w_guse, w_dse);

    rmsnorm_k<<<SEQ, 256>>>(hidden, w_in, nullptr, hnh, HID, HID, HID);
    gemm_tc<0,1><<<dim3(QKV_N/128, SEQ/64), 128, SMEM_TOTAL_G>>>(
        hnh, wqkvh, qkv, nullptr, nullptr, HID, HID, QKV_N, QKV_N, 0, 0);
    rmsnorm_k<<<SEQ, 256>>>(qkv, w_inter, nullptr, qnh, QDIM, QKV_N, QDIM);
    gemm_tc<0,1><<<dim3(2048/128, SEQ/64), 128, SMEM_TOTAL_G>>>(
        qnh, wqh, qproj, nullptr, nullptr, QDIM, QDIM, 2048, 2048, 0, 0);
    rope_q_k<<<SEQ, 256>>>(qproj, qh, ql);
    kv_prep_k<<<SEQ, 128>>>(qkv);
    attn_k<<<256, 256, ATTN_SMEM>>>(qh, ql, aoh);
    gemm_tc<0,1><<<dim3(HID/128, SEQ/64), 128, SMEM_TOTAL_G>>>(
        aoh, woh, resid2, nullptr, hidden, 2048, 2048, HID, HID, 0, 0);
    rmsnorm_k<<<SEQ, 256>>>(resid2, w_post, h2, h2h, HID, HID, HID);
    gemm_tc<1,1><<<dim3(IDIM/64, SEQ/64), 128, SMEM_TOTAL_G>>>(
        h2h, wguh, nullptr, aseh, nullptr, HID, HID, 2*IDIM, IDIM, IDIM, 0);
    gemm_tc<0,1><<<dim3(HID/128, SEQ/64), 128, SMEM_TOTAL_G>>>(
        aseh, wdh, out, nullptr, resid2, IDIM, IDIM, HID, HID, 0, 0);
    router_k<<<SEQ, 256>>>(h2, w_router);
    scan_k<<<1, 32>>>();
    fill_k<<<SEQ/256, 256>>>();
    gemm_tc<2,0><<<dim3(IDIM/64, 32, NEXP), 128, SMEM_TOTAL_G>>>(
        h2h, w_gue, nullptr, aceh, nullptr, HID, HID, 2*IDIM, IDIM, IDIM,
        (size_t)HID * 2 * IDIM);
    gemm_tc<3,0><<<dim3(HID/128, 32, NEXP), 128, SMEM_TOTAL_G>>>(
        aceh, w_de, out, nullptr, nullptr, IDIM, IDIM, HID, HID, 0,
        (size_t)IDIM * HID);
}

// round 15
// speedup vs baseline: 1.7597x; 1.0602x over previous
#include <cuda_runtime.h>
#include <cuda_bf16.h>
#include <math.h>
#include <stdint.h>

#define SEQ 2048
#define HID 1024
#define NHEAD 16
#define HD 128
#define QDIM 512
#define NEXP 32
#define IDIM 1024
#define QKV_N 768
#define SCALE 0.08838834764831845f   // 1/sqrt(128)

// ------------------------- device scratch ----------------------------------
__device__ float g_qkv[SEQ*QKV_N];
__device__ float g_qproj[SEQ*NHEAD*HD];
__device__ float g_resid2[SEQ*HID];
__device__ float g_h2[SEQ*HID];
__device__ float2 g_cs[SEQ*64];

__device__ __nv_bfloat16 g_hnh[SEQ*HID];
__device__ __nv_bfloat16 g_qnh[SEQ*QDIM];
__device__ __nv_bfloat16 g_qh[SEQ*2048],  g_ql[SEQ*2048];
__device__ __nv_bfloat16 g_kth[128*SEQ],  g_ktl[128*SEQ];   // transposed [d][token]
__device__ __nv_bfloat16 g_vh[SEQ*128];
__device__ __nv_bfloat16 g_aoh[SEQ*2048];
__device__ __nv_bfloat16 g_h2h[SEQ*HID];
__device__ __nv_bfloat16 g_aseh[SEQ*IDIM];
__device__ __nv_bfloat16 g_aceh[SEQ*3*IDIM];

// pre-rounded dense weights (single bf16)
__device__ __nv_bfloat16 g_wqkvh[HID*QKV_N];
__device__ __nv_bfloat16 g_wqh[QDIM*2048];
__device__ __nv_bfloat16 g_woh[2048*HID];
__device__ __nv_bfloat16 g_wguh[HID*2*IDIM];
__device__ __nv_bfloat16 g_wdh[IDIM*HID];

__device__ int   g_topi[SEQ*3];
__device__ float g_topw[SEQ*3];
__device__ int   g_cnt[NEXP];
__device__ int   g_off[NEXP];
__device__ int   g_fill[NEXP];
__device__ int   g_ptok[SEQ*3];
__device__ float g_pw[SEQ*3];

// ------------------------- helpers -----------------------------------------
__device__ __forceinline__ uint32_t s2u(const void* p) {
    uint32_t a;
    asm("{ .reg .u64 t; cvta.to.shared.u64 t, %1; cvt.u32.u64 %0, t; }" : "=r"(a) : "l"(p));
    return a;
}
__device__ __forceinline__ void ldsm4(uint32_t* r, uint32_t addr) {
    asm volatile("ldmatrix.sync.aligned.m8n8.x4.shared.b16 {%0,%1,%2,%3}, [%4];"
        : "=r"(r[0]), "=r"(r[1]), "=r"(r[2]), "=r"(r[3]) : "r"(addr));
}
__device__ __forceinline__ void ldsm4t(uint32_t* r, uint32_t addr) {
    asm volatile("ldmatrix.sync.aligned.m8n8.x4.trans.shared.b16 {%0,%1,%2,%3}, [%4];"
        : "=r"(r[0]), "=r"(r[1]), "=r"(r[2]), "=r"(r[3]) : "r"(addr));
}
__device__ __forceinline__ void mma16816(float* c, const uint32_t* a, uint32_t b0, uint32_t b1) {
    asm volatile("mma.sync.aligned.m16n8k16.row.col.f32.bf16.bf16.f32 "
        "{%0,%1,%2,%3}, {%4,%5,%6,%7}, {%8,%9}, {%0,%1,%2,%3};"
        : "+f"(c[0]), "+f"(c[1]), "+f"(c[2]), "+f"(c[3])
        : "r"(a[0]), "r"(a[1]), "r"(a[2]), "r"(a[3]), "r"(b0), "r"(b1));
}
__device__ __forceinline__ void cpa16(uint32_t dst, const void* src) {
    asm volatile("cp.async.cg.shared.global [%0], [%1], 16;" :: "r"(dst), "l"(src));
}
#define CPA_COMMIT() asm volatile("cp.async.commit_group;" ::: "memory")
#define CPA_WAIT0()  asm volatile("cp.async.wait_group 0;" ::: "memory")
#define CPA_WAIT1()  asm volatile("cp.async.wait_group 1;" ::: "memory")

__device__ __forceinline__ uint32_t pack_hi(float f0, float f1) {
    __nv_bfloat162 h = __floats2bfloat162_rn(f0, f1);
    return *(uint32_t*)&h;
}
__device__ __forceinline__ uint32_t pack_lo(float f0, float f1, uint32_t hibits) {
    __nv_bfloat162 h = *(__nv_bfloat162*)&hibits;
    __nv_bfloat162 l = __floats2bfloat162_rn(f0 - __bfloat162float(h.x),
                                             f1 - __bfloat162float(h.y));
    return *(uint32_t*)&l;
}
__device__ __forceinline__ void split2(float a, float b, uint32_t& hi, uint32_t& lo) {
    hi = pack_hi(a, b);
    lo = pack_lo(a, b, hi);
}
// FFMA-only exp (rel err ~4e-5), avoids MUFU
__device__ __forceinline__ float fexp(float x) {
    x = fminf(fmaxf(x, -80.f), 80.f);
    float y = x * 1.4426950408889634f;
    float n = rintf(y);
    float f = y - n;
    float p = fmaf(f, 0.009618130f, 0.055504110f);
    p = fmaf(p, f, 0.240226507f);
    p = fmaf(p, f, 0.693147181f);
    p = fmaf(p, f, 1.0f);
    return p * __int_as_float(((int)n + 127) << 23);
}

// fused weight pre-round: all 5 dense weights -> single bf16, one launch
#define SPL0 (HID*QKV_N/4)
#define SPL1 (SPL0 + QDIM*2048/4)
#define SPL2 (SPL1 + 2048*HID/4)
#define SPL3 (SPL2 + HID*2*IDIM/4)
#define SPL4 (SPL3 + IDIM*HID/4)
__global__ void split_all_k(const float* __restrict__ W0, const float* __restrict__ W1,
                            const float* __restrict__ W2, const float* __restrict__ W3,
                            const float* __restrict__ W4)
{
    int i = blockIdx.x * 256 + threadIdx.x;
    if (i >= SPL4) return;
    const float* W; __nv_bfloat16 *Wh; int j;
    if (i < SPL0)      { W = W0; Wh = g_wqkvh; j = i; }
    else if (i < SPL1) { W = W1; Wh = g_wqh;   j = i - SPL0; }
    else if (i < SPL2) { W = W2; Wh = g_woh;   j = i - SPL1; }
    else if (i < SPL3) { W = W3; Wh = g_wguh;  j = i - SPL2; }
    else               { W = W4; Wh = g_wdh;   j = i - SPL3; }
    float4 v = ((const float4*)W)[j];
    uint32_t h0 = pack_hi(v.x, v.y), h1 = pack_hi(v.z, v.w);
    ((uint2*)Wh)[j] = make_uint2(h0, h1);
}

// ------------------------- GEMM: 64-row tiles, 128 thr, 1-pass bf16 ---------
#define LDA 40
#define LDB 136
#define ASZ (64*LDA*2)           // 5120 bytes per A buffer
#define BSZ (32*LDB*2)           // 8704 bytes per B buffer
#define OFF_AH(b) ((b) * ASZ)
#define OFF_BH(b) (3*ASZ + (b) * BSZ)
#define OFF_TOK   (3*ASZ + 3*BSZ)
#define SMEM_TOTAL_G (OFF_TOK + 64*4)

// MODE 0: plain  C = A@B (+add) fp32       (64 rows x 128 out cols / CTA)
// MODE 1: gated  Ch = bf16(silu(A@Bg)*(A@Bu))  (64 rows x 64 cols, up at +upOff)
// MODE 2: moe gathered gated -> Ch rows off+r
// MODE 3: moe scatter: C[tok] += w * (A@B)  fp32 atomic
// BSPLIT=1: B1 pre-rounded bf16 (pure cp.async, 3-stage ring)
// BSPLIT=0: B1 fp32, inline convert to bf16 (2-stage)
template<int MODE, int BSPLIT>
__global__ __launch_bounds__(128, 4) void gemm_tc(
    const __nv_bfloat16* __restrict__ Ah,
    const void* __restrict__ B1,
    float* __restrict__ C, __nv_bfloat16* __restrict__ Ch,
    const float* __restrict__ add,
    int K, int lda, int ldb, int ldc, int upOff, size_t bStride)
{
    int cnt = 0, off = 0;
    size_t bOff = 0;
    if (MODE >= 2) {
        int e = blockIdx.z;
        cnt = g_cnt[e];
        if ((int)blockIdx.y * 64 >= cnt) return;
        off = g_off[e];
        bOff = bStride * e;
    }
    const int m0 = blockIdx.y * 64;
    const int nb = blockIdx.x * ((MODE == 1 || MODE == 2) ? 64 : 128);

    extern __shared__ __align__(16) char sm[];
    int* sTok = (int*)(sm + OFF_TOK);
    const uint32_t sb = s2u(sm);

    const int tid = threadIdx.x;
    const int wid = tid >> 5, lane = tid & 31;
    const int wm = wid >> 1, wn = wid & 1;

    if (MODE == 2 && tid < 64) {
        int gr = m0 + tid;
        sTok[tid] = (gr < cnt) ? g_ptok[off + gr] : 0;
    }
    __syncthreads();

    float acc[2][8][4] = {};
    const int lrow = lane & 15, lcol8 = (lane >> 4) * 8;
    const int nkt = K >> 5;

    // per-thread A cp.async indices: 2 segments (tid, tid+128); 256 segs total
    const int am0 = tid >> 2, aseg0 = (tid & 3);
    const int am1 = (tid + 128) >> 2, aseg1 = ((tid + 128) & 3);
    size_t arow0, arow1;
    {
        if (MODE == 2) {
            arow0 = (size_t)sTok[am0] * lda;
            arow1 = (size_t)sTok[am1] * lda;
        } else if (MODE == 3) {
            int r0 = (m0 + am0 < cnt) ? m0 + am0 : 0;
            int r1 = (m0 + am1 < cnt) ? m0 + am1 : 0;
            arow0 = (size_t)(off + r0) * lda;
            arow1 = (size_t)(off + r1) * lda;
        } else {
            arow0 = (size_t)(m0 + am0) * lda;
            arow1 = (size_t)(m0 + am1) * lda;
        }
    }
    const uint32_t adst0 = sb + am0 * (LDA*2) + aseg0 * 16;
    const uint32_t adst1 = sb + am1 * (LDA*2) + aseg1 * 16;
    const int aoff0 = aseg0 * 8, aoff1 = aseg1 * 8;

    if (BSPLIT) {
        // ============= pure cp.async path (dense, B pre-rounded bf16) ========
        const __nv_bfloat16* Bh = (const __nv_bfloat16*)B1;

        uint32_t bdst[4]; size_t bsrc[4];
        #pragma unroll
        for (int it = 0; it < 4; it++) {
            int seg = tid + it * 128;
            int kk = seg >> 4, cs = (seg & 15) * 8;
            int col;
            if (MODE == 1) col = (cs < 64) ? nb + cs : upOff + nb + (cs - 64);
            else           col = nb + cs;
            bsrc[it] = (size_t)kk * ldb + col;
            bdst[it] = sb + kk * (LDB*2) + cs * 2;
        }

        auto issue = [&](int bf, int k0) {
            cpa16(adst0 + OFF_AH(bf), Ah + arow0 + k0 + aoff0);
            cpa16(adst1 + OFF_AH(bf), Ah + arow1 + k0 + aoff1);
            #pragma unroll
            for (int it = 0; it < 4; it++) {
                size_t s = bsrc[it] + (size_t)k0 * ldb;
                cpa16(bdst[it] + OFF_BH(bf), Bh + s);
            }
            CPA_COMMIT();
        };

        issue(0, 0);
        if (nkt > 1) issue(1, 32);

        int bf = 0;
        for (int c = 0; c < nkt; c++) {
            if (c + 1 < nkt) { CPA_WAIT1(); } else { CPA_WAIT0(); }
            __syncthreads();
            if (c + 2 < nkt) {
                int nb3 = bf + 2; if (nb3 >= 3) nb3 -= 3;
                issue(nb3, (c + 2) << 5);
            }
            const uint32_t uAh = sb + OFF_AH(bf);
            const uint32_t uBh = sb + OFF_BH(bf);
            #pragma unroll
            for (int ks = 0; ks < 2; ks++) {
                uint32_t ah[2][4];
                #pragma unroll
                for (int mf = 0; mf < 2; mf++) {
                    uint32_t ro = (uint32_t)((wm * 32 + mf * 16 + lrow) * LDA + ks * 16 + lcol8) * 2;
                    ldsm4(ah[mf], uAh + ro);
                }
                #pragma unroll
                for (int nh = 0; nh < 4; nh++) {
                    uint32_t bh[4];
                    uint32_t ro = (uint32_t)((ks * 16 + lrow) * LDB + wn * 64 + nh * 16 + lcol8) * 2;
                    ldsm4t(bh, uBh + ro);
                    #pragma unroll
                    for (int mf = 0; mf < 2; mf++)
                        #pragma unroll
                        for (int sub = 0; sub < 2; sub++) {
                            int nf = nh * 2 + sub;
                            mma16816(acc[mf][nf], ah[mf], bh[sub*2], bh[sub*2+1]);
                        }
                }
            }
            bf++; if (bf >= 3) bf = 0;
        }
        __syncthreads();
    } else {
        // ============= MoE path: fp32 B -> single bf16 =======================
        const float* B = (const float*)B1 + bOff;
        int bcol[8]; size_t brow[8];
        #pragma unroll
        for (int it = 0; it < 8; it++) {
            int i = tid + it * 128;
            int kk = i >> 5;
            int n4 = (i & 31) << 2;
            int col;
            if (MODE == 2) col = (n4 < 64) ? nb + n4 : upOff + nb + (n4 - 64);
            else           col = nb + n4;
            bcol[it] = n4;
            brow[it] = (size_t)kk * ldb + col;
        }
        float4 br[8];
        {
            cpa16(adst0 + OFF_AH(0), Ah + arow0 + aoff0);
            cpa16(adst1 + OFF_AH(0), Ah + arow1 + aoff1);
            CPA_COMMIT();
            #pragma unroll
            for (int it = 0; it < 8; it++) br[it] = *(const float4*)(B + brow[it]);
            CPA_WAIT0();
            __syncthreads();
            #pragma unroll
            for (int it = 0; it < 8; it++) {
                int i = tid + it * 128;
                int kk = i >> 5;
                uint32_t h0 = pack_hi(br[it].x, br[it].y), h1 = pack_hi(br[it].z, br[it].w);
                uint32_t* ph = (uint32_t*)(sm + OFF_BH(0) + kk * (LDB*2) + bcol[it] * 2);
                ph[0] = h0; ph[1] = h1;
            }
            __syncthreads();
        }
        int p = 0;
        for (int c = 0; c < nkt; c++) {
            const int q = p ^ 1;
            const bool more = (c + 1 < nkt);
            if (more) {
                const int k1 = (c + 1) << 5;
                cpa16(adst0 + OFF_AH(q), Ah + arow0 + k1 + aoff0);
                cpa16(adst1 + OFF_AH(q), Ah + arow1 + k1 + aoff1);
                CPA_COMMIT();
                #pragma unroll
                for (int it = 0; it < 8; it++)
                    br[it] = *(const float4*)(B + (size_t)k1 * ldb + brow[it]);
            }
            const uint32_t uAh = sb + OFF_AH(p);
            const uint32_t uBh = sb + OFF_BH(p);
            #pragma unroll
            for (int ks = 0; ks < 2; ks++) {
                uint32_t ah[2][4];
                #pragma unroll
                for (int mf = 0; mf < 2; mf++) {
                    uint32_t ro = (uint32_t)((wm * 32 + mf * 16 + lrow) * LDA + ks * 16 + lcol8) * 2;
                    ldsm4(ah[mf], uAh + ro);
                }
                #pragma unroll
                for (int nh = 0; nh < 4; nh++) {
                    uint32_t bh[4];
                    uint32_t ro = (uint32_t)((ks * 16 + lrow) * LDB + wn * 64 + nh * 16 + lcol8) * 2;
                    ldsm4t(bh, uBh + ro);
                    #pragma unroll
                    for (int mf = 0; mf < 2; mf++)
                        #pragma unroll
                        for (int sub = 0; sub < 2; sub++) {
                            int nf = nh * 2 + sub;
                            mma16816(acc[mf][nf], ah[mf], bh[sub*2], bh[sub*2+1]);
                        }
                }
            }
            if (more) {
                #pragma unroll
                for (int it = 0; it < 8; it++) {
                    int i = tid + it * 128;
                    int kk = i >> 5;
                    uint32_t h0 = pack_hi(br[it].x, br[it].y), h1 = pack_hi(br[it].z, br[it].w);
                    uint32_t* ph = (uint32_t*)(sm + OFF_BH(q) + kk * (LDB*2) + bcol[it] * 2);
                    ph[0] = h0; ph[1] = h1;
                }
                CPA_WAIT0();
                __syncthreads();
            }
            p = q;
        }
        __syncthreads();
    }

    // ---- epilogue ----
    const int r4 = lane >> 2, c2 = (lane & 3) * 2;
    if (MODE == 0) {
        #pragma unroll
        for (int mf = 0; mf < 2; mf++) {
            #pragma unroll
            for (int nf = 0; nf < 8; nf++) {
                int col = nb + wn * 64 + nf * 8 + c2;
                size_t r1 = (size_t)(m0 + wm * 32 + mf * 16 + r4);
                size_t r2 = r1 + 8;
                float v0 = acc[mf][nf][0], v1 = acc[mf][nf][1];
                float v2 = acc[mf][nf][2], v3 = acc[mf][nf][3];
                if (add) {
                    v0 += add[r1 * ldc + col]; v1 += add[r1 * ldc + col + 1];
                    v2 += add[r2 * ldc + col]; v3 += add[r2 * ldc + col + 1];
                }
                *(float2*)(C + r1 * ldc + col) = make_float2(v0, v1);
                *(float2*)(C + r2 * ldc + col) = make_float2(v2, v3);
            }
        }
    } else if (MODE == 1 || MODE == 2) {
        float* sG = (float*)sm;              // [64][65]
        if (wn == 0) {                        // gate cols 0..63
            #pragma unroll
            for (int mf = 0; mf < 2; mf++)
                #pragma unroll
                for (int nf = 0; nf < 8; nf++) {
                    int col = nf * 8 + c2;
                    int rr1 = wm * 32 + mf * 16 + r4, rr2 = rr1 + 8;
                    sG[rr1 * 65 + col]     = acc[mf][nf][0];
                    sG[rr1 * 65 + col + 1] = acc[mf][nf][1];
                    sG[rr2 * 65 + col]     = acc[mf][nf][2];
                    sG[rr2 * 65 + col + 1] = acc[mf][nf][3];
                }
        }
        __syncthreads();
        if (wn == 1) {                        // up cols -> combine
            #pragma unroll
            for (int mf = 0; mf < 2; mf++)
                #pragma unroll
                for (int nf = 0; nf < 8; nf++) {
                    int col = nf * 8 + c2;
                    int rr1 = wm * 32 + mf * 16 + r4;
                    #pragma unroll
                    for (int half = 0; half < 2; half++) {
                        int rr = rr1 + half * 8;
                        bool ok = (MODE == 1) || (m0 + rr < cnt);
                        if (ok) {
                            size_t row = (MODE == 1) ? (size_t)(m0 + rr) : (size_t)(off + m0 + rr);
                            float g0 = sG[rr * 65 + col], g1 = sG[rr * 65 + col + 1];
                            float u0 = acc[mf][nf][half * 2], u1 = acc[mf][nf][half * 2 + 1];
                            float o0 = g0 / (1.f + fexp(-g0)) * u0;
                            float o1 = g1 / (1.f + fexp(-g1)) * u1;
                            *(uint32_t*)(Ch + row * ldc + nb + col) = pack_hi(o0, o1);
                        }
                    }
                }
        }
    } else {  // MODE 3
        #pragma unroll
        for (int mf = 0; mf < 2; mf++) {
            int rr1 = wm * 32 + mf * 16 + r4;
            #pragma unroll
            for (int half = 0; half < 2; half++) {
                int rr = rr1 + half * 8;
                if (m0 + rr < cnt) {
                    int tok = g_ptok[off + m0 + rr];
                    float w = g_pw[off + m0 + rr];
                    float* dst = C + (size_t)tok * ldc;
                    #pragma unroll
                    for (int nf = 0; nf < 8; nf++) {
                        int col = nb + wn * 64 + nf * 8 + c2;
                        atomicAdd(dst + col,     w * acc[mf][nf][half * 2]);
                        atomicAdd(dst + col + 1, w * acc[mf][nf][half * 2 + 1]);
                    }
                }
            }
        }
    }
}

// ------------------------- small kernels ------------------------------------
__global__ void cs_prep_k(const int* __restrict__ pos) {
    int t = blockIdx.x, i = threadIdx.x;   // 64 threads
    if (t == 0 && i < NEXP) g_cnt[i] = 0;
    double e = exp(-((double)(2 * i) / 128.0) * log(500000.0));
    float f = (float)pos[t] * (float)e;
    float sn, cs; sincosf(f, &sn, &cs);
    g_cs[t * 64 + i] = make_float2(cs, sn);
}

// rmsnorm: writes optional fp32 y + bf16 yh (hi only)
__global__ void rmsnorm_k(const float* __restrict__ x, const float* __restrict__ w,
                          float* __restrict__ y, __nv_bfloat16* __restrict__ yh,
                          int cols, int ldx, int ldy)
{
    int row = blockIdx.x;
    const float* xr = x + (size_t)row * ldx;
    float ss = 0.f;
    for (int c = threadIdx.x; c < cols; c += 256) { float v = xr[c]; ss = fmaf(v, v, ss); }
    __shared__ float wred[8];
    #pragma unroll
    for (int d = 16; d; d >>= 1) ss += __shfl_xor_sync(0xffffffffu, ss, d);
    if ((threadIdx.x & 31) == 0) wred[threadIdx.x >> 5] = ss;
    __syncthreads();
    if (threadIdx.x < 32) {
        float v = (threadIdx.x < 8) ? wred[threadIdx.x] : 0.f;
        #pragma unroll
        for (int d = 4; d; d >>= 1) v += __shfl_xor_sync(0xffffffffu, v, d);
        if (threadIdx.x == 0) wred[0] = v;
    }
    __syncthreads();
    float r = rsqrtf(wred[0] / (float)cols + 1e-5f);
    for (int c = threadIdx.x; c < cols; c += 256) {
        float v = xr[c] * r * w[c];
        if (y) y[(size_t)row * ldy + c] = v;
        yh[(size_t)row * ldy + c] = __float2bfloat16_rn(v);
    }
}

// rope on q (reads qproj fp32, writes split bf16 with SCALE folded)
__global__ void rope_q_k(const float* __restrict__ qp,
                         __nv_bfloat16* __restrict__ qh, __nv_bfloat16* __restrict__ ql)
{
    int t = blockIdx.x;
    for (int idx = threadIdx.x; idx < NHEAD * 64; idx += 256) {
        int hh = idx >> 6, i = idx & 63;
        float2 cs = g_cs[t * 64 + i];
        const float* b = qp + (size_t)t * 2048 + hh * HD;
        float x1 = b[i], x2 = b[i + 64];
        float y1 = (x1 * cs.x - x2 * cs.y) * SCALE;
        float y2 = (x2 * cs.x + x1 * cs.y) * SCALE;
        size_t o1 = (size_t)t * 2048 + hh * HD + i;
        __nv_bfloat16 h1 = __float2bfloat16_rn(y1);
        qh[o1] = h1; ql[o1] = __float2bfloat16_rn(y1 - __bfloat162float(h1));
        __nv_bfloat16 h2 = __float2bfloat16_rn(y2);
        qh[o1 + 64] = h2; ql[o1 + 64] = __float2bfloat16_rn(y2 - __bfloat162float(h2));
    }
}

// K rope + transpose split; V single bf16
__global__ void kv_prep_k(const float* __restrict__ qkv)
{
    int t = blockIdx.x;
    int tid = threadIdx.x;   // 128
    if (tid < 64) {
        int i = tid;
        float2 cs = g_cs[t * 64 + i];
        const float* kb = qkv + (size_t)t * QKV_N + QDIM;
        float x1 = kb[i], x2 = kb[i + 64];
        float y1 = x1 * cs.x - x2 * cs.y;
        float y2 = x2 * cs.x + x1 * cs.y;
        __nv_bfloat16 h1 = __float2bfloat16_rn(y1);
        g_kth[(size_t)i * SEQ + t] = h1;
        g_ktl[(size_t)i * SEQ + t] = __float2bfloat16_rn(y1 - __bfloat162float(h1));
        __nv_bfloat16 h2 = __float2bfloat16_rn(y2);
        g_kth[(size_t)(i + 64) * SEQ + t] = h2;
        g_ktl[(size_t)(i + 64) * SEQ + t] = __float2bfloat16_rn(y2 - __bfloat162float(h2));
    }
    {
        float v = qkv[(size_t)t * QKV_N + QDIM + HD + tid];
        g_vh[(size_t)t * HD + tid] = __float2bfloat16_rn(v);
    }
}

// ------------------------- attention: FA2-style register-P -----------------
// 8 warps x 16 q-rows; QK 3-pass; P in registers (1-pass bf16); V single bf16
#define AQ_LD 136
#define AK_LD 72
#define AV_LD 136
#define AOF_QH 0
#define AOF_QL 34816
#define AOF_KH 69632
#define AOF_KL 88064
#define AOF_VH 106496
#define ATTN_SMEM 123904

__global__ __launch_bounds__(256, 1) void attn_k(
    const __nv_bfloat16* __restrict__ Qh, const __nv_bfloat16* __restrict__ Ql,
    __nv_bfloat16* __restrict__ Oh)
{
    extern __shared__ __align__(16) char sm[];
    const int bx = blockIdx.x;
    const int qt = 15 - (bx >> 4);     // longest tiles first
    const int h = bx & 15;
    const int q0 = qt * 128;

    const int tid = threadIdx.x;
    const int wid = tid >> 5, lane = tid & 31;
    const int lrow = lane & 15, lcol8 = (lane >> 4) * 8;
    const int r4 = lane >> 2, c2 = (lane & 3) * 2;
    const int mbase = wid * 16;        // this warp's q-row block

    const uint32_t uQh = s2u(sm + AOF_QH), uQl = s2u(sm + AOF_QL);
    const uint32_t uKh = s2u(sm + AOF_KH), uKl = s2u(sm + AOF_KL);
    const uint32_t uVh = s2u(sm + AOF_VH);

    // load Q tile (128 x 128, hi+lo)
    #pragma unroll
    for (int it = 0; it < 8; it++) {
        int i = tid + it * 256;          // 2048 uint4 per copy
        int r = i >> 4, c = (i & 15) << 3;
        size_t src = (size_t)(q0 + r) * 2048 + h * HD + c;
        *(uint4*)(sm + AOF_QH + r * (AQ_LD*2) + c * 2) = *(const uint4*)(Qh + src);
        *(uint4*)(sm + AOF_QL + r * (AQ_LD*2) + c * 2) = *(const uint4*)(Ql + src);
    }

    float m0r = -3.0e30f, m1r = -3.0e30f;   // running max for rows r4, r4+8
    float l0r = 0.f, l1r = 0.f;             // running sum
    float o[16][4] = {};                     // 16 n8-tiles x 128 out cols
    const int nkt = 2 * qt + 2;

    for (int kt = 0; kt < nkt; kt++) {
        const int k0 = kt * 64;
        __syncthreads();
        // load K tile (transposed source [d][tok]): 128 x 64, hi+lo
        #pragma unroll
        for (int it = 0; it < 4; it++) {
            int i = tid + it * 256;      // 1024 uint4 per copy
            int d = i >> 3, tc = (i & 7) << 3;
            size_t src = (size_t)d * SEQ + k0 + tc;
            *(uint4*)(sm + AOF_KH + d * (AK_LD*2) + tc * 2) = *(const uint4*)(g_kth + src);
            *(uint4*)(sm + AOF_KL + d * (AK_LD*2) + tc * 2) = *(const uint4*)(g_ktl + src);
        }
        // load V tile: 64 x 128 (single bf16)
        #pragma unroll
        for (int it = 0; it < 2; it++) {
            int i = tid + it * 256;
            int r = i >> 4, c = (i & 15) << 3;
            size_t src = (size_t)(k0 + r * 2) * HD + c;
            *(uint4*)(sm + AOF_VH + (r * 2) * (AV_LD*2) + c * 2) = *(const uint4*)(g_vh + src);
            *(uint4*)(sm + AOF_VH + (r * 2 + 1) * (AV_LD*2) + c * 2) =
                *(const uint4*)(g_vh + src + HD);
        }
        __syncthreads();

        // ---- S = Q K^T (3-pass split): warp computes 16 rows x 64 cols ----
        float sacc[8][4] = {};
        #pragma unroll
        for (int ks = 0; ks < 8; ks++) {
            uint32_t ah[4], al[4];
            uint32_t roA = (uint32_t)((mbase + lrow) * AQ_LD + ks * 16 + lcol8) * 2;
            ldsm4(ah, uQh + roA);
            ldsm4(al, uQl + roA);
            #pragma unroll
            for (int nh = 0; nh < 4; nh++) {
                uint32_t bh[4], bl[4];
                uint32_t ro = (uint32_t)((ks * 16 + lrow) * AK_LD + nh * 16 + lcol8) * 2;
                ldsm4t(bh, uKh + ro);
                ldsm4t(bl, uKl + ro);
                #pragma unroll
                for (int sub = 0; sub < 2; sub++) {
                    int nf = nh * 2 + sub;
                    mma16816(sacc[nf], ah, bh[sub*2], bh[sub*2+1]);
                    mma16816(sacc[nf], ah, bl[sub*2], bl[sub*2+1]);
                    mma16816(sacc[nf], al, bh[sub*2], bh[sub*2+1]);
                }
            }
        }

        // causal mask on diagonal tiles
        if (kt >= nkt - 2) {
            #pragma unroll
            for (int nf = 0; nf < 8; nf++)
                #pragma unroll
                for (int v = 0; v < 4; v++) {
                    int row = q0 + mbase + r4 + (v >= 2 ? 8 : 0);
                    int col = k0 + nf * 8 + c2 + (v & 1);
                    if (col > row) sacc[nf][v] = -1.0e30f;
                }
        }

        // ---- warp-local row max ----
        float rx0 = -3.0e30f, rx1 = -3.0e30f;
        #pragma unroll
        for (int nf = 0; nf < 8; nf++) {
            rx0 = fmaxf(rx0, fmaxf(sacc[nf][0], sacc[nf][1]));
            rx1 = fmaxf(rx1, fmaxf(sacc[nf][2], sacc[nf][3]));
        }
        rx0 = fmaxf(rx0, __shfl_xor_sync(0xffffffffu, rx0, 1));
        rx0 = fmaxf(rx0, __shfl_xor_sync(0xffffffffu, rx0, 2));
        rx1 = fmaxf(rx1, __shfl_xor_sync(0xffffffffu, rx1, 1));
        rx1 = fmaxf(rx1, __shfl_xor_sync(0xffffffffu, rx1, 2));
        float mn0 = fmaxf(m0r, rx0), mn1 = fmaxf(m1r, rx1);
        float f0 = fexp(m0r - mn0), f1 = fexp(m1r - mn1);

        // ---- p = exp(s-mn) -> pack directly into PV A-fragments ----
        uint32_t pk[4][4];   // 4 k16 fragments covering k=64
        float rs0 = 0.f, rs1 = 0.f;
        #pragma unroll
        for (int kf = 0; kf < 4; kf++) {
            #pragma unroll
            for (int half = 0; half < 2; half++) {
                int nf = kf * 2 + half;
                float p0 = fexp(sacc[nf][0] - mn0);
                float p1 = fexp(sacc[nf][1] - mn0);
                float p2 = fexp(sacc[nf][2] - mn1);
                float p3 = fexp(sacc[nf][3] - mn1);
                rs0 += p0 + p1;
                rs1 += p2 + p3;
                pk[kf][half * 2]     = pack_hi(p0, p1);
                pk[kf][half * 2 + 1] = pack_hi(p2, p3);
            }
        }
        rs0 += __shfl_xor_sync(0xffffffffu, rs0, 1);
        rs0 += __shfl_xor_sync(0xffffffffu, rs0, 2);
        rs1 += __shfl_xor_sync(0xffffffffu, rs1, 1);
        rs1 += __shfl_xor_sync(0xffffffffu, rs1, 2);
        l0r = l0r * f0 + rs0;
        l1r = l1r * f1 + rs1;
        m0r = mn0; m1r = mn1;

        // rescale o
        #pragma unroll
        for (int nf = 0; nf < 16; nf++) {
            o[nf][0] *= f0; o[nf][1] *= f0;
            o[nf][2] *= f1; o[nf][3] *= f1;
        }

        // ---- O += P V (P in regs, V single bf16) ----
        #pragma unroll
        for (int ks2 = 0; ks2 < 4; ks2++) {
            #pragma unroll
            for (int nh = 0; nh < 8; nh++) {
                uint32_t bv[4];
                uint32_t ro = (uint32_t)((ks2 * 16 + lrow) * AV_LD + nh * 16 + lcol8) * 2;
                ldsm4t(bv, uVh + ro);
                mma16816(o[nh * 2],     pk[ks2], bv[0], bv[1]);
                mma16816(o[nh * 2 + 1], pk[ks2], bv[2], bv[3]);
            }
        }
    }

    // ---- write O (hi bf16) ----
    float inv0 = 1.f / l0r, inv1 = 1.f / l1r;
    int row0 = q0 + mbase + r4;
    #pragma unroll
    for (int nf = 0; nf < 16; nf++) {
        int col = h * HD + nf * 8 + c2;
        *(uint32_t*)(Oh + (size_t)row0 * 2048 + col) = pack_hi(o[nf][0] * inv0, o[nf][1] * inv0);
        *(uint32_t*)(Oh + (size_t)(row0 + 8) * 2048 + col) = pack_hi(o[nf][2] * inv1, o[nf][3] * inv1);
    }
}

// ------------------------- router / topk / scan / fill ---------------------
__global__ __launch_bounds__(256) void router_k(const float* __restrict__ X,
                                                const float* __restrict__ Wr)
{
    __shared__ float part[8][32];
    int t = blockIdx.x;
    int e = threadIdx.x & 31, p = threadIdx.x >> 5;
    const float* xr = X + (size_t)t * HID;
    float s = 0.f;
    for (int k = p * 128; k < p * 128 + 128; k++) s = fmaf(xr[k], Wr[k * 32 + e], s);
    part[p][e] = s;
    __syncthreads();
    if (threadIdx.x < 32) {
        float logit = 0.f;
        #pragma unroll
        for (int q = 0; q < 8; q++) logit += part[q][e];
        float m = logit;
        for (int d = 16; d; d >>= 1) m = fmaxf(m, __shfl_xor_sync(0xffffffffu, m, d));
        float ex = __expf(logit - m);
        float cur = ex;
        float wsel[3]; int isel[3];
        #pragma unroll
        for (int kk = 0; kk < 3; kk++) {
            float v = cur; int idx = e;
            for (int d = 16; d; d >>= 1) {
                float v2 = __shfl_xor_sync(0xffffffffu, v, d);
                int   i2 = __shfl_xor_sync(0xffffffffu, idx, d);
                if (v2 > v || (v2 == v && i2 < idx)) { v = v2; idx = i2; }
            }
            wsel[kk] = v; isel[kk] = idx;
            if (e == idx) cur = -1.f;
        }
        float tot = wsel[0] + wsel[1] + wsel[2];
        if (e < 3) { g_topi[t * 3 + e] = isel[e]; g_topw[t * 3 + e] = wsel[e] / tot; }
        if (e == 0) {
            atomicAdd(&g_cnt[isel[0]], 1);
            atomicAdd(&g_cnt[isel[1]], 1);
            atomicAdd(&g_cnt[isel[2]], 1);
        }
    }
}

__global__ void scan_k()
{
    int e = threadIdx.x;
    int c = g_cnt[e];
    int x = c;
    for (int d = 1; d < 32; d <<= 1) {
        int y = __shfl_up_sync(0xffffffffu, x, d);
        if (e >= d) x += y;
    }
    int excl = x - c;
    g_off[e] = excl;
    g_fill[e] = excl;
}

__global__ void fill_k()
{
    int t = blockIdx.x * 256 + threadIdx.x;
    if (t < SEQ) {
        #pragma unroll
        for (int k = 0; k < 3; k++) {
            int e = g_topi[t * 3 + k];
            int slot = atomicAdd(&g_fill[e], 1);
            g_ptok[slot] = t;
            g_pw[slot] = g_topw[t * 3 + k];
        }
    }
}

// ------------------------- launch ------------------------------------------
extern "C" void kernel_launch(void* const* d_in, const int* in_sizes, int n_in,
                              void* d_out, int out_size)
{
    const float* hidden   = (const float*)d_in[0];
    const float* w_in     = (const float*)d_in[1];
    const float* w_qkv    = (const float*)d_in[2];
    const float* w_inter  = (const float*)d_in[3];
    const float* w_q      = (const float*)d_in[4];
    const float* w_o      = (const float*)d_in[5];
    const float* w_post   = (const float*)d_in[6];
    const float* w_guse   = (const float*)d_in[7];
    const float* w_dse    = (const float*)d_in[8];
    const float* w_router = (const float*)d_in[9];
    const float* w_gue    = (const float*)d_in[10];
    const float* w_de     = (const float*)d_in[11];
    const int*   pos      = (const int*)d_in[12];
    float* out = (float*)d_out;

    float *qkv, *qproj, *resid2, *h2;
    cudaGetSymbolAddress((void**)&qkv,    g_qkv);
    cudaGetSymbolAddress((void**)&qproj,  g_qproj);
    cudaGetSymbolAddress((void**)&resid2, g_resid2);
    cudaGetSymbolAddress((void**)&h2,     g_h2);
    __nv_bfloat16 *hnh,*qnh,*qh,*ql,*aoh,*h2h,*aseh,*aceh;
    __nv_bfloat16 *wqkvh,*wqh,*woh,*wguh,*wdh;
    cudaGetSymbolAddress((void**)&hnh, g_hnh);
    cudaGetSymbolAddress((void**)&qnh, g_qnh);
    cudaGetSymbolAddress((void**)&qh,  g_qh);    cudaGetSymbolAddress((void**)&ql,  g_ql);
    cudaGetSymbolAddress((void**)&aoh, g_aoh);
    cudaGetSymbolAddress((void**)&h2h, g_h2h);
    cudaGetSymbolAddress((void**)&aseh,g_aseh);
    cudaGetSymbolAddress((void**)&aceh,g_aceh);
    cudaGetSymbolAddress((void**)&wqkvh,g_wqkvh);
    cudaGetSymbolAddress((void**)&wqh, g_wqh);
    cudaGetSymbolAddress((void**)&woh, g_woh);
    cudaGetSymbolAddress((void**)&wguh,g_wguh);
    cudaGetSymbolAddress((void**)&wdh, g_wdh);

    cudaFuncSetAttribute(attn_k, cudaFuncAttributeMaxDynamicSharedMemorySize, ATTN_SMEM);
    cudaFuncSetAttribute((gemm_tc<0,1>), cudaFuncAttributeMaxDynamicSharedMemorySize, SMEM_TOTAL_G);
    cudaFuncSetAttribute((gemm_tc<1,1>), cudaFuncAttributeMaxDynamicSharedMemorySize, SMEM_TOTAL_G);
    cudaFuncSetAttribute((gemm_tc<2,0>), cudaFuncAttributeMaxDynamicSharedMemorySize, SMEM_TOTAL_G);
    cudaFuncSetAttribute((gemm_tc<3,0>), cudaFuncAttributeMaxDynamicSharedMemorySize, SMEM_TOTAL_G);

    cs_prep_k<<<SEQ, 64>>>(pos);
    split_all_k<<<(SPL4 + 255)/256, 256>>>(w_qkv, w_q, w_o, w_guse, w_dse);

    rmsnorm_k<<<SEQ, 256>>>(hidden, w_in, nullptr, hnh, HID, HID, HID);
    gemm_tc<0,1><<<dim3(QKV_N/128, SEQ/64), 128, SMEM_TOTAL_G>>>(
        hnh, wqkvh, qkv, nullptr, nullptr, HID, HID, QKV_N, QKV_N, 0, 0);
    rmsnorm_k<<<SEQ, 256>>>(qkv, w_inter, nullptr, qnh, QDIM, QKV_N, QDIM);
    gemm_tc<0,1><<<dim3(2048/128, SEQ/64), 128, SMEM_TOTAL_G>>>(
        qnh, wqh, qproj, nullptr, nullptr, QDIM, QDIM, 2048, 2048, 0, 0);
    rope_q_k<<<SEQ, 256>>>(qproj, qh, ql);
    kv_prep_k<<<SEQ, 128>>>(qkv);
    attn_k<<<256, 256, ATTN_SMEM>>>(qh, ql, aoh);
    gemm_tc<0,1><<<dim3(HID/128, SEQ/64), 128, SMEM_TOTAL_G>>>(
        aoh, woh, resid2, nullptr, hidden, 2048, 2048, HID, HID, 0, 0);
    rmsnorm_k<<<SEQ, 256>>>(resid2, w_post, h2, h2h, HID, HID, HID);
    gemm_tc<1,1><<<dim3(IDIM/64, SEQ/64), 128, SMEM_TOTAL_G>>>(
        h2h, wguh, nullptr, aseh, nullptr, HID, HID, 2*IDIM, IDIM, IDIM, 0);
    gemm_tc<0,1><<<dim3(HID/128, SEQ/64), 128, SMEM_TOTAL_G>>>(
        aseh, wdh, out, nullptr, resid2, IDIM, IDIM, HID, HID, 0, 0);
    router_k<<<SEQ, 256>>>(h2, w_router);
    scan_k<<<1, 32>>>();
    fill_k<<<SEQ/256, 256>>>();
    gemm_tc<2,0><<<dim3(IDIM/64, 32, NEXP), 128, SMEM_TOTAL_G>>>(
        h2h, w_gue, nullptr, aceh, nullptr, HID, HID, 2*IDIM, IDIM, IDIM,
        (size_t)HID * 2 * IDIM);
    gemm_tc<3,0><<<dim3(HID/128, 32, NEXP), 128, SMEM_TOTAL_G>>>(
        aceh, w_de, out, nullptr, nullptr, IDIM, IDIM, HID, HID, 0,
        (size_t)IDIM * HID);
}

// round 16
// speedup vs baseline: 1.7666x; 1.0040x over previous
#include <cuda_runtime.h>
#include <cuda_bf16.h>
#include <math.h>
#include <stdint.h>

#define SEQ 2048
#define HID 1024
#define NHEAD 16
#define HD 128
#define QDIM 512
#define NEXP 32
#define IDIM 1024
#define QKV_N 768
#define SCALE 0.08838834764831845f   // 1/sqrt(128)

// ------------------------- device scratch ----------------------------------
__device__ float g_qkv[SEQ*QKV_N];
__device__ float g_qproj[SEQ*NHEAD*HD];
__device__ float g_resid2[SEQ*HID];
__device__ float g_h2[SEQ*HID];
__device__ float2 g_cs[SEQ*64];

__device__ __nv_bfloat16 g_hnh[SEQ*HID];
__device__ __nv_bfloat16 g_qnh[SEQ*QDIM];
__device__ __nv_bfloat16 g_qh[SEQ*2048],  g_ql[SEQ*2048];
__device__ __nv_bfloat16 g_kth[128*SEQ],  g_ktl[128*SEQ];   // transposed [d][token]
__device__ __nv_bfloat16 g_vh[SEQ*128];
__device__ __nv_bfloat16 g_aoh[SEQ*2048];
__device__ __nv_bfloat16 g_h2h[SEQ*HID];
__device__ __nv_bfloat16 g_aseh[SEQ*IDIM];
__device__ __nv_bfloat16 g_aceh[SEQ*3*IDIM];

// pre-rounded dense weights (single bf16)
__device__ __nv_bfloat16 g_wqkvh[HID*QKV_N];
__device__ __nv_bfloat16 g_wqh[QDIM*2048];
__device__ __nv_bfloat16 g_woh[2048*HID];
__device__ __nv_bfloat16 g_wguh[HID*2*IDIM];
__device__ __nv_bfloat16 g_wdh[IDIM*HID];

__device__ int   g_topi[SEQ*3];
__device__ float g_topw[SEQ*3];
__device__ int   g_cnt[NEXP];
__device__ int   g_off[NEXP];
__device__ int   g_fill[NEXP];
__device__ int   g_ptok[SEQ*3];
__device__ float g_pw[SEQ*3];

// ------------------------- helpers -----------------------------------------
__device__ __forceinline__ uint32_t s2u(const void* p) {
    uint32_t a;
    asm("{ .reg .u64 t; cvta.to.shared.u64 t, %1; cvt.u32.u64 %0, t; }" : "=r"(a) : "l"(p));
    return a;
}
__device__ __forceinline__ void ldsm4(uint32_t* r, uint32_t addr) {
    asm volatile("ldmatrix.sync.aligned.m8n8.x4.shared.b16 {%0,%1,%2,%3}, [%4];"
        : "=r"(r[0]), "=r"(r[1]), "=r"(r[2]), "=r"(r[3]) : "r"(addr));
}
__device__ __forceinline__ void ldsm4t(uint32_t* r, uint32_t addr) {
    asm volatile("ldmatrix.sync.aligned.m8n8.x4.trans.shared.b16 {%0,%1,%2,%3}, [%4];"
        : "=r"(r[0]), "=r"(r[1]), "=r"(r[2]), "=r"(r[3]) : "r"(addr));
}
__device__ __forceinline__ void mma16816(float* c, const uint32_t* a, uint32_t b0, uint32_t b1) {
    asm volatile("mma.sync.aligned.m16n8k16.row.col.f32.bf16.bf16.f32 "
        "{%0,%1,%2,%3}, {%4,%5,%6,%7}, {%8,%9}, {%0,%1,%2,%3};"
        : "+f"(c[0]), "+f"(c[1]), "+f"(c[2]), "+f"(c[3])
        : "r"(a[0]), "r"(a[1]), "r"(a[2]), "r"(a[3]), "r"(b0), "r"(b1));
}
__device__ __forceinline__ void cpa16(uint32_t dst, const void* src) {
    asm volatile("cp.async.cg.shared.global [%0], [%1], 16;" :: "r"(dst), "l"(src));
}
#define CPA_COMMIT() asm volatile("cp.async.commit_group;" ::: "memory")
#define CPA_WAIT0()  asm volatile("cp.async.wait_group 0;" ::: "memory")
#define CPA_WAIT1()  asm volatile("cp.async.wait_group 1;" ::: "memory")

__device__ __forceinline__ uint32_t pack_hi(float f0, float f1) {
    __nv_bfloat162 h = __floats2bfloat162_rn(f0, f1);
    return *(uint32_t*)&h;
}
__device__ __forceinline__ uint32_t pack_lo(float f0, float f1, uint32_t hibits) {
    __nv_bfloat162 h = *(__nv_bfloat162*)&hibits;
    __nv_bfloat162 l = __floats2bfloat162_rn(f0 - __bfloat162float(h.x),
                                             f1 - __bfloat162float(h.y));
    return *(uint32_t*)&l;
}
__device__ __forceinline__ void split2(float a, float b, uint32_t& hi, uint32_t& lo) {
    hi = pack_hi(a, b);
    lo = pack_lo(a, b, hi);
}
// FFMA-only exp (rel err ~4e-5), avoids MUFU
__device__ __forceinline__ float fexp(float x) {
    x = fminf(fmaxf(x, -80.f), 80.f);
    float y = x * 1.4426950408889634f;
    float n = rintf(y);
    float f = y - n;
    float p = fmaf(f, 0.009618130f, 0.055504110f);
    p = fmaf(p, f, 0.240226507f);
    p = fmaf(p, f, 0.693147181f);
    p = fmaf(p, f, 1.0f);
    return p * __int_as_float(((int)n + 127) << 23);
}

// fused weight pre-round: all 5 dense weights -> single bf16, one launch
#define SPL0 (HID*QKV_N/4)
#define SPL1 (SPL0 + QDIM*2048/4)
#define SPL2 (SPL1 + 2048*HID/4)
#define SPL3 (SPL2 + HID*2*IDIM/4)
#define SPL4 (SPL3 + IDIM*HID/4)
__global__ void split_all_k(const float* __restrict__ W0, const float* __restrict__ W1,
                            const float* __restrict__ W2, const float* __restrict__ W3,
                            const float* __restrict__ W4)
{
    int i = blockIdx.x * 256 + threadIdx.x;
    if (i >= SPL4) return;
    const float* W; __nv_bfloat16 *Wh; int j;
    if (i < SPL0)      { W = W0; Wh = g_wqkvh; j = i; }
    else if (i < SPL1) { W = W1; Wh = g_wqh;   j = i - SPL0; }
    else if (i < SPL2) { W = W2; Wh = g_woh;   j = i - SPL1; }
    else if (i < SPL3) { W = W3; Wh = g_wguh;  j = i - SPL2; }
    else               { W = W4; Wh = g_wdh;   j = i - SPL3; }
    float4 v = ((const float4*)W)[j];
    uint32_t h0 = pack_hi(v.x, v.y), h1 = pack_hi(v.z, v.w);
    ((uint2*)Wh)[j] = make_uint2(h0, h1);
}

// ------------------------- GEMM -------------------------------------------
// dense (BSPLIT=1): BK=64, 3-stage ring, pure cp.async
// MoE   (BSPLIT=0): BK=32, 2-stage, inline B convert
#define LDB 136
// MoE layout (BK=32)
#define LDA_M 40
#define ASZ_M (64*LDA_M*2)           // 5120
#define BSZ_M (32*LDB*2)             // 8704
#define OFF_AM(b) ((b) * ASZ_M)
#define OFF_BM(b) (2*ASZ_M + (b) * BSZ_M)
#define OFF_TOK   (2*ASZ_M + 2*BSZ_M)
#define SMEM_MOE  (OFF_TOK + 64*4)
// dense layout (BK=64)
#define LDA_D 72
#define ASZ_D (64*LDA_D*2)           // 9216
#define BSZ_D (64*LDB*2)             // 17408
#define OFF_AD(b) ((b) * ASZ_D)
#define OFF_BD(b) (3*ASZ_D + (b) * BSZ_D)
#define SMEM_DENSE (3*ASZ_D + 3*BSZ_D)   // 79872

// MODE 0: plain  C = A@B (+add) fp32       (64 rows x 128 out cols / CTA)
// MODE 1: gated  Ch = bf16(silu(A@Bg)*(A@Bu))  (64 rows x 64 cols, up at +upOff)
// MODE 2: moe gathered gated -> Ch rows off+r
// MODE 3: moe scatter: C[tok] += w * (A@B)  fp32 atomic
template<int MODE, int BSPLIT>
__global__ __launch_bounds__(128, 4) void gemm_tc(
    const __nv_bfloat16* __restrict__ Ah,
    const void* __restrict__ B1,
    float* __restrict__ C, __nv_bfloat16* __restrict__ Ch,
    const float* __restrict__ add,
    int K, int lda, int ldb, int ldc, int upOff, size_t bStride)
{
    int cnt = 0, off = 0;
    size_t bOff = 0;
    if (MODE >= 2) {
        int e = blockIdx.z;
        cnt = g_cnt[e];
        if ((int)blockIdx.y * 64 >= cnt) return;
        off = g_off[e];
        bOff = bStride * e;
    }
    const int m0 = blockIdx.y * 64;
    const int nb = blockIdx.x * ((MODE == 1 || MODE == 2) ? 64 : 128);

    extern __shared__ __align__(16) char sm[];
    int* sTok = (int*)(sm + OFF_TOK);
    const uint32_t sb = s2u(sm);

    const int tid = threadIdx.x;
    const int wid = tid >> 5, lane = tid & 31;
    const int wm = wid >> 1, wn = wid & 1;

    if (MODE == 2 && tid < 64) {
        int gr = m0 + tid;
        sTok[tid] = (gr < cnt) ? g_ptok[off + gr] : 0;
    }
    __syncthreads();

    float acc[2][8][4] = {};
    const int lrow = lane & 15, lcol8 = (lane >> 4) * 8;

    if (BSPLIT) {
        // ============= dense: BK=64, pure cp.async, 3-stage ring =============
        const __nv_bfloat16* Bh = (const __nv_bfloat16*)B1;
        const int nkt = K >> 6;

        // A cp.async: 512 segs of 16B (64 rows x 8 segs); 4 per thread
        size_t asrc[4]; uint32_t adst[4];
        #pragma unroll
        for (int it = 0; it < 4; it++) {
            int s = tid + it * 128;
            int m = s >> 3, seg = s & 7;
            asrc[it] = (size_t)(m0 + m) * lda + seg * 8;
            adst[it] = sb + m * (LDA_D*2) + seg * 16;
        }
        // B cp.async: 1024 segs (64 k x 16 segs); 8 per thread
        size_t bsrc[8]; uint32_t bdst[8];
        #pragma unroll
        for (int it = 0; it < 8; it++) {
            int s = tid + it * 128;
            int kk = s >> 4, cs = (s & 15) * 8;
            int col;
            if (MODE == 1) col = (cs < 64) ? nb + cs : upOff + nb + (cs - 64);
            else           col = nb + cs;
            bsrc[it] = (size_t)kk * ldb + col;
            bdst[it] = sb + kk * (LDB*2) + cs * 2;
        }

        auto issue = [&](int bf, int k0) {
            #pragma unroll
            for (int it = 0; it < 4; it++)
                cpa16(adst[it] + OFF_AD(bf), Ah + asrc[it] + k0);
            #pragma unroll
            for (int it = 0; it < 8; it++)
                cpa16(bdst[it] + OFF_BD(bf), Bh + bsrc[it] + (size_t)k0 * ldb);
            CPA_COMMIT();
        };

        issue(0, 0);
        if (nkt > 1) issue(1, 64);

        int bf = 0;
        for (int c = 0; c < nkt; c++) {
            if (c + 1 < nkt) { CPA_WAIT1(); } else { CPA_WAIT0(); }
            __syncthreads();
            if (c + 2 < nkt) {
                int nb3 = bf + 2; if (nb3 >= 3) nb3 -= 3;
                issue(nb3, (c + 2) << 6);
            }
            const uint32_t uAh = sb + OFF_AD(bf);
            const uint32_t uBh = sb + OFF_BD(bf);
            #pragma unroll
            for (int ks = 0; ks < 4; ks++) {
                uint32_t ah[2][4];
                #pragma unroll
                for (int mf = 0; mf < 2; mf++) {
                    uint32_t ro = (uint32_t)((wm * 32 + mf * 16 + lrow) * LDA_D + ks * 16 + lcol8) * 2;
                    ldsm4(ah[mf], uAh + ro);
                }
                #pragma unroll
                for (int nh = 0; nh < 4; nh++) {
                    uint32_t bh[4];
                    uint32_t ro = (uint32_t)((ks * 16 + lrow) * LDB + wn * 64 + nh * 16 + lcol8) * 2;
                    ldsm4t(bh, uBh + ro);
                    #pragma unroll
                    for (int mf = 0; mf < 2; mf++)
                        #pragma unroll
                        for (int sub = 0; sub < 2; sub++) {
                            int nf = nh * 2 + sub;
                            mma16816(acc[mf][nf], ah[mf], bh[sub*2], bh[sub*2+1]);
                        }
                }
            }
            bf++; if (bf >= 3) bf = 0;
        }
        __syncthreads();
    } else {
        // ============= MoE: BK=32, fp32 B -> single bf16 =====================
        const float* B = (const float*)B1 + bOff;
        const int nkt = K >> 5;
        const int am0 = tid >> 2, aseg0 = (tid & 3);
        const int am1 = (tid + 128) >> 2, aseg1 = ((tid + 128) & 3);
        size_t arow0, arow1;
        if (MODE == 2) {
            arow0 = (size_t)sTok[am0] * lda;
            arow1 = (size_t)sTok[am1] * lda;
        } else {
            int r0 = (m0 + am0 < cnt) ? m0 + am0 : 0;
            int r1 = (m0 + am1 < cnt) ? m0 + am1 : 0;
            arow0 = (size_t)(off + r0) * lda;
            arow1 = (size_t)(off + r1) * lda;
        }
        const uint32_t adst0 = sb + am0 * (LDA_M*2) + aseg0 * 16;
        const uint32_t adst1 = sb + am1 * (LDA_M*2) + aseg1 * 16;
        const int aoff0 = aseg0 * 8, aoff1 = aseg1 * 8;

        int bcol[8]; size_t brow[8];
        #pragma unroll
        for (int it = 0; it < 8; it++) {
            int i = tid + it * 128;
            int kk = i >> 5;
            int n4 = (i & 31) << 2;
            int col;
            if (MODE == 2) col = (n4 < 64) ? nb + n4 : upOff + nb + (n4 - 64);
            else           col = nb + n4;
            bcol[it] = n4;
            brow[it] = (size_t)kk * ldb + col;
        }
        float4 br[8];
        {
            cpa16(adst0 + OFF_AM(0), Ah + arow0 + aoff0);
            cpa16(adst1 + OFF_AM(0), Ah + arow1 + aoff1);
            CPA_COMMIT();
            #pragma unroll
            for (int it = 0; it < 8; it++) br[it] = *(const float4*)(B + brow[it]);
            CPA_WAIT0();
            __syncthreads();
            #pragma unroll
            for (int it = 0; it < 8; it++) {
                int i = tid + it * 128;
                int kk = i >> 5;
                uint32_t h0 = pack_hi(br[it].x, br[it].y), h1 = pack_hi(br[it].z, br[it].w);
                uint32_t* ph = (uint32_t*)(sm + OFF_BM(0) + kk * (LDB*2) + bcol[it] * 2);
                ph[0] = h0; ph[1] = h1;
            }
            __syncthreads();
        }
        int p = 0;
        for (int c = 0; c < nkt; c++) {
            const int q = p ^ 1;
            const bool more = (c + 1 < nkt);
            if (more) {
                const int k1 = (c + 1) << 5;
                cpa16(adst0 + OFF_AM(q), Ah + arow0 + k1 + aoff0);
                cpa16(adst1 + OFF_AM(q), Ah + arow1 + k1 + aoff1);
                CPA_COMMIT();
                #pragma unroll
                for (int it = 0; it < 8; it++)
                    br[it] = *(const float4*)(B + (size_t)k1 * ldb + brow[it]);
            }
            const uint32_t uAh = sb + OFF_AM(p);
            const uint32_t uBh = sb + OFF_BM(p);
            #pragma unroll
            for (int ks = 0; ks < 2; ks++) {
                uint32_t ah[2][4];
                #pragma unroll
                for (int mf = 0; mf < 2; mf++) {
                    uint32_t ro = (uint32_t)((wm * 32 + mf * 16 + lrow) * LDA_M + ks * 16 + lcol8) * 2;
                    ldsm4(ah[mf], uAh + ro);
                }
                #pragma unroll
                for (int nh = 0; nh < 4; nh++) {
                    uint32_t bh[4];
                    uint32_t ro = (uint32_t)((ks * 16 + lrow) * LDB + wn * 64 + nh * 16 + lcol8) * 2;
                    ldsm4t(bh, uBh + ro);
                    #pragma unroll
                    for (int mf = 0; mf < 2; mf++)
                        #pragma unroll
                        for (int sub = 0; sub < 2; sub++) {
                            int nf = nh * 2 + sub;
                            mma16816(acc[mf][nf], ah[mf], bh[sub*2], bh[sub*2+1]);
                        }
                }
            }
            if (more) {
                #pragma unroll
                for (int it = 0; it < 8; it++) {
                    int i = tid + it * 128;
                    int kk = i >> 5;
                    uint32_t h0 = pack_hi(br[it].x, br[it].y), h1 = pack_hi(br[it].z, br[it].w);
                    uint32_t* ph = (uint32_t*)(sm + OFF_BM(q) + kk * (LDB*2) + bcol[it] * 2);
                    ph[0] = h0; ph[1] = h1;
                }
                CPA_WAIT0();
                __syncthreads();
            }
            p = q;
        }
        __syncthreads();
    }

    // ---- epilogue ----
    const int r4 = lane >> 2, c2 = (lane & 3) * 2;
    if (MODE == 0) {
        #pragma unroll
        for (int mf = 0; mf < 2; mf++) {
            #pragma unroll
            for (int nf = 0; nf < 8; nf++) {
                int col = nb + wn * 64 + nf * 8 + c2;
                size_t r1 = (size_t)(m0 + wm * 32 + mf * 16 + r4);
                size_t r2 = r1 + 8;
                float v0 = acc[mf][nf][0], v1 = acc[mf][nf][1];
                float v2 = acc[mf][nf][2], v3 = acc[mf][nf][3];
                if (add) {
                    v0 += add[r1 * ldc + col]; v1 += add[r1 * ldc + col + 1];
                    v2 += add[r2 * ldc + col]; v3 += add[r2 * ldc + col + 1];
                }
                *(float2*)(C + r1 * ldc + col) = make_float2(v0, v1);
                *(float2*)(C + r2 * ldc + col) = make_float2(v2, v3);
            }
        }
    } else if (MODE == 1 || MODE == 2) {
        float* sG = (float*)sm;              // [64][65]
        if (wn == 0) {                        // gate cols 0..63
            #pragma unroll
            for (int mf = 0; mf < 2; mf++)
                #pragma unroll
                for (int nf = 0; nf < 8; nf++) {
                    int col = nf * 8 + c2;
                    int rr1 = wm * 32 + mf * 16 + r4, rr2 = rr1 + 8;
                    sG[rr1 * 65 + col]     = acc[mf][nf][0];
                    sG[rr1 * 65 + col + 1] = acc[mf][nf][1];
                    sG[rr2 * 65 + col]     = acc[mf][nf][2];
                    sG[rr2 * 65 + col + 1] = acc[mf][nf][3];
                }
        }
        __syncthreads();
        if (wn == 1) {                        // up cols -> combine
            #pragma unroll
            for (int mf = 0; mf < 2; mf++)
                #pragma unroll
                for (int nf = 0; nf < 8; nf++) {
                    int col = nf * 8 + c2;
                    int rr1 = wm * 32 + mf * 16 + r4;
                    #pragma unroll
                    for (int half = 0; half < 2; half++) {
                        int rr = rr1 + half * 8;
                        bool ok = (MODE == 1) || (m0 + rr < cnt);
                        if (ok) {
                            size_t row = (MODE == 1) ? (size_t)(m0 + rr) : (size_t)(off + m0 + rr);
                            float g0 = sG[rr * 65 + col], g1 = sG[rr * 65 + col + 1];
                            float u0 = acc[mf][nf][half * 2], u1 = acc[mf][nf][half * 2 + 1];
                            float o0 = g0 / (1.f + fexp(-g0)) * u0;
                            float o1 = g1 / (1.f + fexp(-g1)) * u1;
                            *(uint32_t*)(Ch + row * ldc + nb + col) = pack_hi(o0, o1);
                        }
                    }
                }
        }
    } else {  // MODE 3
        #pragma unroll
        for (int mf = 0; mf < 2; mf++) {
            int rr1 = wm * 32 + mf * 16 + r4;
            #pragma unroll
            for (int half = 0; half < 2; half++) {
                int rr = rr1 + half * 8;
                if (m0 + rr < cnt) {
                    int tok = g_ptok[off + m0 + rr];
                    float w = g_pw[off + m0 + rr];
                    float* dst = C + (size_t)tok * ldc;
                    #pragma unroll
                    for (int nf = 0; nf < 8; nf++) {
                        int col = nb + wn * 64 + nf * 8 + c2;
                        atomicAdd(dst + col,     w * acc[mf][nf][half * 2]);
                        atomicAdd(dst + col + 1, w * acc[mf][nf][half * 2 + 1]);
                    }
                }
            }
        }
    }
}

// ------------------------- small kernels ------------------------------------
__global__ void cs_prep_k(const int* __restrict__ pos) {
    int t = blockIdx.x, i = threadIdx.x;   // 64 threads
    if (t == 0 && i < NEXP) g_cnt[i] = 0;
    double e = exp(-((double)(2 * i) / 128.0) * log(500000.0));
    float f = (float)pos[t] * (float)e;
    float sn, cs; sincosf(f, &sn, &cs);
    g_cs[t * 64 + i] = make_float2(cs, sn);
}

// rmsnorm: writes optional fp32 y + bf16 yh (hi only)
__global__ void rmsnorm_k(const float* __restrict__ x, const float* __restrict__ w,
                          float* __restrict__ y, __nv_bfloat16* __restrict__ yh,
                          int cols, int ldx, int ldy)
{
    int row = blockIdx.x;
    const float* xr = x + (size_t)row * ldx;
    float ss = 0.f;
    for (int c = threadIdx.x; c < cols; c += 256) { float v = xr[c]; ss = fmaf(v, v, ss); }
    __shared__ float wred[8];
    #pragma unroll
    for (int d = 16; d; d >>= 1) ss += __shfl_xor_sync(0xffffffffu, ss, d);
    if ((threadIdx.x & 31) == 0) wred[threadIdx.x >> 5] = ss;
    __syncthreads();
    if (threadIdx.x < 32) {
        float v = (threadIdx.x < 8) ? wred[threadIdx.x] : 0.f;
        #pragma unroll
        for (int d = 4; d; d >>= 1) v += __shfl_xor_sync(0xffffffffu, v, d);
        if (threadIdx.x == 0) wred[0] = v;
    }
    __syncthreads();
    float r = rsqrtf(wred[0] / (float)cols + 1e-5f);
    for (int c = threadIdx.x; c < cols; c += 256) {
        float v = xr[c] * r * w[c];
        if (y) y[(size_t)row * ldy + c] = v;
        yh[(size_t)row * ldy + c] = __float2bfloat16_rn(v);
    }
}

// fused: Q rope (split bf16, SCALE folded) + K rope transpose split + V round
__global__ void qkv_prep_k(const float* __restrict__ qp, const float* __restrict__ qkv,
                           __nv_bfloat16* __restrict__ qh, __nv_bfloat16* __restrict__ ql)
{
    int t = blockIdx.x;
    int tid = threadIdx.x;   // 256
    for (int idx = tid; idx < NHEAD * 64; idx += 256) {
        int hh = idx >> 6, i = idx & 63;
        float2 cs = g_cs[t * 64 + i];
        const float* b = qp + (size_t)t * 2048 + hh * HD;
        float x1 = b[i], x2 = b[i + 64];
        float y1 = (x1 * cs.x - x2 * cs.y) * SCALE;
        float y2 = (x2 * cs.x + x1 * cs.y) * SCALE;
        size_t o1 = (size_t)t * 2048 + hh * HD + i;
        __nv_bfloat16 h1 = __float2bfloat16_rn(y1);
        qh[o1] = h1; ql[o1] = __float2bfloat16_rn(y1 - __bfloat162float(h1));
        __nv_bfloat16 h2 = __float2bfloat16_rn(y2);
        qh[o1 + 64] = h2; ql[o1 + 64] = __float2bfloat16_rn(y2 - __bfloat162float(h2));
    }
    if (tid < 64) {
        int i = tid;
        float2 cs = g_cs[t * 64 + i];
        const float* kb = qkv + (size_t)t * QKV_N + QDIM;
        float x1 = kb[i], x2 = kb[i + 64];
        float y1 = x1 * cs.x - x2 * cs.y;
        float y2 = x2 * cs.x + x1 * cs.y;
        __nv_bfloat16 h1 = __float2bfloat16_rn(y1);
        g_kth[(size_t)i * SEQ + t] = h1;
        g_ktl[(size_t)i * SEQ + t] = __float2bfloat16_rn(y1 - __bfloat162float(h1));
        __nv_bfloat16 h2 = __float2bfloat16_rn(y2);
        g_kth[(size_t)(i + 64) * SEQ + t] = h2;
        g_ktl[(size_t)(i + 64) * SEQ + t] = __float2bfloat16_rn(y2 - __bfloat162float(h2));
    }
    if (tid < 128) {
        float v = qkv[(size_t)t * QKV_N + QDIM + HD + tid];
        g_vh[(size_t)t * HD + tid] = __float2bfloat16_rn(v);
    }
}

// ------------------------- attention: FA2-style register-P -----------------
// 8 warps x 16 q-rows; QK 3-pass; P in registers (1-pass bf16); V single bf16
#define AQ_LD 136
#define AK_LD 72
#define AV_LD 136
#define AOF_QH 0
#define AOF_QL 34816
#define AOF_KH 69632
#define AOF_KL 88064
#define AOF_VH 106496
#define ATTN_SMEM 123904

__global__ __launch_bounds__(256, 1) void attn_k(
    const __nv_bfloat16* __restrict__ Qh, const __nv_bfloat16* __restrict__ Ql,
    __nv_bfloat16* __restrict__ Oh)
{
    extern __shared__ __align__(16) char sm[];
    const int bx = blockIdx.x;
    const int qt = 15 - (bx >> 4);     // longest tiles first
    const int h = bx & 15;
    const int q0 = qt * 128;

    const int tid = threadIdx.x;
    const int wid = tid >> 5, lane = tid & 31;
    const int lrow = lane & 15, lcol8 = (lane >> 4) * 8;
    const int r4 = lane >> 2, c2 = (lane & 3) * 2;
    const int mbase = wid * 16;        // this warp's q-row block

    const uint32_t uQh = s2u(sm + AOF_QH), uQl = s2u(sm + AOF_QL);
    const uint32_t uKh = s2u(sm + AOF_KH), uKl = s2u(sm + AOF_KL);
    const uint32_t uVh = s2u(sm + AOF_VH);

    // load Q tile (128 x 128, hi+lo)
    #pragma unroll
    for (int it = 0; it < 8; it++) {
        int i = tid + it * 256;          // 2048 uint4 per copy
        int r = i >> 4, c = (i & 15) << 3;
        size_t src = (size_t)(q0 + r) * 2048 + h * HD + c;
        *(uint4*)(sm + AOF_QH + r * (AQ_LD*2) + c * 2) = *(const uint4*)(Qh + src);
        *(uint4*)(sm + AOF_QL + r * (AQ_LD*2) + c * 2) = *(const uint4*)(Ql + src);
    }

    float m0r = -3.0e30f, m1r = -3.0e30f;   // running max for rows r4, r4+8
    float l0r = 0.f, l1r = 0.f;             // running sum
    float o[16][4] = {};                     // 16 n8-tiles x 128 out cols
    const int nkt = 2 * qt + 2;

    for (int kt = 0; kt < nkt; kt++) {
        const int k0 = kt * 64;
        __syncthreads();
        // load K tile (transposed source [d][tok]): 128 x 64, hi+lo
        #pragma unroll
        for (int it = 0; it < 4; it++) {
            int i = tid + it * 256;      // 1024 uint4 per copy
            int d = i >> 3, tc = (i & 7) << 3;
            size_t src = (size_t)d * SEQ + k0 + tc;
            *(uint4*)(sm + AOF_KH + d * (AK_LD*2) + tc * 2) = *(const uint4*)(g_kth + src);
            *(uint4*)(sm + AOF_KL + d * (AK_LD*2) + tc * 2) = *(const uint4*)(g_ktl + src);
        }
        // load V tile: 64 x 128 (single bf16)
        #pragma unroll
        for (int it = 0; it < 2; it++) {
            int i = tid + it * 256;
            int r = i >> 4, c = (i & 15) << 3;
            size_t src = (size_t)(k0 + r * 2) * HD + c;
            *(uint4*)(sm + AOF_VH + (r * 2) * (AV_LD*2) + c * 2) = *(const uint4*)(g_vh + src);
            *(uint4*)(sm + AOF_VH + (r * 2 + 1) * (AV_LD*2) + c * 2) =
                *(const uint4*)(g_vh + src + HD);
        }
        __syncthreads();

        // ---- S = Q K^T (3-pass split): warp computes 16 rows x 64 cols ----
        float sacc[8][4] = {};
        #pragma unroll
        for (int ks = 0; ks < 8; ks++) {
            uint32_t ah[4], al[4];
            uint32_t roA = (uint32_t)((mbase + lrow) * AQ_LD + ks * 16 + lcol8) * 2;
            ldsm4(ah, uQh + roA);
            ldsm4(al, uQl + roA);
            #pragma unroll
            for (int nh = 0; nh < 4; nh++) {
                uint32_t bh[4], bl[4];
                uint32_t ro = (uint32_t)((ks * 16 + lrow) * AK_LD + nh * 16 + lcol8) * 2;
                ldsm4t(bh, uKh + ro);
                ldsm4t(bl, uKl + ro);
                #pragma unroll
                for (int sub = 0; sub < 2; sub++) {
                    int nf = nh * 2 + sub;
                    mma16816(sacc[nf], ah, bh[sub*2], bh[sub*2+1]);
                    mma16816(sacc[nf], ah, bl[sub*2], bl[sub*2+1]);
                    mma16816(sacc[nf], al, bh[sub*2], bh[sub*2+1]);
                }
            }
        }

        // causal mask on diagonal tiles
        if (kt >= nkt - 2) {
            #pragma unroll
            for (int nf = 0; nf < 8; nf++)
                #pragma unroll
                for (int v = 0; v < 4; v++) {
                    int row = q0 + mbase + r4 + (v >= 2 ? 8 : 0);
                    int col = k0 + nf * 8 + c2 + (v & 1);
                    if (col > row) sacc[nf][v] = -1.0e30f;
                }
        }

        // ---- warp-local row max ----
        float rx0 = -3.0e30f, rx1 = -3.0e30f;
        #pragma unroll
        for (int nf = 0; nf < 8; nf++) {
            rx0 = fmaxf(rx0, fmaxf(sacc[nf][0], sacc[nf][1]));
            rx1 = fmaxf(rx1, fmaxf(sacc[nf][2], sacc[nf][3]));
        }
        rx0 = fmaxf(rx0, __shfl_xor_sync(0xffffffffu, rx0, 1));
        rx0 = fmaxf(rx0, __shfl_xor_sync(0xffffffffu, rx0, 2));
        rx1 = fmaxf(rx1, __shfl_xor_sync(0xffffffffu, rx1, 1));
        rx1 = fmaxf(rx1, __shfl_xor_sync(0xffffffffu, rx1, 2));
        float mn0 = fmaxf(m0r, rx0), mn1 = fmaxf(m1r, rx1);
        float f0 = fexp(m0r - mn0), f1 = fexp(m1r - mn1);

        // ---- p = exp(s-mn) -> pack directly into PV A-fragments ----
        uint32_t pk[4][4];   // 4 k16 fragments covering k=64
        float rs0 = 0.f, rs1 = 0.f;
        #pragma unroll
        for (int kf = 0; kf < 4; kf++) {
            #pragma unroll
            for (int half = 0; half < 2; half++) {
                int nf = kf * 2 + half;
                float p0 = fexp(sacc[nf][0] - mn0);
                float p1 = fexp(sacc[nf][1] - mn0);
                float p2 = fexp(sacc[nf][2] - mn1);
                float p3 = fexp(sacc[nf][3] - mn1);
                rs0 += p0 + p1;
                rs1 += p2 + p3;
                pk[kf][half * 2]     = pack_hi(p0, p1);
                pk[kf][half * 2 + 1] = pack_hi(p2, p3);
            }
        }
        rs0 += __shfl_xor_sync(0xffffffffu, rs0, 1);
        rs0 += __shfl_xor_sync(0xffffffffu, rs0, 2);
        rs1 += __shfl_xor_sync(0xffffffffu, rs1, 1);
        rs1 += __shfl_xor_sync(0xffffffffu, rs1, 2);
        l0r = l0r * f0 + rs0;
        l1r = l1r * f1 + rs1;
        m0r = mn0; m1r = mn1;

        // rescale o
        #pragma unroll
        for (int nf = 0; nf < 16; nf++) {
            o[nf][0] *= f0; o[nf][1] *= f0;
            o[nf][2] *= f1; o[nf][3] *= f1;
        }

        // ---- O += P V (P in regs, V single bf16) ----
        #pragma unroll
        for (int ks2 = 0; ks2 < 4; ks2++) {
            #pragma unroll
            for (int nh = 0; nh < 8; nh++) {
                uint32_t bv[4];
                uint32_t ro = (uint32_t)((ks2 * 16 + lrow) * AV_LD + nh * 16 + lcol8) * 2;
                ldsm4t(bv, uVh + ro);
                mma16816(o[nh * 2],     pk[ks2], bv[0], bv[1]);
                mma16816(o[nh * 2 + 1], pk[ks2], bv[2], bv[3]);
            }
        }
    }

    // ---- write O (hi bf16) ----
    float inv0 = 1.f / l0r, inv1 = 1.f / l1r;
    int row0 = q0 + mbase + r4;
    #pragma unroll
    for (int nf = 0; nf < 16; nf++) {
        int col = h * HD + nf * 8 + c2;
        *(uint32_t*)(Oh + (size_t)row0 * 2048 + col) = pack_hi(o[nf][0] * inv0, o[nf][1] * inv0);
        *(uint32_t*)(Oh + (size_t)(row0 + 8) * 2048 + col) = pack_hi(o[nf][2] * inv1, o[nf][3] * inv1);
    }
}

// ------------------------- router / topk / scan / fill ---------------------
__global__ __launch_bounds__(256) void router_k(const float* __restrict__ X,
                                                const float* __restrict__ Wr)
{
    __shared__ float part[8][32];
    int t = blockIdx.x;
    int e = threadIdx.x & 31, p = threadIdx.x >> 5;
    const float* xr = X + (size_t)t * HID;
    float s = 0.f;
    for (int k = p * 128; k < p * 128 + 128; k++) s = fmaf(xr[k], Wr[k * 32 + e], s);
    part[p][e] = s;
    __syncthreads();
    if (threadIdx.x < 32) {
        float logit = 0.f;
        #pragma unroll
        for (int q = 0; q < 8; q++) logit += part[q][e];
        float m = logit;
        for (int d = 16; d; d >>= 1) m = fmaxf(m, __shfl_xor_sync(0xffffffffu, m, d));
        float ex = __expf(logit - m);
        float cur = ex;
        float wsel[3]; int isel[3];
        #pragma unroll
        for (int kk = 0; kk < 3; kk++) {
            float v = cur; int idx = e;
            for (int d = 16; d; d >>= 1) {
                float v2 = __shfl_xor_sync(0xffffffffu, v, d);
                int   i2 = __shfl_xor_sync(0xffffffffu, idx, d);
                if (v2 > v || (v2 == v && i2 < idx)) { v = v2; idx = i2; }
            }
            wsel[kk] = v; isel[kk] = idx;
            if (e == idx) cur = -1.f;
        }
        float tot = wsel[0] + wsel[1] + wsel[2];
        if (e < 3) { g_topi[t * 3 + e] = isel[e]; g_topw[t * 3 + e] = wsel[e] / tot; }
        if (e == 0) {
            atomicAdd(&g_cnt[isel[0]], 1);
            atomicAdd(&g_cnt[isel[1]], 1);
            atomicAdd(&g_cnt[isel[2]], 1);
        }
    }
}

__global__ void scan_k()
{
    int e = threadIdx.x;
    int c = g_cnt[e];
    int x = c;
    for (int d = 1; d < 32; d <<= 1) {
        int y = __shfl_up_sync(0xffffffffu, x, d);
        if (e >= d) x += y;
    }
    int excl = x - c;
    g_off[e] = excl;
    g_fill[e] = excl;
}

__global__ void fill_k()
{
    int t = blockIdx.x * 256 + threadIdx.x;
    if (t < SEQ) {
        #pragma unroll
        for (int k = 0; k < 3; k++) {
            int e = g_topi[t * 3 + k];
            int slot = atomicAdd(&g_fill[e], 1);
            g_ptok[slot] = t;
            g_pw[slot] = g_topw[t * 3 + k];
        }
    }
}

// ------------------------- launch ------------------------------------------
extern "C" void kernel_launch(void* const* d_in, const int* in_sizes, int n_in,
                              void* d_out, int out_size)
{
    const float* hidden   = (const float*)d_in[0];
    const float* w_in     = (const float*)d_in[1];
    const float* w_qkv    = (const float*)d_in[2];
    const float* w_inter  = (const float*)d_in[3];
    const float* w_q      = (const float*)d_in[4];
    const float* w_o      = (const float*)d_in[5];
    const float* w_post   = (const float*)d_in[6];
    const float* w_guse   = (const float*)d_in[7];
    const float* w_dse    = (const float*)d_in[8];
    const float* w_router = (const float*)d_in[9];
    const float* w_gue    = (const float*)d_in[10];
    const float* w_de     = (const float*)d_in[11];
    const int*   pos      = (const int*)d_in[12];
    float* out = (float*)d_out;

    float *qkv, *qproj, *resid2, *h2;
    cudaGetSymbolAddress((void**)&qkv,    g_qkv);
    cudaGetSymbolAddress((void**)&qproj,  g_qproj);
    cudaGetSymbolAddress((void**)&resid2, g_resid2);
    cudaGetSymbolAddress((void**)&h2,     g_h2);
    __nv_bfloat16 *hnh,*qnh,*qh,*ql,*aoh,*h2h,*aseh,*aceh;
    __nv_bfloat16 *wqkvh,*wqh,*woh,*wguh,*wdh;
    cudaGetSymbolAddress((void**)&hnh, g_hnh);
    cudaGetSymbolAddress((void**)&qnh, g_qnh);
    cudaGetSymbolAddress((void**)&qh,  g_qh);    cudaGetSymbolAddress((void**)&ql,  g_ql);
    cudaGetSymbolAddress((void**)&aoh, g_aoh);
    cudaGetSymbolAddress((void**)&h2h, g_h2h);
    cudaGetSymbolAddress((void**)&aseh,g_aseh);
    cudaGetSymbolAddress((void**)&aceh,g_aceh);
    cudaGetSymbolAddress((void**)&wqkvh,g_wqkvh);
    cudaGetSymbolAddress((void**)&wqh, g_wqh);
    cudaGetSymbolAddress((void**)&woh, g_woh);
    cudaGetSymbolAddress((void**)&wguh,g_wguh);
    cudaGetSymbolAddress((void**)&wdh, g_wdh);

    cudaFuncSetAttribute(attn_k, cudaFuncAttributeMaxDynamicSharedMemorySize, ATTN_SMEM);
    cudaFuncSetAttribute((gemm_tc<0,1>), cudaFuncAttributeMaxDynamicSharedMemorySize, SMEM_DENSE);
    cudaFuncSetAttribute((gemm_tc<1,1>), cudaFuncAttributeMaxDynamicSharedMemorySize, SMEM_DENSE);
    cudaFuncSetAttribute((gemm_tc<2,0>), cudaFuncAttributeMaxDynamicSharedMemorySize, SMEM_MOE);
    cudaFuncSetAttribute((gemm_tc<3,0>), cudaFuncAttributeMaxDynamicSharedMemorySize, SMEM_MOE);

    cs_prep_k<<<SEQ, 64>>>(pos);
    split_all_k<<<(SPL4 + 255)/256, 256>>>(w_qkv, w_q, w_o, w_guse, w_dse);

    rmsnorm_k<<<SEQ, 256>>>(hidden, w_in, nullptr, hnh, HID, HID, HID);
    gemm_tc<0,1><<<dim3(QKV_N/128, SEQ/64), 128, SMEM_DENSE>>>(
        hnh, wqkvh, qkv, nullptr, nullptr, HID, HID, QKV_N, QKV_N, 0, 0);
    rmsnorm_k<<<SEQ, 256>>>(qkv, w_inter, nullptr, qnh, QDIM, QKV_N, QDIM);
    gemm_tc<0,1><<<dim3(2048/128, SEQ/64), 128, SMEM_DENSE>>>(
        qnh, wqh, qproj, nullptr, nullptr, QDIM, QDIM, 2048, 2048, 0, 0);
    qkv_prep_k<<<SEQ, 256>>>(qproj, qkv, qh, ql);
    attn_k<<<256, 256, ATTN_SMEM>>>(qh, ql, aoh);
    gemm_tc<0,1><<<dim3(HID/128, SEQ/64), 128, SMEM_DENSE>>>(
        aoh, woh, resid2, nullptr, hidden, 2048, 2048, HID, HID, 0, 0);
    rmsnorm_k<<<SEQ, 256>>>(resid2, w_post, h2, h2h, HID, HID, HID);
    gemm_tc<1,1><<<dim3(IDIM/64, SEQ/64), 128, SMEM_DENSE>>>(
        h2h, wguh, nullptr, aseh, nullptr, HID, HID, 2*IDIM, IDIM, IDIM, 0);
    gemm_tc<0,1><<<dim3(HID/128, SEQ/64), 128, SMEM_DENSE>>>(
        aseh, wdh, out, nullptr, resid2, IDIM, IDIM, HID, HID, 0, 0);
    router_k<<<SEQ, 256>>>(h2, w_router);
    scan_k<<<1, 32>>>();
    fill_k<<<SEQ/256, 256>>>();
    gemm_tc<2,0><<<dim3(IDIM/64, 32, NEXP), 128, SMEM_MOE>>>(
        h2h, w_gue, nullptr, aceh, nullptr, HID, HID, 2*IDIM, IDIM, IDIM,
        (size_t)HID * 2 * IDIM);
    gemm_tc<3,0><<<dim3(HID/128, 32, NEXP), 128, SMEM_MOE>>>(
        aceh, w_de, out, nullptr, nullptr, IDIM, IDIM, HID, HID, 0,
        (size_t)IDIM * HID);
}

// round 17
// speedup vs baseline: 1.8772x; 1.0626x over previous
#include <cuda_runtime.h>
#include <cuda_bf16.h>
#include <math.h>
#include <stdint.h>

#define SEQ 2048
#define HID 1024
#define NHEAD 16
#define HD 128
#define QDIM 512
#define NEXP 32
#define IDIM 1024
#define QKV_N 768
#define SCALE 0.08838834764831845f   // 1/sqrt(128)

// ------------------------- device scratch ----------------------------------
__device__ float g_qkv[SEQ*QKV_N];
__device__ float g_qproj[SEQ*NHEAD*HD];
__device__ float g_resid2[SEQ*HID];
__device__ float g_h2[SEQ*HID];
__device__ float2 g_cs[SEQ*64];

__device__ __nv_bfloat16 g_hnh[SEQ*HID];
__device__ __nv_bfloat16 g_qnh[SEQ*QDIM];
__device__ __nv_bfloat16 g_qh[SEQ*2048];
__device__ __nv_bfloat16 g_kth[128*SEQ];   // transposed [d][token]
__device__ __nv_bfloat16 g_vh[SEQ*128];
__device__ __nv_bfloat16 g_aoh[SEQ*2048];
__device__ __nv_bfloat16 g_h2h[SEQ*HID];
__device__ __nv_bfloat16 g_aseh[SEQ*IDIM];
__device__ __nv_bfloat16 g_aceh[SEQ*3*IDIM];

// pre-rounded dense weights (single bf16)
__device__ __nv_bfloat16 g_wqkvh[HID*QKV_N];
__device__ __nv_bfloat16 g_wqh[QDIM*2048];
__device__ __nv_bfloat16 g_woh[2048*HID];
__device__ __nv_bfloat16 g_wguh[HID*2*IDIM];
__device__ __nv_bfloat16 g_wdh[IDIM*HID];

__device__ int   g_topi[SEQ*3];
__device__ float g_topw[SEQ*3];
__device__ int   g_cnt[NEXP];
__device__ int   g_off[NEXP];
__device__ int   g_fill[NEXP];
__device__ int   g_ptok[SEQ*3];
__device__ float g_pw[SEQ*3];

// ------------------------- helpers -----------------------------------------
__device__ __forceinline__ uint32_t s2u(const void* p) {
    uint32_t a;
    asm("{ .reg .u64 t; cvta.to.shared.u64 t, %1; cvt.u32.u64 %0, t; }" : "=r"(a) : "l"(p));
    return a;
}
__device__ __forceinline__ void ldsm4(uint32_t* r, uint32_t addr) {
    asm volatile("ldmatrix.sync.aligned.m8n8.x4.shared.b16 {%0,%1,%2,%3}, [%4];"
        : "=r"(r[0]), "=r"(r[1]), "=r"(r[2]), "=r"(r[3]) : "r"(addr));
}
__device__ __forceinline__ void ldsm4t(uint32_t* r, uint32_t addr) {
    asm volatile("ldmatrix.sync.aligned.m8n8.x4.trans.shared.b16 {%0,%1,%2,%3}, [%4];"
        : "=r"(r[0]), "=r"(r[1]), "=r"(r[2]), "=r"(r[3]) : "r"(addr));
}
__device__ __forceinline__ void mma16816(float* c, const uint32_t* a, uint32_t b0, uint32_t b1) {
    asm volatile("mma.sync.aligned.m16n8k16.row.col.f32.bf16.bf16.f32 "
        "{%0,%1,%2,%3}, {%4,%5,%6,%7}, {%8,%9}, {%0,%1,%2,%3};"
        : "+f"(c[0]), "+f"(c[1]), "+f"(c[2]), "+f"(c[3])
        : "r"(a[0]), "r"(a[1]), "r"(a[2]), "r"(a[3]), "r"(b0), "r"(b1));
}
__device__ __forceinline__ void cpa16(uint32_t dst, const void* src) {
    asm volatile("cp.async.cg.shared.global [%0], [%1], 16;" :: "r"(dst), "l"(src));
}
#define CPA_COMMIT() asm volatile("cp.async.commit_group;" ::: "memory")
#define CPA_WAIT0()  asm volatile("cp.async.wait_group 0;" ::: "memory")
#define CPA_WAIT1()  asm volatile("cp.async.wait_group 1;" ::: "memory")

__device__ __forceinline__ uint32_t pack_hi(float f0, float f1) {
    __nv_bfloat162 h = __floats2bfloat162_rn(f0, f1);
    return *(uint32_t*)&h;
}
// FFMA-only exp (rel err ~4e-5), avoids MUFU
__device__ __forceinline__ float fexp(float x) {
    x = fminf(fmaxf(x, -80.f), 80.f);
    float y = x * 1.4426950408889634f;
    float n = rintf(y);
    float f = y - n;
    float p = fmaf(f, 0.009618130f, 0.055504110f);
    p = fmaf(p, f, 0.240226507f);
    p = fmaf(p, f, 0.693147181f);
    p = fmaf(p, f, 1.0f);
    return p * __int_as_float(((int)n + 127) << 23);
}

// fused weight pre-round: all 5 dense weights -> single bf16, one launch
#define SPL0 (HID*QKV_N/4)
#define SPL1 (SPL0 + QDIM*2048/4)
#define SPL2 (SPL1 + 2048*HID/4)
#define SPL3 (SPL2 + HID*2*IDIM/4)
#define SPL4 (SPL3 + IDIM*HID/4)
__global__ void split_all_k(const float* __restrict__ W0, const float* __restrict__ W1,
                            const float* __restrict__ W2, const float* __restrict__ W3,
                            const float* __restrict__ W4)
{
    int i = blockIdx.x * 256 + threadIdx.x;
    if (i >= SPL4) return;
    const float* W; __nv_bfloat16 *Wh; int j;
    if (i < SPL0)      { W = W0; Wh = g_wqkvh; j = i; }
    else if (i < SPL1) { W = W1; Wh = g_wqh;   j = i - SPL0; }
    else if (i < SPL2) { W = W2; Wh = g_woh;   j = i - SPL1; }
    else if (i < SPL3) { W = W3; Wh = g_wguh;  j = i - SPL2; }
    else               { W = W4; Wh = g_wdh;   j = i - SPL3; }
    float4 v = ((const float4*)W)[j];
    uint32_t h0 = pack_hi(v.x, v.y), h1 = pack_hi(v.z, v.w);
    ((uint2*)Wh)[j] = make_uint2(h0, h1);
}

// ------------------------- GEMM -------------------------------------------
// dense (BSPLIT=1): BK=64, 3-stage ring, pure cp.async
// MoE   (BSPLIT=0): BK=32, 2-stage, inline B convert
#define LDB 136
// MoE layout (BK=32)
#define LDA_M 40
#define ASZ_M (64*LDA_M*2)           // 5120
#define BSZ_M (32*LDB*2)             // 8704
#define OFF_AM(b) ((b) * ASZ_M)
#define OFF_BM(b) (2*ASZ_M + (b) * BSZ_M)
#define OFF_TOK   (2*ASZ_M + 2*BSZ_M)
#define SMEM_MOE  (OFF_TOK + 64*4)
// dense layout (BK=64)
#define LDA_D 72
#define ASZ_D (64*LDA_D*2)           // 9216
#define BSZ_D (64*LDB*2)             // 17408
#define OFF_AD(b) ((b) * ASZ_D)
#define OFF_BD(b) (3*ASZ_D + (b) * BSZ_D)
#define SMEM_DENSE (3*ASZ_D + 3*BSZ_D)   // 79872

// MODE 0: plain  C = A@B (+add) fp32       (64 rows x 128 out cols / CTA)
// MODE 1: gated  Ch = bf16(silu(A@Bg)*(A@Bu))  (64 rows x 64 cols, up at +upOff)
// MODE 2: moe gathered gated -> Ch rows off+r
// MODE 3: moe scatter: C[tok] += w * (A@B)  fp32 atomic
template<int MODE, int BSPLIT>
__global__ __launch_bounds__(128, 4) void gemm_tc(
    const __nv_bfloat16* __restrict__ Ah,
    const void* __restrict__ B1,
    float* __restrict__ C, __nv_bfloat16* __restrict__ Ch,
    const float* __restrict__ add,
    int K, int lda, int ldb, int ldc, int upOff, size_t bStride)
{
    int cnt = 0, off = 0;
    size_t bOff = 0;
    if (MODE >= 2) {
        int e = blockIdx.z;
        cnt = g_cnt[e];
        if ((int)blockIdx.y * 64 >= cnt) return;
        off = g_off[e];
        bOff = bStride * e;
    }
    const int m0 = blockIdx.y * 64;
    const int nb = blockIdx.x * ((MODE == 1 || MODE == 2) ? 64 : 128);

    extern __shared__ __align__(16) char sm[];
    int* sTok = (int*)(sm + OFF_TOK);
    const uint32_t sb = s2u(sm);

    const int tid = threadIdx.x;
    const int wid = tid >> 5, lane = tid & 31;
    const int wm = wid >> 1, wn = wid & 1;

    if (MODE == 2 && tid < 64) {
        int gr = m0 + tid;
        sTok[tid] = (gr < cnt) ? g_ptok[off + gr] : 0;
    }
    __syncthreads();

    float acc[2][8][4] = {};
    const int lrow = lane & 15, lcol8 = (lane >> 4) * 8;

    if (BSPLIT) {
        // ============= dense: BK=64, pure cp.async, 3-stage ring =============
        const __nv_bfloat16* Bh = (const __nv_bfloat16*)B1;
        const int nkt = K >> 6;

        size_t asrc[4]; uint32_t adst[4];
        #pragma unroll
        for (int it = 0; it < 4; it++) {
            int s = tid + it * 128;
            int m = s >> 3, seg = s & 7;
            asrc[it] = (size_t)(m0 + m) * lda + seg * 8;
            adst[it] = sb + m * (LDA_D*2) + seg * 16;
        }
        size_t bsrc[8]; uint32_t bdst[8];
        #pragma unroll
        for (int it = 0; it < 8; it++) {
            int s = tid + it * 128;
            int kk = s >> 4, cs = (s & 15) * 8;
            int col;
            if (MODE == 1) col = (cs < 64) ? nb + cs : upOff + nb + (cs - 64);
            else           col = nb + cs;
            bsrc[it] = (size_t)kk * ldb + col;
            bdst[it] = sb + kk * (LDB*2) + cs * 2;
        }

        auto issue = [&](int bf, int k0) {
            #pragma unroll
            for (int it = 0; it < 4; it++)
                cpa16(adst[it] + OFF_AD(bf), Ah + asrc[it] + k0);
            #pragma unroll
            for (int it = 0; it < 8; it++)
                cpa16(bdst[it] + OFF_BD(bf), Bh + bsrc[it] + (size_t)k0 * ldb);
            CPA_COMMIT();
        };

        issue(0, 0);
        if (nkt > 1) issue(1, 64);

        int bf = 0;
        for (int c = 0; c < nkt; c++) {
            if (c + 1 < nkt) { CPA_WAIT1(); } else { CPA_WAIT0(); }
            __syncthreads();
            if (c + 2 < nkt) {
                int nb3 = bf + 2; if (nb3 >= 3) nb3 -= 3;
                issue(nb3, (c + 2) << 6);
            }
            const uint32_t uAh = sb + OFF_AD(bf);
            const uint32_t uBh = sb + OFF_BD(bf);
            #pragma unroll
            for (int ks = 0; ks < 4; ks++) {
                uint32_t ah[2][4];
                #pragma unroll
                for (int mf = 0; mf < 2; mf++) {
                    uint32_t ro = (uint32_t)((wm * 32 + mf * 16 + lrow) * LDA_D + ks * 16 + lcol8) * 2;
                    ldsm4(ah[mf], uAh + ro);
                }
                #pragma unroll
                for (int nh = 0; nh < 4; nh++) {
                    uint32_t bh[4];
                    uint32_t ro = (uint32_t)((ks * 16 + lrow) * LDB + wn * 64 + nh * 16 + lcol8) * 2;
                    ldsm4t(bh, uBh + ro);
                    #pragma unroll
                    for (int mf = 0; mf < 2; mf++)
                        #pragma unroll
                        for (int sub = 0; sub < 2; sub++) {
                            int nf = nh * 2 + sub;
                            mma16816(acc[mf][nf], ah[mf], bh[sub*2], bh[sub*2+1]);
                        }
                }
            }
            bf++; if (bf >= 3) bf = 0;
        }
        __syncthreads();
    } else {
        // ============= MoE: BK=32, fp32 B -> single bf16 =====================
        const float* B = (const float*)B1 + bOff;
        const int nkt = K >> 5;
        const int am0 = tid >> 2, aseg0 = (tid & 3);
        const int am1 = (tid + 128) >> 2, aseg1 = ((tid + 128) & 3);
        size_t arow0, arow1;
        if (MODE == 2) {
            arow0 = (size_t)sTok[am0] * lda;
            arow1 = (size_t)sTok[am1] * lda;
        } else {
            int r0 = (m0 + am0 < cnt) ? m0 + am0 : 0;
            int r1 = (m0 + am1 < cnt) ? m0 + am1 : 0;
            arow0 = (size_t)(off + r0) * lda;
            arow1 = (size_t)(off + r1) * lda;
        }
        const uint32_t adst0 = sb + am0 * (LDA_M*2) + aseg0 * 16;
        const uint32_t adst1 = sb + am1 * (LDA_M*2) + aseg1 * 16;
        const int aoff0 = aseg0 * 8, aoff1 = aseg1 * 8;

        int bcol[8]; size_t brow[8];
        #pragma unroll
        for (int it = 0; it < 8; it++) {
            int i = tid + it * 128;
            int kk = i >> 5;
            int n4 = (i & 31) << 2;
            int col;
            if (MODE == 2) col = (n4 < 64) ? nb + n4 : upOff + nb + (n4 - 64);
            else           col = nb + n4;
            bcol[it] = n4;
            brow[it] = (size_t)kk * ldb + col;
        }
        float4 br[8];
        {
            cpa16(adst0 + OFF_AM(0), Ah + arow0 + aoff0);
            cpa16(adst1 + OFF_AM(0), Ah + arow1 + aoff1);
            CPA_COMMIT();
            #pragma unroll
            for (int it = 0; it < 8; it++) br[it] = *(const float4*)(B + brow[it]);
            CPA_WAIT0();
            __syncthreads();
            #pragma unroll
            for (int it = 0; it < 8; it++) {
                int i = tid + it * 128;
                int kk = i >> 5;
                uint32_t h0 = pack_hi(br[it].x, br[it].y), h1 = pack_hi(br[it].z, br[it].w);
                uint32_t* ph = (uint32_t*)(sm + OFF_BM(0) + kk * (LDB*2) + bcol[it] * 2);
                ph[0] = h0; ph[1] = h1;
            }
            __syncthreads();
        }
        int p = 0;
        for (int c = 0; c < nkt; c++) {
            const int q = p ^ 1;
            const bool more = (c + 1 < nkt);
            if (more) {
                const int k1 = (c + 1) << 5;
                cpa16(adst0 + OFF_AM(q), Ah + arow0 + k1 + aoff0);
                cpa16(adst1 + OFF_AM(q), Ah + arow1 + k1 + aoff1);
                CPA_COMMIT();
                #pragma unroll
                for (int it = 0; it < 8; it++)
                    br[it] = *(const float4*)(B + (size_t)k1 * ldb + brow[it]);
            }
            const uint32_t uAh = sb + OFF_AM(p);
            const uint32_t uBh = sb + OFF_BM(p);
            #pragma unroll
            for (int ks = 0; ks < 2; ks++) {
                uint32_t ah[2][4];
                #pragma unroll
                for (int mf = 0; mf < 2; mf++) {
                    uint32_t ro = (uint32_t)((wm * 32 + mf * 16 + lrow) * LDA_M + ks * 16 + lcol8) * 2;
                    ldsm4(ah[mf], uAh + ro);
                }
                #pragma unroll
                for (int nh = 0; nh < 4; nh++) {
                    uint32_t bh[4];
                    uint32_t ro = (uint32_t)((ks * 16 + lrow) * LDB + wn * 64 + nh * 16 + lcol8) * 2;
                    ldsm4t(bh, uBh + ro);
                    #pragma unroll
                    for (int mf = 0; mf < 2; mf++)
                        #pragma unroll
                        for (int sub = 0; sub < 2; sub++) {
                            int nf = nh * 2 + sub;
                            mma16816(acc[mf][nf], ah[mf], bh[sub*2], bh[sub*2+1]);
                        }
                }
            }
            if (more) {
                #pragma unroll
                for (int it = 0; it < 8; it++) {
                    int i = tid + it * 128;
                    int kk = i >> 5;
                    uint32_t h0 = pack_hi(br[it].x, br[it].y), h1 = pack_hi(br[it].z, br[it].w);
                    uint32_t* ph = (uint32_t*)(sm + OFF_BM(q) + kk * (LDB*2) + bcol[it] * 2);
                    ph[0] = h0; ph[1] = h1;
                }
                CPA_WAIT0();
                __syncthreads();
            }
            p = q;
        }
        __syncthreads();
    }

    // ---- epilogue ----
    const int r4 = lane >> 2, c2 = (lane & 3) * 2;
    if (MODE == 0) {
        #pragma unroll
        for (int mf = 0; mf < 2; mf++) {
            #pragma unroll
            for (int nf = 0; nf < 8; nf++) {
                int col = nb + wn * 64 + nf * 8 + c2;
                size_t r1 = (size_t)(m0 + wm * 32 + mf * 16 + r4);
                size_t r2 = r1 + 8;
                float v0 = acc[mf][nf][0], v1 = acc[mf][nf][1];
                float v2 = acc[mf][nf][2], v3 = acc[mf][nf][3];
                if (add) {
                    v0 += add[r1 * ldc + col]; v1 += add[r1 * ldc + col + 1];
                    v2 += add[r2 * ldc + col]; v3 += add[r2 * ldc + col + 1];
                }
                *(float2*)(C + r1 * ldc + col) = make_float2(v0, v1);
                *(float2*)(C + r2 * ldc + col) = make_float2(v2, v3);
            }
        }
    } else if (MODE == 1 || MODE == 2) {
        float* sG = (float*)sm;              // [64][65]
        if (wn == 0) {                        // gate cols 0..63
            #pragma unroll
            for (int mf = 0; mf < 2; mf++)
                #pragma unroll
                for (int nf = 0; nf < 8; nf++) {
                    int col = nf * 8 + c2;
                    int rr1 = wm * 32 + mf * 16 + r4, rr2 = rr1 + 8;
                    sG[rr1 * 65 + col]     = acc[mf][nf][0];
                    sG[rr1 * 65 + col + 1] = acc[mf][nf][1];
                    sG[rr2 * 65 + col]     = acc[mf][nf][2];
                    sG[rr2 * 65 + col + 1] = acc[mf][nf][3];
                }
        }
        __syncthreads();
        if (wn == 1) {                        // up cols -> combine
            #pragma unroll
            for (int mf = 0; mf < 2; mf++)
                #pragma unroll
                for (int nf = 0; nf < 8; nf++) {
                    int col = nf * 8 + c2;
                    int rr1 = wm * 32 + mf * 16 + r4;
                    #pragma unroll
                    for (int half = 0; half < 2; half++) {
                        int rr = rr1 + half * 8;
                        bool ok = (MODE == 1) || (m0 + rr < cnt);
                        if (ok) {
                            size_t row = (MODE == 1) ? (size_t)(m0 + rr) : (size_t)(off + m0 + rr);
                            float g0 = sG[rr * 65 + col], g1 = sG[rr * 65 + col + 1];
                            float u0 = acc[mf][nf][half * 2], u1 = acc[mf][nf][half * 2 + 1];
                            float o0 = g0 / (1.f + fexp(-g0)) * u0;
                            float o1 = g1 / (1.f + fexp(-g1)) * u1;
                            *(uint32_t*)(Ch + row * ldc + nb + col) = pack_hi(o0, o1);
                        }
                    }
                }
        }
    } else {  // MODE 3
        #pragma unroll
        for (int mf = 0; mf < 2; mf++) {
            int rr1 = wm * 32 + mf * 16 + r4;
            #pragma unroll
            for (int half = 0; half < 2; half++) {
                int rr = rr1 + half * 8;
                if (m0 + rr < cnt) {
                    int tok = g_ptok[off + m0 + rr];
                    float w = g_pw[off + m0 + rr];
                    float* dst = C + (size_t)tok * ldc;
                    #pragma unroll
                    for (int nf = 0; nf < 8; nf++) {
                        int col = nb + wn * 64 + nf * 8 + c2;
                        atomicAdd(dst + col,     w * acc[mf][nf][half * 2]);
                        atomicAdd(dst + col + 1, w * acc[mf][nf][half * 2 + 1]);
                    }
                }
            }
        }
    }
}

// ------------------------- small kernels ------------------------------------
__global__ void cs_prep_k(const int* __restrict__ pos) {
    int t = blockIdx.x, i = threadIdx.x;   // 64 threads
    if (t == 0 && i < NEXP) g_cnt[i] = 0;
    double e = exp(-((double)(2 * i) / 128.0) * log(500000.0));
    float f = (float)pos[t] * (float)e;
    float sn, cs; sincosf(f, &sn, &cs);
    g_cs[t * 64 + i] = make_float2(cs, sn);
}

// rmsnorm: writes optional fp32 y + bf16 yh (hi only)
__global__ void rmsnorm_k(const float* __restrict__ x, const float* __restrict__ w,
                          float* __restrict__ y, __nv_bfloat16* __restrict__ yh,
                          int cols, int ldx, int ldy)
{
    int row = blockIdx.x;
    const float* xr = x + (size_t)row * ldx;
    float ss = 0.f;
    for (int c = threadIdx.x; c < cols; c += 256) { float v = xr[c]; ss = fmaf(v, v, ss); }
    __shared__ float wred[8];
    #pragma unroll
    for (int d = 16; d; d >>= 1) ss += __shfl_xor_sync(0xffffffffu, ss, d);
    if ((threadIdx.x & 31) == 0) wred[threadIdx.x >> 5] = ss;
    __syncthreads();
    if (threadIdx.x < 32) {
        float v = (threadIdx.x < 8) ? wred[threadIdx.x] : 0.f;
        #pragma unroll
        for (int d = 4; d; d >>= 1) v += __shfl_xor_sync(0xffffffffu, v, d);
        if (threadIdx.x == 0) wred[0] = v;
    }
    __syncthreads();
    float r = rsqrtf(wred[0] / (float)cols + 1e-5f);
    for (int c = threadIdx.x; c < cols; c += 256) {
        float v = xr[c] * r * w[c];
        if (y) y[(size_t)row * ldy + c] = v;
        yh[(size_t)row * ldy + c] = __float2bfloat16_rn(v);
    }
}

// fused: Q rope (single bf16, SCALE folded) + K rope transpose (single) + V round
__global__ void qkv_prep_k(const float* __restrict__ qp, const float* __restrict__ qkv,
                           __nv_bfloat16* __restrict__ qh)
{
    int t = blockIdx.x;
    int tid = threadIdx.x;   // 256
    for (int idx = tid; idx < NHEAD * 64; idx += 256) {
        int hh = idx >> 6, i = idx & 63;
        float2 cs = g_cs[t * 64 + i];
        const float* b = qp + (size_t)t * 2048 + hh * HD;
        float x1 = b[i], x2 = b[i + 64];
        float y1 = (x1 * cs.x - x2 * cs.y) * SCALE;
        float y2 = (x2 * cs.x + x1 * cs.y) * SCALE;
        size_t o1 = (size_t)t * 2048 + hh * HD + i;
        qh[o1]      = __float2bfloat16_rn(y1);
        qh[o1 + 64] = __float2bfloat16_rn(y2);
    }
    if (tid < 64) {
        int i = tid;
        float2 cs = g_cs[t * 64 + i];
        const float* kb = qkv + (size_t)t * QKV_N + QDIM;
        float x1 = kb[i], x2 = kb[i + 64];
        float y1 = x1 * cs.x - x2 * cs.y;
        float y2 = x2 * cs.x + x1 * cs.y;
        g_kth[(size_t)i * SEQ + t]        = __float2bfloat16_rn(y1);
        g_kth[(size_t)(i + 64) * SEQ + t] = __float2bfloat16_rn(y2);
    }
    if (tid < 128) {
        float v = qkv[(size_t)t * QKV_N + QDIM + HD + tid];
        g_vh[(size_t)t * HD + tid] = __float2bfloat16_rn(v);
    }
}

// ------------------------- attention: FA2-style register-P -----------------
// 8 warps x 16 q-rows; QK 1-pass bf16; P in registers; V single bf16
#define AQ_LD 136
#define AK_LD 72
#define AV_LD 136
#define AOF_QH 0
#define AOF_KH 34816
#define AOF_VH 53248
#define ATTN_SMEM 70656

__global__ __launch_bounds__(256, 1) void attn_k(
    const __nv_bfloat16* __restrict__ Qh, __nv_bfloat16* __restrict__ Oh)
{
    extern __shared__ __align__(16) char sm[];
    const int bx = blockIdx.x;
    const int qt = 15 - (bx >> 4);     // longest tiles first
    const int h = bx & 15;
    const int q0 = qt * 128;

    const int tid = threadIdx.x;
    const int wid = tid >> 5, lane = tid & 31;
    const int lrow = lane & 15, lcol8 = (lane >> 4) * 8;
    const int r4 = lane >> 2, c2 = (lane & 3) * 2;
    const int mbase = wid * 16;        // this warp's q-row block

    const uint32_t uQh = s2u(sm + AOF_QH);
    const uint32_t uKh = s2u(sm + AOF_KH);
    const uint32_t uVh = s2u(sm + AOF_VH);

    // load Q tile (128 x 128, single bf16)
    #pragma unroll
    for (int it = 0; it < 8; it++) {
        int i = tid + it * 256;          // 2048 uint4
        int r = i >> 4, c = (i & 15) << 3;
        size_t src = (size_t)(q0 + r) * 2048 + h * HD + c;
        *(uint4*)(sm + AOF_QH + r * (AQ_LD*2) + c * 2) = *(const uint4*)(Qh + src);
    }

    float m0r = -3.0e30f, m1r = -3.0e30f;   // running max for rows r4, r4+8
    float l0r = 0.f, l1r = 0.f;             // running sum
    float o[16][4] = {};                     // 16 n8-tiles x 128 out cols
    const int nkt = 2 * qt + 2;

    for (int kt = 0; kt < nkt; kt++) {
        const int k0 = kt * 64;
        __syncthreads();
        // load K tile (transposed source [d][tok]): 128 x 64
        #pragma unroll
        for (int it = 0; it < 2; it++) {
            int i = tid + it * 256;      // 512 uint4
            int d = i >> 2, tc = (i & 3) << 4;
            size_t src = (size_t)d * SEQ + k0 + tc;
            *(uint4*)(sm + AOF_KH + d * (AK_LD*2) + tc * 2) = *(const uint4*)(g_kth + src);
            *(uint4*)(sm + AOF_KH + d * (AK_LD*2) + tc * 2 + 16) = *(const uint4*)(g_kth + src + 8);
        }
        // load V tile: 64 x 128 (single bf16)
        #pragma unroll
        for (int it = 0; it < 2; it++) {
            int i = tid + it * 256;
            int r = i >> 4, c = (i & 15) << 3;
            size_t src = (size_t)(k0 + r * 2) * HD + c;
            *(uint4*)(sm + AOF_VH + (r * 2) * (AV_LD*2) + c * 2) = *(const uint4*)(g_vh + src);
            *(uint4*)(sm + AOF_VH + (r * 2 + 1) * (AV_LD*2) + c * 2) =
                *(const uint4*)(g_vh + src + HD);
        }
        __syncthreads();

        // ---- S = Q K^T (1-pass): warp computes 16 rows x 64 cols ----
        float sacc[8][4] = {};
        #pragma unroll
        for (int ks = 0; ks < 8; ks++) {
            uint32_t ah[4];
            uint32_t roA = (uint32_t)((mbase + lrow) * AQ_LD + ks * 16 + lcol8) * 2;
            ldsm4(ah, uQh + roA);
            #pragma unroll
            for (int nh = 0; nh < 4; nh++) {
                uint32_t bh[4];
                uint32_t ro = (uint32_t)((ks * 16 + lrow) * AK_LD + nh * 16 + lcol8) * 2;
                ldsm4t(bh, uKh + ro);
                mma16816(sacc[nh * 2],     ah, bh[0], bh[1]);
                mma16816(sacc[nh * 2 + 1], ah, bh[2], bh[3]);
            }
        }

        // causal mask on diagonal tiles
        if (kt >= nkt - 2) {
            #pragma unroll
            for (int nf = 0; nf < 8; nf++)
                #pragma unroll
                for (int v = 0; v < 4; v++) {
                    int row = q0 + mbase + r4 + (v >= 2 ? 8 : 0);
                    int col = k0 + nf * 8 + c2 + (v & 1);
                    if (col > row) sacc[nf][v] = -1.0e30f;
                }
        }

        // ---- warp-local row max ----
        float rx0 = -3.0e30f, rx1 = -3.0e30f;
        #pragma unroll
        for (int nf = 0; nf < 8; nf++) {
            rx0 = fmaxf(rx0, fmaxf(sacc[nf][0], sacc[nf][1]));
            rx1 = fmaxf(rx1, fmaxf(sacc[nf][2], sacc[nf][3]));
        }
        rx0 = fmaxf(rx0, __shfl_xor_sync(0xffffffffu, rx0, 1));
        rx0 = fmaxf(rx0, __shfl_xor_sync(0xffffffffu, rx0, 2));
        rx1 = fmaxf(rx1, __shfl_xor_sync(0xffffffffu, rx1, 1));
        rx1 = fmaxf(rx1, __shfl_xor_sync(0xffffffffu, rx1, 2));
        float mn0 = fmaxf(m0r, rx0), mn1 = fmaxf(m1r, rx1);
        float f0 = fexp(m0r - mn0), f1 = fexp(m1r - mn1);

        // ---- p = exp(s-mn) -> pack directly into PV A-fragments ----
        uint32_t pk[4][4];   // 4 k16 fragments covering k=64
        float rs0 = 0.f, rs1 = 0.f;
        #pragma unroll
        for (int kf = 0; kf < 4; kf++) {
            #pragma unroll
            for (int half = 0; half < 2; half++) {
                int nf = kf * 2 + half;
                float p0 = fexp(sacc[nf][0] - mn0);
                float p1 = fexp(sacc[nf][1] - mn0);
                float p2 = fexp(sacc[nf][2] - mn1);
                float p3 = fexp(sacc[nf][3] - mn1);
                rs0 += p0 + p1;
                rs1 += p2 + p3;
                pk[kf][half * 2]     = pack_hi(p0, p1);
                pk[kf][half * 2 + 1] = pack_hi(p2, p3);
            }
        }
        rs0 += __shfl_xor_sync(0xffffffffu, rs0, 1);
        rs0 += __shfl_xor_sync(0xffffffffu, rs0, 2);
        rs1 += __shfl_xor_sync(0xffffffffu, rs1, 1);
        rs1 += __shfl_xor_sync(0xffffffffu, rs1, 2);
        l0r = l0r * f0 + rs0;
        l1r = l1r * f1 + rs1;
        m0r = mn0; m1r = mn1;

        // rescale o
        #pragma unroll
        for (int nf = 0; nf < 16; nf++) {
            o[nf][0] *= f0; o[nf][1] *= f0;
            o[nf][2] *= f1; o[nf][3] *= f1;
        }

        // ---- O += P V (P in regs, V single bf16) ----
        #pragma unroll
        for (int ks2 = 0; ks2 < 4; ks2++) {
            #pragma unroll
            for (int nh = 0; nh < 8; nh++) {
                uint32_t bv[4];
                uint32_t ro = (uint32_t)((ks2 * 16 + lrow) * AV_LD + nh * 16 + lcol8) * 2;
                ldsm4t(bv, uVh + ro);
                mma16816(o[nh * 2],     pk[ks2], bv[0], bv[1]);
                mma16816(o[nh * 2 + 1], pk[ks2], bv[2], bv[3]);
            }
        }
    }

    // ---- write O (hi bf16) ----
    float inv0 = 1.f / l0r, inv1 = 1.f / l1r;
    int row0 = q0 + mbase + r4;
    #pragma unroll
    for (int nf = 0; nf < 16; nf++) {
        int col = h * HD + nf * 8 + c2;
        *(uint32_t*)(Oh + (size_t)row0 * 2048 + col) = pack_hi(o[nf][0] * inv0, o[nf][1] * inv0);
        *(uint32_t*)(Oh + (size_t)(row0 + 8) * 2048 + col) = pack_hi(o[nf][2] * inv1, o[nf][3] * inv1);
    }
}

// ------------------------- router / topk / scan / fill ---------------------
__global__ __launch_bounds__(256) void router_k(const float* __restrict__ X,
                                                const float* __restrict__ Wr)
{
    __shared__ float part[8][32];
    int t = blockIdx.x;
    int e = threadIdx.x & 31, p = threadIdx.x >> 5;
    const float* xr = X + (size_t)t * HID;
    float s = 0.f;
    for (int k = p * 128; k < p * 128 + 128; k++) s = fmaf(xr[k], Wr[k * 32 + e], s);
    part[p][e] = s;
    __syncthreads();
    if (threadIdx.x < 32) {
        float logit = 0.f;
        #pragma unroll
        for (int q = 0; q < 8; q++) logit += part[q][e];
        float m = logit;
        for (int d = 16; d; d >>= 1) m = fmaxf(m, __shfl_xor_sync(0xffffffffu, m, d));
        float ex = __expf(logit - m);
        float cur = ex;
        float wsel[3]; int isel[3];
        #pragma unroll
        for (int kk = 0; kk < 3; kk++) {
            float v = cur; int idx = e;
            for (int d = 16; d; d >>= 1) {
                float v2 = __shfl_xor_sync(0xffffffffu, v, d);
                int   i2 = __shfl_xor_sync(0xffffffffu, idx, d);
                if (v2 > v || (v2 == v && i2 < idx)) { v = v2; idx = i2; }
            }
            wsel[kk] = v; isel[kk] = idx;
            if (e == idx) cur = -1.f;
        }
        float tot = wsel[0] + wsel[1] + wsel[2];
        if (e < 3) { g_topi[t * 3 + e] = isel[e]; g_topw[t * 3 + e] = wsel[e] / tot; }
        if (e == 0) {
            atomicAdd(&g_cnt[isel[0]], 1);
            atomicAdd(&g_cnt[isel[1]], 1);
            atomicAdd(&g_cnt[isel[2]], 1);
        }
    }
}

__global__ void scan_k()
{
    int e = threadIdx.x;
    int c = g_cnt[e];
    int x = c;
    for (int d = 1; d < 32; d <<= 1) {
        int y = __shfl_up_sync(0xffffffffu, x, d);
        if (e >= d) x += y;
    }
    int excl = x - c;
    g_off[e] = excl;
    g_fill[e] = excl;
}

__global__ void fill_k()
{
    int t = blockIdx.x * 256 + threadIdx.x;
    if (t < SEQ) {
        #pragma unroll
        for (int k = 0; k < 3; k++) {
            int e = g_topi[t * 3 + k];
            int slot = atomicAdd(&g_fill[e], 1);
            g_ptok[slot] = t;
            g_pw[slot] = g_topw[t * 3 + k];
        }
    }
}

// ------------------------- launch ------------------------------------------
extern "C" void kernel_launch(void* const* d_in, const int* in_sizes, int n_in,
                              void* d_out, int out_size)
{
    const float* hidden   = (const float*)d_in[0];
    const float* w_in     = (const float*)d_in[1];
    const float* w_qkv    = (const float*)d_in[2];
    const float* w_inter  = (const float*)d_in[3];
    const float* w_q      = (const float*)d_in[4];
    const float* w_o      = (const float*)d_in[5];
    const float* w_post   = (const float*)d_in[6];
    const float* w_guse   = (const float*)d_in[7];
    const float* w_dse    = (const float*)d_in[8];
    const float* w_router = (const float*)d_in[9];
    const float* w_gue    = (const float*)d_in[10];
    const float* w_de     = (const float*)d_in[11];
    const int*   pos      = (const int*)d_in[12];
    float* out = (float*)d_out;

    float *qkv, *qproj, *resid2, *h2;
    cudaGetSymbolAddress((void**)&qkv,    g_qkv);
    cudaGetSymbolAddress((void**)&qproj,  g_qproj);
    cudaGetSymbolAddress((void**)&resid2, g_resid2);
    cudaGetSymbolAddress((void**)&h2,     g_h2);
    __nv_bfloat16 *hnh,*qnh,*qh,*aoh,*h2h,*aseh,*aceh;
    __nv_bfloat16 *wqkvh,*wqh,*woh,*wguh,*wdh;
    cudaGetSymbolAddress((void**)&hnh, g_hnh);
    cudaGetSymbolAddress((void**)&qnh, g_qnh);
    cudaGetSymbolAddress((void**)&qh,  g_qh);
    cudaGetSymbolAddress((void**)&aoh, g_aoh);
    cudaGetSymbolAddress((void**)&h2h, g_h2h);
    cudaGetSymbolAddress((void**)&aseh,g_aseh);
    cudaGetSymbolAddress((void**)&aceh,g_aceh);
    cudaGetSymbolAddress((void**)&wqkvh,g_wqkvh);
    cudaGetSymbolAddress((void**)&wqh, g_wqh);
    cudaGetSymbolAddress((void**)&woh, g_woh);
    cudaGetSymbolAddress((void**)&wguh,g_wguh);
    cudaGetSymbolAddress((void**)&wdh, g_wdh);

    cudaFuncSetAttribute(attn_k, cudaFuncAttributeMaxDynamicSharedMemorySize, ATTN_SMEM);
    cudaFuncSetAttribute((gemm_tc<0,1>), cudaFuncAttributeMaxDynamicSharedMemorySize, SMEM_DENSE);
    cudaFuncSetAttribute((gemm_tc<1,1>), cudaFuncAttributeMaxDynamicSharedMemorySize, SMEM_DENSE);
    cudaFuncSetAttribute((gemm_tc<2,0>), cudaFuncAttributeMaxDynamicSharedMemorySize, SMEM_MOE);
    cudaFuncSetAttribute((gemm_tc<3,0>), cudaFuncAttributeMaxDynamicSharedMemorySize, SMEM_MOE);

    cs_prep_k<<<SEQ, 64>>>(pos);
    split_all_k<<<(SPL4 + 255)/256, 256>>>(w_qkv, w_q, w_o, w_guse, w_dse);

    rmsnorm_k<<<SEQ, 256>>>(hidden, w_in, nullptr, hnh, HID, HID, HID);
    gemm_tc<0,1><<<dim3(QKV_N/128, SEQ/64), 128, SMEM_DENSE>>>(
        hnh, wqkvh, qkv, nullptr, nullptr, HID, HID, QKV_N, QKV_N, 0, 0);
    rmsnorm_k<<<SEQ, 256>>>(qkv, w_inter, nullptr, qnh, QDIM, QKV_N, QDIM);
    gemm_tc<0,1><<<dim3(2048/128, SEQ/64), 128, SMEM_DENSE>>>(
        qnh, wqh, qproj, nullptr, nullptr, QDIM, QDIM, 2048, 2048, 0, 0);
    qkv_prep_k<<<SEQ, 256>>>(qproj, qkv, qh);
    attn_k<<<256, 256, ATTN_SMEM>>>(qh, aoh);
    gemm_tc<0,1><<<dim3(HID/128, SEQ/64), 128, SMEM_DENSE>>>(
        aoh, woh, resid2, nullptr, hidden, 2048, 2048, HID, HID, 0, 0);
    rmsnorm_k<<<SEQ, 256>>>(resid2, w_post, h2, h2h, HID, HID, HID);
    gemm_tc<1,1><<<dim3(IDIM/64, SEQ/64), 128, SMEM_DENSE>>>(
        h2h, wguh, nullptr, aseh, nullptr, HID, HID, 2*IDIM, IDIM, IDIM, 0);
    gemm_tc<0,1><<<dim3(HID/128, SEQ/64), 128, SMEM_DENSE>>>(
        aseh, wdh, out, nullptr, resid2, IDIM, IDIM, HID, HID, 0, 0);
    router_k<<<SEQ, 256>>>(h2, w_router);
    scan_k<<<1, 32>>>();
    fill_k<<<SEQ/256, 256>>>();
    gemm_tc<2,0><<<dim3(IDIM/64, 32, NEXP), 128, SMEM_MOE>>>(
        h2h, w_gue, nullptr, aceh, nullptr, HID, HID, 2*IDIM, IDIM, IDIM,
        (size_t)HID * 2 * IDIM);
    gemm_tc<3,0><<<dim3(HID/128, 32, NEXP), 128, SMEM_MOE>>>(
        aceh, w_de, out, nullptr, nullptr, IDIM, IDIM, HID, HID, 0,
        (size_t)IDIM * HID);
}